// round 2
// baseline (speedup 1.0000x reference)
#include <cuda_runtime.h>
#include <math.h>

#define TT 16
#define CCH 64
#define HHH 48
#define WWI 48
#define HWSZ 2304
#define THWSZ 36864
#define WW2 24
#define SS 576
#define RCC 4
#define NSB 9   // s-blocks of 64 in gemm1

// ---------------- scratch (device globals; no allocations) ----------------
static __device__ float g_x2[CCH * THWSZ];            // [c][t][h][w]
static __device__ float g_off[2 * TT * 2 * SS];       // [branch][t][o][s]
static __device__ float g_part_cs[2][TT * CCH * SS];  // [branch][t][c][s]
static __device__ float g_part_sc[2][TT * SS * CCH];  // [branch][t][s][c]
static __device__ float g_aff[TT * SS * HWSZ];        // [t][s][hw] (reused per branch)
static __device__ float g_psum[TT * NSB * HWSZ];      // partial stats [t][sblk][hw]
static __device__ float g_psq [TT * NSB * HWSZ];
static __device__ float g_pmax[TT * NSB * HWSZ];
static __device__ float g_mean[TT * HWSZ];
static __device__ float g_maxv[TT * HWSZ];
static __device__ float g_varv[TT * HWSZ];
static __device__ float g_yv[TT * HWSZ];
static __device__ float g_feat[TT * HWSZ * CCH];      // [t][hw][c]
static __device__ float g_xd[RCC * THWSZ];
static __device__ float g_agg[RCC * THWSZ];

__device__ __forceinline__ float sigm(float v) { return 1.0f / (1.0f + __expf(-v)); }

// ---------------- x2 = w_dc2 @ x  (64x64 channel GEMM over 36864 positions) --
__global__ void k_x2(const float* __restrict__ x, const float* __restrict__ w) {
    __shared__ float Ws[64][64];  // Ws[c][o]
    __shared__ float Xs[64][64];  // Xs[c][pos]
    int tid = threadIdx.x;
    int pos0 = blockIdx.x * 64;
    for (int i = tid; i < 4096; i += 256) {
        int o = i >> 6, c = i & 63;
        Ws[c][o] = w[i];
    }
    int lr = tid >> 4, lc4 = (tid & 15) * 4;
#pragma unroll
    for (int v = 0; v < 4; v++) {
        int c = lr + v * 16;
        *(float4*)&Xs[c][lc4] = *(const float4*)&x[c * THWSZ + pos0 + lc4];
    }
    __syncthreads();
    int ty = tid >> 4, tx = tid & 15;
    float acc[4][4] = {};
#pragma unroll
    for (int k = 0; k < 64; k++) {
        float4 a = *(float4*)&Ws[k][ty * 4];
        float4 b = *(float4*)&Xs[k][tx * 4];
        float av[4] = {a.x, a.y, a.z, a.w};
        float bv[4] = {b.x, b.y, b.z, b.w};
#pragma unroll
        for (int i = 0; i < 4; i++)
#pragma unroll
            for (int j = 0; j < 4; j++) acc[i][j] = fmaf(av[i], bv[j], acc[i][j]);
    }
#pragma unroll
    for (int i = 0; i < 4; i++) {
        float4 o4 = make_float4(acc[i][0], acc[i][1], acc[i][2], acc[i][3]);
        *(float4*)&g_x2[(ty * 4 + i) * THWSZ + pos0 + tx * 4] = o4;
    }
}

// ---------------- offset convs: stride-2 3x3 over (x + shifted x2) ----------
__global__ void k_off(const float* __restrict__ x,
                      const float* __restrict__ wl, const float* __restrict__ bl,
                      const float* __restrict__ wr, const float* __restrict__ br_) {
    int idx = blockIdx.x * blockDim.x + threadIdx.x;
    if (idx >= 2 * TT * 2 * SS) return;
    int branch = idx / (TT * 2 * SS);
    int r = idx % (TT * 2 * SS);
    int t = r / (2 * SS);
    int o = (r / SS) & 1;
    int s = r % SS;
    int i = s / WW2, j = s % WW2;
    int tsrc = (branch == 0) ? min(t + 1, TT - 1) : max(t - 1, 0);
    const float* wofs = (branch == 0) ? wl : wr;
    float acc = (branch == 0) ? bl[o] : br_[o];
    for (int c = 0; c < CCH; c++) {
        const float* xp = x + c * THWSZ + t * HWSZ;
        const float* x2p = g_x2 + c * THWSZ + tsrc * HWSZ;
        const float* wp = wofs + (o * CCH + c) * 9;
#pragma unroll
        for (int ki = 0; ki < 3; ki++) {
            int h = 2 * i - 1 + ki;
            if (h < 0 || h >= HHH) continue;
#pragma unroll
            for (int kj = 0; kj < 3; kj++) {
                int w = 2 * j - 1 + kj;
                if (w < 0 || w >= WWI) continue;
                acc = fmaf(xp[h * WWI + w] + x2p[h * WWI + w], wp[ki * 3 + kj], acc);
            }
        }
    }
    g_off[idx] = acc;
}

// ---------------- bilinear grid-sample of shifted x2 ------------------------
__global__ void k_sample() {
    int idx = blockIdx.x * blockDim.x + threadIdx.x;
    if (idx >= 2 * TT * SS) return;
    int branch = idx / (TT * SS);
    int t = (idx % (TT * SS)) / SS;
    int s = idx % SS;
    int i = s / WW2, j = s % WW2;
    float off0 = g_off[((branch * TT + t) * 2 + 0) * SS + s];
    float off1 = g_off[((branch * TT + t) * 2 + 1) * SS + s];
    float v0 = 2.0f * (float)j + off0;
    float v1 = 2.0f * (float)i + off1;
    float gh = 2.0f * v0 / 23.0f - 1.0f;
    float gw = 2.0f * v1 / 23.0f - 1.0f;
    float xs = ((gh + 1.0f) * 48.0f - 1.0f) * 0.5f;
    float ys = ((gw + 1.0f) * 48.0f - 1.0f) * 0.5f;
    float x0f = floorf(xs), y0f = floorf(ys);
    int x0 = (int)x0f, y0 = (int)y0f;
    float fx = xs - x0f, fy = ys - y0f;
    float wgt[4] = {(1.0f - fx) * (1.0f - fy), fx * (1.0f - fy),
                    (1.0f - fx) * fy, fx * fy};
    int xi[4] = {x0, x0 + 1, x0, x0 + 1};
    int yi[4] = {y0, y0, y0 + 1, y0 + 1};
    float wv[4];
    int id[4];
#pragma unroll
    for (int k = 0; k < 4; k++) {
        bool valid = (xi[k] >= 0) && (xi[k] < WWI) && (yi[k] >= 0) && (yi[k] < HHH);
        wv[k] = valid ? wgt[k] : 0.0f;
        int cy = min(max(yi[k], 0), HHH - 1);
        int cx = min(max(xi[k], 0), WWI - 1);
        id[k] = cy * WWI + cx;
    }
    int tsrc = (branch == 0) ? min(t + 1, TT - 1) : max(t - 1, 0);
    for (int c = 0; c < CCH; c++) {
        const float* img = g_x2 + c * THWSZ + tsrc * HWSZ;
        float val = wv[0] * img[id[0]] + wv[1] * img[id[1]] +
                    wv[2] * img[id[2]] + wv[3] * img[id[3]];
        g_part_cs[branch][(t * CCH + c) * SS + s] = val;
        g_part_sc[branch][(t * SS + s) * CCH + c] = val;
    }
}

// ---------------- GEMM1 (64s x 128hw tiles, 8x8 micro) + fused stats partials
__global__ void __launch_bounds__(128) k_gemm1(const float* __restrict__ x, int branch) {
    __shared__ float Ps[64][64];   // [k(c)][s]   16KB
    __shared__ float Xs[64][128];  // [k(c)][hw]  32KB
    int t = blockIdx.z;
    int hw0 = blockIdx.x * 128;
    int sblk = blockIdx.y;
    int s0 = sblk * 64;
    const float* P = g_part_cs[branch];
    int tid = threadIdx.x;
    int tx = tid & 15, ty = tid >> 4;  // tx: hw dir, ty: s dir

    // fill Ps: 4096 floats, 8 float4/thread
#pragma unroll
    for (int v = 0; v < 8; v++) {
        int row = v * 8 + (tid >> 4);
        int col = (tid & 15) * 4;
        *(float4*)&Ps[row][col] = *(const float4*)&P[(t * CCH + row) * SS + s0 + col];
    }
    // fill Xs: 8192 floats, 16 float4/thread
#pragma unroll
    for (int v = 0; v < 16; v++) {
        int row = v * 4 + (tid >> 5);
        int col = (tid & 31) * 4;
        *(float4*)&Xs[row][col] = *(const float4*)&x[row * THWSZ + t * HWSZ + hw0 + col];
    }
    __syncthreads();

    float acc[8][8];
#pragma unroll
    for (int i = 0; i < 8; i++)
#pragma unroll
        for (int j = 0; j < 8; j++) acc[i][j] = 0.0f;

#pragma unroll 4
    for (int k = 0; k < 64; k++) {
        float4 a0 = *(float4*)&Ps[k][ty * 8];
        float4 a1 = *(float4*)&Ps[k][ty * 8 + 4];
        float4 b0 = *(float4*)&Xs[k][tx * 4];
        float4 b1 = *(float4*)&Xs[k][64 + tx * 4];
        float av[8] = {a0.x, a0.y, a0.z, a0.w, a1.x, a1.y, a1.z, a1.w};
        float bv[8] = {b0.x, b0.y, b0.z, b0.w, b1.x, b1.y, b1.z, b1.w};
#pragma unroll
        for (int i = 0; i < 8; i++)
#pragma unroll
            for (int j = 0; j < 8; j++) acc[i][j] = fmaf(av[i], bv[j], acc[i][j]);
    }

    // store aff
#pragma unroll
    for (int i = 0; i < 8; i++) {
        int s_g = s0 + ty * 8 + i;
        float4 o0 = make_float4(acc[i][0], acc[i][1], acc[i][2], acc[i][3]);
        float4 o1 = make_float4(acc[i][4], acc[i][5], acc[i][6], acc[i][7]);
        float* dst = &g_aff[(t * SS + s_g) * HWSZ + hw0];
        *(float4*)&dst[tx * 4] = o0;
        *(float4*)&dst[64 + tx * 4] = o1;
    }

    // fused stats partials over this block's 64 s, per hw column
    __syncthreads();  // everyone done reading Ps
    float* red = &Ps[0][0];  // reuse 16KB: [3][8(ty)][128(hw)]
#pragma unroll
    for (int j = 0; j < 8; j++) {
        int hwl = (j < 4) ? (tx * 4 + j) : (64 + tx * 4 + j - 4);
        float sum = 0.0f, sq = 0.0f, mx = -3.4e38f;
#pragma unroll
        for (int i = 0; i < 8; i++) {
            float v = acc[i][j];
            sum += v;
            sq = fmaf(v, v, sq);
            mx = fmaxf(mx, v);
        }
        red[ty * 128 + hwl] = sum;
        red[1024 + ty * 128 + hwl] = sq;
        red[2048 + ty * 128 + hwl] = mx;
    }
    __syncthreads();
    {
        int hwl = tid;  // 128 threads, one hw each
        float sum = 0.0f, sq = 0.0f, mx = -3.4e38f;
#pragma unroll
        for (int r = 0; r < 8; r++) {
            sum += red[r * 128 + hwl];
            sq += red[1024 + r * 128 + hwl];
            mx = fmaxf(mx, red[2048 + r * 128 + hwl]);
        }
        int o = (t * NSB + sblk) * HWSZ + hw0 + hwl;
        g_psum[o] = sum;
        g_psq[o] = sq;
        g_pmax[o] = mx;
    }
}

// ---------------- stats phase2: combine 9 partials ---------------------------
__global__ void k_stats2() {
    int idx = blockIdx.x * 256 + threadIdx.x;
    if (idx >= TT * HWSZ) return;
    int t = idx / HWSZ;
    int hw = idx % HWSZ;
    float sum = 0.0f, sq = 0.0f, mx = -3.4e38f;
#pragma unroll
    for (int b = 0; b < NSB; b++) {
        int o = (t * NSB + b) * HWSZ + hw;
        sum += g_psum[o];
        sq += g_psq[o];
        mx = fmaxf(mx, g_pmax[o]);
    }
    g_mean[idx] = sum / 576.0f;
    g_maxv[idx] = mx;
    g_varv[idx] = (sq - sum * sum / 576.0f) / 575.0f;
}

// ---------------- attention gate: y = sigmoid(conv3x3([avg,mx]) + conv3x3(var))
__global__ void k_y(const float* __restrict__ w1, const float* __restrict__ w2) {
    int idx = blockIdx.x * 256 + threadIdx.x;
    if (idx >= TT * HWSZ) return;
    int t = idx / HWSZ;
    int hw = idx % HWSZ;
    int h = hw / WWI, w = hw % WWI;
    float acc = 0.0f;
#pragma unroll
    for (int dh = 0; dh < 3; dh++) {
        int hh = h + dh - 1;
        if (hh < 0 || hh >= HHH) continue;
#pragma unroll
        for (int dw = 0; dw < 3; dw++) {
            int ww = w + dw - 1;
            if (ww < 0 || ww >= WWI) continue;
            int p = t * HWSZ + hh * WWI + ww;
            acc = fmaf(w1[(0 * 3 + dh) * 3 + dw], g_mean[p], acc);
            acc = fmaf(w1[(3 + dh) * 3 + dw], g_maxv[p], acc);
            acc = fmaf(w2[dh * 3 + dw], g_varv[p], acc);
        }
    }
    g_yv[idx] = sigm(acc);
}

// ---------------- GEMM2 (128hw x 64c tiles, K=576, 8x8 micro) ----------------
__global__ void __launch_bounds__(128) k_gemm2(int branch, const float* __restrict__ w2s, int accum) {
    __shared__ float Gs[64][128];   // [k(s)][hw] 32KB
    __shared__ float Bs[64][64];    // [k(s)][c]  16KB
    int t = blockIdx.y;
    int hw0 = blockIdx.x * 128;
    const float* Psc = g_part_sc[branch];
    float wscale = w2s[branch];
    int tid = threadIdx.x;
    int tx = tid & 15, ty = tid >> 4;  // tx: hw dir (8), ty: c dir (8)

    float acc[8][8];
#pragma unroll
    for (int i = 0; i < 8; i++)
#pragma unroll
        for (int j = 0; j < 8; j++) acc[i][j] = 0.0f;

    for (int k0 = 0; k0 < SS; k0 += 64) {
        __syncthreads();
        // fill Bs: 4096 floats
#pragma unroll
        for (int v = 0; v < 8; v++) {
            int row = v * 8 + (tid >> 4);
            int col = (tid & 15) * 4;
            *(float4*)&Bs[row][col] = *(const float4*)&Psc[(t * SS + k0 + row) * CCH + col];
        }
        // fill Gs with sigmoid transform: 8192 floats
#pragma unroll
        for (int v = 0; v < 16; v++) {
            int row = v * 4 + (tid >> 5);
            int col = (tid & 31) * 4;
            float4 a = *(const float4*)&g_aff[(t * SS + k0 + row) * HWSZ + hw0 + col];
            float4 yv = *(const float4*)&g_yv[t * HWSZ + hw0 + col];
            float4 g;
            g.x = sigm(yv.x * a.x) - 0.5f;
            g.y = sigm(yv.y * a.y) - 0.5f;
            g.z = sigm(yv.z * a.z) - 0.5f;
            g.w = sigm(yv.w * a.w) - 0.5f;
            *(float4*)&Gs[row][col] = g;
        }
        __syncthreads();
#pragma unroll 4
        for (int k = 0; k < 64; k++) {
            float4 a0 = *(float4*)&Gs[k][tx * 4];
            float4 a1 = *(float4*)&Gs[k][64 + tx * 4];
            float4 b0 = *(float4*)&Bs[k][ty * 8];
            float4 b1 = *(float4*)&Bs[k][ty * 8 + 4];
            float av[8] = {a0.x, a0.y, a0.z, a0.w, a1.x, a1.y, a1.z, a1.w};
            float bv[8] = {b0.x, b0.y, b0.z, b0.w, b1.x, b1.y, b1.z, b1.w};
#pragma unroll
            for (int i = 0; i < 8; i++)
#pragma unroll
                for (int j = 0; j < 8; j++) acc[i][j] = fmaf(av[i], bv[j], acc[i][j]);
        }
    }

#pragma unroll
    for (int i = 0; i < 8; i++) {
        int hw_g = hw0 + ((i < 4) ? (tx * 4 + i) : (64 + tx * 4 + i - 4));
        float* dst = &g_feat[(t * HWSZ + hw_g) * CCH + ty * 8];
        float4 o0 = make_float4(wscale * acc[i][0], wscale * acc[i][1],
                                wscale * acc[i][2], wscale * acc[i][3]);
        float4 o1 = make_float4(wscale * acc[i][4], wscale * acc[i][5],
                                wscale * acc[i][6], wscale * acc[i][7]);
        if (accum) {
            float4 p0 = *(float4*)dst;
            float4 p1 = *(float4*)&dst[4];
            o0.x += p0.x; o0.y += p0.y; o0.z += p0.z; o0.w += p0.w;
            o1.x += p1.x; o1.y += p1.y; o1.z += p1.z; o1.w += p1.w;
        }
        *(float4*)dst = o0;
        *(float4*)&dst[4] = o1;
    }
}

// ---------------- xd = w_down @ x -------------------------------------------
__global__ void k_xd(const float* __restrict__ x, const float* __restrict__ wd) {
    int idx = blockIdx.x * blockDim.x + threadIdx.x;
    if (idx >= RCC * THWSZ) return;
    int r = idx / THWSZ, pos = idx % THWSZ;
    float acc = 0.0f;
    for (int c = 0; c < CCH; c++) acc = fmaf(wd[r * CCH + c], x[c * THWSZ + pos], acc);
    g_xd[idx] = acc;
}

// ---------------- 3x depthwise 3D convs, weighted sum -----------------------
__global__ void k_agg(const float* __restrict__ w1, const float* __restrict__ b1,
                      const float* __restrict__ w2, const float* __restrict__ b2,
                      const float* __restrict__ w3, const float* __restrict__ b3,
                      const float* __restrict__ wts) {
    int idx = blockIdx.x * blockDim.x + threadIdx.x;
    if (idx >= RCC * THWSZ) return;
    int r = idx / THWSZ;
    int rem = idx % THWSZ;
    int t = rem / HWSZ;
    int hw = rem % HWSZ;
    int h = hw / WWI, w = hw % WWI;
    const float* xb = g_xd + r * THWSZ;
    const float* ws_[3] = {w1, w2, w3};
    const float* bs_[3] = {b1, b2, b3};
    float total = 0.0f;
#pragma unroll
    for (int m = 0; m < 3; m++) {
        int d = m + 1;
        float cs = bs_[m][r];
        const float* wp = ws_[m] + r * 81;
        for (int kt = 0; kt < 9; kt++) {
            int ti = t + kt - 4;
            if (ti < 0 || ti >= TT) continue;
#pragma unroll
            for (int kh = 0; kh < 3; kh++) {
                int hi = h + (kh - 1) * d;
                if (hi < 0 || hi >= HHH) continue;
#pragma unroll
                for (int kw = 0; kw < 3; kw++) {
                    int wi = w + (kw - 1) * d;
                    if (wi < 0 || wi >= WWI) continue;
                    cs = fmaf(xb[ti * HWSZ + hi * WWI + wi], wp[(kt * 3 + kh) * 3 + kw], cs);
                }
            }
        }
        total = fmaf(wts[m], cs, total);
    }
    g_agg[idx] = total;
}

// ---------------- final: out = feat * (sigmoid(w_back@agg) - 0.5) -----------
__global__ void k_final(float* __restrict__ out, const float* __restrict__ wback) {
    int pos = blockIdx.x * 256 + threadIdx.x;
    if (pos >= THWSZ) return;
    float ag0 = g_agg[pos];
    float ag1 = g_agg[THWSZ + pos];
    float ag2 = g_agg[2 * THWSZ + pos];
    float ag3 = g_agg[3 * THWSZ + pos];
    const float* f = &g_feat[pos * CCH];
    for (int c = 0; c < CCH; c++) {
        float z = wback[c * 4 + 0] * ag0 + wback[c * 4 + 1] * ag1 +
                  wback[c * 4 + 2] * ag2 + wback[c * 4 + 3] * ag3;
        out[c * THWSZ + pos] = f[c] * (sigm(z) - 0.5f);
    }
}

extern "C" void kernel_launch(void* const* d_in, const int* in_sizes, int n_in,
                              void* d_out, int out_size) {
    const float* x       = (const float*)d_in[0];
    const float* w_dc2   = (const float*)d_in[1];
    const float* w_ofs_l = (const float*)d_in[2];
    const float* b_ofs_l = (const float*)d_in[3];
    const float* w_ofs_r = (const float*)d_in[4];
    const float* b_ofs_r = (const float*)d_in[5];
    const float* ca_w1   = (const float*)d_in[6];
    const float* ca_w2   = (const float*)d_in[7];
    const float* w_down  = (const float*)d_in[8];
    const float* sa1_w   = (const float*)d_in[9];
    const float* sa1_b   = (const float*)d_in[10];
    const float* sa2_w   = (const float*)d_in[11];
    const float* sa2_b   = (const float*)d_in[12];
    const float* sa3_w   = (const float*)d_in[13];
    const float* sa3_b   = (const float*)d_in[14];
    const float* weights = (const float*)d_in[15];
    const float* weights2= (const float*)d_in[16];
    const float* w_back  = (const float*)d_in[17];
    float* out = (float*)d_out;

    k_x2<<<THWSZ / 64, 256>>>(x, w_dc2);
    k_off<<<(2 * TT * 2 * SS + 255) / 256, 256>>>(x, w_ofs_l, b_ofs_l, w_ofs_r, b_ofs_r);
    k_sample<<<(2 * TT * SS + 255) / 256, 256>>>();

    for (int br = 0; br < 2; br++) {
        dim3 g1(HWSZ / 128, NSB, TT);
        k_gemm1<<<g1, 128>>>(x, br);
        k_stats2<<<(TT * HWSZ + 255) / 256, 256>>>();
        k_y<<<(TT * HWSZ + 255) / 256, 256>>>(ca_w1, ca_w2);
        dim3 g2(HWSZ / 128, TT);
        k_gemm2<<<g2, 128>>>(br, weights2, br);
    }

    k_xd<<<(RCC * THWSZ + 255) / 256, 256>>>(x, w_down);
    k_agg<<<(RCC * THWSZ + 255) / 256, 256>>>(sa1_w, sa1_b, sa2_w, sa2_b, sa3_w, sa3_b, weights);
    k_final<<<(THWSZ + 255) / 256, 256>>>(out, w_back);
}

// round 3
// speedup vs baseline: 1.1952x; 1.1952x over previous
#include <cuda_runtime.h>
#include <math.h>

#define TT 16
#define CCH 64
#define HHH 48
#define WWI 48
#define HWSZ 2304
#define THWSZ 36864
#define WW2 24
#define SS 576
#define RCC 4
#define NSB 9   // s-blocks of 64 in gemm1

// ---------------- scratch (device globals; no allocations) ----------------
static __device__ float g_x2[CCH * THWSZ];            // [c][t][h][w]
static __device__ float g_off[2 * TT * 2 * SS];       // [branch][t][o][s]
static __device__ float g_part_cs[2][TT * CCH * SS];  // [branch][t][c][s]
static __device__ float g_part_sc[2][TT * SS * CCH];  // [branch][t][s][c]
static __device__ float g_aff[TT * SS * HWSZ];        // [t][s][hw] (reused per branch)
static __device__ float g_psum[TT * NSB * HWSZ];      // partial stats [t][sblk][hw]
static __device__ float g_psq [TT * NSB * HWSZ];
static __device__ float g_pmax[TT * NSB * HWSZ];
static __device__ float g_mean[TT * HWSZ];
static __device__ float g_maxv[TT * HWSZ];
static __device__ float g_varv[TT * HWSZ];
static __device__ float g_yv[TT * HWSZ];
static __device__ float g_feat[TT * HWSZ * CCH];      // [t][hw][c]
static __device__ float g_xd[RCC * THWSZ];
static __device__ float g_agg[RCC * THWSZ];

__device__ __forceinline__ float sigm(float v) { return 1.0f / (1.0f + __expf(-v)); }

// ---------------- x2 = w_dc2 @ x : 128pos x 64out tile, 256 thr, 4x8 micro ---
__global__ void __launch_bounds__(256) k_x2(const float* __restrict__ x, const float* __restrict__ w) {
    __shared__ float Ws[64][64];   // [c][o]
    __shared__ float Xs[64][128];  // [c][pos]
    int tid = threadIdx.x;
    int pos0 = blockIdx.x * 128;
#pragma unroll
    for (int v = 0; v < 16; v++) {
        int i = v * 256 + tid;
        Ws[i & 63][i >> 6] = w[i];
    }
#pragma unroll
    for (int v = 0; v < 8; v++) {
        int i = v * 256 + tid;
        int row = i >> 5, col = (i & 31) * 4;
        *(float4*)&Xs[row][col] = *(const float4*)&x[row * THWSZ + pos0 + col];
    }
    __syncthreads();
    int tx = tid & 31, ty = tid >> 5;
    float acc[4][8];
#pragma unroll
    for (int i = 0; i < 4; i++)
#pragma unroll
        for (int j = 0; j < 8; j++) acc[i][j] = 0.0f;
#pragma unroll 4
    for (int k = 0; k < 64; k++) {
        float4 a = *(float4*)&Xs[k][tx * 4];
        float4 b0 = *(float4*)&Ws[k][ty * 8];
        float4 b1 = *(float4*)&Ws[k][ty * 8 + 4];
        float av[4] = {a.x, a.y, a.z, a.w};
        float bv[8] = {b0.x, b0.y, b0.z, b0.w, b1.x, b1.y, b1.z, b1.w};
#pragma unroll
        for (int i = 0; i < 4; i++)
#pragma unroll
            for (int j = 0; j < 8; j++) acc[i][j] = fmaf(av[i], bv[j], acc[i][j]);
    }
#pragma unroll
    for (int j = 0; j < 8; j++) {
        int o = ty * 8 + j;
        float4 o4 = make_float4(acc[0][j], acc[1][j], acc[2][j], acc[3][j]);
        *(float4*)&g_x2[o * THWSZ + pos0 + tx * 4] = o4;
    }
}

// ---------------- offset convs: tiled, block per (branch, t) -----------------
__global__ void __launch_bounds__(256) k_off(const float* __restrict__ x,
                      const float* __restrict__ wl, const float* __restrict__ bl,
                      const float* __restrict__ wr, const float* __restrict__ br_) {
    __shared__ float buf[HWSZ];    // x + shifted x2, one channel
    __shared__ float wsm[2 * CCH * 9];
    int tid = threadIdx.x;
    int branch = blockIdx.x >> 4;
    int t = blockIdx.x & 15;
    int tsrc = (branch == 0) ? min(t + 1, TT - 1) : max(t - 1, 0);
    const float* wofs = (branch == 0) ? wl : wr;
    const float* bias = (branch == 0) ? bl : br_;
#pragma unroll
    for (int v = 0; v < 5; v++) {
        int i = v * 256 + tid;
        if (i < 2 * CCH * 9) wsm[i] = wofs[i];
    }
    // thread handles s = tid, tid+256, tid+512(<576)
    float a0[3] = {}, a1[3] = {};
    int nS = (tid < 64) ? 3 : 2;
    for (int c = 0; c < CCH; c++) {
        __syncthreads();
        const float* xp = x + c * THWSZ + t * HWSZ;
        const float* x2p = g_x2 + c * THWSZ + tsrc * HWSZ;
#pragma unroll
        for (int v = 0; v < 9; v++) {
            int i = v * 256 + tid;
            buf[i] = xp[i] + x2p[i];
        }
        __syncthreads();
        const float* w0 = &wsm[c * 9];
        const float* w1 = &wsm[(CCH + c) * 9];
        for (int q = 0; q < nS; q++) {
            int s = q * 256 + tid;
            int si = s / WW2, sj = s % WW2;
            float r0 = a0[q], r1 = a1[q];
#pragma unroll
            for (int ki = 0; ki < 3; ki++) {
                int h = 2 * si - 1 + ki;
                if (h < 0 || h >= HHH) continue;
#pragma unroll
                for (int kj = 0; kj < 3; kj++) {
                    int w = 2 * sj - 1 + kj;
                    if (w < 0 || w >= WWI) continue;
                    float v = buf[h * WWI + w];
                    r0 = fmaf(v, w0[ki * 3 + kj], r0);
                    r1 = fmaf(v, w1[ki * 3 + kj], r1);
                }
            }
            a0[q] = r0; a1[q] = r1;
        }
    }
    float b0v = bias[0], b1v = bias[1];
    for (int q = 0; q < nS; q++) {
        int s = q * 256 + tid;
        g_off[((branch * TT + t) * 2 + 0) * SS + s] = a0[q] + b0v;
        g_off[((branch * TT + t) * 2 + 1) * SS + s] = a1[q] + b1v;
    }
}

// ---------------- bilinear grid-sample of shifted x2 ------------------------
__global__ void k_sample() {
    int idx = blockIdx.x * blockDim.x + threadIdx.x;
    if (idx >= 2 * TT * SS) return;
    int branch = idx / (TT * SS);
    int t = (idx % (TT * SS)) / SS;
    int s = idx % SS;
    int i = s / WW2, j = s % WW2;
    float off0 = g_off[((branch * TT + t) * 2 + 0) * SS + s];
    float off1 = g_off[((branch * TT + t) * 2 + 1) * SS + s];
    float v0 = 2.0f * (float)j + off0;
    float v1 = 2.0f * (float)i + off1;
    float gh = 2.0f * v0 / 23.0f - 1.0f;
    float gw = 2.0f * v1 / 23.0f - 1.0f;
    float xs = ((gh + 1.0f) * 48.0f - 1.0f) * 0.5f;
    float ys = ((gw + 1.0f) * 48.0f - 1.0f) * 0.5f;
    float x0f = floorf(xs), y0f = floorf(ys);
    int x0 = (int)x0f, y0 = (int)y0f;
    float fx = xs - x0f, fy = ys - y0f;
    float wgt[4] = {(1.0f - fx) * (1.0f - fy), fx * (1.0f - fy),
                    (1.0f - fx) * fy, fx * fy};
    int xi[4] = {x0, x0 + 1, x0, x0 + 1};
    int yi[4] = {y0, y0, y0 + 1, y0 + 1};
    float wv[4];
    int id[4];
#pragma unroll
    for (int k = 0; k < 4; k++) {
        bool valid = (xi[k] >= 0) && (xi[k] < WWI) && (yi[k] >= 0) && (yi[k] < HHH);
        wv[k] = valid ? wgt[k] : 0.0f;
        int cy = min(max(yi[k], 0), HHH - 1);
        int cx = min(max(xi[k], 0), WWI - 1);
        id[k] = cy * WWI + cx;
    }
    int tsrc = (branch == 0) ? min(t + 1, TT - 1) : max(t - 1, 0);
    for (int c = 0; c < CCH; c++) {
        const float* img = g_x2 + c * THWSZ + tsrc * HWSZ;
        float val = wv[0] * img[id[0]] + wv[1] * img[id[1]] +
                    wv[2] * img[id[2]] + wv[3] * img[id[3]];
        g_part_cs[branch][(t * CCH + c) * SS + s] = val;
        g_part_sc[branch][(t * SS + s) * CCH + c] = val;
    }
}

// ------- GEMM1 (128hw x 64s, 256 thr, 4x8 micro) + fused stats partials -----
__global__ void __launch_bounds__(256) k_gemm1(const float* __restrict__ x, int branch) {
    __shared__ float Ps[64][64];   // [k(c)][s]   16KB
    __shared__ float Xs[64][128];  // [k(c)][hw]  32KB
    int t = blockIdx.z;
    int hw0 = blockIdx.x * 128;
    int sblk = blockIdx.y;
    int s0 = sblk * 64;
    const float* P = g_part_cs[branch];
    int tid = threadIdx.x;

#pragma unroll
    for (int v = 0; v < 4; v++) {
        int i = v * 256 + tid;
        int row = i >> 4, col = (i & 15) * 4;
        *(float4*)&Ps[row][col] = *(const float4*)&P[(t * CCH + row) * SS + s0 + col];
    }
#pragma unroll
    for (int v = 0; v < 8; v++) {
        int i = v * 256 + tid;
        int row = i >> 5, col = (i & 31) * 4;
        *(float4*)&Xs[row][col] = *(const float4*)&x[row * THWSZ + t * HWSZ + hw0 + col];
    }
    __syncthreads();

    int tx = tid & 31, ty = tid >> 5;  // tx: hw(4 each), ty: s(8 each)
    float acc[4][8];
#pragma unroll
    for (int i = 0; i < 4; i++)
#pragma unroll
        for (int j = 0; j < 8; j++) acc[i][j] = 0.0f;

#pragma unroll 4
    for (int k = 0; k < 64; k++) {
        float4 a = *(float4*)&Xs[k][tx * 4];
        float4 b0 = *(float4*)&Ps[k][ty * 8];
        float4 b1 = *(float4*)&Ps[k][ty * 8 + 4];
        float av[4] = {a.x, a.y, a.z, a.w};
        float bv[8] = {b0.x, b0.y, b0.z, b0.w, b1.x, b1.y, b1.z, b1.w};
#pragma unroll
        for (int i = 0; i < 4; i++)
#pragma unroll
            for (int j = 0; j < 8; j++) acc[i][j] = fmaf(av[i], bv[j], acc[i][j]);
    }

    // store aff: per j one float4 across hw
#pragma unroll
    for (int j = 0; j < 8; j++) {
        int s_g = s0 + ty * 8 + j;
        float4 o4 = make_float4(acc[0][j], acc[1][j], acc[2][j], acc[3][j]);
        *(float4*)&g_aff[(t * SS + s_g) * HWSZ + hw0 + tx * 4] = o4;
    }

    // fused stats partials over this block's 64 s per hw column
    __syncthreads();
    float* red = &Ps[0][0];  // reuse: [3][8(ty)][128(hw)] = 12KB
#pragma unroll
    for (int i = 0; i < 4; i++) {
        int hwl = tx * 4 + i;
        float sum = 0.0f, sq = 0.0f, mx = -3.4e38f;
#pragma unroll
        for (int j = 0; j < 8; j++) {
            float v = acc[i][j];
            sum += v;
            sq = fmaf(v, v, sq);
            mx = fmaxf(mx, v);
        }
        red[ty * 128 + hwl] = sum;
        red[1024 + ty * 128 + hwl] = sq;
        red[2048 + ty * 128 + hwl] = mx;
    }
    __syncthreads();
    if (tid < 128) {
        int hwl = tid;
        float sum = 0.0f, sq = 0.0f, mx = -3.4e38f;
#pragma unroll
        for (int r = 0; r < 8; r++) {
            sum += red[r * 128 + hwl];
            sq += red[1024 + r * 128 + hwl];
            mx = fmaxf(mx, red[2048 + r * 128 + hwl]);
        }
        int o = (t * NSB + sblk) * HWSZ + hw0 + hwl;
        g_psum[o] = sum;
        g_psq[o] = sq;
        g_pmax[o] = mx;
    }
}

// ---------------- stats phase2: combine 9 partials ---------------------------
__global__ void k_stats2() {
    int idx = blockIdx.x * 256 + threadIdx.x;
    if (idx >= TT * HWSZ) return;
    int t = idx / HWSZ;
    int hw = idx % HWSZ;
    float sum = 0.0f, sq = 0.0f, mx = -3.4e38f;
#pragma unroll
    for (int b = 0; b < NSB; b++) {
        int o = (t * NSB + b) * HWSZ + hw;
        sum += g_psum[o];
        sq += g_psq[o];
        mx = fmaxf(mx, g_pmax[o]);
    }
    g_mean[idx] = sum / 576.0f;
    g_maxv[idx] = mx;
    g_varv[idx] = (sq - sum * sum / 576.0f) / 575.0f;
}

// ---------------- attention gate ---------------------------------------------
__global__ void k_y(const float* __restrict__ w1, const float* __restrict__ w2) {
    int idx = blockIdx.x * 256 + threadIdx.x;
    if (idx >= TT * HWSZ) return;
    int t = idx / HWSZ;
    int hw = idx % HWSZ;
    int h = hw / WWI, w = hw % WWI;
    float acc = 0.0f;
#pragma unroll
    for (int dh = 0; dh < 3; dh++) {
        int hh = h + dh - 1;
        if (hh < 0 || hh >= HHH) continue;
#pragma unroll
        for (int dw = 0; dw < 3; dw++) {
            int ww = w + dw - 1;
            if (ww < 0 || ww >= WWI) continue;
            int p = t * HWSZ + hh * WWI + ww;
            acc = fmaf(w1[(0 * 3 + dh) * 3 + dw], g_mean[p], acc);
            acc = fmaf(w1[(3 + dh) * 3 + dw], g_maxv[p], acc);
            acc = fmaf(w2[dh * 3 + dw], g_varv[p], acc);
        }
    }
    g_yv[idx] = sigm(acc);
}

// ------- GEMM2 (128hw x 64c, K=576, 256 thr, 4x8 micro) ----------------------
__global__ void __launch_bounds__(256) k_gemm2(int branch, const float* __restrict__ w2s, int accum) {
    __shared__ float Gs[64][128];   // [k(s)][hw] 32KB
    __shared__ float Bs[64][64];    // [k(s)][c]  16KB
    int t = blockIdx.y;
    int hw0 = blockIdx.x * 128;
    const float* Psc = g_part_sc[branch];
    float wscale = w2s[branch];
    int tid = threadIdx.x;
    int tx = tid & 31, ty = tid >> 5;  // tx: hw, ty: c

    // Gs fill column is fixed per thread -> cache yv
    int gcol = (tid & 31) * 4;
    int grow0 = tid >> 5;
    float4 yv = *(const float4*)&g_yv[t * HWSZ + hw0 + gcol];

    float acc[4][8];
#pragma unroll
    for (int i = 0; i < 4; i++)
#pragma unroll
        for (int j = 0; j < 8; j++) acc[i][j] = 0.0f;

    for (int k0 = 0; k0 < SS; k0 += 64) {
        __syncthreads();
#pragma unroll
        for (int v = 0; v < 4; v++) {
            int i = v * 256 + tid;
            int row = i >> 4, col = (i & 15) * 4;
            *(float4*)&Bs[row][col] = *(const float4*)&Psc[(t * SS + k0 + row) * CCH + col];
        }
#pragma unroll
        for (int v = 0; v < 8; v++) {
            int row = v * 8 + grow0;
            float4 a = *(const float4*)&g_aff[(t * SS + k0 + row) * HWSZ + hw0 + gcol];
            float4 g;
            g.x = sigm(yv.x * a.x) - 0.5f;
            g.y = sigm(yv.y * a.y) - 0.5f;
            g.z = sigm(yv.z * a.z) - 0.5f;
            g.w = sigm(yv.w * a.w) - 0.5f;
            *(float4*)&Gs[row][gcol] = g;
        }
        __syncthreads();
#pragma unroll 4
        for (int k = 0; k < 64; k++) {
            float4 a = *(float4*)&Gs[k][tx * 4];
            float4 b0 = *(float4*)&Bs[k][ty * 8];
            float4 b1 = *(float4*)&Bs[k][ty * 8 + 4];
            float av[4] = {a.x, a.y, a.z, a.w};
            float bv[8] = {b0.x, b0.y, b0.z, b0.w, b1.x, b1.y, b1.z, b1.w};
#pragma unroll
            for (int i = 0; i < 4; i++)
#pragma unroll
                for (int j = 0; j < 8; j++) acc[i][j] = fmaf(av[i], bv[j], acc[i][j]);
        }
    }

#pragma unroll
    for (int i = 0; i < 4; i++) {
        int hw_g = hw0 + tx * 4 + i;
        float* dst = &g_feat[(t * HWSZ + hw_g) * CCH + ty * 8];
        float4 o0 = make_float4(wscale * acc[i][0], wscale * acc[i][1],
                                wscale * acc[i][2], wscale * acc[i][3]);
        float4 o1 = make_float4(wscale * acc[i][4], wscale * acc[i][5],
                                wscale * acc[i][6], wscale * acc[i][7]);
        if (accum) {
            float4 p0 = *(float4*)dst;
            float4 p1 = *(float4*)&dst[4];
            o0.x += p0.x; o0.y += p0.y; o0.z += p0.z; o0.w += p0.w;
            o1.x += p1.x; o1.y += p1.y; o1.z += p1.z; o1.w += p1.w;
        }
        *(float4*)dst = o0;
        *(float4*)&dst[4] = o1;
    }
}

// ---------------- xd = w_down @ x -------------------------------------------
__global__ void k_xd(const float* __restrict__ x, const float* __restrict__ wd) {
    int idx = blockIdx.x * blockDim.x + threadIdx.x;
    if (idx >= RCC * THWSZ) return;
    int r = idx / THWSZ, pos = idx % THWSZ;
    float acc = 0.0f;
    for (int c = 0; c < CCH; c++) acc = fmaf(wd[r * CCH + c], x[c * THWSZ + pos], acc);
    g_xd[idx] = acc;
}

// ---------------- 3x depthwise 3D convs, weighted sum -----------------------
__global__ void k_agg(const float* __restrict__ w1, const float* __restrict__ b1,
                      const float* __restrict__ w2, const float* __restrict__ b2,
                      const float* __restrict__ w3, const float* __restrict__ b3,
                      const float* __restrict__ wts) {
    int idx = blockIdx.x * blockDim.x + threadIdx.x;
    if (idx >= RCC * THWSZ) return;
    int r = idx / THWSZ;
    int rem = idx % THWSZ;
    int t = rem / HWSZ;
    int hw = rem % HWSZ;
    int h = hw / WWI, w = hw % WWI;
    const float* xb = g_xd + r * THWSZ;
    const float* ws_[3] = {w1, w2, w3};
    const float* bs_[3] = {b1, b2, b3};
    float total = 0.0f;
#pragma unroll
    for (int m = 0; m < 3; m++) {
        int d = m + 1;
        float cs = bs_[m][r];
        const float* wp = ws_[m] + r * 81;
        for (int kt = 0; kt < 9; kt++) {
            int ti = t + kt - 4;
            if (ti < 0 || ti >= TT) continue;
#pragma unroll
            for (int kh = 0; kh < 3; kh++) {
                int hi = h + (kh - 1) * d;
                if (hi < 0 || hi >= HHH) continue;
#pragma unroll
                for (int kw = 0; kw < 3; kw++) {
                    int wi = w + (kw - 1) * d;
                    if (wi < 0 || wi >= WWI) continue;
                    cs = fmaf(xb[ti * HWSZ + hi * WWI + wi], wp[(kt * 3 + kh) * 3 + kw], cs);
                }
            }
        }
        total = fmaf(wts[m], cs, total);
    }
    g_agg[idx] = total;
}

// ---------------- final: out = feat * (sigmoid(w_back@agg) - 0.5) -----------
__global__ void k_final(float* __restrict__ out, const float* __restrict__ wback) {
    int pos = blockIdx.x * 256 + threadIdx.x;
    if (pos >= THWSZ) return;
    float ag0 = g_agg[pos];
    float ag1 = g_agg[THWSZ + pos];
    float ag2 = g_agg[2 * THWSZ + pos];
    float ag3 = g_agg[3 * THWSZ + pos];
    const float4* f4 = (const float4*)&g_feat[pos * CCH];
#pragma unroll
    for (int c4 = 0; c4 < 16; c4++) {
        float4 f = f4[c4];
        float fv[4] = {f.x, f.y, f.z, f.w};
#pragma unroll
        for (int u = 0; u < 4; u++) {
            int c = c4 * 4 + u;
            float z = wback[c * 4 + 0] * ag0 + wback[c * 4 + 1] * ag1 +
                      wback[c * 4 + 2] * ag2 + wback[c * 4 + 3] * ag3;
            out[c * THWSZ + pos] = fv[u] * (sigm(z) - 0.5f);
        }
    }
}

extern "C" void kernel_launch(void* const* d_in, const int* in_sizes, int n_in,
                              void* d_out, int out_size) {
    const float* x       = (const float*)d_in[0];
    const float* w_dc2   = (const float*)d_in[1];
    const float* w_ofs_l = (const float*)d_in[2];
    const float* b_ofs_l = (const float*)d_in[3];
    const float* w_ofs_r = (const float*)d_in[4];
    const float* b_ofs_r = (const float*)d_in[5];
    const float* ca_w1   = (const float*)d_in[6];
    const float* ca_w2   = (const float*)d_in[7];
    const float* w_down  = (const float*)d_in[8];
    const float* sa1_w   = (const float*)d_in[9];
    const float* sa1_b   = (const float*)d_in[10];
    const float* sa2_w   = (const float*)d_in[11];
    const float* sa2_b   = (const float*)d_in[12];
    const float* sa3_w   = (const float*)d_in[13];
    const float* sa3_b   = (const float*)d_in[14];
    const float* weights = (const float*)d_in[15];
    const float* weights2= (const float*)d_in[16];
    const float* w_back  = (const float*)d_in[17];
    float* out = (float*)d_out;

    k_x2<<<THWSZ / 128, 256>>>(x, w_dc2);
    k_off<<<32, 256>>>(x, w_ofs_l, b_ofs_l, w_ofs_r, b_ofs_r);
    k_sample<<<(2 * TT * SS + 255) / 256, 256>>>();

    for (int br = 0; br < 2; br++) {
        dim3 g1(HWSZ / 128, NSB, TT);
        k_gemm1<<<g1, 256>>>(x, br);
        k_stats2<<<(TT * HWSZ + 255) / 256, 256>>>();
        k_y<<<(TT * HWSZ + 255) / 256, 256>>>(ca_w1, ca_w2);
        dim3 g2(HWSZ / 128, TT);
        k_gemm2<<<g2, 256>>>(br, weights2, br);
    }

    k_xd<<<(RCC * THWSZ + 255) / 256, 256>>>(x, w_down);
    k_agg<<<(RCC * THWSZ + 255) / 256, 256>>>(sa1_w, sa1_b, sa2_w, sa2_b, sa3_w, sa3_b, weights);
    k_final<<<(THWSZ + 255) / 256, 256>>>(out, w_back);
}

// round 4
// speedup vs baseline: 1.2284x; 1.0278x over previous
#include <cuda_runtime.h>
#include <math.h>

#define TT 16
#define CCH 64
#define HHH 48
#define WWI 48
#define HWSZ 2304
#define THWSZ 36864
#define WW2 24
#define SS 576
#define RCC 4
#define NSB 9   // s-blocks of 64 in gemm1

typedef unsigned long long u64t;

#define FMA_F32X2(d, a, b, c) \
    asm("fma.rn.f32x2 %0, %1, %2, %3;" : "=l"(d) : "l"(a), "l"(b), "l"(c))
#define DUP_F32X2(out, v) \
    asm("mov.b64 %0, {%1, %1};" : "=l"(out) : "r"(v))
#define UNPACK_F32X2(lo, hi, in) \
    asm("mov.b64 {%0, %1}, %2;" : "=r"(lo), "=r"(hi) : "l"(in))

// ---------------- scratch (device globals; no allocations) ----------------
static __device__ float g_x2[CCH * THWSZ];            // [c][t][h][w]
static __device__ float g_off[2 * TT * 2 * SS];       // [branch][t][o][s]
static __device__ float g_part_cs[2][TT * CCH * SS];  // [branch][t][c][s]
static __device__ float g_part_sc[2][TT * SS * CCH];  // [branch][t][s][c]
static __device__ float g_aff[TT * SS * HWSZ];        // [t][s][hw] (reused per branch)
static __device__ float g_psum[TT * NSB * HWSZ];      // partial stats [t][sblk][hw]
static __device__ float g_psq [TT * NSB * HWSZ];
static __device__ float g_pmax[TT * NSB * HWSZ];
static __device__ float g_mean[TT * HWSZ];
static __device__ float g_maxv[TT * HWSZ];
static __device__ float g_varv[TT * HWSZ];
static __device__ float g_yv[TT * HWSZ];
static __device__ float g_feat[TT * HWSZ * CCH];      // [t][hw][c]
static __device__ float g_xd[RCC * THWSZ];
static __device__ float g_agg[RCC * THWSZ];

__device__ __forceinline__ float sigm(float v) { return 1.0f / (1.0f + __expf(-v)); }

// 4(row: i, scalar-dup) x 8(col: j, packed pairs) FFMA2 micro-kernel step.
// arow: 4 floats (dup'd), bcol: 4 packed f32x2 (8 cols), accp[4][4].
__device__ __forceinline__ void mma4x8_step(const float4& a, const u64t bp[4], u64t accp[4][4]) {
    float av[4] = {a.x, a.y, a.z, a.w};
#pragma unroll
    for (int i = 0; i < 4; i++) {
        u64t ad;
        DUP_F32X2(ad, __float_as_uint(av[i]));
#pragma unroll
        for (int j = 0; j < 4; j++) FMA_F32X2(accp[i][j], ad, bp[j], accp[i][j]);
    }
}

// ---------------- x2 = w_dc2 @ x : 128pos x 64out tile, 256 thr --------------
__global__ void __launch_bounds__(256) k_x2(const float* __restrict__ x, const float* __restrict__ w) {
    __shared__ float Ws[64][64];   // [c][o]
    __shared__ float Xs[64][128];  // [c][pos]
    int tid = threadIdx.x;
    int pos0 = blockIdx.x * 128;
#pragma unroll
    for (int v = 0; v < 16; v++) {
        int i = v * 256 + tid;
        Ws[i & 63][i >> 6] = w[i];
    }
#pragma unroll
    for (int v = 0; v < 8; v++) {
        int i = v * 256 + tid;
        int row = i >> 5, col = (i & 31) * 4;
        *(float4*)&Xs[row][col] = *(const float4*)&x[row * THWSZ + pos0 + col];
    }
    __syncthreads();
    int tx = tid & 31, ty = tid >> 5;
    u64t accp[4][4];
#pragma unroll
    for (int i = 0; i < 4; i++)
#pragma unroll
        for (int j = 0; j < 4; j++) accp[i][j] = 0ULL;
#pragma unroll 4
    for (int k = 0; k < 64; k++) {
        float4 a = *(float4*)&Xs[k][tx * 4];
        const u64t* bp = (const u64t*)&Ws[k][ty * 8];
        u64t b[4] = {bp[0], bp[1], bp[2], bp[3]};
        mma4x8_step(a, b, accp);
    }
    float acc[4][8];
#pragma unroll
    for (int i = 0; i < 4; i++)
#pragma unroll
        for (int j = 0; j < 4; j++) {
            unsigned lo, hi;
            UNPACK_F32X2(lo, hi, accp[i][j]);
            acc[i][2 * j] = __uint_as_float(lo);
            acc[i][2 * j + 1] = __uint_as_float(hi);
        }
#pragma unroll
    for (int j = 0; j < 8; j++) {
        int o = ty * 8 + j;
        float4 o4 = make_float4(acc[0][j], acc[1][j], acc[2][j], acc[3][j]);
        *(float4*)&g_x2[o * THWSZ + pos0 + tx * 4] = o4;
    }
}

// ---------------- offset convs: tiled, block per (branch, t) -----------------
__global__ void __launch_bounds__(256) k_off(const float* __restrict__ x,
                      const float* __restrict__ wl, const float* __restrict__ bl,
                      const float* __restrict__ wr, const float* __restrict__ br_) {
    __shared__ float buf[HWSZ];
    __shared__ float wsm[2 * CCH * 9];
    int tid = threadIdx.x;
    int branch = blockIdx.x >> 4;
    int t = blockIdx.x & 15;
    int tsrc = (branch == 0) ? min(t + 1, TT - 1) : max(t - 1, 0);
    const float* wofs = (branch == 0) ? wl : wr;
    const float* bias = (branch == 0) ? bl : br_;
#pragma unroll
    for (int v = 0; v < 5; v++) {
        int i = v * 256 + tid;
        if (i < 2 * CCH * 9) wsm[i] = wofs[i];
    }
    float a0[3] = {}, a1[3] = {};
    int nS = (tid < 64) ? 3 : 2;
    for (int c = 0; c < CCH; c++) {
        __syncthreads();
        const float* xp = x + c * THWSZ + t * HWSZ;
        const float* x2p = g_x2 + c * THWSZ + tsrc * HWSZ;
#pragma unroll
        for (int v = 0; v < 9; v++) {
            int i = v * 256 + tid;
            buf[i] = xp[i] + x2p[i];
        }
        __syncthreads();
        const float* w0 = &wsm[c * 9];
        const float* w1 = &wsm[(CCH + c) * 9];
        for (int q = 0; q < nS; q++) {
            int s = q * 256 + tid;
            int si = s / WW2, sj = s % WW2;
            float r0 = a0[q], r1 = a1[q];
#pragma unroll
            for (int ki = 0; ki < 3; ki++) {
                int h = 2 * si - 1 + ki;
                if (h < 0 || h >= HHH) continue;
#pragma unroll
                for (int kj = 0; kj < 3; kj++) {
                    int w = 2 * sj - 1 + kj;
                    if (w < 0 || w >= WWI) continue;
                    float v = buf[h * WWI + w];
                    r0 = fmaf(v, w0[ki * 3 + kj], r0);
                    r1 = fmaf(v, w1[ki * 3 + kj], r1);
                }
            }
            a0[q] = r0; a1[q] = r1;
        }
    }
    float b0v = bias[0], b1v = bias[1];
    for (int q = 0; q < nS; q++) {
        int s = q * 256 + tid;
        g_off[((branch * TT + t) * 2 + 0) * SS + s] = a0[q] + b0v;
        g_off[((branch * TT + t) * 2 + 1) * SS + s] = a1[q] + b1v;
    }
}

// ---------------- bilinear grid-sample of shifted x2 ------------------------
__global__ void k_sample() {
    int idx = blockIdx.x * blockDim.x + threadIdx.x;
    if (idx >= 2 * TT * SS) return;
    int branch = idx / (TT * SS);
    int t = (idx % (TT * SS)) / SS;
    int s = idx % SS;
    int i = s / WW2, j = s % WW2;
    float off0 = g_off[((branch * TT + t) * 2 + 0) * SS + s];
    float off1 = g_off[((branch * TT + t) * 2 + 1) * SS + s];
    float v0 = 2.0f * (float)j + off0;
    float v1 = 2.0f * (float)i + off1;
    float gh = 2.0f * v0 / 23.0f - 1.0f;
    float gw = 2.0f * v1 / 23.0f - 1.0f;
    float xs = ((gh + 1.0f) * 48.0f - 1.0f) * 0.5f;
    float ys = ((gw + 1.0f) * 48.0f - 1.0f) * 0.5f;
    float x0f = floorf(xs), y0f = floorf(ys);
    int x0 = (int)x0f, y0 = (int)y0f;
    float fx = xs - x0f, fy = ys - y0f;
    float wgt[4] = {(1.0f - fx) * (1.0f - fy), fx * (1.0f - fy),
                    (1.0f - fx) * fy, fx * fy};
    int xi[4] = {x0, x0 + 1, x0, x0 + 1};
    int yi[4] = {y0, y0, y0 + 1, y0 + 1};
    float wv[4];
    int id[4];
#pragma unroll
    for (int k = 0; k < 4; k++) {
        bool valid = (xi[k] >= 0) && (xi[k] < WWI) && (yi[k] >= 0) && (yi[k] < HHH);
        wv[k] = valid ? wgt[k] : 0.0f;
        int cy = min(max(yi[k], 0), HHH - 1);
        int cx = min(max(xi[k], 0), WWI - 1);
        id[k] = cy * WWI + cx;
    }
    int tsrc = (branch == 0) ? min(t + 1, TT - 1) : max(t - 1, 0);
    for (int c = 0; c < CCH; c++) {
        const float* img = g_x2 + c * THWSZ + tsrc * HWSZ;
        float val = wv[0] * img[id[0]] + wv[1] * img[id[1]] +
                    wv[2] * img[id[2]] + wv[3] * img[id[3]];
        g_part_cs[branch][(t * CCH + c) * SS + s] = val;
        g_part_sc[branch][(t * SS + s) * CCH + c] = val;
    }
}

// ------- GEMM1 (128hw x 64s, 256 thr, FFMA2) + fused stats partials ----------
__global__ void __launch_bounds__(256) k_gemm1(const float* __restrict__ x, int branch) {
    __shared__ float Ps[64][64];   // [k(c)][s]   16KB
    __shared__ float Xs[64][128];  // [k(c)][hw]  32KB
    int t = blockIdx.z;
    int hw0 = blockIdx.x * 128;
    int sblk = blockIdx.y;
    int s0 = sblk * 64;
    const float* P = g_part_cs[branch];
    int tid = threadIdx.x;

#pragma unroll
    for (int v = 0; v < 4; v++) {
        int i = v * 256 + tid;
        int row = i >> 4, col = (i & 15) * 4;
        *(float4*)&Ps[row][col] = *(const float4*)&P[(t * CCH + row) * SS + s0 + col];
    }
#pragma unroll
    for (int v = 0; v < 8; v++) {
        int i = v * 256 + tid;
        int row = i >> 5, col = (i & 31) * 4;
        *(float4*)&Xs[row][col] = *(const float4*)&x[row * THWSZ + t * HWSZ + hw0 + col];
    }
    __syncthreads();

    int tx = tid & 31, ty = tid >> 5;  // tx: hw(4 each), ty: s(8 each)
    u64t accp[4][4];
#pragma unroll
    for (int i = 0; i < 4; i++)
#pragma unroll
        for (int j = 0; j < 4; j++) accp[i][j] = 0ULL;

#pragma unroll 4
    for (int k = 0; k < 64; k++) {
        float4 a = *(float4*)&Xs[k][tx * 4];
        const u64t* bp = (const u64t*)&Ps[k][ty * 8];
        u64t b[4] = {bp[0], bp[1], bp[2], bp[3]};
        mma4x8_step(a, b, accp);
    }

    float acc[4][8];
#pragma unroll
    for (int i = 0; i < 4; i++)
#pragma unroll
        for (int j = 0; j < 4; j++) {
            unsigned lo, hi;
            UNPACK_F32X2(lo, hi, accp[i][j]);
            acc[i][2 * j] = __uint_as_float(lo);
            acc[i][2 * j + 1] = __uint_as_float(hi);
        }

    // store aff: per j one float4 across hw
#pragma unroll
    for (int j = 0; j < 8; j++) {
        int s_g = s0 + ty * 8 + j;
        float4 o4 = make_float4(acc[0][j], acc[1][j], acc[2][j], acc[3][j]);
        *(float4*)&g_aff[(t * SS + s_g) * HWSZ + hw0 + tx * 4] = o4;
    }

    // fused stats partials over this block's 64 s per hw column
    __syncthreads();
    float* red = &Ps[0][0];
#pragma unroll
    for (int i = 0; i < 4; i++) {
        int hwl = tx * 4 + i;
        float sum = 0.0f, sq = 0.0f, mx = -3.4e38f;
#pragma unroll
        for (int j = 0; j < 8; j++) {
            float v = acc[i][j];
            sum += v;
            sq = fmaf(v, v, sq);
            mx = fmaxf(mx, v);
        }
        red[ty * 128 + hwl] = sum;
        red[1024 + ty * 128 + hwl] = sq;
        red[2048 + ty * 128 + hwl] = mx;
    }
    __syncthreads();
    if (tid < 128) {
        int hwl = tid;
        float sum = 0.0f, sq = 0.0f, mx = -3.4e38f;
#pragma unroll
        for (int r = 0; r < 8; r++) {
            sum += red[r * 128 + hwl];
            sq += red[1024 + r * 128 + hwl];
            mx = fmaxf(mx, red[2048 + r * 128 + hwl]);
        }
        int o = (t * NSB + sblk) * HWSZ + hw0 + hwl;
        g_psum[o] = sum;
        g_psq[o] = sq;
        g_pmax[o] = mx;
    }
}

// ---------------- stats phase2: combine 9 partials ---------------------------
__global__ void k_stats2() {
    int idx = blockIdx.x * 256 + threadIdx.x;
    if (idx >= TT * HWSZ) return;
    int t = idx / HWSZ;
    int hw = idx % HWSZ;
    float sum = 0.0f, sq = 0.0f, mx = -3.4e38f;
#pragma unroll
    for (int b = 0; b < NSB; b++) {
        int o = (t * NSB + b) * HWSZ + hw;
        sum += g_psum[o];
        sq += g_psq[o];
        mx = fmaxf(mx, g_pmax[o]);
    }
    g_mean[idx] = sum / 576.0f;
    g_maxv[idx] = mx;
    g_varv[idx] = (sq - sum * sum / 576.0f) / 575.0f;
}

// ---------------- attention gate ---------------------------------------------
__global__ void k_y(const float* __restrict__ w1, const float* __restrict__ w2) {
    int idx = blockIdx.x * 256 + threadIdx.x;
    if (idx >= TT * HWSZ) return;
    int t = idx / HWSZ;
    int hw = idx % HWSZ;
    int h = hw / WWI, w = hw % WWI;
    float acc = 0.0f;
#pragma unroll
    for (int dh = 0; dh < 3; dh++) {
        int hh = h + dh - 1;
        if (hh < 0 || hh >= HHH) continue;
#pragma unroll
        for (int dw = 0; dw < 3; dw++) {
            int ww = w + dw - 1;
            if (ww < 0 || ww >= WWI) continue;
            int p = t * HWSZ + hh * WWI + ww;
            acc = fmaf(w1[(0 * 3 + dh) * 3 + dw], g_mean[p], acc);
            acc = fmaf(w1[(3 + dh) * 3 + dw], g_maxv[p], acc);
            acc = fmaf(w2[dh * 3 + dw], g_varv[p], acc);
        }
    }
    g_yv[idx] = sigm(acc);
}

// ------- GEMM2 (128hw x 64c, K=576, 256 thr, FFMA2) --------------------------
__global__ void __launch_bounds__(256) k_gemm2(int branch, const float* __restrict__ w2s, int accum) {
    __shared__ float Gs[64][128];   // [k(s)][hw] 32KB
    __shared__ float Bs[64][64];    // [k(s)][c]  16KB
    int t = blockIdx.y;
    int hw0 = blockIdx.x * 128;
    const float* Psc = g_part_sc[branch];
    float wscale = w2s[branch];
    int tid = threadIdx.x;
    int tx = tid & 31, ty = tid >> 5;  // tx: hw, ty: c

    int gcol = (tid & 31) * 4;
    int grow0 = tid >> 5;
    float4 yv = *(const float4*)&g_yv[t * HWSZ + hw0 + gcol];

    u64t accp[4][4];
#pragma unroll
    for (int i = 0; i < 4; i++)
#pragma unroll
        for (int j = 0; j < 4; j++) accp[i][j] = 0ULL;

    for (int k0 = 0; k0 < SS; k0 += 64) {
        __syncthreads();
#pragma unroll
        for (int v = 0; v < 4; v++) {
            int i = v * 256 + tid;
            int row = i >> 4, col = (i & 15) * 4;
            *(float4*)&Bs[row][col] = *(const float4*)&Psc[(t * SS + k0 + row) * CCH + col];
        }
#pragma unroll
        for (int v = 0; v < 8; v++) {
            int row = v * 8 + grow0;
            float4 a = *(const float4*)&g_aff[(t * SS + k0 + row) * HWSZ + hw0 + gcol];
            float4 g;
            g.x = sigm(yv.x * a.x) - 0.5f;
            g.y = sigm(yv.y * a.y) - 0.5f;
            g.z = sigm(yv.z * a.z) - 0.5f;
            g.w = sigm(yv.w * a.w) - 0.5f;
            *(float4*)&Gs[row][gcol] = g;
        }
        __syncthreads();
#pragma unroll 4
        for (int k = 0; k < 64; k++) {
            float4 a = *(float4*)&Gs[k][tx * 4];
            const u64t* bp = (const u64t*)&Bs[k][ty * 8];
            u64t b[4] = {bp[0], bp[1], bp[2], bp[3]};
            mma4x8_step(a, b, accp);
        }
    }

    float acc[4][8];
#pragma unroll
    for (int i = 0; i < 4; i++)
#pragma unroll
        for (int j = 0; j < 4; j++) {
            unsigned lo, hi;
            UNPACK_F32X2(lo, hi, accp[i][j]);
            acc[i][2 * j] = __uint_as_float(lo);
            acc[i][2 * j + 1] = __uint_as_float(hi);
        }

#pragma unroll
    for (int i = 0; i < 4; i++) {
        int hw_g = hw0 + tx * 4 + i;
        float* dst = &g_feat[(t * HWSZ + hw_g) * CCH + ty * 8];
        float4 o0 = make_float4(wscale * acc[i][0], wscale * acc[i][1],
                                wscale * acc[i][2], wscale * acc[i][3]);
        float4 o1 = make_float4(wscale * acc[i][4], wscale * acc[i][5],
                                wscale * acc[i][6], wscale * acc[i][7]);
        if (accum) {
            float4 p0 = *(float4*)dst;
            float4 p1 = *(float4*)&dst[4];
            o0.x += p0.x; o0.y += p0.y; o0.z += p0.z; o0.w += p0.w;
            o1.x += p1.x; o1.y += p1.y; o1.z += p1.z; o1.w += p1.w;
        }
        *(float4*)dst = o0;
        *(float4*)&dst[4] = o1;
    }
}

// ---------------- xd = w_down @ x -------------------------------------------
__global__ void k_xd(const float* __restrict__ x, const float* __restrict__ wd) {
    int idx = blockIdx.x * blockDim.x + threadIdx.x;
    if (idx >= RCC * THWSZ) return;
    int r = idx / THWSZ, pos = idx % THWSZ;
    float acc = 0.0f;
    for (int c = 0; c < CCH; c++) acc = fmaf(wd[r * CCH + c], x[c * THWSZ + pos], acc);
    g_xd[idx] = acc;
}

// ---------------- 3x depthwise 3D convs, weighted sum -----------------------
__global__ void k_agg(const float* __restrict__ w1, const float* __restrict__ b1,
                      const float* __restrict__ w2, const float* __restrict__ b2,
                      const float* __restrict__ w3, const float* __restrict__ b3,
                      const float* __restrict__ wts) {
    int idx = blockIdx.x * blockDim.x + threadIdx.x;
    if (idx >= RCC * THWSZ) return;
    int r = idx / THWSZ;
    int rem = idx % THWSZ;
    int t = rem / HWSZ;
    int hw = rem % HWSZ;
    int h = hw / WWI, w = hw % WWI;
    const float* xb = g_xd + r * THWSZ;
    const float* ws_[3] = {w1, w2, w3};
    const float* bs_[3] = {b1, b2, b3};
    float total = 0.0f;
#pragma unroll
    for (int m = 0; m < 3; m++) {
        int d = m + 1;
        float cs = bs_[m][r];
        const float* wp = ws_[m] + r * 81;
        for (int kt = 0; kt < 9; kt++) {
            int ti = t + kt - 4;
            if (ti < 0 || ti >= TT) continue;
#pragma unroll
            for (int kh = 0; kh < 3; kh++) {
                int hi = h + (kh - 1) * d;
                if (hi < 0 || hi >= HHH) continue;
#pragma unroll
                for (int kw = 0; kw < 3; kw++) {
                    int wi = w + (kw - 1) * d;
                    if (wi < 0 || wi >= WWI) continue;
                    cs = fmaf(xb[ti * HWSZ + hi * WWI + wi], wp[(kt * 3 + kh) * 3 + kw], cs);
                }
            }
        }
        total = fmaf(wts[m], cs, total);
    }
    g_agg[idx] = total;
}

// ---------------- final: out = feat * (sigmoid(w_back@agg) - 0.5) -----------
__global__ void k_final(float* __restrict__ out, const float* __restrict__ wback) {
    int pos = blockIdx.x * 256 + threadIdx.x;
    if (pos >= THWSZ) return;
    float ag0 = g_agg[pos];
    float ag1 = g_agg[THWSZ + pos];
    float ag2 = g_agg[2 * THWSZ + pos];
    float ag3 = g_agg[3 * THWSZ + pos];
    const float4* f4 = (const float4*)&g_feat[pos * CCH];
#pragma unroll
    for (int c4 = 0; c4 < 16; c4++) {
        float4 f = f4[c4];
        float fv[4] = {f.x, f.y, f.z, f.w};
#pragma unroll
        for (int u = 0; u < 4; u++) {
            int c = c4 * 4 + u;
            float z = wback[c * 4 + 0] * ag0 + wback[c * 4 + 1] * ag1 +
                      wback[c * 4 + 2] * ag2 + wback[c * 4 + 3] * ag3;
            out[c * THWSZ + pos] = fv[u] * (sigm(z) - 0.5f);
        }
    }
}

extern "C" void kernel_launch(void* const* d_in, const int* in_sizes, int n_in,
                              void* d_out, int out_size) {
    const float* x       = (const float*)d_in[0];
    const float* w_dc2   = (const float*)d_in[1];
    const float* w_ofs_l = (const float*)d_in[2];
    const float* b_ofs_l = (const float*)d_in[3];
    const float* w_ofs_r = (const float*)d_in[4];
    const float* b_ofs_r = (const float*)d_in[5];
    const float* ca_w1   = (const float*)d_in[6];
    const float* ca_w2   = (const float*)d_in[7];
    const float* w_down  = (const float*)d_in[8];
    const float* sa1_w   = (const float*)d_in[9];
    const float* sa1_b   = (const float*)d_in[10];
    const float* sa2_w   = (const float*)d_in[11];
    const float* sa2_b   = (const float*)d_in[12];
    const float* sa3_w   = (const float*)d_in[13];
    const float* sa3_b   = (const float*)d_in[14];
    const float* weights = (const float*)d_in[15];
    const float* weights2= (const float*)d_in[16];
    const float* w_back  = (const float*)d_in[17];
    float* out = (float*)d_out;

    k_x2<<<THWSZ / 128, 256>>>(x, w_dc2);
    k_off<<<32, 256>>>(x, w_ofs_l, b_ofs_l, w_ofs_r, b_ofs_r);
    k_sample<<<(2 * TT * SS + 255) / 256, 256>>>();

    for (int br = 0; br < 2; br++) {
        dim3 g1(HWSZ / 128, NSB, TT);
        k_gemm1<<<g1, 256>>>(x, br);
        k_stats2<<<(TT * HWSZ + 255) / 256, 256>>>();
        k_y<<<(TT * HWSZ + 255) / 256, 256>>>(ca_w1, ca_w2);
        dim3 g2(HWSZ / 128, TT);
        k_gemm2<<<g2, 256>>>(br, weights2, br);
    }

    k_xd<<<(RCC * THWSZ + 255) / 256, 256>>>(x, w_down);
    k_agg<<<(RCC * THWSZ + 255) / 256, 256>>>(sa1_w, sa1_b, sa2_w, sa2_b, sa3_w, sa3_b, weights);
    k_final<<<(THWSZ + 255) / 256, 256>>>(out, w_back);
}

// round 5
// speedup vs baseline: 1.4741x; 1.2000x over previous
#include <cuda_runtime.h>
#include <math.h>

#define TT 16
#define CCH 64
#define HHH 48
#define WWI 48
#define HWSZ 2304
#define THWSZ 36864
#define WW2 24
#define SS 576
#define RCC 4
#define NSB 9   // s-blocks of 64 in gemm1
#define NCC 16  // channel chunks of 4 in k_offp

typedef unsigned long long u64t;

#define FMA_F32X2(d, a, b, c) \
    asm("fma.rn.f32x2 %0, %1, %2, %3;" : "=l"(d) : "l"(a), "l"(b), "l"(c))
#define DUP_F32X2(out, v) \
    asm("mov.b64 %0, {%1, %1};" : "=l"(out) : "r"(v))
#define UNPACK_F32X2(lo, hi, in) \
    asm("mov.b64 {%0, %1}, %2;" : "=r"(lo), "=r"(hi) : "l"(in))

union F4U { float4 f; u64t u[2]; };

// ---------------- scratch (device globals; no allocations) ----------------
static __device__ float g_x2[CCH * THWSZ];            // [c][t][h][w]
static __device__ float g_offp[NCC][2 * TT * 2 * SS]; // conv partials per c-chunk
static __device__ float g_off[2 * TT * 2 * SS];       // [branch][t][o][s]
static __device__ float g_part_cs[2][TT * CCH * SS];  // [branch][t][c][s]
static __device__ float g_part_sc[2][TT * SS * CCH];  // [branch][t][s][c]
static __device__ float g_aff[TT * SS * HWSZ];        // [t][s][hw] (reused per branch)
static __device__ float g_psum[TT * NSB * HWSZ];
static __device__ float g_psq [TT * NSB * HWSZ];
static __device__ float g_pmax[TT * NSB * HWSZ];
static __device__ float g_mean[TT * HWSZ];
static __device__ float g_maxv[TT * HWSZ];
static __device__ float g_varv[TT * HWSZ];
static __device__ float g_yv[TT * HWSZ];
static __device__ float g_feat[TT * HWSZ * CCH];      // [t][hw][c]
static __device__ float g_xd[RCC * THWSZ];
static __device__ float g_agg[RCC * THWSZ];

__device__ __forceinline__ float sigm(float v) { return 1.0f / (1.0f + __expf(-v)); }

// 4(i, dup) x 8(j, packed) FFMA2 micro step
__device__ __forceinline__ void mma4x8(const float4& a, const F4U& b0, const F4U& b1,
                                       u64t accp[4][4]) {
    float av[4] = {a.x, a.y, a.z, a.w};
    u64t bp[4] = {b0.u[0], b0.u[1], b1.u[0], b1.u[1]};
#pragma unroll
    for (int i = 0; i < 4; i++) {
        u64t ad;
        DUP_F32X2(ad, __float_as_uint(av[i]));
#pragma unroll
        for (int j = 0; j < 4; j++) FMA_F32X2(accp[i][j], ad, bp[j], accp[i][j]);
    }
}

__device__ __forceinline__ void unpack_acc(const u64t accp[4][4], float acc[4][8]) {
#pragma unroll
    for (int i = 0; i < 4; i++)
#pragma unroll
        for (int j = 0; j < 4; j++) {
            unsigned lo, hi;
            UNPACK_F32X2(lo, hi, accp[i][j]);
            acc[i][2 * j] = __uint_as_float(lo);
            acc[i][2 * j + 1] = __uint_as_float(hi);
        }
}

// ---------------- x2 = w_dc2 @ x : 128pos x 64out tile, 256 thr --------------
__global__ void __launch_bounds__(256) k_x2(const float* __restrict__ x, const float* __restrict__ w) {
    __shared__ float Ws[64][64];   // [c][o]
    __shared__ float Xs[64][128];  // [c][pos]
    int tid = threadIdx.x;
    int pos0 = blockIdx.x * 128;
#pragma unroll
    for (int v = 0; v < 16; v++) {
        int i = v * 256 + tid;
        Ws[i & 63][i >> 6] = w[i];
    }
#pragma unroll
    for (int v = 0; v < 8; v++) {
        int i = v * 256 + tid;
        int row = i >> 5, col = (i & 31) * 4;
        *(float4*)&Xs[row][col] = *(const float4*)&x[row * THWSZ + pos0 + col];
    }
    __syncthreads();
    int tx = tid & 31, ty = tid >> 5;
    u64t accp[4][4];
#pragma unroll
    for (int i = 0; i < 4; i++)
#pragma unroll
        for (int j = 0; j < 4; j++) accp[i][j] = 0ULL;

    float4 a_c = *(float4*)&Xs[0][tx * 4];
    F4U b0_c, b1_c;
    b0_c.f = *(float4*)&Ws[0][ty * 8];
    b1_c.f = *(float4*)&Ws[0][ty * 8 + 4];
#pragma unroll 7
    for (int k = 0; k < 63; k++) {
        float4 a_n = *(float4*)&Xs[k + 1][tx * 4];
        F4U b0_n, b1_n;
        b0_n.f = *(float4*)&Ws[k + 1][ty * 8];
        b1_n.f = *(float4*)&Ws[k + 1][ty * 8 + 4];
        mma4x8(a_c, b0_c, b1_c, accp);
        a_c = a_n; b0_c = b0_n; b1_c = b1_n;
    }
    mma4x8(a_c, b0_c, b1_c, accp);

    float acc[4][8];
    unpack_acc(accp, acc);
#pragma unroll
    for (int j = 0; j < 8; j++) {
        int o = ty * 8 + j;
        float4 o4 = make_float4(acc[0][j], acc[1][j], acc[2][j], acc[3][j]);
        *(float4*)&g_x2[o * THWSZ + pos0 + tx * 4] = o4;
    }
}

// ------- offset conv partials: thread per (cchunk, branch, t, o, s) ----------
__global__ void __launch_bounds__(256) k_offp(const float* __restrict__ x,
                      const float* __restrict__ wl, const float* __restrict__ wr) {
    int idx = blockIdx.x * 256 + threadIdx.x;  // 16*2*16*2*576 = 589824
    int s = idx % SS;
    int o = (idx / SS) & 1;
    int t = (idx / (2 * SS)) & 15;
    int branch = (idx / (2 * SS * TT)) & 1;
    int cc = idx / (2 * SS * TT * 2);
    int i = s / WW2, j = s % WW2;
    int tsrc = (branch == 0) ? min(t + 1, TT - 1) : max(t - 1, 0);
    const float* wofs = (branch == 0) ? wl : wr;
    float acc = 0.0f;
#pragma unroll
    for (int u = 0; u < 4; u++) {
        int c = cc * 4 + u;
        const float* xp = x + c * THWSZ + t * HWSZ;
        const float* x2p = g_x2 + c * THWSZ + tsrc * HWSZ;
        const float* wp = wofs + (o * CCH + c) * 9;
#pragma unroll
        for (int ki = 0; ki < 3; ki++) {
            int h = 2 * i - 1 + ki;
            if (h < 0 || h >= HHH) continue;
#pragma unroll
            for (int kj = 0; kj < 3; kj++) {
                int w = 2 * j - 1 + kj;
                if (w < 0 || w >= WWI) continue;
                acc = fmaf(xp[h * WWI + w] + x2p[h * WWI + w], wp[ki * 3 + kj], acc);
            }
        }
    }
    g_offp[cc][((branch * TT + t) * 2 + o) * SS + s] = acc;
}

// ------- reduce offset partials + bias ---------------------------------------
__global__ void k_offred(const float* __restrict__ bl, const float* __restrict__ br_) {
    int i = blockIdx.x * 256 + threadIdx.x;  // 36864
    if (i >= 2 * TT * 2 * SS) return;
    int branch = i / (TT * 2 * SS);
    int o = (i / SS) & 1;
    float acc = (branch == 0) ? bl[o] : br_[o];
#pragma unroll
    for (int cc = 0; cc < NCC; cc++) acc += g_offp[cc][i];
    g_off[i] = acc;
}

// ------- bilinear grid-sample: thread per (branch, t, c4, s) ------------------
__global__ void __launch_bounds__(256) k_sample() {
    int idx = blockIdx.x * 256 + threadIdx.x;  // 2*16*16*576 = 294912
    int s = idx % SS;
    int c4 = (idx / SS) & 15;
    int t = (idx / (SS * 16)) & 15;
    int branch = idx / (SS * 16 * 16);
    int i = s / WW2, j = s % WW2;
    float off0 = g_off[((branch * TT + t) * 2 + 0) * SS + s];
    float off1 = g_off[((branch * TT + t) * 2 + 1) * SS + s];
    float v0 = 2.0f * (float)j + off0;
    float v1 = 2.0f * (float)i + off1;
    float gh = 2.0f * v0 / 23.0f - 1.0f;
    float gw = 2.0f * v1 / 23.0f - 1.0f;
    float xs = ((gh + 1.0f) * 48.0f - 1.0f) * 0.5f;
    float ys = ((gw + 1.0f) * 48.0f - 1.0f) * 0.5f;
    float x0f = floorf(xs), y0f = floorf(ys);
    int x0 = (int)x0f, y0 = (int)y0f;
    float fx = xs - x0f, fy = ys - y0f;
    float wgt[4] = {(1.0f - fx) * (1.0f - fy), fx * (1.0f - fy),
                    (1.0f - fx) * fy, fx * fy};
    int xi[4] = {x0, x0 + 1, x0, x0 + 1};
    int yi[4] = {y0, y0, y0 + 1, y0 + 1};
    float wv[4];
    int id[4];
#pragma unroll
    for (int k = 0; k < 4; k++) {
        bool valid = (xi[k] >= 0) && (xi[k] < WWI) && (yi[k] >= 0) && (yi[k] < HHH);
        wv[k] = valid ? wgt[k] : 0.0f;
        int cy = min(max(yi[k], 0), HHH - 1);
        int cx = min(max(xi[k], 0), WWI - 1);
        id[k] = cy * WWI + cx;
    }
    int tsrc = (branch == 0) ? min(t + 1, TT - 1) : max(t - 1, 0);
    float vals[4];
#pragma unroll
    for (int u = 0; u < 4; u++) {
        int c = c4 * 4 + u;
        const float* img = g_x2 + c * THWSZ + tsrc * HWSZ;
        float val = wv[0] * img[id[0]] + wv[1] * img[id[1]] +
                    wv[2] * img[id[2]] + wv[3] * img[id[3]];
        g_part_cs[branch][(t * CCH + c) * SS + s] = val;
        vals[u] = val;
    }
    *(float4*)&g_part_sc[branch][(t * SS + s) * CCH + c4 * 4] =
        make_float4(vals[0], vals[1], vals[2], vals[3]);
}

// ------- GEMM1 (128hw x 64s, 256 thr, FFMA2, prefetch) + fused stats ----------
__global__ void __launch_bounds__(256) k_gemm1(const float* __restrict__ x, int branch) {
    __shared__ float Ps[64][64];   // [k(c)][s]   16KB
    __shared__ float Xs[64][128];  // [k(c)][hw]  32KB
    int t = blockIdx.z;
    int hw0 = blockIdx.x * 128;
    int sblk = blockIdx.y;
    int s0 = sblk * 64;
    const float* P = g_part_cs[branch];
    int tid = threadIdx.x;

#pragma unroll
    for (int v = 0; v < 4; v++) {
        int i = v * 256 + tid;
        int row = i >> 4, col = (i & 15) * 4;
        *(float4*)&Ps[row][col] = *(const float4*)&P[(t * CCH + row) * SS + s0 + col];
    }
#pragma unroll
    for (int v = 0; v < 8; v++) {
        int i = v * 256 + tid;
        int row = i >> 5, col = (i & 31) * 4;
        *(float4*)&Xs[row][col] = *(const float4*)&x[row * THWSZ + t * HWSZ + hw0 + col];
    }
    __syncthreads();

    int tx = tid & 31, ty = tid >> 5;
    u64t accp[4][4];
#pragma unroll
    for (int i = 0; i < 4; i++)
#pragma unroll
        for (int j = 0; j < 4; j++) accp[i][j] = 0ULL;

    float4 a_c = *(float4*)&Xs[0][tx * 4];
    F4U b0_c, b1_c;
    b0_c.f = *(float4*)&Ps[0][ty * 8];
    b1_c.f = *(float4*)&Ps[0][ty * 8 + 4];
#pragma unroll 7
    for (int k = 0; k < 63; k++) {
        float4 a_n = *(float4*)&Xs[k + 1][tx * 4];
        F4U b0_n, b1_n;
        b0_n.f = *(float4*)&Ps[k + 1][ty * 8];
        b1_n.f = *(float4*)&Ps[k + 1][ty * 8 + 4];
        mma4x8(a_c, b0_c, b1_c, accp);
        a_c = a_n; b0_c = b0_n; b1_c = b1_n;
    }
    mma4x8(a_c, b0_c, b1_c, accp);

    float acc[4][8];
    unpack_acc(accp, acc);

#pragma unroll
    for (int j = 0; j < 8; j++) {
        int s_g = s0 + ty * 8 + j;
        float4 o4 = make_float4(acc[0][j], acc[1][j], acc[2][j], acc[3][j]);
        *(float4*)&g_aff[(t * SS + s_g) * HWSZ + hw0 + tx * 4] = o4;
    }

    __syncthreads();
    float* red = &Ps[0][0];
#pragma unroll
    for (int i = 0; i < 4; i++) {
        int hwl = tx * 4 + i;
        float sum = 0.0f, sq = 0.0f, mx = -3.4e38f;
#pragma unroll
        for (int j = 0; j < 8; j++) {
            float v = acc[i][j];
            sum += v;
            sq = fmaf(v, v, sq);
            mx = fmaxf(mx, v);
        }
        red[ty * 128 + hwl] = sum;
        red[1024 + ty * 128 + hwl] = sq;
        red[2048 + ty * 128 + hwl] = mx;
    }
    __syncthreads();
    if (tid < 128) {
        int hwl = tid;
        float sum = 0.0f, sq = 0.0f, mx = -3.4e38f;
#pragma unroll
        for (int r = 0; r < 8; r++) {
            sum += red[r * 128 + hwl];
            sq += red[1024 + r * 128 + hwl];
            mx = fmaxf(mx, red[2048 + r * 128 + hwl]);
        }
        int o = (t * NSB + sblk) * HWSZ + hw0 + hwl;
        g_psum[o] = sum;
        g_psq[o] = sq;
        g_pmax[o] = mx;
    }
}

// ---------------- stats phase2: combine 9 partials ---------------------------
__global__ void k_stats2() {
    int idx = blockIdx.x * 256 + threadIdx.x;
    if (idx >= TT * HWSZ) return;
    int t = idx / HWSZ;
    int hw = idx % HWSZ;
    float sum = 0.0f, sq = 0.0f, mx = -3.4e38f;
#pragma unroll
    for (int b = 0; b < NSB; b++) {
        int o = (t * NSB + b) * HWSZ + hw;
        sum += g_psum[o];
        sq += g_psq[o];
        mx = fmaxf(mx, g_pmax[o]);
    }
    g_mean[idx] = sum / 576.0f;
    g_maxv[idx] = mx;
    g_varv[idx] = (sq - sum * sum / 576.0f) / 575.0f;
}

// ---------------- attention gate ---------------------------------------------
__global__ void k_y(const float* __restrict__ w1, const float* __restrict__ w2) {
    int idx = blockIdx.x * 256 + threadIdx.x;
    if (idx >= TT * HWSZ) return;
    int t = idx / HWSZ;
    int hw = idx % HWSZ;
    int h = hw / WWI, w = hw % WWI;
    float acc = 0.0f;
#pragma unroll
    for (int dh = 0; dh < 3; dh++) {
        int hh = h + dh - 1;
        if (hh < 0 || hh >= HHH) continue;
#pragma unroll
        for (int dw = 0; dw < 3; dw++) {
            int ww = w + dw - 1;
            if (ww < 0 || ww >= WWI) continue;
            int p = t * HWSZ + hh * WWI + ww;
            acc = fmaf(w1[(0 * 3 + dh) * 3 + dw], g_mean[p], acc);
            acc = fmaf(w1[(3 + dh) * 3 + dw], g_maxv[p], acc);
            acc = fmaf(w2[dh * 3 + dw], g_varv[p], acc);
        }
    }
    g_yv[idx] = sigm(acc);
}

// ------- GEMM2 (128hw x 64c, K=576, 256 thr, FFMA2, prefetch) -----------------
__global__ void __launch_bounds__(256) k_gemm2(int branch, const float* __restrict__ w2s, int accum) {
    __shared__ float Gs[64][128];   // [k(s)][hw] 32KB
    __shared__ float Bs[64][64];    // [k(s)][c]  16KB
    int t = blockIdx.y;
    int hw0 = blockIdx.x * 128;
    const float* Psc = g_part_sc[branch];
    float wscale = w2s[branch];
    int tid = threadIdx.x;
    int tx = tid & 31, ty = tid >> 5;

    int gcol = (tid & 31) * 4;
    int grow0 = tid >> 5;
    float4 yv = *(const float4*)&g_yv[t * HWSZ + hw0 + gcol];

    u64t accp[4][4];
#pragma unroll
    for (int i = 0; i < 4; i++)
#pragma unroll
        for (int j = 0; j < 4; j++) accp[i][j] = 0ULL;

    for (int k0 = 0; k0 < SS; k0 += 64) {
        __syncthreads();
#pragma unroll
        for (int v = 0; v < 4; v++) {
            int i = v * 256 + tid;
            int row = i >> 4, col = (i & 15) * 4;
            *(float4*)&Bs[row][col] = *(const float4*)&Psc[(t * SS + k0 + row) * CCH + col];
        }
#pragma unroll
        for (int v = 0; v < 8; v++) {
            int row = v * 8 + grow0;
            float4 a = *(const float4*)&g_aff[(t * SS + k0 + row) * HWSZ + hw0 + gcol];
            float4 g;
            g.x = sigm(yv.x * a.x) - 0.5f;
            g.y = sigm(yv.y * a.y) - 0.5f;
            g.z = sigm(yv.z * a.z) - 0.5f;
            g.w = sigm(yv.w * a.w) - 0.5f;
            *(float4*)&Gs[row][gcol] = g;
        }
        __syncthreads();

        float4 a_c = *(float4*)&Gs[0][tx * 4];
        F4U b0_c, b1_c;
        b0_c.f = *(float4*)&Bs[0][ty * 8];
        b1_c.f = *(float4*)&Bs[0][ty * 8 + 4];
#pragma unroll 7
        for (int k = 0; k < 63; k++) {
            float4 a_n = *(float4*)&Gs[k + 1][tx * 4];
            F4U b0_n, b1_n;
            b0_n.f = *(float4*)&Bs[k + 1][ty * 8];
            b1_n.f = *(float4*)&Bs[k + 1][ty * 8 + 4];
            mma4x8(a_c, b0_c, b1_c, accp);
            a_c = a_n; b0_c = b0_n; b1_c = b1_n;
        }
        mma4x8(a_c, b0_c, b1_c, accp);
    }

    float acc[4][8];
    unpack_acc(accp, acc);

#pragma unroll
    for (int i = 0; i < 4; i++) {
        int hw_g = hw0 + tx * 4 + i;
        float* dst = &g_feat[(t * HWSZ + hw_g) * CCH + ty * 8];
        float4 o0 = make_float4(wscale * acc[i][0], wscale * acc[i][1],
                                wscale * acc[i][2], wscale * acc[i][3]);
        float4 o1 = make_float4(wscale * acc[i][4], wscale * acc[i][5],
                                wscale * acc[i][6], wscale * acc[i][7]);
        if (accum) {
            float4 p0 = *(float4*)dst;
            float4 p1 = *(float4*)&dst[4];
            o0.x += p0.x; o0.y += p0.y; o0.z += p0.z; o0.w += p0.w;
            o1.x += p1.x; o1.y += p1.y; o1.z += p1.z; o1.w += p1.w;
        }
        *(float4*)dst = o0;
        *(float4*)&dst[4] = o1;
    }
}

// ---------------- xd = w_down @ x -------------------------------------------
__global__ void k_xd(const float* __restrict__ x, const float* __restrict__ wd) {
    int idx = blockIdx.x * blockDim.x + threadIdx.x;
    if (idx >= RCC * THWSZ) return;
    int r = idx / THWSZ, pos = idx % THWSZ;
    float acc = 0.0f;
    for (int c = 0; c < CCH; c++) acc = fmaf(wd[r * CCH + c], x[c * THWSZ + pos], acc);
    g_xd[idx] = acc;
}

// ---------------- 3x depthwise 3D convs, weighted sum -----------------------
__global__ void k_agg(const float* __restrict__ w1, const float* __restrict__ b1,
                      const float* __restrict__ w2, const float* __restrict__ b2,
                      const float* __restrict__ w3, const float* __restrict__ b3,
                      const float* __restrict__ wts) {
    int idx = blockIdx.x * blockDim.x + threadIdx.x;
    if (idx >= RCC * THWSZ) return;
    int r = idx / THWSZ;
    int rem = idx % THWSZ;
    int t = rem / HWSZ;
    int hw = rem % HWSZ;
    int h = hw / WWI, w = hw % WWI;
    const float* xb = g_xd + r * THWSZ;
    const float* ws_[3] = {w1, w2, w3};
    const float* bs_[3] = {b1, b2, b3};
    float total = 0.0f;
#pragma unroll
    for (int m = 0; m < 3; m++) {
        int d = m + 1;
        float cs = bs_[m][r];
        const float* wp = ws_[m] + r * 81;
        for (int kt = 0; kt < 9; kt++) {
            int ti = t + kt - 4;
            if (ti < 0 || ti >= TT) continue;
#pragma unroll
            for (int kh = 0; kh < 3; kh++) {
                int hi = h + (kh - 1) * d;
                if (hi < 0 || hi >= HHH) continue;
#pragma unroll
                for (int kw = 0; kw < 3; kw++) {
                    int wi = w + (kw - 1) * d;
                    if (wi < 0 || wi >= WWI) continue;
                    cs = fmaf(xb[ti * HWSZ + hi * WWI + wi], wp[(kt * 3 + kh) * 3 + kw], cs);
                }
            }
        }
        total = fmaf(wts[m], cs, total);
    }
    g_agg[idx] = total;
}

// ---------------- final: out = feat * (sigmoid(w_back@agg) - 0.5) -----------
__global__ void k_final(float* __restrict__ out, const float* __restrict__ wback) {
    int pos = blockIdx.x * 256 + threadIdx.x;
    if (pos >= THWSZ) return;
    float ag0 = g_agg[pos];
    float ag1 = g_agg[THWSZ + pos];
    float ag2 = g_agg[2 * THWSZ + pos];
    float ag3 = g_agg[3 * THWSZ + pos];
    const float4* f4 = (const float4*)&g_feat[pos * CCH];
#pragma unroll
    for (int c4 = 0; c4 < 16; c4++) {
        float4 f = f4[c4];
        float fv[4] = {f.x, f.y, f.z, f.w};
#pragma unroll
        for (int u = 0; u < 4; u++) {
            int c = c4 * 4 + u;
            float z = wback[c * 4 + 0] * ag0 + wback[c * 4 + 1] * ag1 +
                      wback[c * 4 + 2] * ag2 + wback[c * 4 + 3] * ag3;
            out[c * THWSZ + pos] = fv[u] * (sigm(z) - 0.5f);
        }
    }
}

extern "C" void kernel_launch(void* const* d_in, const int* in_sizes, int n_in,
                              void* d_out, int out_size) {
    const float* x       = (const float*)d_in[0];
    const float* w_dc2   = (const float*)d_in[1];
    const float* w_ofs_l = (const float*)d_in[2];
    const float* b_ofs_l = (const float*)d_in[3];
    const float* w_ofs_r = (const float*)d_in[4];
    const float* b_ofs_r = (const float*)d_in[5];
    const float* ca_w1   = (const float*)d_in[6];
    const float* ca_w2   = (const float*)d_in[7];
    const float* w_down  = (const float*)d_in[8];
    const float* sa1_w   = (const float*)d_in[9];
    const float* sa1_b   = (const float*)d_in[10];
    const float* sa2_w   = (const float*)d_in[11];
    const float* sa2_b   = (const float*)d_in[12];
    const float* sa3_w   = (const float*)d_in[13];
    const float* sa3_b   = (const float*)d_in[14];
    const float* weights = (const float*)d_in[15];
    const float* weights2= (const float*)d_in[16];
    const float* w_back  = (const float*)d_in[17];
    float* out = (float*)d_out;

    k_x2<<<THWSZ / 128, 256>>>(x, w_dc2);
    k_offp<<<(NCC * 2 * TT * 2 * SS) / 256, 256>>>(x, w_ofs_l, w_ofs_r);
    k_offred<<<(2 * TT * 2 * SS + 255) / 256, 256>>>(b_ofs_l, b_ofs_r);
    k_sample<<<(2 * TT * 16 * SS) / 256, 256>>>();

    for (int br = 0; br < 2; br++) {
        dim3 g1(HWSZ / 128, NSB, TT);
        k_gemm1<<<g1, 256>>>(x, br);
        k_stats2<<<(TT * HWSZ + 255) / 256, 256>>>();
        k_y<<<(TT * HWSZ + 255) / 256, 256>>>(ca_w1, ca_w2);
        dim3 g2(HWSZ / 128, TT);
        k_gemm2<<<g2, 256>>>(br, weights2, br);
    }

    k_xd<<<(RCC * THWSZ + 255) / 256, 256>>>(x, w_down);
    k_agg<<<(RCC * THWSZ + 255) / 256, 256>>>(sa1_w, sa1_b, sa2_w, sa2_b, sa3_w, sa3_b, weights);
    k_final<<<(THWSZ + 255) / 256, 256>>>(out, w_back);
}

// round 7
// speedup vs baseline: 1.7800x; 1.2075x over previous
#include <cuda_runtime.h>
#include <cuda_bf16.h>
#include <math.h>
#include <stdint.h>

#define TT 16
#define CCH 64
#define HHH 48
#define WWI 48
#define HWSZ 2304
#define THWSZ 36864
#define WW2 24
#define SS 576
#define RCC 4
#define NSB 9    // s-blocks of 64 in gemm1
#define NCC 16   // channel chunks of 4 in k_offp

typedef unsigned long long u64t;

// ---------------- FFMA2 helpers (k_x2) ----------------
#define FMA_F32X2(d, a, b, c) \
    asm("fma.rn.f32x2 %0, %1, %2, %3;" : "=l"(d) : "l"(a), "l"(b), "l"(c))
#define DUP_F32X2(out, v) \
    asm("mov.b64 %0, {%1, %1};" : "=l"(out) : "r"(v))
#define UNPACK_F32X2(lo, hi, in) \
    asm("mov.b64 {%0, %1}, %2;" : "=r"(lo), "=r"(hi) : "l"(in))
union F4U { float4 f; u64t u[2]; };

// ---------------- mma.sync / ldmatrix helpers ----------------
__device__ __forceinline__ uint32_t smem_to_u32(const void* p) {
    uint32_t a;
    asm("{ .reg .u64 tmp; cvta.to.shared.u64 tmp, %1; cvt.u32.u64 %0, tmp; }"
        : "=r"(a) : "l"(p));
    return a;
}
#define LDSM_X4(r0, r1, r2, r3, addr) \
    asm volatile("ldmatrix.sync.aligned.m8n8.x4.shared.b16 {%0,%1,%2,%3}, [%4];" \
        : "=r"(r0), "=r"(r1), "=r"(r2), "=r"(r3) : "r"(addr))
#define MMA_BF16(d, a, b) \
    asm volatile("mma.sync.aligned.m16n8k16.row.col.f32.bf16.bf16.f32 " \
        "{%0,%1,%2,%3}, {%4,%5,%6,%7}, {%8,%9}, {%0,%1,%2,%3};" \
        : "+f"((d)[0]), "+f"((d)[1]), "+f"((d)[2]), "+f"((d)[3]) \
        : "r"((a)[0]), "r"((a)[1]), "r"((a)[2]), "r"((a)[3]), "r"((b)[0]), "r"((b)[1]))

// smem tile geometry: bf16 rows padded to 72 elems (144 B, 16B-aligned, conflict-free LDSM)
#define SA 144
#define A_TILE_B (128 * SA)   // 18432
#define B_TILE_B (64 * SA)    // 9216
#define SMEM_TOT (2 * A_TILE_B + 2 * B_TILE_B)  // 55296
#define STG 68                // f32 stage stride

// ---------------- scratch (device globals; no allocations) ----------------
static __device__ float g_x2[CCH * THWSZ];            // [c][t][h][w]
static __device__ float g_offp[NCC][2 * TT * 2 * SS];
static __device__ float g_off[2 * TT * 2 * SS];
static __device__ __align__(16) unsigned short g_xt_hi[THWSZ * CCH];  // [t][hw][c]
static __device__ __align__(16) unsigned short g_xt_lo[THWSZ * CCH];
static __device__ __align__(16) unsigned short pb_sc_hi[2][TT * SS * CCH]; // [t][s][c]
static __device__ __align__(16) unsigned short pb_sc_lo[2][TT * SS * CCH];
static __device__ __align__(16) unsigned short pb_cs_hi[2][TT * CCH * SS]; // [t][c][s]
static __device__ __align__(16) unsigned short pb_cs_lo[2][TT * CCH * SS];
static __device__ float g_aff[(size_t)TT * HWSZ * SS];  // [t][hw][s]
static __device__ float g_psum[TT * NSB * HWSZ];
static __device__ float g_psq [TT * NSB * HWSZ];
static __device__ float g_pmax[TT * NSB * HWSZ];
static __device__ float g_mean[TT * HWSZ];
static __device__ float g_maxv[TT * HWSZ];
static __device__ float g_varv[TT * HWSZ];
static __device__ float g_yv[TT * HWSZ];
static __device__ float g_feat[TT * HWSZ * CCH];      // [t][hw][c]
static __device__ float g_xd[RCC * THWSZ];
static __device__ float g_agg[RCC * THWSZ];

__device__ __forceinline__ float sigm(float v) { return 1.0f / (1.0f + __expf(-v)); }

__device__ __forceinline__ void bf16_split(float v, unsigned short& hs, unsigned short& ls) {
    __nv_bfloat16 h = __float2bfloat16(v);
    float hf = __bfloat162float(h);
    __nv_bfloat16 l = __float2bfloat16(v - hf);
    hs = *(unsigned short*)&h;
    ls = *(unsigned short*)&l;
}

// ---------------- x2 = w_dc2 @ x (FFMA2, proven) -----------------------------
__device__ __forceinline__ void mma4x8(const float4& a, const F4U& b0, const F4U& b1,
                                       u64t accp[4][4]) {
    float av[4] = {a.x, a.y, a.z, a.w};
    u64t bp[4] = {b0.u[0], b0.u[1], b1.u[0], b1.u[1]};
#pragma unroll
    for (int i = 0; i < 4; i++) {
        u64t ad;
        DUP_F32X2(ad, __float_as_uint(av[i]));
#pragma unroll
        for (int j = 0; j < 4; j++) FMA_F32X2(accp[i][j], ad, bp[j], accp[i][j]);
    }
}
__device__ __forceinline__ void unpack_acc(const u64t accp[4][4], float acc[4][8]) {
#pragma unroll
    for (int i = 0; i < 4; i++)
#pragma unroll
        for (int j = 0; j < 4; j++) {
            unsigned lo, hi;
            UNPACK_F32X2(lo, hi, accp[i][j]);
            acc[i][2 * j] = __uint_as_float(lo);
            acc[i][2 * j + 1] = __uint_as_float(hi);
        }
}

__global__ void __launch_bounds__(256) k_x2(const float* __restrict__ x, const float* __restrict__ w) {
    __shared__ float Ws[64][64];
    __shared__ float Xs[64][128];
    int tid = threadIdx.x;
    int pos0 = blockIdx.x * 128;
#pragma unroll
    for (int v = 0; v < 16; v++) {
        int i = v * 256 + tid;
        Ws[i & 63][i >> 6] = w[i];
    }
#pragma unroll
    for (int v = 0; v < 8; v++) {
        int i = v * 256 + tid;
        int row = i >> 5, col = (i & 31) * 4;
        *(float4*)&Xs[row][col] = *(const float4*)&x[row * THWSZ + pos0 + col];
    }
    __syncthreads();
    int tx = tid & 31, ty = tid >> 5;
    u64t accp[4][4];
#pragma unroll
    for (int i = 0; i < 4; i++)
#pragma unroll
        for (int j = 0; j < 4; j++) accp[i][j] = 0ULL;
    float4 a_c = *(float4*)&Xs[0][tx * 4];
    F4U b0_c, b1_c;
    b0_c.f = *(float4*)&Ws[0][ty * 8];
    b1_c.f = *(float4*)&Ws[0][ty * 8 + 4];
#pragma unroll 7
    for (int k = 0; k < 63; k++) {
        float4 a_n = *(float4*)&Xs[k + 1][tx * 4];
        F4U b0_n, b1_n;
        b0_n.f = *(float4*)&Ws[k + 1][ty * 8];
        b1_n.f = *(float4*)&Ws[k + 1][ty * 8 + 4];
        mma4x8(a_c, b0_c, b1_c, accp);
        a_c = a_n; b0_c = b0_n; b1_c = b1_n;
    }
    mma4x8(a_c, b0_c, b1_c, accp);
    float acc[4][8];
    unpack_acc(accp, acc);
#pragma unroll
    for (int j = 0; j < 8; j++) {
        int o = ty * 8 + j;
        float4 o4 = make_float4(acc[0][j], acc[1][j], acc[2][j], acc[3][j]);
        *(float4*)&g_x2[o * THWSZ + pos0 + tx * 4] = o4;
    }
}

// ---------------- x transpose + bf16 split: [t][hw][c] -----------------------
__global__ void __launch_bounds__(256) k_xt(const float* __restrict__ x) {
    int idx = blockIdx.x * 256 + threadIdx.x;
    if (idx >= THWSZ) return;
    unsigned short* dh = &g_xt_hi[(size_t)idx * 64];
    unsigned short* dl = &g_xt_lo[(size_t)idx * 64];
#pragma unroll 8
    for (int c = 0; c < CCH; c++) {
        float v = x[c * THWSZ + idx];
        unsigned short hs, ls;
        bf16_split(v, hs, ls);
        dh[c] = hs; dl[c] = ls;
    }
}

// ------- offset conv partials -------------------------------------------------
__global__ void __launch_bounds__(256) k_offp(const float* __restrict__ x,
                      const float* __restrict__ wl, const float* __restrict__ wr) {
    int idx = blockIdx.x * 256 + threadIdx.x;
    int s = idx % SS;
    int o = (idx / SS) & 1;
    int t = (idx / (2 * SS)) & 15;
    int branch = (idx / (2 * SS * TT)) & 1;
    int cc = idx / (2 * SS * TT * 2);
    int i = s / WW2, j = s % WW2;
    int tsrc = (branch == 0) ? min(t + 1, TT - 1) : max(t - 1, 0);
    const float* wofs = (branch == 0) ? wl : wr;
    float acc = 0.0f;
#pragma unroll
    for (int u = 0; u < 4; u++) {
        int c = cc * 4 + u;
        const float* xp = x + c * THWSZ + t * HWSZ;
        const float* x2p = g_x2 + c * THWSZ + tsrc * HWSZ;
        const float* wp = wofs + (o * CCH + c) * 9;
#pragma unroll
        for (int ki = 0; ki < 3; ki++) {
            int h = 2 * i - 1 + ki;
            if (h < 0 || h >= HHH) continue;
#pragma unroll
            for (int kj = 0; kj < 3; kj++) {
                int w = 2 * j - 1 + kj;
                if (w < 0 || w >= WWI) continue;
                acc = fmaf(xp[h * WWI + w] + x2p[h * WWI + w], wp[ki * 3 + kj], acc);
            }
        }
    }
    g_offp[cc][((branch * TT + t) * 2 + o) * SS + s] = acc;
}

__global__ void k_offred(const float* __restrict__ bl, const float* __restrict__ br_) {
    int i = blockIdx.x * 256 + threadIdx.x;
    if (i >= 2 * TT * 2 * SS) return;
    int branch = i / (TT * 2 * SS);
    int o = (i / SS) & 1;
    float acc = (branch == 0) ? bl[o] : br_[o];
#pragma unroll
    for (int cc = 0; cc < NCC; cc++) acc += g_offp[cc][i];
    g_off[i] = acc;
}

// ------- bilinear grid-sample -> bf16 split parts -----------------------------
__global__ void __launch_bounds__(256) k_sample() {
    int idx = blockIdx.x * 256 + threadIdx.x;
    int s = idx % SS;
    int c4 = (idx / SS) & 15;
    int t = (idx / (SS * 16)) & 15;
    int branch = idx / (SS * 16 * 16);
    int i = s / WW2, j = s % WW2;
    float off0 = g_off[((branch * TT + t) * 2 + 0) * SS + s];
    float off1 = g_off[((branch * TT + t) * 2 + 1) * SS + s];
    float v0 = 2.0f * (float)j + off0;
    float v1 = 2.0f * (float)i + off1;
    float gh = 2.0f * v0 / 23.0f - 1.0f;
    float gw = 2.0f * v1 / 23.0f - 1.0f;
    float xs = ((gh + 1.0f) * 48.0f - 1.0f) * 0.5f;
    float ys = ((gw + 1.0f) * 48.0f - 1.0f) * 0.5f;
    float x0f = floorf(xs), y0f = floorf(ys);
    int x0 = (int)x0f, y0 = (int)y0f;
    float fx = xs - x0f, fy = ys - y0f;
    float wgt[4] = {(1.0f - fx) * (1.0f - fy), fx * (1.0f - fy),
                    (1.0f - fx) * fy, fx * fy};
    int xi[4] = {x0, x0 + 1, x0, x0 + 1};
    int yi[4] = {y0, y0, y0 + 1, y0 + 1};
    float wv[4];
    int id[4];
#pragma unroll
    for (int k = 0; k < 4; k++) {
        bool valid = (xi[k] >= 0) && (xi[k] < WWI) && (yi[k] >= 0) && (yi[k] < HHH);
        wv[k] = valid ? wgt[k] : 0.0f;
        int cy = min(max(yi[k], 0), HHH - 1);
        int cx = min(max(xi[k], 0), WWI - 1);
        id[k] = cy * WWI + cx;
    }
    int tsrc = (branch == 0) ? min(t + 1, TT - 1) : max(t - 1, 0);
#pragma unroll
    for (int u = 0; u < 4; u++) {
        int c = c4 * 4 + u;
        const float* img = g_x2 + c * THWSZ + tsrc * HWSZ;
        float val = wv[0] * img[id[0]] + wv[1] * img[id[1]] +
                    wv[2] * img[id[2]] + wv[3] * img[id[3]];
        unsigned short hs, ls;
        bf16_split(val, hs, ls);
        pb_sc_hi[branch][(t * SS + s) * CCH + c] = hs;
        pb_sc_lo[branch][(t * SS + s) * CCH + c] = ls;
        pb_cs_hi[branch][(t * CCH + c) * SS + s] = hs;
        pb_cs_lo[branch][(t * CCH + c) * SS + s] = ls;
    }
}

// ------- GEMM1 mma.sync: aff[t][hw][s] + fused stats partials -----------------
// block: M=128 hw x N=64 s, K=64 c. 8 warps (4m x 2n). grid (18, 9, 16).
__global__ void __launch_bounds__(256) k_gemm1_mma(int branch) {
    extern __shared__ __align__(16) char sm[];
    char* A_hi = sm;
    char* A_lo = sm + A_TILE_B;
    char* B_hi = sm + 2 * A_TILE_B;
    char* B_lo = sm + 2 * A_TILE_B + B_TILE_B;
    int tid = threadIdx.x;
    int t = blockIdx.z, sblk = blockIdx.y, hw0 = blockIdx.x * 128;
    int s0 = sblk * 64;

    // A: 128 rows x 64 c ; B: 64 rows(s) x 64 c
    {
        const uint4* sh = (const uint4*)&g_xt_hi[(size_t)(t * HWSZ + hw0) * 64];
        const uint4* sl = (const uint4*)&g_xt_lo[(size_t)(t * HWSZ + hw0) * 64];
#pragma unroll
        for (int v = 0; v < 4; v++) {
            int i = v * 256 + tid;
            int row = i >> 3, j = i & 7;
            *(uint4*)(A_hi + row * SA + j * 16) = sh[i];
            *(uint4*)(A_lo + row * SA + j * 16) = sl[i];
        }
        const uint4* bh = (const uint4*)&pb_sc_hi[branch][(t * SS + s0) * 64];
        const uint4* bl = (const uint4*)&pb_sc_lo[branch][(t * SS + s0) * 64];
#pragma unroll
        for (int v = 0; v < 2; v++) {
            int i = v * 256 + tid;
            int row = i >> 3, j = i & 7;
            *(uint4*)(B_hi + row * SA + j * 16) = bh[i];
            *(uint4*)(B_lo + row * SA + j * 16) = bl[i];
        }
    }
    __syncthreads();

    int wid = tid >> 5, lane = tid & 31;
    int wm = (wid & 3) * 32;
    int wn = (wid >> 2) * 32;
    uint32_t ah_u = smem_to_u32(A_hi), al_u = smem_to_u32(A_lo);
    uint32_t bh_u = smem_to_u32(B_hi), bl_u = smem_to_u32(B_lo);
    int arow = lane & 15;
    int akoff = (lane >> 4) * 16;           // bytes
    int brow = (lane & 7) + ((lane & 16) ? 8 : 0);
    int bkoff = ((lane >> 3) & 1) * 16;     // bytes

    float d[2][4][4] = {};
#pragma unroll
    for (int ks = 0; ks < 4; ks++) {
        int kb = ks * 32;  // 16 bf16 = 32 bytes
        uint32_t Ah[2][4], Al[2][4], Bh[4][2], Bl[4][2];
#pragma unroll
        for (int mt = 0; mt < 2; mt++) {
            uint32_t off = (uint32_t)((wm + mt * 16 + arow) * SA + kb + akoff);
            LDSM_X4(Ah[mt][0], Ah[mt][1], Ah[mt][2], Ah[mt][3], ah_u + off);
            LDSM_X4(Al[mt][0], Al[mt][1], Al[mt][2], Al[mt][3], al_u + off);
        }
#pragma unroll
        for (int np = 0; np < 2; np++) {
            uint32_t off = (uint32_t)((wn + np * 16 + brow) * SA + kb + bkoff);
            uint32_t r0, r1, r2, r3;
            LDSM_X4(r0, r1, r2, r3, bh_u + off);
            Bh[np * 2][0] = r0; Bh[np * 2][1] = r1;
            Bh[np * 2 + 1][0] = r2; Bh[np * 2 + 1][1] = r3;
            LDSM_X4(r0, r1, r2, r3, bl_u + off);
            Bl[np * 2][0] = r0; Bl[np * 2][1] = r1;
            Bl[np * 2 + 1][0] = r2; Bl[np * 2 + 1][1] = r3;
        }
#pragma unroll
        for (int mt = 0; mt < 2; mt++)
#pragma unroll
            for (int nt = 0; nt < 4; nt++) {
                MMA_BF16(d[mt][nt], Ah[mt], Bh[nt]);
                MMA_BF16(d[mt][nt], Ah[mt], Bl[nt]);
                MMA_BF16(d[mt][nt], Al[mt], Bh[nt]);
            }
    }

    // stage D -> smem for coalesced writes + stats
    __syncthreads();
    float* stage = (float*)sm;  // 128 x STG
#pragma unroll
    for (int mt = 0; mt < 2; mt++)
#pragma unroll
        for (int nt = 0; nt < 4; nt++)
#pragma unroll
            for (int r = 0; r < 4; r++) {
                int m = wm + mt * 16 + (lane >> 2) + ((r >> 1) & 1) * 8;
                int n = wn + nt * 8 + (lane & 3) * 2 + (r & 1);
                stage[m * STG + n] = d[mt][nt][r];
            }
    __syncthreads();
    int row = tid >> 1, half = tid & 1;
    const float* srow = &stage[row * STG + half * 32];
    float sum = 0.0f, sq = 0.0f, mx = -3.4e38f;
    float* arow_g = &g_aff[((size_t)t * HWSZ + hw0 + row) * SS + s0 + half * 32];
#pragma unroll
    for (int q = 0; q < 8; q++) {
        float4 b = *(const float4*)&srow[q * 4];
        sum += b.x + b.y + b.z + b.w;
        sq = fmaf(b.x, b.x, sq); sq = fmaf(b.y, b.y, sq);
        sq = fmaf(b.z, b.z, sq); sq = fmaf(b.w, b.w, sq);
        mx = fmaxf(mx, fmaxf(fmaxf(b.x, b.y), fmaxf(b.z, b.w)));
        *(float4*)&arow_g[q * 4] = b;
    }
    sum += __shfl_xor_sync(0xFFFFFFFFu, sum, 1);
    sq += __shfl_xor_sync(0xFFFFFFFFu, sq, 1);
    mx = fmaxf(mx, __shfl_xor_sync(0xFFFFFFFFu, mx, 1));
    if (half == 0) {
        int o = (t * NSB + sblk) * HWSZ + hw0 + row;
        g_psum[o] = sum;
        g_psq[o] = sq;
        g_pmax[o] = mx;
    }
}

// ---------------- stats phase2 ------------------------------------------------
__global__ void k_stats2() {
    int idx = blockIdx.x * 256 + threadIdx.x;
    if (idx >= TT * HWSZ) return;
    int t = idx / HWSZ;
    int hw = idx % HWSZ;
    float sum = 0.0f, sq = 0.0f, mx = -3.4e38f;
#pragma unroll
    for (int b = 0; b < NSB; b++) {
        int o = (t * NSB + b) * HWSZ + hw;
        sum += g_psum[o];
        sq += g_psq[o];
        mx = fmaxf(mx, g_pmax[o]);
    }
    g_mean[idx] = sum / 576.0f;
    g_maxv[idx] = mx;
    g_varv[idx] = (sq - sum * sum / 576.0f) / 575.0f;
}

// ---------------- attention gate -----------------------------------------------
__global__ void k_y(const float* __restrict__ w1, const float* __restrict__ w2) {
    int idx = blockIdx.x * 256 + threadIdx.x;
    if (idx >= TT * HWSZ) return;
    int t = idx / HWSZ;
    int hw = idx % HWSZ;
    int h = hw / WWI, w = hw % WWI;
    float acc = 0.0f;
#pragma unroll
    for (int dh = 0; dh < 3; dh++) {
        int hh = h + dh - 1;
        if (hh < 0 || hh >= HHH) continue;
#pragma unroll
        for (int dw = 0; dw < 3; dw++) {
            int ww = w + dw - 1;
            if (ww < 0 || ww >= WWI) continue;
            int p = t * HWSZ + hh * WWI + ww;
            acc = fmaf(w1[(0 * 3 + dh) * 3 + dw], g_mean[p], acc);
            acc = fmaf(w1[(3 + dh) * 3 + dw], g_maxv[p], acc);
            acc = fmaf(w2[dh * 3 + dw], g_varv[p], acc);
        }
    }
    g_yv[idx] = sigm(acc);
}

// ------- GEMM2 mma.sync: feat[t][hw][c], K=576 in 9 chunks --------------------
// block: M=128 hw x N=64 c. 8 warps (4m x 2n). grid (18, 16).
__global__ void __launch_bounds__(256) k_gemm2_mma(int branch, const float* __restrict__ w2s,
                                                   int accum) {
    extern __shared__ __align__(16) char sm[];
    char* A_hi = sm;
    char* A_lo = sm + A_TILE_B;
    char* B_hi = sm + 2 * A_TILE_B;
    char* B_lo = sm + 2 * A_TILE_B + B_TILE_B;
    int tid = threadIdx.x;
    int t = blockIdx.y, hw0 = blockIdx.x * 128;

    int wid = tid >> 5, lane = tid & 31;
    int wm = (wid & 3) * 32;
    int wn = (wid >> 2) * 32;
    uint32_t ah_u = smem_to_u32(A_hi), al_u = smem_to_u32(A_lo);
    uint32_t bh_u = smem_to_u32(B_hi), bl_u = smem_to_u32(B_lo);
    int arow = lane & 15;
    int akoff = (lane >> 4) * 16;
    int brow = (lane & 7) + ((lane & 16) ? 8 : 0);
    int bkoff = ((lane >> 3) & 1) * 16;

    int row = tid >> 1, half = tid & 1;
    float y = g_yv[t * HWSZ + hw0 + row];

    float d[2][4][4] = {};
    for (int kc = 0; kc < 9; kc++) {
        __syncthreads();
        // build gated A tile: row x 32 s (per thread half-row)
        {
            const float* ap = &g_aff[((size_t)t * HWSZ + hw0 + row) * SS + kc * 64 + half * 32];
#pragma unroll
            for (int q = 0; q < 4; q++) {
                float4 a0 = *(const float4*)&ap[q * 8];
                float4 a1 = *(const float4*)&ap[q * 8 + 4];
                float gv[8] = {sigm(y * a0.x) - 0.5f, sigm(y * a0.y) - 0.5f,
                               sigm(y * a0.z) - 0.5f, sigm(y * a0.w) - 0.5f,
                               sigm(y * a1.x) - 0.5f, sigm(y * a1.y) - 0.5f,
                               sigm(y * a1.z) - 0.5f, sigm(y * a1.w) - 0.5f};
                unsigned hs[8], ls[8];
#pragma unroll
                for (int jj = 0; jj < 8; jj++) {
                    unsigned short h, l;
                    bf16_split(gv[jj], h, l);
                    hs[jj] = h; ls[jj] = l;
                }
                uint4 hv, lv;
                hv.x = hs[0] | (hs[1] << 16); hv.y = hs[2] | (hs[3] << 16);
                hv.z = hs[4] | (hs[5] << 16); hv.w = hs[6] | (hs[7] << 16);
                lv.x = ls[0] | (ls[1] << 16); lv.y = ls[2] | (ls[3] << 16);
                lv.z = ls[4] | (ls[5] << 16); lv.w = ls[6] | (ls[7] << 16);
                int off = row * SA + half * 64 + q * 16;
                *(uint4*)(A_hi + off) = hv;
                *(uint4*)(A_lo + off) = lv;
            }
        }
        // B tile: 64 rows(c) x 64 s slice
        {
#pragma unroll
            for (int v = 0; v < 2; v++) {
                int i = v * 256 + tid;
                int br2 = i >> 3, j = i & 7;
                size_t src = (size_t)(t * CCH + br2) * SS + kc * 64 + j * 8;
                *(uint4*)(B_hi + br2 * SA + j * 16) = *(const uint4*)&pb_cs_hi[branch][src];
                *(uint4*)(B_lo + br2 * SA + j * 16) = *(const uint4*)&pb_cs_lo[branch][src];
            }
        }
        __syncthreads();

#pragma unroll
        for (int ks = 0; ks < 4; ks++) {
            int kb = ks * 32;
            uint32_t Ah[2][4], Al[2][4], Bh[4][2], Bl[4][2];
#pragma unroll
            for (int mt = 0; mt < 2; mt++) {
                uint32_t off = (uint32_t)((wm + mt * 16 + arow) * SA + kb + akoff);
                LDSM_X4(Ah[mt][0], Ah[mt][1], Ah[mt][2], Ah[mt][3], ah_u + off);
                LDSM_X4(Al[mt][0], Al[mt][1], Al[mt][2], Al[mt][3], al_u + off);
            }
#pragma unroll
            for (int np = 0; np < 2; np++) {
                uint32_t off = (uint32_t)((wn + np * 16 + brow) * SA + kb + bkoff);
                uint32_t r0, r1, r2, r3;
                LDSM_X4(r0, r1, r2, r3, bh_u + off);
                Bh[np * 2][0] = r0; Bh[np * 2][1] = r1;
                Bh[np * 2 + 1][0] = r2; Bh[np * 2 + 1][1] = r3;
                LDSM_X4(r0, r1, r2, r3, bl_u + off);
                Bl[np * 2][0] = r0; Bl[np * 2][1] = r1;
                Bl[np * 2 + 1][0] = r2; Bl[np * 2 + 1][1] = r3;
            }
#pragma unroll
            for (int mt = 0; mt < 2; mt++)
#pragma unroll
                for (int nt = 0; nt < 4; nt++) {
                    MMA_BF16(d[mt][nt], Ah[mt], Bh[nt]);
                    MMA_BF16(d[mt][nt], Ah[mt], Bl[nt]);
                    MMA_BF16(d[mt][nt], Al[mt], Bh[nt]);
                }
        }
    }

    // stage + scaled (accumulating) store
    __syncthreads();
    float* stage = (float*)sm;
#pragma unroll
    for (int mt = 0; mt < 2; mt++)
#pragma unroll
        for (int nt = 0; nt < 4; nt++)
#pragma unroll
            for (int r = 0; r < 4; r++) {
                int m = wm + mt * 16 + (lane >> 2) + ((r >> 1) & 1) * 8;
                int n = wn + nt * 8 + (lane & 3) * 2 + (r & 1);
                stage[m * STG + n] = d[mt][nt][r];
            }
    __syncthreads();
    float wscale = w2s[branch];
    const float* srow = &stage[row * STG + half * 32];
    float* dst = &g_feat[((size_t)t * HWSZ + hw0 + row) * CCH + half * 32];
#pragma unroll
    for (int q = 0; q < 8; q++) {
        float4 b = *(const float4*)&srow[q * 4];
        float4 o4 = make_float4(b.x * wscale, b.y * wscale, b.z * wscale, b.w * wscale);
        if (accum) {
            float4 p = *(float4*)&dst[q * 4];
            o4.x += p.x; o4.y += p.y; o4.z += p.z; o4.w += p.w;
        }
        *(float4*)&dst[q * 4] = o4;
    }
}

// ---------------- xd = w_down @ x ----------------------------------------------
__global__ void k_xd(const float* __restrict__ x, const float* __restrict__ wd) {
    int idx = blockIdx.x * blockDim.x + threadIdx.x;
    if (idx >= RCC * THWSZ) return;
    int r = idx / THWSZ, pos = idx % THWSZ;
    float acc = 0.0f;
    for (int c = 0; c < CCH; c++) acc = fmaf(wd[r * CCH + c], x[c * THWSZ + pos], acc);
    g_xd[idx] = acc;
}

// ---------------- 3x depthwise 3D convs ------------------------------------------
__global__ void k_agg(const float* __restrict__ w1, const float* __restrict__ b1,
                      const float* __restrict__ w2, const float* __restrict__ b2,
                      const float* __restrict__ w3, const float* __restrict__ b3,
                      const float* __restrict__ wts) {
    int idx = blockIdx.x * blockDim.x + threadIdx.x;
    if (idx >= RCC * THWSZ) return;
    int r = idx / THWSZ;
    int rem = idx % THWSZ;
    int t = rem / HWSZ;
    int hw = rem % HWSZ;
    int h = hw / WWI, w = hw % WWI;
    const float* xb = g_xd + r * THWSZ;
    const float* ws_[3] = {w1, w2, w3};
    const float* bs_[3] = {b1, b2, b3};
    float total = 0.0f;
#pragma unroll
    for (int m = 0; m < 3; m++) {
        int d = m + 1;
        float cs = bs_[m][r];
        const float* wp = ws_[m] + r * 81;
        for (int kt = 0; kt < 9; kt++) {
            int ti = t + kt - 4;
            if (ti < 0 || ti >= TT) continue;
#pragma unroll
            for (int kh = 0; kh < 3; kh++) {
                int hi = h + (kh - 1) * d;
                if (hi < 0 || hi >= HHH) continue;
#pragma unroll
                for (int kw = 0; kw < 3; kw++) {
                    int wi = w + (kw - 1) * d;
                    if (wi < 0 || wi >= WWI) continue;
                    cs = fmaf(xb[ti * HWSZ + hi * WWI + wi], wp[(kt * 3 + kh) * 3 + kw], cs);
                }
            }
        }
        total = fmaf(wts[m], cs, total);
    }
    g_agg[idx] = total;
}

// ---------------- final ----------------------------------------------------------
__global__ void k_final(float* __restrict__ out, const float* __restrict__ wback) {
    int pos = blockIdx.x * 256 + threadIdx.x;
    if (pos >= THWSZ) return;
    float ag0 = g_agg[pos];
    float ag1 = g_agg[THWSZ + pos];
    float ag2 = g_agg[2 * THWSZ + pos];
    float ag3 = g_agg[3 * THWSZ + pos];
    const float4* f4 = (const float4*)&g_feat[(size_t)pos * CCH];
#pragma unroll
    for (int c4 = 0; c4 < 16; c4++) {
        float4 f = f4[c4];
        float fv[4] = {f.x, f.y, f.z, f.w};
#pragma unroll
        for (int u = 0; u < 4; u++) {
            int c = c4 * 4 + u;
            float z = wback[c * 4 + 0] * ag0 + wback[c * 4 + 1] * ag1 +
                      wback[c * 4 + 2] * ag2 + wback[c * 4 + 3] * ag3;
            out[c * THWSZ + pos] = fv[u] * (sigm(z) - 0.5f);
        }
    }
}

extern "C" void kernel_launch(void* const* d_in, const int* in_sizes, int n_in,
                              void* d_out, int out_size) {
    const float* x       = (const float*)d_in[0];
    const float* w_dc2   = (const float*)d_in[1];
    const float* w_ofs_l = (const float*)d_in[2];
    const float* b_ofs_l = (const float*)d_in[3];
    const float* w_ofs_r = (const float*)d_in[4];
    const float* b_ofs_r = (const float*)d_in[5];
    const float* ca_w1   = (const float*)d_in[6];
    const float* ca_w2   = (const float*)d_in[7];
    const float* w_down  = (const float*)d_in[8];
    const float* sa1_w   = (const float*)d_in[9];
    const float* sa1_b   = (const float*)d_in[10];
    const float* sa2_w   = (const float*)d_in[11];
    const float* sa2_b   = (const float*)d_in[12];
    const float* sa3_w   = (const float*)d_in[13];
    const float* sa3_b   = (const float*)d_in[14];
    const float* weights = (const float*)d_in[15];
    const float* weights2= (const float*)d_in[16];
    const float* w_back  = (const float*)d_in[17];
    float* out = (float*)d_out;

    cudaFuncSetAttribute(k_gemm1_mma, cudaFuncAttributeMaxDynamicSharedMemorySize, SMEM_TOT);
    cudaFuncSetAttribute(k_gemm2_mma, cudaFuncAttributeMaxDynamicSharedMemorySize, SMEM_TOT);

    k_x2<<<THWSZ / 128, 256>>>(x, w_dc2);
    k_xt<<<(THWSZ + 255) / 256, 256>>>(x);
    k_offp<<<(NCC * 2 * TT * 2 * SS) / 256, 256>>>(x, w_ofs_l, w_ofs_r);
    k_offred<<<(2 * TT * 2 * SS + 255) / 256, 256>>>(b_ofs_l, b_ofs_r);
    k_sample<<<(2 * TT * 16 * SS) / 256, 256>>>();

    for (int br = 0; br < 2; br++) {
        dim3 g1(HWSZ / 128, NSB, TT);
        k_gemm1_mma<<<g1, 256, SMEM_TOT>>>(br);
        k_stats2<<<(TT * HWSZ + 255) / 256, 256>>>();
        k_y<<<(TT * HWSZ + 255) / 256, 256>>>(ca_w1, ca_w2);
        dim3 g2(HWSZ / 128, TT);
        k_gemm2_mma<<<g2, 256, SMEM_TOT>>>(br, weights2, br);
    }

    k_xd<<<(RCC * THWSZ + 255) / 256, 256>>>(x, w_down);
    k_agg<<<(RCC * THWSZ + 255) / 256, 256>>>(sa1_w, sa1_b, sa2_w, sa2_b, sa3_w, sa3_b, weights);
    k_final<<<(THWSZ + 255) / 256, 256>>>(out, w_back);
}

// round 8
// speedup vs baseline: 2.2799x; 1.2808x over previous
#include <cuda_runtime.h>
#include <cuda_bf16.h>
#include <math.h>
#include <stdint.h>

#define TT 16
#define CCH 64
#define HHH 48
#define WWI 48
#define HWSZ 2304
#define THWSZ 36864
#define WW2 24
#define SS 576
#define RCC 4
#define NCC 16   // channel chunks of 4 in k_offp

typedef unsigned long long u64t;

// ---------------- FFMA2 helpers (k_x2) ----------------
#define FMA_F32X2(d, a, b, c) \
    asm("fma.rn.f32x2 %0, %1, %2, %3;" : "=l"(d) : "l"(a), "l"(b), "l"(c))
#define DUP_F32X2(out, v) \
    asm("mov.b64 %0, {%1, %1};" : "=l"(out) : "r"(v))
#define UNPACK_F32X2(lo, hi, in) \
    asm("mov.b64 {%0, %1}, %2;" : "=r"(lo), "=r"(hi) : "l"(in))
union F4U { float4 f; u64t u[2]; };

// ---------------- mma.sync / ldmatrix helpers ----------------
__device__ __forceinline__ uint32_t smem_to_u32(const void* p) {
    uint32_t a;
    asm("{ .reg .u64 tmp; cvta.to.shared.u64 tmp, %1; cvt.u32.u64 %0, tmp; }"
        : "=r"(a) : "l"(p));
    return a;
}
#define LDSM_X4(r0, r1, r2, r3, addr) \
    asm volatile("ldmatrix.sync.aligned.m8n8.x4.shared.b16 {%0,%1,%2,%3}, [%4];" \
        : "=r"(r0), "=r"(r1), "=r"(r2), "=r"(r3) : "r"(addr))
#define MMA_BF16(d, a, b) \
    asm volatile("mma.sync.aligned.m16n8k16.row.col.f32.bf16.bf16.f32 " \
        "{%0,%1,%2,%3}, {%4,%5,%6,%7}, {%8,%9}, {%0,%1,%2,%3};" \
        : "+f"((d)[0]), "+f"((d)[1]), "+f"((d)[2]), "+f"((d)[3]) \
        : "r"((a)[0]), "r"((a)[1]), "r"((a)[2]), "r"((a)[3]), "r"((b)[0]), "r"((b)[1]))

// smem tile geometry: bf16 rows padded to 72 elems (144 B)
#define SA 144
#define A_TILE_B (128 * SA)   // 18432
#define B_TILE_B (64 * SA)    // 9216
#define SM1_TOT (2 * A_TILE_B + 2 * B_TILE_B)                    // 55296 (gemm1_stats)
#define SM2_TOT (4 * A_TILE_B + 4 * B_TILE_B)                    // 110592 (fused gemm2)
#define STG 68

// ---------------- scratch (device globals; no allocations) ----------------
static __device__ float g_x2[CCH * THWSZ];            // [c][t][h][w]
static __device__ float g_offp[NCC][2 * TT * 2 * SS];
static __device__ float g_off[2 * TT * 2 * SS];
static __device__ __align__(16) unsigned short g_xt_hi[THWSZ * CCH];  // [t][hw][c]
static __device__ __align__(16) unsigned short g_xt_lo[THWSZ * CCH];
static __device__ __align__(16) unsigned short pb_sc_hi[2][TT * SS * CCH]; // [t][s][c]
static __device__ __align__(16) unsigned short pb_sc_lo[2][TT * SS * CCH];
static __device__ __align__(16) unsigned short pb_cs_hi[2][TT * CCH * SS]; // [t][c][s]
static __device__ __align__(16) unsigned short pb_cs_lo[2][TT * CCH * SS];
static __device__ float g_mean[TT * HWSZ];
static __device__ float g_maxv[TT * HWSZ];
static __device__ float g_varv[TT * HWSZ];
static __device__ float g_yv[TT * HWSZ];
static __device__ float g_feat[TT * HWSZ * CCH];      // [t][hw][c]
static __device__ float g_xd[RCC * THWSZ];
static __device__ float g_agg[RCC * THWSZ];

__device__ __forceinline__ float sigm(float v) { return 1.0f / (1.0f + __expf(-v)); }

__device__ __forceinline__ void bf16_split(float v, unsigned short& hs, unsigned short& ls) {
    __nv_bfloat16 h = __float2bfloat16(v);
    float hf = __bfloat162float(h);
    __nv_bfloat16 l = __float2bfloat16(v - hf);
    hs = *(unsigned short*)&h;
    ls = *(unsigned short*)&l;
}

// ---------------- x2 = w_dc2 @ x (FFMA2) -------------------------------------
__device__ __forceinline__ void mma4x8(const float4& a, const F4U& b0, const F4U& b1,
                                       u64t accp[4][4]) {
    float av[4] = {a.x, a.y, a.z, a.w};
    u64t bp[4] = {b0.u[0], b0.u[1], b1.u[0], b1.u[1]};
#pragma unroll
    for (int i = 0; i < 4; i++) {
        u64t ad;
        DUP_F32X2(ad, __float_as_uint(av[i]));
#pragma unroll
        for (int j = 0; j < 4; j++) FMA_F32X2(accp[i][j], ad, bp[j], accp[i][j]);
    }
}
__device__ __forceinline__ void unpack_acc(const u64t accp[4][4], float acc[4][8]) {
#pragma unroll
    for (int i = 0; i < 4; i++)
#pragma unroll
        for (int j = 0; j < 4; j++) {
            unsigned lo, hi;
            UNPACK_F32X2(lo, hi, accp[i][j]);
            acc[i][2 * j] = __uint_as_float(lo);
            acc[i][2 * j + 1] = __uint_as_float(hi);
        }
}

__global__ void __launch_bounds__(256) k_x2(const float* __restrict__ x, const float* __restrict__ w) {
    __shared__ float Ws[64][64];
    __shared__ float Xs[64][128];
    int tid = threadIdx.x;
    int pos0 = blockIdx.x * 128;
#pragma unroll
    for (int v = 0; v < 16; v++) {
        int i = v * 256 + tid;
        Ws[i & 63][i >> 6] = w[i];
    }
#pragma unroll
    for (int v = 0; v < 8; v++) {
        int i = v * 256 + tid;
        int row = i >> 5, col = (i & 31) * 4;
        *(float4*)&Xs[row][col] = *(const float4*)&x[row * THWSZ + pos0 + col];
    }
    __syncthreads();
    int tx = tid & 31, ty = tid >> 5;
    u64t accp[4][4];
#pragma unroll
    for (int i = 0; i < 4; i++)
#pragma unroll
        for (int j = 0; j < 4; j++) accp[i][j] = 0ULL;
    float4 a_c = *(float4*)&Xs[0][tx * 4];
    F4U b0_c, b1_c;
    b0_c.f = *(float4*)&Ws[0][ty * 8];
    b1_c.f = *(float4*)&Ws[0][ty * 8 + 4];
#pragma unroll 7
    for (int k = 0; k < 63; k++) {
        float4 a_n = *(float4*)&Xs[k + 1][tx * 4];
        F4U b0_n, b1_n;
        b0_n.f = *(float4*)&Ws[k + 1][ty * 8];
        b1_n.f = *(float4*)&Ws[k + 1][ty * 8 + 4];
        mma4x8(a_c, b0_c, b1_c, accp);
        a_c = a_n; b0_c = b0_n; b1_c = b1_n;
    }
    mma4x8(a_c, b0_c, b1_c, accp);
    float acc[4][8];
    unpack_acc(accp, acc);
#pragma unroll
    for (int j = 0; j < 8; j++) {
        int o = ty * 8 + j;
        float4 o4 = make_float4(acc[0][j], acc[1][j], acc[2][j], acc[3][j]);
        *(float4*)&g_x2[o * THWSZ + pos0 + tx * 4] = o4;
    }
}

// ---------------- x transpose + bf16 split -----------------------------------
__global__ void __launch_bounds__(256) k_xt(const float* __restrict__ x) {
    int idx = blockIdx.x * 256 + threadIdx.x;
    if (idx >= THWSZ) return;
    unsigned short* dh = &g_xt_hi[(size_t)idx * 64];
    unsigned short* dl = &g_xt_lo[(size_t)idx * 64];
#pragma unroll 8
    for (int c = 0; c < CCH; c++) {
        float v = x[c * THWSZ + idx];
        unsigned short hs, ls;
        bf16_split(v, hs, ls);
        dh[c] = hs; dl[c] = ls;
    }
}

// ------- offset conv partials + reduce ----------------------------------------
__global__ void __launch_bounds__(256) k_offp(const float* __restrict__ x,
                      const float* __restrict__ wl, const float* __restrict__ wr) {
    int idx = blockIdx.x * 256 + threadIdx.x;
    int s = idx % SS;
    int o = (idx / SS) & 1;
    int t = (idx / (2 * SS)) & 15;
    int branch = (idx / (2 * SS * TT)) & 1;
    int cc = idx / (2 * SS * TT * 2);
    int i = s / WW2, j = s % WW2;
    int tsrc = (branch == 0) ? min(t + 1, TT - 1) : max(t - 1, 0);
    const float* wofs = (branch == 0) ? wl : wr;
    float acc = 0.0f;
#pragma unroll
    for (int u = 0; u < 4; u++) {
        int c = cc * 4 + u;
        const float* xp = x + c * THWSZ + t * HWSZ;
        const float* x2p = g_x2 + c * THWSZ + tsrc * HWSZ;
        const float* wp = wofs + (o * CCH + c) * 9;
#pragma unroll
        for (int ki = 0; ki < 3; ki++) {
            int h = 2 * i - 1 + ki;
            if (h < 0 || h >= HHH) continue;
#pragma unroll
            for (int kj = 0; kj < 3; kj++) {
                int w = 2 * j - 1 + kj;
                if (w < 0 || w >= WWI) continue;
                acc = fmaf(xp[h * WWI + w] + x2p[h * WWI + w], wp[ki * 3 + kj], acc);
            }
        }
    }
    g_offp[cc][((branch * TT + t) * 2 + o) * SS + s] = acc;
}

__global__ void k_offred(const float* __restrict__ bl, const float* __restrict__ br_) {
    int i = blockIdx.x * 256 + threadIdx.x;
    if (i >= 2 * TT * 2 * SS) return;
    int branch = i / (TT * 2 * SS);
    int o = (i / SS) & 1;
    float acc = (branch == 0) ? bl[o] : br_[o];
#pragma unroll
    for (int cc = 0; cc < NCC; cc++) acc += g_offp[cc][i];
    g_off[i] = acc;
}

// ------- bilinear grid-sample -> bf16 split parts -----------------------------
__global__ void __launch_bounds__(256) k_sample() {
    int idx = blockIdx.x * 256 + threadIdx.x;
    int s = idx % SS;
    int c4 = (idx / SS) & 15;
    int t = (idx / (SS * 16)) & 15;
    int branch = idx / (SS * 16 * 16);
    int i = s / WW2, j = s % WW2;
    float off0 = g_off[((branch * TT + t) * 2 + 0) * SS + s];
    float off1 = g_off[((branch * TT + t) * 2 + 1) * SS + s];
    float v0 = 2.0f * (float)j + off0;
    float v1 = 2.0f * (float)i + off1;
    float gh = 2.0f * v0 / 23.0f - 1.0f;
    float gw = 2.0f * v1 / 23.0f - 1.0f;
    float xs = ((gh + 1.0f) * 48.0f - 1.0f) * 0.5f;
    float ys = ((gw + 1.0f) * 48.0f - 1.0f) * 0.5f;
    float x0f = floorf(xs), y0f = floorf(ys);
    int x0 = (int)x0f, y0 = (int)y0f;
    float fx = xs - x0f, fy = ys - y0f;
    float wgt[4] = {(1.0f - fx) * (1.0f - fy), fx * (1.0f - fy),
                    (1.0f - fx) * fy, fx * fy};
    int xi[4] = {x0, x0 + 1, x0, x0 + 1};
    int yi[4] = {y0, y0, y0 + 1, y0 + 1};
    float wv[4];
    int id[4];
#pragma unroll
    for (int k = 0; k < 4; k++) {
        bool valid = (xi[k] >= 0) && (xi[k] < WWI) && (yi[k] >= 0) && (yi[k] < HHH);
        wv[k] = valid ? wgt[k] : 0.0f;
        int cy = min(max(yi[k], 0), HHH - 1);
        int cx = min(max(xi[k], 0), WWI - 1);
        id[k] = cy * WWI + cx;
    }
    int tsrc = (branch == 0) ? min(t + 1, TT - 1) : max(t - 1, 0);
#pragma unroll
    for (int u = 0; u < 4; u++) {
        int c = c4 * 4 + u;
        const float* img = g_x2 + c * THWSZ + tsrc * HWSZ;
        float val = wv[0] * img[id[0]] + wv[1] * img[id[1]] +
                    wv[2] * img[id[2]] + wv[3] * img[id[3]];
        unsigned short hs, ls;
        bf16_split(val, hs, ls);
        pb_sc_hi[branch][(t * SS + s) * CCH + c] = hs;
        pb_sc_lo[branch][(t * SS + s) * CCH + c] = ls;
        pb_cs_hi[branch][(t * CCH + c) * SS + s] = hs;
        pb_cs_lo[branch][(t * CCH + c) * SS + s] = ls;
    }
}

// ------- GEMM1-stats: full 576-s strip per block, stats only, NO aff store ----
// block: M=128 hw, K=64 c, N=576 s in 9 chunks. 8 warps. grid (18, 16).
__global__ void __launch_bounds__(256) k_gemm1_stats(int branch) {
    extern __shared__ __align__(16) char sm[];
    char* A_hi = sm;
    char* A_lo = sm + A_TILE_B;
    char* B_hi = sm + 2 * A_TILE_B;
    char* B_lo = sm + 2 * A_TILE_B + B_TILE_B;
    float* red = (float*)(sm + 2 * A_TILE_B);  // reused AFTER last mma
    int tid = threadIdx.x;
    int t = blockIdx.y, hw0 = blockIdx.x * 128;

    // A: 128 rows x 64 c (persistent)
    {
        const uint4* sh = (const uint4*)&g_xt_hi[(size_t)(t * HWSZ + hw0) * 64];
        const uint4* sl = (const uint4*)&g_xt_lo[(size_t)(t * HWSZ + hw0) * 64];
#pragma unroll
        for (int v = 0; v < 4; v++) {
            int i = v * 256 + tid;
            int row = i >> 3, j = i & 7;
            *(uint4*)(A_hi + row * SA + j * 16) = sh[i];
            *(uint4*)(A_lo + row * SA + j * 16) = sl[i];
        }
    }

    int wid = tid >> 5, lane = tid & 31;
    int wm = (wid & 3) * 32;
    int wn = (wid >> 2) * 32;
    uint32_t ah_u = smem_to_u32(A_hi), al_u = smem_to_u32(A_lo);
    uint32_t bh_u = smem_to_u32(B_hi), bl_u = smem_to_u32(B_lo);
    int arow = lane & 15;
    int akoff = (lane >> 4) * 16;
    int brow = (lane & 7) + ((lane & 16) ? 8 : 0);
    int bkoff = ((lane >> 3) & 1) * 16;

    float s_sum[2][2] = {}, s_sq[2][2] = {};
    float s_mx[2][2] = {{-3.4e38f, -3.4e38f}, {-3.4e38f, -3.4e38f}};

    for (int kc = 0; kc < 9; kc++) {
        __syncthreads();
        {
            const uint4* bh = (const uint4*)&pb_sc_hi[branch][(size_t)(t * SS + kc * 64) * 64];
            const uint4* bl = (const uint4*)&pb_sc_lo[branch][(size_t)(t * SS + kc * 64) * 64];
#pragma unroll
            for (int v = 0; v < 2; v++) {
                int i = v * 256 + tid;
                int row = i >> 3, j = i & 7;
                *(uint4*)(B_hi + row * SA + j * 16) = bh[i];
                *(uint4*)(B_lo + row * SA + j * 16) = bl[i];
            }
        }
        __syncthreads();

        float d[2][4][4] = {};
#pragma unroll
        for (int ks = 0; ks < 4; ks++) {
            int kb = ks * 32;
            uint32_t Ah[2][4], Al[2][4], Bh[4][2], Bl[4][2];
#pragma unroll
            for (int mt = 0; mt < 2; mt++) {
                uint32_t off = (uint32_t)((wm + mt * 16 + arow) * SA + kb + akoff);
                LDSM_X4(Ah[mt][0], Ah[mt][1], Ah[mt][2], Ah[mt][3], ah_u + off);
                LDSM_X4(Al[mt][0], Al[mt][1], Al[mt][2], Al[mt][3], al_u + off);
            }
#pragma unroll
            for (int np = 0; np < 2; np++) {
                uint32_t off = (uint32_t)((wn + np * 16 + brow) * SA + kb + bkoff);
                uint32_t r0, r1, r2, r3;
                LDSM_X4(r0, r1, r2, r3, bh_u + off);
                Bh[np * 2][0] = r0; Bh[np * 2][1] = r1;
                Bh[np * 2 + 1][0] = r2; Bh[np * 2 + 1][1] = r3;
                LDSM_X4(r0, r1, r2, r3, bl_u + off);
                Bl[np * 2][0] = r0; Bl[np * 2][1] = r1;
                Bl[np * 2 + 1][0] = r2; Bl[np * 2 + 1][1] = r3;
            }
#pragma unroll
            for (int mt = 0; mt < 2; mt++)
#pragma unroll
                for (int nt = 0; nt < 4; nt++) {
                    MMA_BF16(d[mt][nt], Ah[mt], Bh[nt]);
                    MMA_BF16(d[mt][nt], Ah[mt], Bl[nt]);
                    MMA_BF16(d[mt][nt], Al[mt], Bh[nt]);
                }
        }
        // accumulate stats
#pragma unroll
        for (int mt = 0; mt < 2; mt++)
#pragma unroll
            for (int nt = 0; nt < 4; nt++)
#pragma unroll
                for (int r = 0; r < 4; r++) {
                    int rh = (r >> 1) & 1;
                    float v = d[mt][nt][r];
                    s_sum[mt][rh] += v;
                    s_sq[mt][rh] = fmaf(v, v, s_sq[mt][rh]);
                    s_mx[mt][rh] = fmaxf(s_mx[mt][rh], v);
                }
    }

    // quad reduce over lane&3 (cols)
#pragma unroll
    for (int mt = 0; mt < 2; mt++)
#pragma unroll
        for (int rh = 0; rh < 2; rh++) {
            s_sum[mt][rh] += __shfl_xor_sync(0xFFFFFFFFu, s_sum[mt][rh], 1);
            s_sum[mt][rh] += __shfl_xor_sync(0xFFFFFFFFu, s_sum[mt][rh], 2);
            s_sq[mt][rh] += __shfl_xor_sync(0xFFFFFFFFu, s_sq[mt][rh], 1);
            s_sq[mt][rh] += __shfl_xor_sync(0xFFFFFFFFu, s_sq[mt][rh], 2);
            s_mx[mt][rh] = fmaxf(s_mx[mt][rh], __shfl_xor_sync(0xFFFFFFFFu, s_mx[mt][rh], 1));
            s_mx[mt][rh] = fmaxf(s_mx[mt][rh], __shfl_xor_sync(0xFFFFFFFFu, s_mx[mt][rh], 2));
        }
    __syncthreads();  // all mma reads of B region done -> safe to reuse as red
    if ((lane & 3) == 0) {
        int nw = wid >> 2;
#pragma unroll
        for (int mt = 0; mt < 2; mt++)
#pragma unroll
            for (int rh = 0; rh < 2; rh++) {
                int m = wm + mt * 16 + (lane >> 2) + 8 * rh;
                float* p = &red[(nw * 128 + m) * 3];
                p[0] = s_sum[mt][rh];
                p[1] = s_sq[mt][rh];
                p[2] = s_mx[mt][rh];
            }
    }
    __syncthreads();
    if (tid < 128) {
        int m = tid;
        const float* p0 = &red[m * 3];
        const float* p1 = &red[(128 + m) * 3];
        float sum = p0[0] + p1[0];
        float sq = p0[1] + p1[1];
        float mx = fmaxf(p0[2], p1[2]);
        int o = t * HWSZ + hw0 + m;
        g_mean[o] = sum / 576.0f;
        g_maxv[o] = mx;
        g_varv[o] = (sq - sum * sum / 576.0f) / 575.0f;
    }
}

// ---------------- attention gate -----------------------------------------------
__global__ void k_y(const float* __restrict__ w1, const float* __restrict__ w2) {
    int idx = blockIdx.x * 256 + threadIdx.x;
    if (idx >= TT * HWSZ) return;
    int t = idx / HWSZ;
    int hw = idx % HWSZ;
    int h = hw / WWI, w = hw % WWI;
    float acc = 0.0f;
#pragma unroll
    for (int dh = 0; dh < 3; dh++) {
        int hh = h + dh - 1;
        if (hh < 0 || hh >= HHH) continue;
#pragma unroll
        for (int dw = 0; dw < 3; dw++) {
            int ww = w + dw - 1;
            if (ww < 0 || ww >= WWI) continue;
            int p = t * HWSZ + hh * WWI + ww;
            acc = fmaf(w1[(0 * 3 + dh) * 3 + dw], g_mean[p], acc);
            acc = fmaf(w1[(3 + dh) * 3 + dw], g_maxv[p], acc);
            acc = fmaf(w2[dh * 3 + dw], g_varv[p], acc);
        }
    }
    g_yv[idx] = sigm(acc);
}

// ------- fused GEMM2: recompute aff chunk, gate, multiply. No aff in global. ---
// block: M=128 hw x N=64 c, K=576 s in 9 chunks. 8 warps. grid (18, 16).
__global__ void __launch_bounds__(256) k_gemm2f(int branch, const float* __restrict__ w2s,
                                                int accum) {
    extern __shared__ __align__(16) char sm[];
    char* A1_hi = sm;                                   // xt [128hw x 64c]
    char* A1_lo = sm + A_TILE_B;
    char* B1_hi = sm + 2 * A_TILE_B;                    // part_sc [64s x 64c]
    char* B1_lo = sm + 2 * A_TILE_B + B_TILE_B;
    char* A2_hi = sm + 2 * A_TILE_B + 2 * B_TILE_B;     // gated aff [128hw x 64s]
    char* A2_lo = A2_hi + A_TILE_B;
    char* B2_hi = A2_hi + 2 * A_TILE_B;                 // part_cs [64c x 64s]
    char* B2_lo = B2_hi + B_TILE_B;
    int tid = threadIdx.x;
    int t = blockIdx.y, hw0 = blockIdx.x * 128;

    // A1 persistent load
    {
        const uint4* sh = (const uint4*)&g_xt_hi[(size_t)(t * HWSZ + hw0) * 64];
        const uint4* sl = (const uint4*)&g_xt_lo[(size_t)(t * HWSZ + hw0) * 64];
#pragma unroll
        for (int v = 0; v < 4; v++) {
            int i = v * 256 + tid;
            int row = i >> 3, j = i & 7;
            *(uint4*)(A1_hi + row * SA + j * 16) = sh[i];
            *(uint4*)(A1_lo + row * SA + j * 16) = sl[i];
        }
    }

    int wid = tid >> 5, lane = tid & 31;
    int wm = (wid & 3) * 32;
    int wn = (wid >> 2) * 32;
    uint32_t a1h_u = smem_to_u32(A1_hi), a1l_u = smem_to_u32(A1_lo);
    uint32_t b1h_u = smem_to_u32(B1_hi), b1l_u = smem_to_u32(B1_lo);
    uint32_t a2h_u = smem_to_u32(A2_hi), a2l_u = smem_to_u32(A2_lo);
    uint32_t b2h_u = smem_to_u32(B2_hi), b2l_u = smem_to_u32(B2_lo);
    int arow = lane & 15;
    int akoff = (lane >> 4) * 16;
    int brow = (lane & 7) + ((lane & 16) ? 8 : 0);
    int bkoff = ((lane >> 3) & 1) * 16;

    // y values for this thread's fragment rows
    float yv_[2][2];
#pragma unroll
    for (int mt = 0; mt < 2; mt++)
#pragma unroll
        for (int rh = 0; rh < 2; rh++) {
            int m = wm + mt * 16 + (lane >> 2) + 8 * rh;
            yv_[mt][rh] = g_yv[t * HWSZ + hw0 + m];
        }

    float d2[2][4][4] = {};
    for (int kc = 0; kc < 9; kc++) {
        __syncthreads();
        // B1 chunk (rows s, cols c) and B2 chunk (rows c, cols s slice)
        {
            const uint4* bh = (const uint4*)&pb_sc_hi[branch][(size_t)(t * SS + kc * 64) * 64];
            const uint4* bl = (const uint4*)&pb_sc_lo[branch][(size_t)(t * SS + kc * 64) * 64];
#pragma unroll
            for (int v = 0; v < 2; v++) {
                int i = v * 256 + tid;
                int row = i >> 3, j = i & 7;
                *(uint4*)(B1_hi + row * SA + j * 16) = bh[i];
                *(uint4*)(B1_lo + row * SA + j * 16) = bl[i];
            }
#pragma unroll
            for (int v = 0; v < 2; v++) {
                int i = v * 256 + tid;
                int row = i >> 3, j = i & 7;
                size_t src = (size_t)(t * CCH + row) * SS + kc * 64 + j * 8;
                *(uint4*)(B2_hi + row * SA + j * 16) = *(const uint4*)&pb_cs_hi[branch][src];
                *(uint4*)(B2_lo + row * SA + j * 16) = *(const uint4*)&pb_cs_lo[branch][src];
            }
        }
        __syncthreads();

        // mma1: recompute aff fragment d1 = A1 x B1 (m=hw, n=s, k=c)
        float d1[2][4][4] = {};
#pragma unroll
        for (int ks = 0; ks < 4; ks++) {
            int kb = ks * 32;
            uint32_t Ah[2][4], Al[2][4], Bh[4][2], Bl[4][2];
#pragma unroll
            for (int mt = 0; mt < 2; mt++) {
                uint32_t off = (uint32_t)((wm + mt * 16 + arow) * SA + kb + akoff);
                LDSM_X4(Ah[mt][0], Ah[mt][1], Ah[mt][2], Ah[mt][3], a1h_u + off);
                LDSM_X4(Al[mt][0], Al[mt][1], Al[mt][2], Al[mt][3], a1l_u + off);
            }
#pragma unroll
            for (int np = 0; np < 2; np++) {
                uint32_t off = (uint32_t)((wn + np * 16 + brow) * SA + kb + bkoff);
                uint32_t r0, r1, r2, r3;
                LDSM_X4(r0, r1, r2, r3, b1h_u + off);
                Bh[np * 2][0] = r0; Bh[np * 2][1] = r1;
                Bh[np * 2 + 1][0] = r2; Bh[np * 2 + 1][1] = r3;
                LDSM_X4(r0, r1, r2, r3, b1l_u + off);
                Bl[np * 2][0] = r0; Bl[np * 2][1] = r1;
                Bl[np * 2 + 1][0] = r2; Bl[np * 2 + 1][1] = r3;
            }
#pragma unroll
            for (int mt = 0; mt < 2; mt++)
#pragma unroll
                for (int nt = 0; nt < 4; nt++) {
                    MMA_BF16(d1[mt][nt], Ah[mt], Bh[nt]);
                    MMA_BF16(d1[mt][nt], Ah[mt], Bl[nt]);
                    MMA_BF16(d1[mt][nt], Al[mt], Bh[nt]);
                }
        }

        // gate + split -> A2 smem (rows hw, cols s-in-chunk)
#pragma unroll
        for (int mt = 0; mt < 2; mt++)
#pragma unroll
            for (int nt = 0; nt < 4; nt++)
#pragma unroll
                for (int rh = 0; rh < 2; rh++) {
                    float y = yv_[mt][rh];
                    float g0 = sigm(y * d1[mt][nt][rh * 2 + 0]) - 0.5f;
                    float g1 = sigm(y * d1[mt][nt][rh * 2 + 1]) - 0.5f;
                    unsigned short h0, l0, h1, l1;
                    bf16_split(g0, h0, l0);
                    bf16_split(g1, h1, l1);
                    int m = wm + mt * 16 + (lane >> 2) + 8 * rh;
                    int coff = (wn + nt * 8 + (lane & 3) * 2) * 2;
                    *(uint32_t*)(A2_hi + m * SA + coff) = (uint32_t)h0 | ((uint32_t)h1 << 16);
                    *(uint32_t*)(A2_lo + m * SA + coff) = (uint32_t)l0 | ((uint32_t)l1 << 16);
                }
        __syncthreads();

        // mma2: d2 += A2 x B2 (m=hw, n=c, k=s-chunk)
#pragma unroll
        for (int ks = 0; ks < 4; ks++) {
            int kb = ks * 32;
            uint32_t Ah[2][4], Al[2][4], Bh[4][2], Bl[4][2];
#pragma unroll
            for (int mt = 0; mt < 2; mt++) {
                uint32_t off = (uint32_t)((wm + mt * 16 + arow) * SA + kb + akoff);
                LDSM_X4(Ah[mt][0], Ah[mt][1], Ah[mt][2], Ah[mt][3], a2h_u + off);
                LDSM_X4(Al[mt][0], Al[mt][1], Al[mt][2], Al[mt][3], a2l_u + off);
            }
#pragma unroll
            for (int np = 0; np < 2; np++) {
                uint32_t off = (uint32_t)((wn + np * 16 + brow) * SA + kb + bkoff);
                uint32_t r0, r1, r2, r3;
                LDSM_X4(r0, r1, r2, r3, b2h_u + off);
                Bh[np * 2][0] = r0; Bh[np * 2][1] = r1;
                Bh[np * 2 + 1][0] = r2; Bh[np * 2 + 1][1] = r3;
                LDSM_X4(r0, r1, r2, r3, b2l_u + off);
                Bl[np * 2][0] = r0; Bl[np * 2][1] = r1;
                Bl[np * 2 + 1][0] = r2; Bl[np * 2 + 1][1] = r3;
            }
#pragma unroll
            for (int mt = 0; mt < 2; mt++)
#pragma unroll
                for (int nt = 0; nt < 4; nt++) {
                    MMA_BF16(d2[mt][nt], Ah[mt], Bh[nt]);
                    MMA_BF16(d2[mt][nt], Ah[mt], Bl[nt]);
                    MMA_BF16(d2[mt][nt], Al[mt], Bh[nt]);
                }
        }
    }

    // stage + scaled store
    __syncthreads();
    float* stage = (float*)sm;
#pragma unroll
    for (int mt = 0; mt < 2; mt++)
#pragma unroll
        for (int nt = 0; nt < 4; nt++)
#pragma unroll
            for (int r = 0; r < 4; r++) {
                int m = wm + mt * 16 + (lane >> 2) + ((r >> 1) & 1) * 8;
                int n = wn + nt * 8 + (lane & 3) * 2 + (r & 1);
                stage[m * STG + n] = d2[mt][nt][r];
            }
    __syncthreads();
    float wscale = w2s[branch];
    int row = tid >> 1, half = tid & 1;
    const float* srow = &stage[row * STG + half * 32];
    float* dst = &g_feat[((size_t)t * HWSZ + hw0 + row) * CCH + half * 32];
#pragma unroll
    for (int q = 0; q < 8; q++) {
        float4 b = *(const float4*)&srow[q * 4];
        float4 o4 = make_float4(b.x * wscale, b.y * wscale, b.z * wscale, b.w * wscale);
        if (accum) {
            float4 p = *(float4*)&dst[q * 4];
            o4.x += p.x; o4.y += p.y; o4.z += p.z; o4.w += p.w;
        }
        *(float4*)&dst[q * 4] = o4;
    }
}

// ---------------- xd = w_down @ x ----------------------------------------------
__global__ void k_xd(const float* __restrict__ x, const float* __restrict__ wd) {
    int idx = blockIdx.x * blockDim.x + threadIdx.x;
    if (idx >= RCC * THWSZ) return;
    int r = idx / THWSZ, pos = idx % THWSZ;
    float acc = 0.0f;
    for (int c = 0; c < CCH; c++) acc = fmaf(wd[r * CCH + c], x[c * THWSZ + pos], acc);
    g_xd[idx] = acc;
}

// ---------------- 3x depthwise 3D convs ------------------------------------------
__global__ void k_agg(const float* __restrict__ w1, const float* __restrict__ b1,
                      const float* __restrict__ w2, const float* __restrict__ b2,
                      const float* __restrict__ w3, const float* __restrict__ b3,
                      const float* __restrict__ wts) {
    int idx = blockIdx.x * blockDim.x + threadIdx.x;
    if (idx >= RCC * THWSZ) return;
    int r = idx / THWSZ;
    int rem = idx % THWSZ;
    int t = rem / HWSZ;
    int hw = rem % HWSZ;
    int h = hw / WWI, w = hw % WWI;
    const float* xb = g_xd + r * THWSZ;
    const float* ws_[3] = {w1, w2, w3};
    const float* bs_[3] = {b1, b2, b3};
    float total = 0.0f;
#pragma unroll
    for (int m = 0; m < 3; m++) {
        int d = m + 1;
        float cs = bs_[m][r];
        const float* wp = ws_[m] + r * 81;
        for (int kt = 0; kt < 9; kt++) {
            int ti = t + kt - 4;
            if (ti < 0 || ti >= TT) continue;
#pragma unroll
            for (int kh = 0; kh < 3; kh++) {
                int hi = h + (kh - 1) * d;
                if (hi < 0 || hi >= HHH) continue;
#pragma unroll
                for (int kw = 0; kw < 3; kw++) {
                    int wi = w + (kw - 1) * d;
                    if (wi < 0 || wi >= WWI) continue;
                    cs = fmaf(xb[ti * HWSZ + hi * WWI + wi], wp[(kt * 3 + kh) * 3 + kw], cs);
                }
            }
        }
        total = fmaf(wts[m], cs, total);
    }
    g_agg[idx] = total;
}

// ---------------- final ----------------------------------------------------------
__global__ void k_final(float* __restrict__ out, const float* __restrict__ wback) {
    int pos = blockIdx.x * 256 + threadIdx.x;
    if (pos >= THWSZ) return;
    float ag0 = g_agg[pos];
    float ag1 = g_agg[THWSZ + pos];
    float ag2 = g_agg[2 * THWSZ + pos];
    float ag3 = g_agg[3 * THWSZ + pos];
    const float4* f4 = (const float4*)&g_feat[(size_t)pos * CCH];
#pragma unroll
    for (int c4 = 0; c4 < 16; c4++) {
        float4 f = f4[c4];
        float fv[4] = {f.x, f.y, f.z, f.w};
#pragma unroll
        for (int u = 0; u < 4; u++) {
            int c = c4 * 4 + u;
            float z = wback[c * 4 + 0] * ag0 + wback[c * 4 + 1] * ag1 +
                      wback[c * 4 + 2] * ag2 + wback[c * 4 + 3] * ag3;
            out[c * THWSZ + pos] = fv[u] * (sigm(z) - 0.5f);
        }
    }
}

extern "C" void kernel_launch(void* const* d_in, const int* in_sizes, int n_in,
                              void* d_out, int out_size) {
    const float* x       = (const float*)d_in[0];
    const float* w_dc2   = (const float*)d_in[1];
    const float* w_ofs_l = (const float*)d_in[2];
    const float* b_ofs_l = (const float*)d_in[3];
    const float* w_ofs_r = (const float*)d_in[4];
    const float* b_ofs_r = (const float*)d_in[5];
    const float* ca_w1   = (const float*)d_in[6];
    const float* ca_w2   = (const float*)d_in[7];
    const float* w_down  = (const float*)d_in[8];
    const float* sa1_w   = (const float*)d_in[9];
    const float* sa1_b   = (const float*)d_in[10];
    const float* sa2_w   = (const float*)d_in[11];
    const float* sa2_b   = (const float*)d_in[12];
    const float* sa3_w   = (const float*)d_in[13];
    const float* sa3_b   = (const float*)d_in[14];
    const float* weights = (const float*)d_in[15];
    const float* weights2= (const float*)d_in[16];
    const float* w_back  = (const float*)d_in[17];
    float* out = (float*)d_out;

    cudaFuncSetAttribute(k_gemm1_stats, cudaFuncAttributeMaxDynamicSharedMemorySize, SM1_TOT);
    cudaFuncSetAttribute(k_gemm2f, cudaFuncAttributeMaxDynamicSharedMemorySize, SM2_TOT);

    k_x2<<<THWSZ / 128, 256>>>(x, w_dc2);
    k_xt<<<(THWSZ + 255) / 256, 256>>>(x);
    k_offp<<<(NCC * 2 * TT * 2 * SS) / 256, 256>>>(x, w_ofs_l, w_ofs_r);
    k_offred<<<(2 * TT * 2 * SS + 255) / 256, 256>>>(b_ofs_l, b_ofs_r);
    k_sample<<<(2 * TT * 16 * SS) / 256, 256>>>();

    for (int br = 0; br < 2; br++) {
        dim3 g1(HWSZ / 128, TT);
        k_gemm1_stats<<<g1, 256, SM1_TOT>>>(br);
        k_y<<<(TT * HWSZ + 255) / 256, 256>>>(ca_w1, ca_w2);
        k_gemm2f<<<g1, 256, SM2_TOT>>>(br, weights2, br);
    }

    k_xd<<<(RCC * THWSZ + 255) / 256, 256>>>(x, w_down);
    k_agg<<<(RCC * THWSZ + 255) / 256, 256>>>(sa1_w, sa1_b, sa2_w, sa2_b, sa3_w, sa3_b, weights);
    k_final<<<(THWSZ + 255) / 256, 256>>>(out, w_back);
}

// round 9
// speedup vs baseline: 2.3652x; 1.0374x over previous
#include <cuda_runtime.h>
#include <cuda_bf16.h>
#include <math.h>
#include <stdint.h>

#define TT 16
#define CCH 64
#define HHH 48
#define WWI 48
#define HWSZ 2304
#define THWSZ 36864
#define WW2 24
#define SS 576
#define RCC 4
#define NCC 16   // channel chunks of 4 in k_offp

typedef unsigned long long u64t;

// ---------------- FFMA2 helpers (k_x2) ----------------
#define FMA_F32X2(d, a, b, c) \
    asm("fma.rn.f32x2 %0, %1, %2, %3;" : "=l"(d) : "l"(a), "l"(b), "l"(c))
#define DUP_F32X2(out, v) \
    asm("mov.b64 %0, {%1, %1};" : "=l"(out) : "r"(v))
#define UNPACK_F32X2(lo, hi, in) \
    asm("mov.b64 {%0, %1}, %2;" : "=r"(lo), "=r"(hi) : "l"(in))
union F4U { float4 f; u64t u[2]; };

// ---------------- mma.sync / ldmatrix helpers ----------------
__device__ __forceinline__ uint32_t smem_to_u32(const void* p) {
    uint32_t a;
    asm("{ .reg .u64 tmp; cvta.to.shared.u64 tmp, %1; cvt.u32.u64 %0, tmp; }"
        : "=r"(a) : "l"(p));
    return a;
}
#define LDSM_X4(r0, r1, r2, r3, addr) \
    asm volatile("ldmatrix.sync.aligned.m8n8.x4.shared.b16 {%0,%1,%2,%3}, [%4];" \
        : "=r"(r0), "=r"(r1), "=r"(r2), "=r"(r3) : "r"(addr))
#define MMA_BF16(d, a, b) \
    asm volatile("mma.sync.aligned.m16n8k16.row.col.f32.bf16.bf16.f32 " \
        "{%0,%1,%2,%3}, {%4,%5,%6,%7}, {%8,%9}, {%0,%1,%2,%3};" \
        : "+f"((d)[0]), "+f"((d)[1]), "+f"((d)[2]), "+f"((d)[3]) \
        : "r"((a)[0]), "r"((a)[1]), "r"((a)[2]), "r"((a)[3]), "r"((b)[0]), "r"((b)[1]))

// smem tile geometry: bf16 rows padded to 72 elems (144 B)
#define SA 144
#define A_TILE_B (128 * SA)   // 18432
#define B_TILE_B (64 * SA)    // 9216
#define SM1_TOT (2 * A_TILE_B + 2 * B_TILE_B)                    // 55296
#define SM2_TOT (4 * A_TILE_B + 4 * B_TILE_B)                    // 110592
#define STG 68

// ---------------- scratch (device globals; no allocations) ----------------
static __device__ float g_x2[CCH * THWSZ];            // [c][t][h][w]
static __device__ float g_offp[NCC][2 * TT * 2 * SS];
static __device__ float g_off[2 * TT * 2 * SS];
static __device__ __align__(16) unsigned short g_xt_hi[THWSZ * CCH];  // [t][hw][c]
static __device__ __align__(16) unsigned short g_xt_lo[THWSZ * CCH];
static __device__ __align__(16) unsigned short pb_sc_hi[2][TT * SS * CCH]; // [t][s][c]
static __device__ __align__(16) unsigned short pb_sc_lo[2][TT * SS * CCH];
static __device__ __align__(16) unsigned short pb_cs_hi[2][TT * CCH * SS]; // [t][c][s]
static __device__ __align__(16) unsigned short pb_cs_lo[2][TT * CCH * SS];
static __device__ float g_mean[2][TT * HWSZ];
static __device__ float g_maxv[2][TT * HWSZ];
static __device__ float g_varv[2][TT * HWSZ];
static __device__ float g_yv[2][TT * HWSZ];
static __device__ float g_featb[2][TT * HWSZ * CCH]; // [branch][t][hw][c]
static __device__ float g_xd[RCC * THWSZ];
static __device__ float g_agg[RCC * THWSZ];

__device__ __forceinline__ float sigm(float v) { return 1.0f / (1.0f + __expf(-v)); }

__device__ __forceinline__ void bf16_split(float v, unsigned short& hs, unsigned short& ls) {
    __nv_bfloat16 h = __float2bfloat16(v);
    float hf = __bfloat162float(h);
    __nv_bfloat16 l = __float2bfloat16(v - hf);
    hs = *(unsigned short*)&h;
    ls = *(unsigned short*)&l;
}

// ---------------- x2 = w_dc2 @ x (FFMA2) -------------------------------------
__device__ __forceinline__ void mma4x8(const float4& a, const F4U& b0, const F4U& b1,
                                       u64t accp[4][4]) {
    float av[4] = {a.x, a.y, a.z, a.w};
    u64t bp[4] = {b0.u[0], b0.u[1], b1.u[0], b1.u[1]};
#pragma unroll
    for (int i = 0; i < 4; i++) {
        u64t ad;
        DUP_F32X2(ad, __float_as_uint(av[i]));
#pragma unroll
        for (int j = 0; j < 4; j++) FMA_F32X2(accp[i][j], ad, bp[j], accp[i][j]);
    }
}
__device__ __forceinline__ void unpack_acc(const u64t accp[4][4], float acc[4][8]) {
#pragma unroll
    for (int i = 0; i < 4; i++)
#pragma unroll
        for (int j = 0; j < 4; j++) {
            unsigned lo, hi;
            UNPACK_F32X2(lo, hi, accp[i][j]);
            acc[i][2 * j] = __uint_as_float(lo);
            acc[i][2 * j + 1] = __uint_as_float(hi);
        }
}

__global__ void __launch_bounds__(256) k_x2(const float* __restrict__ x, const float* __restrict__ w) {
    __shared__ float Ws[64][64];
    __shared__ float Xs[64][128];
    int tid = threadIdx.x;
    int pos0 = blockIdx.x * 128;
#pragma unroll
    for (int v = 0; v < 16; v++) {
        int i = v * 256 + tid;
        Ws[i & 63][i >> 6] = w[i];
    }
#pragma unroll
    for (int v = 0; v < 8; v++) {
        int i = v * 256 + tid;
        int row = i >> 5, col = (i & 31) * 4;
        *(float4*)&Xs[row][col] = *(const float4*)&x[row * THWSZ + pos0 + col];
    }
    __syncthreads();
    int tx = tid & 31, ty = tid >> 5;
    u64t accp[4][4];
#pragma unroll
    for (int i = 0; i < 4; i++)
#pragma unroll
        for (int j = 0; j < 4; j++) accp[i][j] = 0ULL;
    float4 a_c = *(float4*)&Xs[0][tx * 4];
    F4U b0_c, b1_c;
    b0_c.f = *(float4*)&Ws[0][ty * 8];
    b1_c.f = *(float4*)&Ws[0][ty * 8 + 4];
#pragma unroll 7
    for (int k = 0; k < 63; k++) {
        float4 a_n = *(float4*)&Xs[k + 1][tx * 4];
        F4U b0_n, b1_n;
        b0_n.f = *(float4*)&Ws[k + 1][ty * 8];
        b1_n.f = *(float4*)&Ws[k + 1][ty * 8 + 4];
        mma4x8(a_c, b0_c, b1_c, accp);
        a_c = a_n; b0_c = b0_n; b1_c = b1_n;
    }
    mma4x8(a_c, b0_c, b1_c, accp);
    float acc[4][8];
    unpack_acc(accp, acc);
#pragma unroll
    for (int j = 0; j < 8; j++) {
        int o = ty * 8 + j;
        float4 o4 = make_float4(acc[0][j], acc[1][j], acc[2][j], acc[3][j]);
        *(float4*)&g_x2[o * THWSZ + pos0 + tx * 4] = o4;
    }
}

// ---------------- x transpose + bf16 split -----------------------------------
__global__ void __launch_bounds__(256) k_xt(const float* __restrict__ x) {
    int idx = blockIdx.x * 256 + threadIdx.x;
    if (idx >= THWSZ) return;
    unsigned short* dh = &g_xt_hi[(size_t)idx * 64];
    unsigned short* dl = &g_xt_lo[(size_t)idx * 64];
#pragma unroll 8
    for (int c = 0; c < CCH; c++) {
        float v = x[c * THWSZ + idx];
        unsigned short hs, ls;
        bf16_split(v, hs, ls);
        dh[c] = hs; dl[c] = ls;
    }
}

// ------- offset conv partials + reduce ----------------------------------------
__global__ void __launch_bounds__(256) k_offp(const float* __restrict__ x,
                      const float* __restrict__ wl, const float* __restrict__ wr) {
    int idx = blockIdx.x * 256 + threadIdx.x;
    int s = idx % SS;
    int o = (idx / SS) & 1;
    int t = (idx / (2 * SS)) & 15;
    int branch = (idx / (2 * SS * TT)) & 1;
    int cc = idx / (2 * SS * TT * 2);
    int i = s / WW2, j = s % WW2;
    int tsrc = (branch == 0) ? min(t + 1, TT - 1) : max(t - 1, 0);
    const float* wofs = (branch == 0) ? wl : wr;
    float acc = 0.0f;
#pragma unroll
    for (int u = 0; u < 4; u++) {
        int c = cc * 4 + u;
        const float* xp = x + c * THWSZ + t * HWSZ;
        const float* x2p = g_x2 + c * THWSZ + tsrc * HWSZ;
        const float* wp = wofs + (o * CCH + c) * 9;
#pragma unroll
        for (int ki = 0; ki < 3; ki++) {
            int h = 2 * i - 1 + ki;
            if (h < 0 || h >= HHH) continue;
#pragma unroll
            for (int kj = 0; kj < 3; kj++) {
                int w = 2 * j - 1 + kj;
                if (w < 0 || w >= WWI) continue;
                acc = fmaf(xp[h * WWI + w] + x2p[h * WWI + w], wp[ki * 3 + kj], acc);
            }
        }
    }
    g_offp[cc][((branch * TT + t) * 2 + o) * SS + s] = acc;
}

__global__ void k_offred(const float* __restrict__ bl, const float* __restrict__ br_) {
    int i = blockIdx.x * 256 + threadIdx.x;
    if (i >= 2 * TT * 2 * SS) return;
    int branch = i / (TT * 2 * SS);
    int o = (i / SS) & 1;
    float acc = (branch == 0) ? bl[o] : br_[o];
#pragma unroll
    for (int cc = 0; cc < NCC; cc++) acc += g_offp[cc][i];
    g_off[i] = acc;
}

// ------- bilinear grid-sample -> bf16 split parts -----------------------------
__global__ void __launch_bounds__(256) k_sample() {
    int idx = blockIdx.x * 256 + threadIdx.x;
    int s = idx % SS;
    int c4 = (idx / SS) & 15;
    int t = (idx / (SS * 16)) & 15;
    int branch = idx / (SS * 16 * 16);
    int i = s / WW2, j = s % WW2;
    float off0 = g_off[((branch * TT + t) * 2 + 0) * SS + s];
    float off1 = g_off[((branch * TT + t) * 2 + 1) * SS + s];
    float v0 = 2.0f * (float)j + off0;
    float v1 = 2.0f * (float)i + off1;
    float gh = 2.0f * v0 / 23.0f - 1.0f;
    float gw = 2.0f * v1 / 23.0f - 1.0f;
    float xs = ((gh + 1.0f) * 48.0f - 1.0f) * 0.5f;
    float ys = ((gw + 1.0f) * 48.0f - 1.0f) * 0.5f;
    float x0f = floorf(xs), y0f = floorf(ys);
    int x0 = (int)x0f, y0 = (int)y0f;
    float fx = xs - x0f, fy = ys - y0f;
    float wgt[4] = {(1.0f - fx) * (1.0f - fy), fx * (1.0f - fy),
                    (1.0f - fx) * fy, fx * fy};
    int xi[4] = {x0, x0 + 1, x0, x0 + 1};
    int yi[4] = {y0, y0, y0 + 1, y0 + 1};
    float wv[4];
    int id[4];
#pragma unroll
    for (int k = 0; k < 4; k++) {
        bool valid = (xi[k] >= 0) && (xi[k] < WWI) && (yi[k] >= 0) && (yi[k] < HHH);
        wv[k] = valid ? wgt[k] : 0.0f;
        int cy = min(max(yi[k], 0), HHH - 1);
        int cx = min(max(xi[k], 0), WWI - 1);
        id[k] = cy * WWI + cx;
    }
    int tsrc = (branch == 0) ? min(t + 1, TT - 1) : max(t - 1, 0);
#pragma unroll
    for (int u = 0; u < 4; u++) {
        int c = c4 * 4 + u;
        const float* img = g_x2 + c * THWSZ + tsrc * HWSZ;
        float val = wv[0] * img[id[0]] + wv[1] * img[id[1]] +
                    wv[2] * img[id[2]] + wv[3] * img[id[3]];
        unsigned short hs, ls;
        bf16_split(val, hs, ls);
        pb_sc_hi[branch][(t * SS + s) * CCH + c] = hs;
        pb_sc_lo[branch][(t * SS + s) * CCH + c] = ls;
        pb_cs_hi[branch][(t * CCH + c) * SS + s] = hs;
        pb_cs_lo[branch][(t * CCH + c) * SS + s] = ls;
    }
}

// ------- GEMM1-stats: both branches in one launch -----------------------------
// block: M=128 hw, K=64 c, N=576 s in 9 chunks. grid (18, 16, 2).
__global__ void __launch_bounds__(256) k_gemm1_stats() {
    extern __shared__ __align__(16) char sm[];
    char* A_hi = sm;
    char* A_lo = sm + A_TILE_B;
    char* B_hi = sm + 2 * A_TILE_B;
    char* B_lo = sm + 2 * A_TILE_B + B_TILE_B;
    float* red = (float*)(sm + 2 * A_TILE_B);
    int tid = threadIdx.x;
    int t = blockIdx.y, hw0 = blockIdx.x * 128, branch = blockIdx.z;

    {
        const uint4* sh = (const uint4*)&g_xt_hi[(size_t)(t * HWSZ + hw0) * 64];
        const uint4* sl = (const uint4*)&g_xt_lo[(size_t)(t * HWSZ + hw0) * 64];
#pragma unroll
        for (int v = 0; v < 4; v++) {
            int i = v * 256 + tid;
            int row = i >> 3, j = i & 7;
            *(uint4*)(A_hi + row * SA + j * 16) = sh[i];
            *(uint4*)(A_lo + row * SA + j * 16) = sl[i];
        }
    }

    int wid = tid >> 5, lane = tid & 31;
    int wm = (wid & 3) * 32;
    int wn = (wid >> 2) * 32;
    uint32_t ah_u = smem_to_u32(A_hi), al_u = smem_to_u32(A_lo);
    uint32_t bh_u = smem_to_u32(B_hi), bl_u = smem_to_u32(B_lo);
    int arow = lane & 15;
    int akoff = (lane >> 4) * 16;
    int brow = (lane & 7) + ((lane & 16) ? 8 : 0);
    int bkoff = ((lane >> 3) & 1) * 16;

    float s_sum[2][2] = {}, s_sq[2][2] = {};
    float s_mx[2][2] = {{-3.4e38f, -3.4e38f}, {-3.4e38f, -3.4e38f}};

    for (int kc = 0; kc < 9; kc++) {
        __syncthreads();
        {
            const uint4* bh = (const uint4*)&pb_sc_hi[branch][(size_t)(t * SS + kc * 64) * 64];
            const uint4* bl = (const uint4*)&pb_sc_lo[branch][(size_t)(t * SS + kc * 64) * 64];
#pragma unroll
            for (int v = 0; v < 2; v++) {
                int i = v * 256 + tid;
                int row = i >> 3, j = i & 7;
                *(uint4*)(B_hi + row * SA + j * 16) = bh[i];
                *(uint4*)(B_lo + row * SA + j * 16) = bl[i];
            }
        }
        __syncthreads();

        float d[2][4][4] = {};
#pragma unroll
        for (int ks = 0; ks < 4; ks++) {
            int kb = ks * 32;
            uint32_t Ah[2][4], Al[2][4], Bh[4][2], Bl[4][2];
#pragma unroll
            for (int mt = 0; mt < 2; mt++) {
                uint32_t off = (uint32_t)((wm + mt * 16 + arow) * SA + kb + akoff);
                LDSM_X4(Ah[mt][0], Ah[mt][1], Ah[mt][2], Ah[mt][3], ah_u + off);
                LDSM_X4(Al[mt][0], Al[mt][1], Al[mt][2], Al[mt][3], al_u + off);
            }
#pragma unroll
            for (int np = 0; np < 2; np++) {
                uint32_t off = (uint32_t)((wn + np * 16 + brow) * SA + kb + bkoff);
                uint32_t r0, r1, r2, r3;
                LDSM_X4(r0, r1, r2, r3, bh_u + off);
                Bh[np * 2][0] = r0; Bh[np * 2][1] = r1;
                Bh[np * 2 + 1][0] = r2; Bh[np * 2 + 1][1] = r3;
                LDSM_X4(r0, r1, r2, r3, bl_u + off);
                Bl[np * 2][0] = r0; Bl[np * 2][1] = r1;
                Bl[np * 2 + 1][0] = r2; Bl[np * 2 + 1][1] = r3;
            }
#pragma unroll
            for (int mt = 0; mt < 2; mt++)
#pragma unroll
                for (int nt = 0; nt < 4; nt++) {
                    MMA_BF16(d[mt][nt], Ah[mt], Bh[nt]);
                    MMA_BF16(d[mt][nt], Ah[mt], Bl[nt]);
                    MMA_BF16(d[mt][nt], Al[mt], Bh[nt]);
                }
        }
#pragma unroll
        for (int mt = 0; mt < 2; mt++)
#pragma unroll
            for (int nt = 0; nt < 4; nt++)
#pragma unroll
                for (int r = 0; r < 4; r++) {
                    int rh = (r >> 1) & 1;
                    float v = d[mt][nt][r];
                    s_sum[mt][rh] += v;
                    s_sq[mt][rh] = fmaf(v, v, s_sq[mt][rh]);
                    s_mx[mt][rh] = fmaxf(s_mx[mt][rh], v);
                }
    }

#pragma unroll
    for (int mt = 0; mt < 2; mt++)
#pragma unroll
        for (int rh = 0; rh < 2; rh++) {
            s_sum[mt][rh] += __shfl_xor_sync(0xFFFFFFFFu, s_sum[mt][rh], 1);
            s_sum[mt][rh] += __shfl_xor_sync(0xFFFFFFFFu, s_sum[mt][rh], 2);
            s_sq[mt][rh] += __shfl_xor_sync(0xFFFFFFFFu, s_sq[mt][rh], 1);
            s_sq[mt][rh] += __shfl_xor_sync(0xFFFFFFFFu, s_sq[mt][rh], 2);
            s_mx[mt][rh] = fmaxf(s_mx[mt][rh], __shfl_xor_sync(0xFFFFFFFFu, s_mx[mt][rh], 1));
            s_mx[mt][rh] = fmaxf(s_mx[mt][rh], __shfl_xor_sync(0xFFFFFFFFu, s_mx[mt][rh], 2));
        }
    __syncthreads();
    if ((lane & 3) == 0) {
        int nw = wid >> 2;
#pragma unroll
        for (int mt = 0; mt < 2; mt++)
#pragma unroll
            for (int rh = 0; rh < 2; rh++) {
                int m = wm + mt * 16 + (lane >> 2) + 8 * rh;
                float* p = &red[(nw * 128 + m) * 3];
                p[0] = s_sum[mt][rh];
                p[1] = s_sq[mt][rh];
                p[2] = s_mx[mt][rh];
            }
    }
    __syncthreads();
    if (tid < 128) {
        int m = tid;
        const float* p0 = &red[m * 3];
        const float* p1 = &red[(128 + m) * 3];
        float sum = p0[0] + p1[0];
        float sq = p0[1] + p1[1];
        float mx = fmaxf(p0[2], p1[2]);
        int o = t * HWSZ + hw0 + m;
        g_mean[branch][o] = sum / 576.0f;
        g_maxv[branch][o] = mx;
        g_varv[branch][o] = (sq - sum * sum / 576.0f) / 575.0f;
    }
}

// ---------------- attention gate (both branches) --------------------------------
__global__ void k_y(const float* __restrict__ w1, const float* __restrict__ w2) {
    int gidx = blockIdx.x * 256 + threadIdx.x;
    if (gidx >= 2 * TT * HWSZ) return;
    int branch = gidx / (TT * HWSZ);
    int idx = gidx % (TT * HWSZ);
    int t = idx / HWSZ;
    int hw = idx % HWSZ;
    int h = hw / WWI, w = hw % WWI;
    float acc = 0.0f;
#pragma unroll
    for (int dh = 0; dh < 3; dh++) {
        int hh = h + dh - 1;
        if (hh < 0 || hh >= HHH) continue;
#pragma unroll
        for (int dw = 0; dw < 3; dw++) {
            int ww = w + dw - 1;
            if (ww < 0 || ww >= WWI) continue;
            int p = t * HWSZ + hh * WWI + ww;
            acc = fmaf(w1[(0 * 3 + dh) * 3 + dw], g_mean[branch][p], acc);
            acc = fmaf(w1[(3 + dh) * 3 + dw], g_maxv[branch][p], acc);
            acc = fmaf(w2[dh * 3 + dw], g_varv[branch][p], acc);
        }
    }
    g_yv[branch][idx] = sigm(acc);
}

// ------- fused GEMM2, both branches, no accumulate -----------------------------
// grid (18, 16, 2).
__global__ void __launch_bounds__(256) k_gemm2f(const float* __restrict__ w2s) {
    extern __shared__ __align__(16) char sm[];
    char* A1_hi = sm;
    char* A1_lo = sm + A_TILE_B;
    char* B1_hi = sm + 2 * A_TILE_B;
    char* B1_lo = sm + 2 * A_TILE_B + B_TILE_B;
    char* A2_hi = sm + 2 * A_TILE_B + 2 * B_TILE_B;
    char* A2_lo = A2_hi + A_TILE_B;
    char* B2_hi = A2_hi + 2 * A_TILE_B;
    char* B2_lo = B2_hi + B_TILE_B;
    int tid = threadIdx.x;
    int t = blockIdx.y, hw0 = blockIdx.x * 128, branch = blockIdx.z;

    {
        const uint4* sh = (const uint4*)&g_xt_hi[(size_t)(t * HWSZ + hw0) * 64];
        const uint4* sl = (const uint4*)&g_xt_lo[(size_t)(t * HWSZ + hw0) * 64];
#pragma unroll
        for (int v = 0; v < 4; v++) {
            int i = v * 256 + tid;
            int row = i >> 3, j = i & 7;
            *(uint4*)(A1_hi + row * SA + j * 16) = sh[i];
            *(uint4*)(A1_lo + row * SA + j * 16) = sl[i];
        }
    }

    int wid = tid >> 5, lane = tid & 31;
    int wm = (wid & 3) * 32;
    int wn = (wid >> 2) * 32;
    uint32_t a1h_u = smem_to_u32(A1_hi), a1l_u = smem_to_u32(A1_lo);
    uint32_t b1h_u = smem_to_u32(B1_hi), b1l_u = smem_to_u32(B1_lo);
    uint32_t a2h_u = smem_to_u32(A2_hi), a2l_u = smem_to_u32(A2_lo);
    uint32_t b2h_u = smem_to_u32(B2_hi), b2l_u = smem_to_u32(B2_lo);
    int arow = lane & 15;
    int akoff = (lane >> 4) * 16;
    int brow = (lane & 7) + ((lane & 16) ? 8 : 0);
    int bkoff = ((lane >> 3) & 1) * 16;

    float yv_[2][2];
#pragma unroll
    for (int mt = 0; mt < 2; mt++)
#pragma unroll
        for (int rh = 0; rh < 2; rh++) {
            int m = wm + mt * 16 + (lane >> 2) + 8 * rh;
            yv_[mt][rh] = g_yv[branch][t * HWSZ + hw0 + m];
        }

    float d2[2][4][4] = {};
    for (int kc = 0; kc < 9; kc++) {
        __syncthreads();
        {
            const uint4* bh = (const uint4*)&pb_sc_hi[branch][(size_t)(t * SS + kc * 64) * 64];
            const uint4* bl = (const uint4*)&pb_sc_lo[branch][(size_t)(t * SS + kc * 64) * 64];
#pragma unroll
            for (int v = 0; v < 2; v++) {
                int i = v * 256 + tid;
                int row = i >> 3, j = i & 7;
                *(uint4*)(B1_hi + row * SA + j * 16) = bh[i];
                *(uint4*)(B1_lo + row * SA + j * 16) = bl[i];
            }
#pragma unroll
            for (int v = 0; v < 2; v++) {
                int i = v * 256 + tid;
                int row = i >> 3, j = i & 7;
                size_t src = (size_t)(t * CCH + row) * SS + kc * 64 + j * 8;
                *(uint4*)(B2_hi + row * SA + j * 16) = *(const uint4*)&pb_cs_hi[branch][src];
                *(uint4*)(B2_lo + row * SA + j * 16) = *(const uint4*)&pb_cs_lo[branch][src];
            }
        }
        __syncthreads();

        float d1[2][4][4] = {};
#pragma unroll
        for (int ks = 0; ks < 4; ks++) {
            int kb = ks * 32;
            uint32_t Ah[2][4], Al[2][4], Bh[4][2], Bl[4][2];
#pragma unroll
            for (int mt = 0; mt < 2; mt++) {
                uint32_t off = (uint32_t)((wm + mt * 16 + arow) * SA + kb + akoff);
                LDSM_X4(Ah[mt][0], Ah[mt][1], Ah[mt][2], Ah[mt][3], a1h_u + off);
                LDSM_X4(Al[mt][0], Al[mt][1], Al[mt][2], Al[mt][3], a1l_u + off);
            }
#pragma unroll
            for (int np = 0; np < 2; np++) {
                uint32_t off = (uint32_t)((wn + np * 16 + brow) * SA + kb + bkoff);
                uint32_t r0, r1, r2, r3;
                LDSM_X4(r0, r1, r2, r3, b1h_u + off);
                Bh[np * 2][0] = r0; Bh[np * 2][1] = r1;
                Bh[np * 2 + 1][0] = r2; Bh[np * 2 + 1][1] = r3;
                LDSM_X4(r0, r1, r2, r3, b1l_u + off);
                Bl[np * 2][0] = r0; Bl[np * 2][1] = r1;
                Bl[np * 2 + 1][0] = r2; Bl[np * 2 + 1][1] = r3;
            }
#pragma unroll
            for (int mt = 0; mt < 2; mt++)
#pragma unroll
                for (int nt = 0; nt < 4; nt++) {
                    MMA_BF16(d1[mt][nt], Ah[mt], Bh[nt]);
                    MMA_BF16(d1[mt][nt], Ah[mt], Bl[nt]);
                    MMA_BF16(d1[mt][nt], Al[mt], Bh[nt]);
                }
        }

#pragma unroll
        for (int mt = 0; mt < 2; mt++)
#pragma unroll
            for (int nt = 0; nt < 4; nt++)
#pragma unroll
                for (int rh = 0; rh < 2; rh++) {
                    float y = yv_[mt][rh];
                    float g0 = sigm(y * d1[mt][nt][rh * 2 + 0]) - 0.5f;
                    float g1 = sigm(y * d1[mt][nt][rh * 2 + 1]) - 0.5f;
                    unsigned short h0, l0, h1, l1;
                    bf16_split(g0, h0, l0);
                    bf16_split(g1, h1, l1);
                    int m = wm + mt * 16 + (lane >> 2) + 8 * rh;
                    int coff = (wn + nt * 8 + (lane & 3) * 2) * 2;
                    *(uint32_t*)(A2_hi + m * SA + coff) = (uint32_t)h0 | ((uint32_t)h1 << 16);
                    *(uint32_t*)(A2_lo + m * SA + coff) = (uint32_t)l0 | ((uint32_t)l1 << 16);
                }
        __syncthreads();

#pragma unroll
        for (int ks = 0; ks < 4; ks++) {
            int kb = ks * 32;
            uint32_t Ah[2][4], Al[2][4], Bh[4][2], Bl[4][2];
#pragma unroll
            for (int mt = 0; mt < 2; mt++) {
                uint32_t off = (uint32_t)((wm + mt * 16 + arow) * SA + kb + akoff);
                LDSM_X4(Ah[mt][0], Ah[mt][1], Ah[mt][2], Ah[mt][3], a2h_u + off);
                LDSM_X4(Al[mt][0], Al[mt][1], Al[mt][2], Al[mt][3], a2l_u + off);
            }
#pragma unroll
            for (int np = 0; np < 2; np++) {
                uint32_t off = (uint32_t)((wn + np * 16 + brow) * SA + kb + bkoff);
                uint32_t r0, r1, r2, r3;
                LDSM_X4(r0, r1, r2, r3, b2h_u + off);
                Bh[np * 2][0] = r0; Bh[np * 2][1] = r1;
                Bh[np * 2 + 1][0] = r2; Bh[np * 2 + 1][1] = r3;
                LDSM_X4(r0, r1, r2, r3, b2l_u + off);
                Bl[np * 2][0] = r0; Bl[np * 2][1] = r1;
                Bl[np * 2 + 1][0] = r2; Bl[np * 2 + 1][1] = r3;
            }
#pragma unroll
            for (int mt = 0; mt < 2; mt++)
#pragma unroll
                for (int nt = 0; nt < 4; nt++) {
                    MMA_BF16(d2[mt][nt], Ah[mt], Bh[nt]);
                    MMA_BF16(d2[mt][nt], Ah[mt], Bl[nt]);
                    MMA_BF16(d2[mt][nt], Al[mt], Bh[nt]);
                }
        }
    }

    __syncthreads();
    float* stage = (float*)sm;
#pragma unroll
    for (int mt = 0; mt < 2; mt++)
#pragma unroll
        for (int nt = 0; nt < 4; nt++)
#pragma unroll
            for (int r = 0; r < 4; r++) {
                int m = wm + mt * 16 + (lane >> 2) + ((r >> 1) & 1) * 8;
                int n = wn + nt * 8 + (lane & 3) * 2 + (r & 1);
                stage[m * STG + n] = d2[mt][nt][r];
            }
    __syncthreads();
    float wscale = w2s[branch];
    int row = tid >> 1, half = tid & 1;
    const float* srow = &stage[row * STG + half * 32];
    float* dst = &g_featb[branch][((size_t)t * HWSZ + hw0 + row) * CCH + half * 32];
#pragma unroll
    for (int q = 0; q < 8; q++) {
        float4 b = *(const float4*)&srow[q * 4];
        float4 o4 = make_float4(b.x * wscale, b.y * wscale, b.z * wscale, b.w * wscale);
        *(float4*)&dst[q * 4] = o4;
    }
}

// ---------------- xd = w_down @ x (one thread per pos, 4 outputs) ---------------
__global__ void k_xd(const float* __restrict__ x, const float* __restrict__ wd) {
    int pos = blockIdx.x * blockDim.x + threadIdx.x;
    if (pos >= THWSZ) return;
    float a0 = 0.0f, a1 = 0.0f, a2 = 0.0f, a3 = 0.0f;
    for (int c = 0; c < CCH; c++) {
        float v = x[c * THWSZ + pos];
        a0 = fmaf(wd[c], v, a0);
        a1 = fmaf(wd[CCH + c], v, a1);
        a2 = fmaf(wd[2 * CCH + c], v, a2);
        a3 = fmaf(wd[3 * CCH + c], v, a3);
    }
    g_xd[pos] = a0;
    g_xd[THWSZ + pos] = a1;
    g_xd[2 * THWSZ + pos] = a2;
    g_xd[3 * THWSZ + pos] = a3;
}

// ---------------- 3x depthwise 3D convs ------------------------------------------
__global__ void k_agg(const float* __restrict__ w1, const float* __restrict__ b1,
                      const float* __restrict__ w2, const float* __restrict__ b2,
                      const float* __restrict__ w3, const float* __restrict__ b3,
                      const float* __restrict__ wts) {
    int idx = blockIdx.x * blockDim.x + threadIdx.x;
    if (idx >= RCC * THWSZ) return;
    int r = idx / THWSZ;
    int rem = idx % THWSZ;
    int t = rem / HWSZ;
    int hw = rem % HWSZ;
    int h = hw / WWI, w = hw % WWI;
    const float* xb = g_xd + r * THWSZ;
    const float* ws_[3] = {w1, w2, w3};
    const float* bs_[3] = {b1, b2, b3};
    float total = 0.0f;
#pragma unroll
    for (int m = 0; m < 3; m++) {
        int d = m + 1;
        float cs = bs_[m][r];
        const float* wp = ws_[m] + r * 81;
        for (int kt = 0; kt < 9; kt++) {
            int ti = t + kt - 4;
            if (ti < 0 || ti >= TT) continue;
#pragma unroll
            for (int kh = 0; kh < 3; kh++) {
                int hi = h + (kh - 1) * d;
                if (hi < 0 || hi >= HHH) continue;
#pragma unroll
                for (int kw = 0; kw < 3; kw++) {
                    int wi = w + (kw - 1) * d;
                    if (wi < 0 || wi >= WWI) continue;
                    cs = fmaf(xb[ti * HWSZ + hi * WWI + wi], wp[(kt * 3 + kh) * 3 + kw], cs);
                }
            }
        }
        total = fmaf(wts[m], cs, total);
    }
    g_agg[idx] = total;
}

// ---------------- final ----------------------------------------------------------
__global__ void k_final(float* __restrict__ out, const float* __restrict__ wback) {
    int pos = blockIdx.x * 256 + threadIdx.x;
    if (pos >= THWSZ) return;
    float ag0 = g_agg[pos];
    float ag1 = g_agg[THWSZ + pos];
    float ag2 = g_agg[2 * THWSZ + pos];
    float ag3 = g_agg[3 * THWSZ + pos];
    const float4* f0 = (const float4*)&g_featb[0][(size_t)pos * CCH];
    const float4* f1 = (const float4*)&g_featb[1][(size_t)pos * CCH];
#pragma unroll
    for (int c4 = 0; c4 < 16; c4++) {
        float4 a = f0[c4];
        float4 b = f1[c4];
        float fv[4] = {a.x + b.x, a.y + b.y, a.z + b.z, a.w + b.w};
#pragma unroll
        for (int u = 0; u < 4; u++) {
            int c = c4 * 4 + u;
            float z = wback[c * 4 + 0] * ag0 + wback[c * 4 + 1] * ag1 +
                      wback[c * 4 + 2] * ag2 + wback[c * 4 + 3] * ag3;
            out[c * THWSZ + pos] = fv[u] * (sigm(z) - 0.5f);
        }
    }
}

extern "C" void kernel_launch(void* const* d_in, const int* in_sizes, int n_in,
                              void* d_out, int out_size) {
    const float* x       = (const float*)d_in[0];
    const float* w_dc2   = (const float*)d_in[1];
    const float* w_ofs_l = (const float*)d_in[2];
    const float* b_ofs_l = (const float*)d_in[3];
    const float* w_ofs_r = (const float*)d_in[4];
    const float* b_ofs_r = (const float*)d_in[5];
    const float* ca_w1   = (const float*)d_in[6];
    const float* ca_w2   = (const float*)d_in[7];
    const float* w_down  = (const float*)d_in[8];
    const float* sa1_w   = (const float*)d_in[9];
    const float* sa1_b   = (const float*)d_in[10];
    const float* sa2_w   = (const float*)d_in[11];
    const float* sa2_b   = (const float*)d_in[12];
    const float* sa3_w   = (const float*)d_in[13];
    const float* sa3_b   = (const float*)d_in[14];
    const float* weights = (const float*)d_in[15];
    const float* weights2= (const float*)d_in[16];
    const float* w_back  = (const float*)d_in[17];
    float* out = (float*)d_out;

    cudaFuncSetAttribute(k_gemm1_stats, cudaFuncAttributeMaxDynamicSharedMemorySize, SM1_TOT);
    cudaFuncSetAttribute(k_gemm2f, cudaFuncAttributeMaxDynamicSharedMemorySize, SM2_TOT);

    k_x2<<<THWSZ / 128, 256>>>(x, w_dc2);
    k_xt<<<(THWSZ + 255) / 256, 256>>>(x);
    k_offp<<<(NCC * 2 * TT * 2 * SS) / 256, 256>>>(x, w_ofs_l, w_ofs_r);
    k_offred<<<(2 * TT * 2 * SS + 255) / 256, 256>>>(b_ofs_l, b_ofs_r);
    k_sample<<<(2 * TT * 16 * SS) / 256, 256>>>();

    dim3 gg(HWSZ / 128, TT, 2);
    k_gemm1_stats<<<gg, 256, SM1_TOT>>>();
    k_y<<<(2 * TT * HWSZ + 255) / 256, 256>>>(ca_w1, ca_w2);
    k_gemm2f<<<gg, 256, SM2_TOT>>>(weights2);

    k_xd<<<(THWSZ + 255) / 256, 256>>>(x, w_down);
    k_agg<<<(RCC * THWSZ + 255) / 256, 256>>>(sa1_w, sa1_b, sa2_w, sa2_b, sa3_w, sa3_b, weights);
    k_final<<<(THWSZ + 255) / 256, 256>>>(out, w_back);
}

// round 10
// speedup vs baseline: 2.7524x; 1.1637x over previous
#include <cuda_runtime.h>
#include <cuda_fp16.h>
#include <math.h>
#include <stdint.h>

#define TT 16
#define CCH 64
#define HHH 48
#define WWI 48
#define HWSZ 2304
#define THWSZ 36864
#define WW2 24
#define SS 576
#define RCC 4
#define NCC 16   // channel chunks of 4 in k_offp

typedef unsigned long long u64t;

// ---------------- FFMA2 helpers (k_x2) ----------------
#define FMA_F32X2(d, a, b, c) \
    asm("fma.rn.f32x2 %0, %1, %2, %3;" : "=l"(d) : "l"(a), "l"(b), "l"(c))
#define DUP_F32X2(out, v) \
    asm("mov.b64 %0, {%1, %1};" : "=l"(out) : "r"(v))
#define UNPACK_F32X2(lo, hi, in) \
    asm("mov.b64 {%0, %1}, %2;" : "=r"(lo), "=r"(hi) : "l"(in))
union F4U { float4 f; u64t u[2]; };

// ---------------- mma.sync / ldmatrix helpers ----------------
__device__ __forceinline__ uint32_t smem_to_u32(const void* p) {
    uint32_t a;
    asm("{ .reg .u64 tmp; cvta.to.shared.u64 tmp, %1; cvt.u32.u64 %0, tmp; }"
        : "=r"(a) : "l"(p));
    return a;
}
#define LDSM_X4(r0, r1, r2, r3, addr) \
    asm volatile("ldmatrix.sync.aligned.m8n8.x4.shared.b16 {%0,%1,%2,%3}, [%4];" \
        : "=r"(r0), "=r"(r1), "=r"(r2), "=r"(r3) : "r"(addr))
#define MMA_F16(d, a, b) \
    asm volatile("mma.sync.aligned.m16n8k16.row.col.f32.f16.f16.f32 " \
        "{%0,%1,%2,%3}, {%4,%5,%6,%7}, {%8,%9}, {%0,%1,%2,%3};" \
        : "+f"((d)[0]), "+f"((d)[1]), "+f"((d)[2]), "+f"((d)[3]) \
        : "r"((a)[0]), "r"((a)[1]), "r"((a)[2]), "r"((a)[3]), "r"((b)[0]), "r"((b)[1]))

// smem tile geometry: fp16 rows padded to 72 elems (144 B)
#define SA 144
#define A_TILE_B (128 * SA)   // 18432
#define B_TILE_B (64 * SA)    // 9216
#define SM1_TOT (2 * A_TILE_B + B_TILE_B)                 // 46080
#define SM2_TOT (4 * A_TILE_B + 2 * B_TILE_B)             // 92160
#define STG 68

// ---------------- scratch (device globals; no allocations) ----------------
static __device__ float g_x2[CCH * THWSZ];            // [c][t][h][w]
static __device__ float g_offp[NCC][2 * TT * 2 * SS];
static __device__ float g_off[2 * TT * 2 * SS];
static __device__ __align__(16) unsigned short g_xt_hi[THWSZ * CCH];  // fp16 [t][hw][c]
static __device__ __align__(16) unsigned short g_xt_lo[THWSZ * CCH];
static __device__ __align__(16) unsigned short pb_sc_hi[2][TT * SS * CCH]; // fp16 [t][s][c]
static __device__ __align__(16) unsigned short pb_cs_hi[2][TT * CCH * SS]; // fp16 [t][c][s]
static __device__ float g_mean[2][TT * HWSZ];
static __device__ float g_maxv[2][TT * HWSZ];
static __device__ float g_varv[2][TT * HWSZ];
static __device__ float g_yv[2][TT * HWSZ];
static __device__ float g_featb[2][TT * HWSZ * CCH]; // [branch][t][hw][c]
static __device__ float g_xd[RCC * THWSZ];
static __device__ float g_agg[RCC * THWSZ];

__device__ __forceinline__ float sigm(float v) { return 1.0f / (1.0f + __expf(-v)); }

__device__ __forceinline__ void f16_split(float v, unsigned short& hs, unsigned short& ls) {
    __half h = __float2half_rn(v);
    float hf = __half2float(h);
    __half l = __float2half_rn(v - hf);
    hs = *(unsigned short*)&h;
    ls = *(unsigned short*)&l;
}
__device__ __forceinline__ unsigned short f16_of(float v) {
    __half h = __float2half_rn(v);
    return *(unsigned short*)&h;
}

// ---------------- x2 = w_dc2 @ x (FFMA2) -------------------------------------
__device__ __forceinline__ void mma4x8(const float4& a, const F4U& b0, const F4U& b1,
                                       u64t accp[4][4]) {
    float av[4] = {a.x, a.y, a.z, a.w};
    u64t bp[4] = {b0.u[0], b0.u[1], b1.u[0], b1.u[1]};
#pragma unroll
    for (int i = 0; i < 4; i++) {
        u64t ad;
        DUP_F32X2(ad, __float_as_uint(av[i]));
#pragma unroll
        for (int j = 0; j < 4; j++) FMA_F32X2(accp[i][j], ad, bp[j], accp[i][j]);
    }
}
__device__ __forceinline__ void unpack_acc(const u64t accp[4][4], float acc[4][8]) {
#pragma unroll
    for (int i = 0; i < 4; i++)
#pragma unroll
        for (int j = 0; j < 4; j++) {
            unsigned lo, hi;
            UNPACK_F32X2(lo, hi, accp[i][j]);
            acc[i][2 * j] = __uint_as_float(lo);
            acc[i][2 * j + 1] = __uint_as_float(hi);
        }
}

__global__ void __launch_bounds__(256) k_x2(const float* __restrict__ x, const float* __restrict__ w) {
    __shared__ float Ws[64][64];
    __shared__ float Xs[64][128];
    int tid = threadIdx.x;
    int pos0 = blockIdx.x * 128;
#pragma unroll
    for (int v = 0; v < 16; v++) {
        int i = v * 256 + tid;
        Ws[i & 63][i >> 6] = w[i];
    }
#pragma unroll
    for (int v = 0; v < 8; v++) {
        int i = v * 256 + tid;
        int row = i >> 5, col = (i & 31) * 4;
        *(float4*)&Xs[row][col] = *(const float4*)&x[row * THWSZ + pos0 + col];
    }
    __syncthreads();
    int tx = tid & 31, ty = tid >> 5;
    u64t accp[4][4];
#pragma unroll
    for (int i = 0; i < 4; i++)
#pragma unroll
        for (int j = 0; j < 4; j++) accp[i][j] = 0ULL;
    float4 a_c = *(float4*)&Xs[0][tx * 4];
    F4U b0_c, b1_c;
    b0_c.f = *(float4*)&Ws[0][ty * 8];
    b1_c.f = *(float4*)&Ws[0][ty * 8 + 4];
#pragma unroll 7
    for (int k = 0; k < 63; k++) {
        float4 a_n = *(float4*)&Xs[k + 1][tx * 4];
        F4U b0_n, b1_n;
        b0_n.f = *(float4*)&Ws[k + 1][ty * 8];
        b1_n.f = *(float4*)&Ws[k + 1][ty * 8 + 4];
        mma4x8(a_c, b0_c, b1_c, accp);
        a_c = a_n; b0_c = b0_n; b1_c = b1_n;
    }
    mma4x8(a_c, b0_c, b1_c, accp);
    float acc[4][8];
    unpack_acc(accp, acc);
#pragma unroll
    for (int j = 0; j < 8; j++) {
        int o = ty * 8 + j;
        float4 o4 = make_float4(acc[0][j], acc[1][j], acc[2][j], acc[3][j]);
        *(float4*)&g_x2[o * THWSZ + pos0 + tx * 4] = o4;
    }
}

// ---------------- x transpose + fp16 split -----------------------------------
__global__ void __launch_bounds__(256) k_xt(const float* __restrict__ x) {
    int idx = blockIdx.x * 256 + threadIdx.x;
    if (idx >= THWSZ) return;
    unsigned short* dh = &g_xt_hi[(size_t)idx * 64];
    unsigned short* dl = &g_xt_lo[(size_t)idx * 64];
#pragma unroll 8
    for (int c = 0; c < CCH; c++) {
        float v = x[c * THWSZ + idx];
        unsigned short hs, ls;
        f16_split(v, hs, ls);
        dh[c] = hs; dl[c] = ls;
    }
}

// ------- offset conv partials + reduce ----------------------------------------
__global__ void __launch_bounds__(256) k_offp(const float* __restrict__ x,
                      const float* __restrict__ wl, const float* __restrict__ wr) {
    int idx = blockIdx.x * 256 + threadIdx.x;
    int s = idx % SS;
    int o = (idx / SS) & 1;
    int t = (idx / (2 * SS)) & 15;
    int branch = (idx / (2 * SS * TT)) & 1;
    int cc = idx / (2 * SS * TT * 2);
    int i = s / WW2, j = s % WW2;
    int tsrc = (branch == 0) ? min(t + 1, TT - 1) : max(t - 1, 0);
    const float* wofs = (branch == 0) ? wl : wr;
    float acc = 0.0f;
#pragma unroll
    for (int u = 0; u < 4; u++) {
        int c = cc * 4 + u;
        const float* xp = x + c * THWSZ + t * HWSZ;
        const float* x2p = g_x2 + c * THWSZ + tsrc * HWSZ;
        const float* wp = wofs + (o * CCH + c) * 9;
#pragma unroll
        for (int ki = 0; ki < 3; ki++) {
            int h = 2 * i - 1 + ki;
            if (h < 0 || h >= HHH) continue;
#pragma unroll
            for (int kj = 0; kj < 3; kj++) {
                int w = 2 * j - 1 + kj;
                if (w < 0 || w >= WWI) continue;
                acc = fmaf(xp[h * WWI + w] + x2p[h * WWI + w], wp[ki * 3 + kj], acc);
            }
        }
    }
    g_offp[cc][((branch * TT + t) * 2 + o) * SS + s] = acc;
}

__global__ void k_offred(const float* __restrict__ bl, const float* __restrict__ br_) {
    int i = blockIdx.x * 256 + threadIdx.x;
    if (i >= 2 * TT * 2 * SS) return;
    int branch = i / (TT * 2 * SS);
    int o = (i / SS) & 1;
    float acc = (branch == 0) ? bl[o] : br_[o];
#pragma unroll
    for (int cc = 0; cc < NCC; cc++) acc += g_offp[cc][i];
    g_off[i] = acc;
}

// ------- bilinear grid-sample -> fp16 parts ------------------------------------
__global__ void __launch_bounds__(256) k_sample() {
    int idx = blockIdx.x * 256 + threadIdx.x;
    int s = idx % SS;
    int c4 = (idx / SS) & 15;
    int t = (idx / (SS * 16)) & 15;
    int branch = idx / (SS * 16 * 16);
    int i = s / WW2, j = s % WW2;
    float off0 = g_off[((branch * TT + t) * 2 + 0) * SS + s];
    float off1 = g_off[((branch * TT + t) * 2 + 1) * SS + s];
    float v0 = 2.0f * (float)j + off0;
    float v1 = 2.0f * (float)i + off1;
    float gh = 2.0f * v0 / 23.0f - 1.0f;
    float gw = 2.0f * v1 / 23.0f - 1.0f;
    float xs = ((gh + 1.0f) * 48.0f - 1.0f) * 0.5f;
    float ys = ((gw + 1.0f) * 48.0f - 1.0f) * 0.5f;
    float x0f = floorf(xs), y0f = floorf(ys);
    int x0 = (int)x0f, y0 = (int)y0f;
    float fx = xs - x0f, fy = ys - y0f;
    float wgt[4] = {(1.0f - fx) * (1.0f - fy), fx * (1.0f - fy),
                    (1.0f - fx) * fy, fx * fy};
    int xi[4] = {x0, x0 + 1, x0, x0 + 1};
    int yi[4] = {y0, y0, y0 + 1, y0 + 1};
    float wv[4];
    int id[4];
#pragma unroll
    for (int k = 0; k < 4; k++) {
        bool valid = (xi[k] >= 0) && (xi[k] < WWI) && (yi[k] >= 0) && (yi[k] < HHH);
        wv[k] = valid ? wgt[k] : 0.0f;
        int cy = min(max(yi[k], 0), HHH - 1);
        int cx = min(max(xi[k], 0), WWI - 1);
        id[k] = cy * WWI + cx;
    }
    int tsrc = (branch == 0) ? min(t + 1, TT - 1) : max(t - 1, 0);
#pragma unroll
    for (int u = 0; u < 4; u++) {
        int c = c4 * 4 + u;
        const float* img = g_x2 + c * THWSZ + tsrc * HWSZ;
        float val = wv[0] * img[id[0]] + wv[1] * img[id[1]] +
                    wv[2] * img[id[2]] + wv[3] * img[id[3]];
        unsigned short hs = f16_of(val);
        pb_sc_hi[branch][(t * SS + s) * CCH + c] = hs;
        pb_cs_hi[branch][(t * CCH + c) * SS + s] = hs;
    }
}

// ------- GEMM1-stats: 2-pass fp16, both branches -------------------------------
// grid (18, 16, 2), 256 thr, 2 CTA/SM.
__global__ void __launch_bounds__(256, 2) k_gemm1_stats() {
    extern __shared__ __align__(16) char sm[];
    char* A_hi = sm;
    char* A_lo = sm + A_TILE_B;
    char* B_hi = sm + 2 * A_TILE_B;
    float* red = (float*)(sm + 2 * A_TILE_B);  // reused after last mma
    int tid = threadIdx.x;
    int t = blockIdx.y, hw0 = blockIdx.x * 128, branch = blockIdx.z;

    {
        const uint4* sh = (const uint4*)&g_xt_hi[(size_t)(t * HWSZ + hw0) * 64];
        const uint4* sl = (const uint4*)&g_xt_lo[(size_t)(t * HWSZ + hw0) * 64];
#pragma unroll
        for (int v = 0; v < 4; v++) {
            int i = v * 256 + tid;
            int row = i >> 3, j = i & 7;
            *(uint4*)(A_hi + row * SA + j * 16) = sh[i];
            *(uint4*)(A_lo + row * SA + j * 16) = sl[i];
        }
    }

    int wid = tid >> 5, lane = tid & 31;
    int wm = (wid & 3) * 32;
    int wn = (wid >> 2) * 32;
    uint32_t ah_u = smem_to_u32(A_hi), al_u = smem_to_u32(A_lo);
    uint32_t bh_u = smem_to_u32(B_hi);
    int arow = lane & 15;
    int akoff = (lane >> 4) * 16;
    int brow = (lane & 7) + ((lane & 16) ? 8 : 0);
    int bkoff = ((lane >> 3) & 1) * 16;

    float s_sum[2][2] = {}, s_sq[2][2] = {};
    float s_mx[2][2] = {{-3.4e38f, -3.4e38f}, {-3.4e38f, -3.4e38f}};

    for (int kc = 0; kc < 9; kc++) {
        __syncthreads();
        {
            const uint4* bh = (const uint4*)&pb_sc_hi[branch][(size_t)(t * SS + kc * 64) * 64];
#pragma unroll
            for (int v = 0; v < 2; v++) {
                int i = v * 256 + tid;
                int row = i >> 3, j = i & 7;
                *(uint4*)(B_hi + row * SA + j * 16) = bh[i];
            }
        }
        __syncthreads();

        float d[2][4][4] = {};
#pragma unroll
        for (int ks = 0; ks < 4; ks++) {
            int kb = ks * 32;
            uint32_t Ah[2][4], Al[2][4], Bh[4][2];
#pragma unroll
            for (int mt = 0; mt < 2; mt++) {
                uint32_t off = (uint32_t)((wm + mt * 16 + arow) * SA + kb + akoff);
                LDSM_X4(Ah[mt][0], Ah[mt][1], Ah[mt][2], Ah[mt][3], ah_u + off);
                LDSM_X4(Al[mt][0], Al[mt][1], Al[mt][2], Al[mt][3], al_u + off);
            }
#pragma unroll
            for (int np = 0; np < 2; np++) {
                uint32_t off = (uint32_t)((wn + np * 16 + brow) * SA + kb + bkoff);
                uint32_t r0, r1, r2, r3;
                LDSM_X4(r0, r1, r2, r3, bh_u + off);
                Bh[np * 2][0] = r0; Bh[np * 2][1] = r1;
                Bh[np * 2 + 1][0] = r2; Bh[np * 2 + 1][1] = r3;
            }
#pragma unroll
            for (int mt = 0; mt < 2; mt++)
#pragma unroll
                for (int nt = 0; nt < 4; nt++) {
                    MMA_F16(d[mt][nt], Ah[mt], Bh[nt]);
                    MMA_F16(d[mt][nt], Al[mt], Bh[nt]);
                }
        }
#pragma unroll
        for (int mt = 0; mt < 2; mt++)
#pragma unroll
            for (int nt = 0; nt < 4; nt++)
#pragma unroll
                for (int r = 0; r < 4; r++) {
                    int rh = (r >> 1) & 1;
                    float v = d[mt][nt][r];
                    s_sum[mt][rh] += v;
                    s_sq[mt][rh] = fmaf(v, v, s_sq[mt][rh]);
                    s_mx[mt][rh] = fmaxf(s_mx[mt][rh], v);
                }
    }

#pragma unroll
    for (int mt = 0; mt < 2; mt++)
#pragma unroll
        for (int rh = 0; rh < 2; rh++) {
            s_sum[mt][rh] += __shfl_xor_sync(0xFFFFFFFFu, s_sum[mt][rh], 1);
            s_sum[mt][rh] += __shfl_xor_sync(0xFFFFFFFFu, s_sum[mt][rh], 2);
            s_sq[mt][rh] += __shfl_xor_sync(0xFFFFFFFFu, s_sq[mt][rh], 1);
            s_sq[mt][rh] += __shfl_xor_sync(0xFFFFFFFFu, s_sq[mt][rh], 2);
            s_mx[mt][rh] = fmaxf(s_mx[mt][rh], __shfl_xor_sync(0xFFFFFFFFu, s_mx[mt][rh], 1));
            s_mx[mt][rh] = fmaxf(s_mx[mt][rh], __shfl_xor_sync(0xFFFFFFFFu, s_mx[mt][rh], 2));
        }
    __syncthreads();
    if ((lane & 3) == 0) {
        int nw = wid >> 2;
#pragma unroll
        for (int mt = 0; mt < 2; mt++)
#pragma unroll
            for (int rh = 0; rh < 2; rh++) {
                int m = wm + mt * 16 + (lane >> 2) + 8 * rh;
                float* p = &red[(nw * 128 + m) * 3];
                p[0] = s_sum[mt][rh];
                p[1] = s_sq[mt][rh];
                p[2] = s_mx[mt][rh];
            }
    }
    __syncthreads();
    if (tid < 128) {
        int m = tid;
        const float* p0 = &red[m * 3];
        const float* p1 = &red[(128 + m) * 3];
        float sum = p0[0] + p1[0];
        float sq = p0[1] + p1[1];
        float mx = fmaxf(p0[2], p1[2]);
        int o = t * HWSZ + hw0 + m;
        g_mean[branch][o] = sum / 576.0f;
        g_maxv[branch][o] = mx;
        g_varv[branch][o] = (sq - sum * sum / 576.0f) / 575.0f;
    }
}

// ---------------- attention gate (both branches) --------------------------------
__global__ void k_y(const float* __restrict__ w1, const float* __restrict__ w2) {
    int gidx = blockIdx.x * 256 + threadIdx.x;
    if (gidx >= 2 * TT * HWSZ) return;
    int branch = gidx / (TT * HWSZ);
    int idx = gidx % (TT * HWSZ);
    int t = idx / HWSZ;
    int hw = idx % HWSZ;
    int h = hw / WWI, w = hw % WWI;
    float acc = 0.0f;
#pragma unroll
    for (int dh = 0; dh < 3; dh++) {
        int hh = h + dh - 1;
        if (hh < 0 || hh >= HHH) continue;
#pragma unroll
        for (int dw = 0; dw < 3; dw++) {
            int ww = w + dw - 1;
            if (ww < 0 || ww >= WWI) continue;
            int p = t * HWSZ + hh * WWI + ww;
            acc = fmaf(w1[(0 * 3 + dh) * 3 + dw], g_mean[branch][p], acc);
            acc = fmaf(w1[(3 + dh) * 3 + dw], g_maxv[branch][p], acc);
            acc = fmaf(w2[dh * 3 + dw], g_varv[branch][p], acc);
        }
    }
    g_yv[branch][idx] = sigm(acc);
}

// ------- fused GEMM2: 2-pass fp16, recompute aff, gate, multiply ----------------
// grid (18, 16, 2), 256 thr, 2 CTA/SM.
__global__ void __launch_bounds__(256, 2) k_gemm2f(const float* __restrict__ w2s) {
    extern __shared__ __align__(16) char sm[];
    char* A1_hi = sm;
    char* A1_lo = sm + A_TILE_B;
    char* B1_hi = sm + 2 * A_TILE_B;
    char* A2_hi = sm + 2 * A_TILE_B + B_TILE_B;
    char* A2_lo = A2_hi + A_TILE_B;
    char* B2_hi = A2_hi + 2 * A_TILE_B;
    int tid = threadIdx.x;
    int t = blockIdx.y, hw0 = blockIdx.x * 128, branch = blockIdx.z;

    {
        const uint4* sh = (const uint4*)&g_xt_hi[(size_t)(t * HWSZ + hw0) * 64];
        const uint4* sl = (const uint4*)&g_xt_lo[(size_t)(t * HWSZ + hw0) * 64];
#pragma unroll
        for (int v = 0; v < 4; v++) {
            int i = v * 256 + tid;
            int row = i >> 3, j = i & 7;
            *(uint4*)(A1_hi + row * SA + j * 16) = sh[i];
            *(uint4*)(A1_lo + row * SA + j * 16) = sl[i];
        }
    }

    int wid = tid >> 5, lane = tid & 31;
    int wm = (wid & 3) * 32;
    int wn = (wid >> 2) * 32;
    uint32_t a1h_u = smem_to_u32(A1_hi), a1l_u = smem_to_u32(A1_lo);
    uint32_t b1h_u = smem_to_u32(B1_hi);
    uint32_t a2h_u = smem_to_u32(A2_hi), a2l_u = smem_to_u32(A2_lo);
    uint32_t b2h_u = smem_to_u32(B2_hi);
    int arow = lane & 15;
    int akoff = (lane >> 4) * 16;
    int brow = (lane & 7) + ((lane & 16) ? 8 : 0);
    int bkoff = ((lane >> 3) & 1) * 16;

    float yv_[2][2];
#pragma unroll
    for (int mt = 0; mt < 2; mt++)
#pragma unroll
        for (int rh = 0; rh < 2; rh++) {
            int m = wm + mt * 16 + (lane >> 2) + 8 * rh;
            yv_[mt][rh] = g_yv[branch][t * HWSZ + hw0 + m];
        }

    float d2[2][4][4] = {};
    for (int kc = 0; kc < 9; kc++) {
        __syncthreads();
        {
            const uint4* bh = (const uint4*)&pb_sc_hi[branch][(size_t)(t * SS + kc * 64) * 64];
#pragma unroll
            for (int v = 0; v < 2; v++) {
                int i = v * 256 + tid;
                int row = i >> 3, j = i & 7;
                *(uint4*)(B1_hi + row * SA + j * 16) = bh[i];
            }
#pragma unroll
            for (int v = 0; v < 2; v++) {
                int i = v * 256 + tid;
                int row = i >> 3, j = i & 7;
                size_t src = (size_t)(t * CCH + row) * SS + kc * 64 + j * 8;
                *(uint4*)(B2_hi + row * SA + j * 16) = *(const uint4*)&pb_cs_hi[branch][src];
            }
        }
        __syncthreads();

        float d1[2][4][4] = {};
#pragma unroll
        for (int ks = 0; ks < 4; ks++) {
            int kb = ks * 32;
            uint32_t Ah[2][4], Al[2][4], Bh[4][2];
#pragma unroll
            for (int mt = 0; mt < 2; mt++) {
                uint32_t off = (uint32_t)((wm + mt * 16 + arow) * SA + kb + akoff);
                LDSM_X4(Ah[mt][0], Ah[mt][1], Ah[mt][2], Ah[mt][3], a1h_u + off);
                LDSM_X4(Al[mt][0], Al[mt][1], Al[mt][2], Al[mt][3], a1l_u + off);
            }
#pragma unroll
            for (int np = 0; np < 2; np++) {
                uint32_t off = (uint32_t)((wn + np * 16 + brow) * SA + kb + bkoff);
                uint32_t r0, r1, r2, r3;
                LDSM_X4(r0, r1, r2, r3, b1h_u + off);
                Bh[np * 2][0] = r0; Bh[np * 2][1] = r1;
                Bh[np * 2 + 1][0] = r2; Bh[np * 2 + 1][1] = r3;
            }
#pragma unroll
            for (int mt = 0; mt < 2; mt++)
#pragma unroll
                for (int nt = 0; nt < 4; nt++) {
                    MMA_F16(d1[mt][nt], Ah[mt], Bh[nt]);
                    MMA_F16(d1[mt][nt], Al[mt], Bh[nt]);
                }
        }

#pragma unroll
        for (int mt = 0; mt < 2; mt++)
#pragma unroll
            for (int nt = 0; nt < 4; nt++)
#pragma unroll
                for (int rh = 0; rh < 2; rh++) {
                    float y = yv_[mt][rh];
                    float g0 = sigm(y * d1[mt][nt][rh * 2 + 0]) - 0.5f;
                    float g1 = sigm(y * d1[mt][nt][rh * 2 + 1]) - 0.5f;
                    unsigned short h0, l0, h1, l1;
                    f16_split(g0, h0, l0);
                    f16_split(g1, h1, l1);
                    int m = wm + mt * 16 + (lane >> 2) + 8 * rh;
                    int coff = (wn + nt * 8 + (lane & 3) * 2) * 2;
                    *(uint32_t*)(A2_hi + m * SA + coff) = (uint32_t)h0 | ((uint32_t)h1 << 16);
                    *(uint32_t*)(A2_lo + m * SA + coff) = (uint32_t)l0 | ((uint32_t)l1 << 16);
                }
        __syncthreads();

#pragma unroll
        for (int ks = 0; ks < 4; ks++) {
            int kb = ks * 32;
            uint32_t Ah[2][4], Al[2][4], Bh[4][2];
#pragma unroll
            for (int mt = 0; mt < 2; mt++) {
                uint32_t off = (uint32_t)((wm + mt * 16 + arow) * SA + kb + akoff);
                LDSM_X4(Ah[mt][0], Ah[mt][1], Ah[mt][2], Ah[mt][3], a2h_u + off);
                LDSM_X4(Al[mt][0], Al[mt][1], Al[mt][2], Al[mt][3], a2l_u + off);
            }
#pragma unroll
            for (int np = 0; np < 2; np++) {
                uint32_t off = (uint32_t)((wn + np * 16 + brow) * SA + kb + bkoff);
                uint32_t r0, r1, r2, r3;
                LDSM_X4(r0, r1, r2, r3, b2h_u + off);
                Bh[np * 2][0] = r0; Bh[np * 2][1] = r1;
                Bh[np * 2 + 1][0] = r2; Bh[np * 2 + 1][1] = r3;
            }
#pragma unroll
            for (int mt = 0; mt < 2; mt++)
#pragma unroll
                for (int nt = 0; nt < 4; nt++) {
                    MMA_F16(d2[mt][nt], Ah[mt], Bh[nt]);
                    MMA_F16(d2[mt][nt], Al[mt], Bh[nt]);
                }
        }
    }

    __syncthreads();
    float* stage = (float*)sm;
#pragma unroll
    for (int mt = 0; mt < 2; mt++)
#pragma unroll
        for (int nt = 0; nt < 4; nt++)
#pragma unroll
            for (int r = 0; r < 4; r++) {
                int m = wm + mt * 16 + (lane >> 2) + ((r >> 1) & 1) * 8;
                int n = wn + nt * 8 + (lane & 3) * 2 + (r & 1);
                stage[m * STG + n] = d2[mt][nt][r];
            }
    __syncthreads();
    float wscale = w2s[branch];
    int row = tid >> 1, half = tid & 1;
    const float* srow = &stage[row * STG + half * 32];
    float* dst = &g_featb[branch][((size_t)t * HWSZ + hw0 + row) * CCH + half * 32];
#pragma unroll
    for (int q = 0; q < 8; q++) {
        float4 b = *(const float4*)&srow[q * 4];
        float4 o4 = make_float4(b.x * wscale, b.y * wscale, b.z * wscale, b.w * wscale);
        *(float4*)&dst[q * 4] = o4;
    }
}

// ---------------- xd = w_down @ x (one thread per pos, 4 outputs) ---------------
__global__ void k_xd(const float* __restrict__ x, const float* __restrict__ wd) {
    int pos = blockIdx.x * blockDim.x + threadIdx.x;
    if (pos >= THWSZ) return;
    float a0 = 0.0f, a1 = 0.0f, a2 = 0.0f, a3 = 0.0f;
    for (int c = 0; c < CCH; c++) {
        float v = x[c * THWSZ + pos];
        a0 = fmaf(wd[c], v, a0);
        a1 = fmaf(wd[CCH + c], v, a1);
        a2 = fmaf(wd[2 * CCH + c], v, a2);
        a3 = fmaf(wd[3 * CCH + c], v, a3);
    }
    g_xd[pos] = a0;
    g_xd[THWSZ + pos] = a1;
    g_xd[2 * THWSZ + pos] = a2;
    g_xd[3 * THWSZ + pos] = a3;
}

// ---------------- 3x depthwise 3D convs ------------------------------------------
__global__ void k_agg(const float* __restrict__ w1, const float* __restrict__ b1,
                      const float* __restrict__ w2, const float* __restrict__ b2,
                      const float* __restrict__ w3, const float* __restrict__ b3,
                      const float* __restrict__ wts) {
    int idx = blockIdx.x * blockDim.x + threadIdx.x;
    if (idx >= RCC * THWSZ) return;
    int r = idx / THWSZ;
    int rem = idx % THWSZ;
    int t = rem / HWSZ;
    int hw = rem % HWSZ;
    int h = hw / WWI, w = hw % WWI;
    const float* xb = g_xd + r * THWSZ;
    const float* ws_[3] = {w1, w2, w3};
    const float* bs_[3] = {b1, b2, b3};
    float total = 0.0f;
#pragma unroll
    for (int m = 0; m < 3; m++) {
        int d = m + 1;
        float cs = bs_[m][r];
        const float* wp = ws_[m] + r * 81;
        for (int kt = 0; kt < 9; kt++) {
            int ti = t + kt - 4;
            if (ti < 0 || ti >= TT) continue;
#pragma unroll
            for (int kh = 0; kh < 3; kh++) {
                int hi = h + (kh - 1) * d;
                if (hi < 0 || hi >= HHH) continue;
#pragma unroll
                for (int kw = 0; kw < 3; kw++) {
                    int wi = w + (kw - 1) * d;
                    if (wi < 0 || wi >= WWI) continue;
                    cs = fmaf(xb[ti * HWSZ + hi * WWI + wi], wp[(kt * 3 + kh) * 3 + kw], cs);
                }
            }
        }
        total = fmaf(wts[m], cs, total);
    }
    g_agg[idx] = total;
}

// ---------------- final ----------------------------------------------------------
__global__ void k_final(float* __restrict__ out, const float* __restrict__ wback) {
    int pos = blockIdx.x * 256 + threadIdx.x;
    if (pos >= THWSZ) return;
    float ag0 = g_agg[pos];
    float ag1 = g_agg[THWSZ + pos];
    float ag2 = g_agg[2 * THWSZ + pos];
    float ag3 = g_agg[3 * THWSZ + pos];
    const float4* f0 = (const float4*)&g_featb[0][(size_t)pos * CCH];
    const float4* f1 = (const float4*)&g_featb[1][(size_t)pos * CCH];
#pragma unroll
    for (int c4 = 0; c4 < 16; c4++) {
        float4 a = f0[c4];
        float4 b = f1[c4];
        float fv[4] = {a.x + b.x, a.y + b.y, a.z + b.z, a.w + b.w};
#pragma unroll
        for (int u = 0; u < 4; u++) {
            int c = c4 * 4 + u;
            float z = wback[c * 4 + 0] * ag0 + wback[c * 4 + 1] * ag1 +
                      wback[c * 4 + 2] * ag2 + wback[c * 4 + 3] * ag3;
            out[c * THWSZ + pos] = fv[u] * (sigm(z) - 0.5f);
        }
    }
}

extern "C" void kernel_launch(void* const* d_in, const int* in_sizes, int n_in,
                              void* d_out, int out_size) {
    const float* x       = (const float*)d_in[0];
    const float* w_dc2   = (const float*)d_in[1];
    const float* w_ofs_l = (const float*)d_in[2];
    const float* b_ofs_l = (const float*)d_in[3];
    const float* w_ofs_r = (const float*)d_in[4];
    const float* b_ofs_r = (const float*)d_in[5];
    const float* ca_w1   = (const float*)d_in[6];
    const float* ca_w2   = (const float*)d_in[7];
    const float* w_down  = (const float*)d_in[8];
    const float* sa1_w   = (const float*)d_in[9];
    const float* sa1_b   = (const float*)d_in[10];
    const float* sa2_w   = (const float*)d_in[11];
    const float* sa2_b   = (const float*)d_in[12];
    const float* sa3_w   = (const float*)d_in[13];
    const float* sa3_b   = (const float*)d_in[14];
    const float* weights = (const float*)d_in[15];
    const float* weights2= (const float*)d_in[16];
    const float* w_back  = (const float*)d_in[17];
    float* out = (float*)d_out;

    cudaFuncSetAttribute(k_gemm1_stats, cudaFuncAttributeMaxDynamicSharedMemorySize, SM1_TOT);
    cudaFuncSetAttribute(k_gemm2f, cudaFuncAttributeMaxDynamicSharedMemorySize, SM2_TOT);

    k_x2<<<THWSZ / 128, 256>>>(x, w_dc2);
    k_xt<<<(THWSZ + 255) / 256, 256>>>(x);
    k_offp<<<(NCC * 2 * TT * 2 * SS) / 256, 256>>>(x, w_ofs_l, w_ofs_r);
    k_offred<<<(2 * TT * 2 * SS + 255) / 256, 256>>>(b_ofs_l, b_ofs_r);
    k_sample<<<(2 * TT * 16 * SS) / 256, 256>>>();

    dim3 gg(HWSZ / 128, TT, 2);
    k_gemm1_stats<<<gg, 256, SM1_TOT>>>();
    k_y<<<(2 * TT * HWSZ + 255) / 256, 256>>>(ca_w1, ca_w2);
    k_gemm2f<<<gg, 256, SM2_TOT>>>(weights2);

    k_xd<<<(THWSZ + 255) / 256, 256>>>(x, w_down);
    k_agg<<<(RCC * THWSZ + 255) / 256, 256>>>(sa1_w, sa1_b, sa2_w, sa2_b, sa3_w, sa3_b, weights);
    k_final<<<(THWSZ + 255) / 256, 256>>>(out, w_back);
}

// round 11
// speedup vs baseline: 3.2459x; 1.1793x over previous
#include <cuda_runtime.h>
#include <cuda_fp16.h>
#include <math.h>
#include <stdint.h>

#define TT 16
#define CCH 64
#define HHH 48
#define WWI 48
#define HWSZ 2304
#define THWSZ 36864
#define WW2 24
#define SS 576
#define RCC 4
#define NCC 16   // channel chunks of 4 in k_offp

typedef unsigned long long u64t;

// ---------------- FFMA2 helpers (k_x2) ----------------
#define FMA_F32X2(d, a, b, c) \
    asm("fma.rn.f32x2 %0, %1, %2, %3;" : "=l"(d) : "l"(a), "l"(b), "l"(c))
#define DUP_F32X2(out, v) \
    asm("mov.b64 %0, {%1, %1};" : "=l"(out) : "r"(v))
#define UNPACK_F32X2(lo, hi, in) \
    asm("mov.b64 {%0, %1}, %2;" : "=r"(lo), "=r"(hi) : "l"(in))
union F4U { float4 f; u64t u[2]; };

// ---------------- mma.sync / ldmatrix helpers ----------------
__device__ __forceinline__ uint32_t smem_to_u32(const void* p) {
    uint32_t a;
    asm("{ .reg .u64 tmp; cvta.to.shared.u64 tmp, %1; cvt.u32.u64 %0, tmp; }"
        : "=r"(a) : "l"(p));
    return a;
}
#define LDSM_X4(r0, r1, r2, r3, addr) \
    asm volatile("ldmatrix.sync.aligned.m8n8.x4.shared.b16 {%0,%1,%2,%3}, [%4];" \
        : "=r"(r0), "=r"(r1), "=r"(r2), "=r"(r3) : "r"(addr))
#define MMA_F16(d, a, b) \
    asm volatile("mma.sync.aligned.m16n8k16.row.col.f32.f16.f16.f32 " \
        "{%0,%1,%2,%3}, {%4,%5,%6,%7}, {%8,%9}, {%0,%1,%2,%3};" \
        : "+f"((d)[0]), "+f"((d)[1]), "+f"((d)[2]), "+f"((d)[3]) \
        : "r"((a)[0]), "r"((a)[1]), "r"((a)[2]), "r"((a)[3]), "r"((b)[0]), "r"((b)[1]))
#define TANH_APPROX(d, a) \
    asm("tanh.approx.f32 %0, %1;" : "=f"(d) : "f"(a))

// smem tile geometry: fp16 rows padded to 72 elems (144 B)
#define SA 144
#define A_TILE_B (128 * SA)   // 18432
#define B_TILE_B (64 * SA)    // 9216
#define SM1_TOT (A_TILE_B + B_TILE_B)                     // 27648 (single-pass gemm1)
#define SM2_TOT (4 * A_TILE_B + 2 * B_TILE_B)             // 92160
#define STG 68

// ---------------- scratch (device globals; no allocations) ----------------
static __device__ float g_x2[CCH * THWSZ];            // [c][t][h][w]
static __device__ float g_offp[NCC][2 * TT * 2 * SS];
static __device__ float g_off[2 * TT * 2 * SS];
static __device__ __align__(16) unsigned short g_xt_hi[THWSZ * CCH];  // fp16 [t][hw][c]
static __device__ __align__(16) unsigned short g_xt_lo[THWSZ * CCH];
static __device__ __align__(16) unsigned short pb_sc_hi[2][TT * SS * CCH]; // fp16 [t][s][c]
static __device__ __align__(16) unsigned short pb_cs_hi[2][TT * CCH * SS]; // fp16 [t][c][s]
static __device__ float g_mean[2][TT * HWSZ];
static __device__ float g_maxv[2][TT * HWSZ];
static __device__ float g_varv[2][TT * HWSZ];
static __device__ float g_yv[2][TT * HWSZ];
static __device__ float g_featb[2][TT * HWSZ * CCH]; // [branch][t][hw][c]
static __device__ float g_xd[RCC * THWSZ];
static __device__ float g_agg[RCC * THWSZ];

__device__ __forceinline__ float sigm(float v) { return 1.0f / (1.0f + __expf(-v)); }

__device__ __forceinline__ void f16_split(float v, unsigned short& hs, unsigned short& ls) {
    __half h = __float2half_rn(v);
    float hf = __half2float(h);
    __half l = __float2half_rn(v - hf);
    hs = *(unsigned short*)&h;
    ls = *(unsigned short*)&l;
}
__device__ __forceinline__ unsigned short f16_of(float v) {
    __half h = __float2half_rn(v);
    return *(unsigned short*)&h;
}

// ---------------- x2 = w_dc2 @ x (FFMA2) -------------------------------------
__device__ __forceinline__ void mma4x8(const float4& a, const F4U& b0, const F4U& b1,
                                       u64t accp[4][4]) {
    float av[4] = {a.x, a.y, a.z, a.w};
    u64t bp[4] = {b0.u[0], b0.u[1], b1.u[0], b1.u[1]};
#pragma unroll
    for (int i = 0; i < 4; i++) {
        u64t ad;
        DUP_F32X2(ad, __float_as_uint(av[i]));
#pragma unroll
        for (int j = 0; j < 4; j++) FMA_F32X2(accp[i][j], ad, bp[j], accp[i][j]);
    }
}
__device__ __forceinline__ void unpack_acc(const u64t accp[4][4], float acc[4][8]) {
#pragma unroll
    for (int i = 0; i < 4; i++)
#pragma unroll
        for (int j = 0; j < 4; j++) {
            unsigned lo, hi;
            UNPACK_F32X2(lo, hi, accp[i][j]);
            acc[i][2 * j] = __uint_as_float(lo);
            acc[i][2 * j + 1] = __uint_as_float(hi);
        }
}

__global__ void __launch_bounds__(256) k_x2(const float* __restrict__ x, const float* __restrict__ w) {
    __shared__ float Ws[64][64];
    __shared__ float Xs[64][128];
    int tid = threadIdx.x;
    int pos0 = blockIdx.x * 128;
#pragma unroll
    for (int v = 0; v < 16; v++) {
        int i = v * 256 + tid;
        Ws[i & 63][i >> 6] = w[i];
    }
#pragma unroll
    for (int v = 0; v < 8; v++) {
        int i = v * 256 + tid;
        int row = i >> 5, col = (i & 31) * 4;
        *(float4*)&Xs[row][col] = *(const float4*)&x[row * THWSZ + pos0 + col];
    }
    __syncthreads();
    int tx = tid & 31, ty = tid >> 5;
    u64t accp[4][4];
#pragma unroll
    for (int i = 0; i < 4; i++)
#pragma unroll
        for (int j = 0; j < 4; j++) accp[i][j] = 0ULL;
    float4 a_c = *(float4*)&Xs[0][tx * 4];
    F4U b0_c, b1_c;
    b0_c.f = *(float4*)&Ws[0][ty * 8];
    b1_c.f = *(float4*)&Ws[0][ty * 8 + 4];
#pragma unroll 7
    for (int k = 0; k < 63; k++) {
        float4 a_n = *(float4*)&Xs[k + 1][tx * 4];
        F4U b0_n, b1_n;
        b0_n.f = *(float4*)&Ws[k + 1][ty * 8];
        b1_n.f = *(float4*)&Ws[k + 1][ty * 8 + 4];
        mma4x8(a_c, b0_c, b1_c, accp);
        a_c = a_n; b0_c = b0_n; b1_c = b1_n;
    }
    mma4x8(a_c, b0_c, b1_c, accp);
    float acc[4][8];
    unpack_acc(accp, acc);
#pragma unroll
    for (int j = 0; j < 8; j++) {
        int o = ty * 8 + j;
        float4 o4 = make_float4(acc[0][j], acc[1][j], acc[2][j], acc[3][j]);
        *(float4*)&g_x2[o * THWSZ + pos0 + tx * 4] = o4;
    }
}

// ---------------- x transpose + fp16 split -----------------------------------
__global__ void __launch_bounds__(256) k_xt(const float* __restrict__ x) {
    int idx = blockIdx.x * 256 + threadIdx.x;
    if (idx >= THWSZ) return;
    unsigned short* dh = &g_xt_hi[(size_t)idx * 64];
    unsigned short* dl = &g_xt_lo[(size_t)idx * 64];
#pragma unroll 8
    for (int c = 0; c < CCH; c++) {
        float v = x[c * THWSZ + idx];
        unsigned short hs, ls;
        f16_split(v, hs, ls);
        dh[c] = hs; dl[c] = ls;
    }
}

// ------- offset conv partials + reduce ----------------------------------------
__global__ void __launch_bounds__(256) k_offp(const float* __restrict__ x,
                      const float* __restrict__ wl, const float* __restrict__ wr) {
    int idx = blockIdx.x * 256 + threadIdx.x;
    int s = idx % SS;
    int o = (idx / SS) & 1;
    int t = (idx / (2 * SS)) & 15;
    int branch = (idx / (2 * SS * TT)) & 1;
    int cc = idx / (2 * SS * TT * 2);
    int i = s / WW2, j = s % WW2;
    int tsrc = (branch == 0) ? min(t + 1, TT - 1) : max(t - 1, 0);
    const float* wofs = (branch == 0) ? wl : wr;
    float acc = 0.0f;
#pragma unroll
    for (int u = 0; u < 4; u++) {
        int c = cc * 4 + u;
        const float* xp = x + c * THWSZ + t * HWSZ;
        const float* x2p = g_x2 + c * THWSZ + tsrc * HWSZ;
        const float* wp = wofs + (o * CCH + c) * 9;
#pragma unroll
        for (int ki = 0; ki < 3; ki++) {
            int h = 2 * i - 1 + ki;
            if (h < 0 || h >= HHH) continue;
#pragma unroll
            for (int kj = 0; kj < 3; kj++) {
                int w = 2 * j - 1 + kj;
                if (w < 0 || w >= WWI) continue;
                acc = fmaf(xp[h * WWI + w] + x2p[h * WWI + w], wp[ki * 3 + kj], acc);
            }
        }
    }
    g_offp[cc][((branch * TT + t) * 2 + o) * SS + s] = acc;
}

__global__ void k_offred(const float* __restrict__ bl, const float* __restrict__ br_) {
    int i = blockIdx.x * 256 + threadIdx.x;
    if (i >= 2 * TT * 2 * SS) return;
    int branch = i / (TT * 2 * SS);
    int o = (i / SS) & 1;
    float acc = (branch == 0) ? bl[o] : br_[o];
#pragma unroll
    for (int cc = 0; cc < NCC; cc++) acc += g_offp[cc][i];
    g_off[i] = acc;
}

// ------- bilinear grid-sample -> fp16 parts ------------------------------------
__global__ void __launch_bounds__(256) k_sample() {
    int idx = blockIdx.x * 256 + threadIdx.x;
    int s = idx % SS;
    int c4 = (idx / SS) & 15;
    int t = (idx / (SS * 16)) & 15;
    int branch = idx / (SS * 16 * 16);
    int i = s / WW2, j = s % WW2;
    float off0 = g_off[((branch * TT + t) * 2 + 0) * SS + s];
    float off1 = g_off[((branch * TT + t) * 2 + 1) * SS + s];
    float v0 = 2.0f * (float)j + off0;
    float v1 = 2.0f * (float)i + off1;
    float gh = 2.0f * v0 / 23.0f - 1.0f;
    float gw = 2.0f * v1 / 23.0f - 1.0f;
    float xs = ((gh + 1.0f) * 48.0f - 1.0f) * 0.5f;
    float ys = ((gw + 1.0f) * 48.0f - 1.0f) * 0.5f;
    float x0f = floorf(xs), y0f = floorf(ys);
    int x0 = (int)x0f, y0 = (int)y0f;
    float fx = xs - x0f, fy = ys - y0f;
    float wgt[4] = {(1.0f - fx) * (1.0f - fy), fx * (1.0f - fy),
                    (1.0f - fx) * fy, fx * fy};
    int xi[4] = {x0, x0 + 1, x0, x0 + 1};
    int yi[4] = {y0, y0, y0 + 1, y0 + 1};
    float wv[4];
    int id[4];
#pragma unroll
    for (int k = 0; k < 4; k++) {
        bool valid = (xi[k] >= 0) && (xi[k] < WWI) && (yi[k] >= 0) && (yi[k] < HHH);
        wv[k] = valid ? wgt[k] : 0.0f;
        int cy = min(max(yi[k], 0), HHH - 1);
        int cx = min(max(xi[k], 0), WWI - 1);
        id[k] = cy * WWI + cx;
    }
    int tsrc = (branch == 0) ? min(t + 1, TT - 1) : max(t - 1, 0);
#pragma unroll
    for (int u = 0; u < 4; u++) {
        int c = c4 * 4 + u;
        const float* img = g_x2 + c * THWSZ + tsrc * HWSZ;
        float val = wv[0] * img[id[0]] + wv[1] * img[id[1]] +
                    wv[2] * img[id[2]] + wv[3] * img[id[3]];
        unsigned short hs = f16_of(val);
        pb_sc_hi[branch][(t * SS + s) * CCH + c] = hs;
        pb_cs_hi[branch][(t * CCH + c) * SS + s] = hs;
    }
}

// ------- GEMM1-stats: SINGLE-pass fp16 (stats only), both branches --------------
// grid (18, 16, 2), 256 thr, 3 CTA/SM.
__global__ void __launch_bounds__(256, 3) k_gemm1_stats() {
    extern __shared__ __align__(16) char sm[];
    char* A_hi = sm;
    char* B_hi = sm + A_TILE_B;
    float* red = (float*)(sm + A_TILE_B);  // reused after last mma (overlaps B)
    int tid = threadIdx.x;
    int t = blockIdx.y, hw0 = blockIdx.x * 128, branch = blockIdx.z;

    {
        const uint4* sh = (const uint4*)&g_xt_hi[(size_t)(t * HWSZ + hw0) * 64];
#pragma unroll
        for (int v = 0; v < 4; v++) {
            int i = v * 256 + tid;
            int row = i >> 3, j = i & 7;
            *(uint4*)(A_hi + row * SA + j * 16) = sh[i];
        }
    }

    int wid = tid >> 5, lane = tid & 31;
    int wm = (wid & 3) * 32;
    int wn = (wid >> 2) * 32;
    uint32_t ah_u = smem_to_u32(A_hi);
    uint32_t bh_u = smem_to_u32(B_hi);
    int arow = lane & 15;
    int akoff = (lane >> 4) * 16;
    int brow = (lane & 7) + ((lane & 16) ? 8 : 0);
    int bkoff = ((lane >> 3) & 1) * 16;

    float s_sum[2][2] = {}, s_sq[2][2] = {};
    float s_mx[2][2] = {{-3.4e38f, -3.4e38f}, {-3.4e38f, -3.4e38f}};

    for (int kc = 0; kc < 9; kc++) {
        __syncthreads();
        {
            const uint4* bh = (const uint4*)&pb_sc_hi[branch][(size_t)(t * SS + kc * 64) * 64];
#pragma unroll
            for (int v = 0; v < 2; v++) {
                int i = v * 256 + tid;
                int row = i >> 3, j = i & 7;
                *(uint4*)(B_hi + row * SA + j * 16) = bh[i];
            }
        }
        __syncthreads();

        float d[2][4][4] = {};
#pragma unroll
        for (int ks = 0; ks < 4; ks++) {
            int kb = ks * 32;
            uint32_t Ah[2][4], Bh[4][2];
#pragma unroll
            for (int mt = 0; mt < 2; mt++) {
                uint32_t off = (uint32_t)((wm + mt * 16 + arow) * SA + kb + akoff);
                LDSM_X4(Ah[mt][0], Ah[mt][1], Ah[mt][2], Ah[mt][3], ah_u + off);
            }
#pragma unroll
            for (int np = 0; np < 2; np++) {
                uint32_t off = (uint32_t)((wn + np * 16 + brow) * SA + kb + bkoff);
                uint32_t r0, r1, r2, r3;
                LDSM_X4(r0, r1, r2, r3, bh_u + off);
                Bh[np * 2][0] = r0; Bh[np * 2][1] = r1;
                Bh[np * 2 + 1][0] = r2; Bh[np * 2 + 1][1] = r3;
            }
#pragma unroll
            for (int mt = 0; mt < 2; mt++)
#pragma unroll
                for (int nt = 0; nt < 4; nt++)
                    MMA_F16(d[mt][nt], Ah[mt], Bh[nt]);
        }
#pragma unroll
        for (int mt = 0; mt < 2; mt++)
#pragma unroll
            for (int nt = 0; nt < 4; nt++)
#pragma unroll
                for (int r = 0; r < 4; r++) {
                    int rh = (r >> 1) & 1;
                    float v = d[mt][nt][r];
                    s_sum[mt][rh] += v;
                    s_sq[mt][rh] = fmaf(v, v, s_sq[mt][rh]);
                    s_mx[mt][rh] = fmaxf(s_mx[mt][rh], v);
                }
    }

#pragma unroll
    for (int mt = 0; mt < 2; mt++)
#pragma unroll
        for (int rh = 0; rh < 2; rh++) {
            s_sum[mt][rh] += __shfl_xor_sync(0xFFFFFFFFu, s_sum[mt][rh], 1);
            s_sum[mt][rh] += __shfl_xor_sync(0xFFFFFFFFu, s_sum[mt][rh], 2);
            s_sq[mt][rh] += __shfl_xor_sync(0xFFFFFFFFu, s_sq[mt][rh], 1);
            s_sq[mt][rh] += __shfl_xor_sync(0xFFFFFFFFu, s_sq[mt][rh], 2);
            s_mx[mt][rh] = fmaxf(s_mx[mt][rh], __shfl_xor_sync(0xFFFFFFFFu, s_mx[mt][rh], 1));
            s_mx[mt][rh] = fmaxf(s_mx[mt][rh], __shfl_xor_sync(0xFFFFFFFFu, s_mx[mt][rh], 2));
        }
    __syncthreads();
    if ((lane & 3) == 0) {
        int nw = wid >> 2;
#pragma unroll
        for (int mt = 0; mt < 2; mt++)
#pragma unroll
            for (int rh = 0; rh < 2; rh++) {
                int m = wm + mt * 16 + (lane >> 2) + 8 * rh;
                float* p = &red[(nw * 128 + m) * 3];
                p[0] = s_sum[mt][rh];
                p[1] = s_sq[mt][rh];
                p[2] = s_mx[mt][rh];
            }
    }
    __syncthreads();
    if (tid < 128) {
        int m = tid;
        const float* p0 = &red[m * 3];
        const float* p1 = &red[(128 + m) * 3];
        float sum = p0[0] + p1[0];
        float sq = p0[1] + p1[1];
        float mx = fmaxf(p0[2], p1[2]);
        int o = t * HWSZ + hw0 + m;
        g_mean[branch][o] = sum / 576.0f;
        g_maxv[branch][o] = mx;
        g_varv[branch][o] = (sq - sum * sum / 576.0f) / 575.0f;
    }
}

// ---------------- attention gate (both branches) --------------------------------
__global__ void k_y(const float* __restrict__ w1, const float* __restrict__ w2) {
    int gidx = blockIdx.x * 256 + threadIdx.x;
    if (gidx >= 2 * TT * HWSZ) return;
    int branch = gidx / (TT * HWSZ);
    int idx = gidx % (TT * HWSZ);
    int t = idx / HWSZ;
    int hw = idx % HWSZ;
    int h = hw / WWI, w = hw % WWI;
    float acc = 0.0f;
#pragma unroll
    for (int dh = 0; dh < 3; dh++) {
        int hh = h + dh - 1;
        if (hh < 0 || hh >= HHH) continue;
#pragma unroll
        for (int dw = 0; dw < 3; dw++) {
            int ww = w + dw - 1;
            if (ww < 0 || ww >= WWI) continue;
            int p = t * HWSZ + hh * WWI + ww;
            acc = fmaf(w1[(0 * 3 + dh) * 3 + dw], g_mean[branch][p], acc);
            acc = fmaf(w1[(3 + dh) * 3 + dw], g_maxv[branch][p], acc);
            acc = fmaf(w2[dh * 3 + dw], g_varv[branch][p], acc);
        }
    }
    g_yv[branch][idx] = sigm(acc);
}

// ------- fused GEMM2: 2-pass fp16, tanh gate ------------------------------------
// grid (18, 16, 2), 256 thr, 2 CTA/SM.
__global__ void __launch_bounds__(256, 2) k_gemm2f(const float* __restrict__ w2s) {
    extern __shared__ __align__(16) char sm[];
    char* A1_hi = sm;
    char* A1_lo = sm + A_TILE_B;
    char* B1_hi = sm + 2 * A_TILE_B;
    char* A2_hi = sm + 2 * A_TILE_B + B_TILE_B;
    char* A2_lo = A2_hi + A_TILE_B;
    char* B2_hi = A2_hi + 2 * A_TILE_B;
    int tid = threadIdx.x;
    int t = blockIdx.y, hw0 = blockIdx.x * 128, branch = blockIdx.z;

    {
        const uint4* sh = (const uint4*)&g_xt_hi[(size_t)(t * HWSZ + hw0) * 64];
        const uint4* sl = (const uint4*)&g_xt_lo[(size_t)(t * HWSZ + hw0) * 64];
#pragma unroll
        for (int v = 0; v < 4; v++) {
            int i = v * 256 + tid;
            int row = i >> 3, j = i & 7;
            *(uint4*)(A1_hi + row * SA + j * 16) = sh[i];
            *(uint4*)(A1_lo + row * SA + j * 16) = sl[i];
        }
    }

    int wid = tid >> 5, lane = tid & 31;
    int wm = (wid & 3) * 32;
    int wn = (wid >> 2) * 32;
    uint32_t a1h_u = smem_to_u32(A1_hi), a1l_u = smem_to_u32(A1_lo);
    uint32_t b1h_u = smem_to_u32(B1_hi);
    uint32_t a2h_u = smem_to_u32(A2_hi), a2l_u = smem_to_u32(A2_lo);
    uint32_t b2h_u = smem_to_u32(B2_hi);
    int arow = lane & 15;
    int akoff = (lane >> 4) * 16;
    int brow = (lane & 7) + ((lane & 16) ? 8 : 0);
    int bkoff = ((lane >> 3) & 1) * 16;

    // pre-scale y by 0.5 for the tanh identity: sigm(u)-0.5 = 0.5*tanh(u/2)
    float yv_[2][2];
#pragma unroll
    for (int mt = 0; mt < 2; mt++)
#pragma unroll
        for (int rh = 0; rh < 2; rh++) {
            int m = wm + mt * 16 + (lane >> 2) + 8 * rh;
            yv_[mt][rh] = 0.5f * g_yv[branch][t * HWSZ + hw0 + m];
        }

    float d2[2][4][4] = {};
    for (int kc = 0; kc < 9; kc++) {
        __syncthreads();
        {
            const uint4* bh = (const uint4*)&pb_sc_hi[branch][(size_t)(t * SS + kc * 64) * 64];
#pragma unroll
            for (int v = 0; v < 2; v++) {
                int i = v * 256 + tid;
                int row = i >> 3, j = i & 7;
                *(uint4*)(B1_hi + row * SA + j * 16) = bh[i];
            }
#pragma unroll
            for (int v = 0; v < 2; v++) {
                int i = v * 256 + tid;
                int row = i >> 3, j = i & 7;
                size_t src = (size_t)(t * CCH + row) * SS + kc * 64 + j * 8;
                *(uint4*)(B2_hi + row * SA + j * 16) = *(const uint4*)&pb_cs_hi[branch][src];
            }
        }
        __syncthreads();

        float d1[2][4][4] = {};
#pragma unroll
        for (int ks = 0; ks < 4; ks++) {
            int kb = ks * 32;
            uint32_t Ah[2][4], Al[2][4], Bh[4][2];
#pragma unroll
            for (int mt = 0; mt < 2; mt++) {
                uint32_t off = (uint32_t)((wm + mt * 16 + arow) * SA + kb + akoff);
                LDSM_X4(Ah[mt][0], Ah[mt][1], Ah[mt][2], Ah[mt][3], a1h_u + off);
                LDSM_X4(Al[mt][0], Al[mt][1], Al[mt][2], Al[mt][3], a1l_u + off);
            }
#pragma unroll
            for (int np = 0; np < 2; np++) {
                uint32_t off = (uint32_t)((wn + np * 16 + brow) * SA + kb + bkoff);
                uint32_t r0, r1, r2, r3;
                LDSM_X4(r0, r1, r2, r3, b1h_u + off);
                Bh[np * 2][0] = r0; Bh[np * 2][1] = r1;
                Bh[np * 2 + 1][0] = r2; Bh[np * 2 + 1][1] = r3;
            }
#pragma unroll
            for (int mt = 0; mt < 2; mt++)
#pragma unroll
                for (int nt = 0; nt < 4; nt++) {
                    MMA_F16(d1[mt][nt], Ah[mt], Bh[nt]);
                    MMA_F16(d1[mt][nt], Al[mt], Bh[nt]);
                }
        }

#pragma unroll
        for (int mt = 0; mt < 2; mt++)
#pragma unroll
            for (int nt = 0; nt < 4; nt++)
#pragma unroll
                for (int rh = 0; rh < 2; rh++) {
                    float yh = yv_[mt][rh];
                    float t0, t1;
                    TANH_APPROX(t0, yh * d1[mt][nt][rh * 2 + 0]);
                    TANH_APPROX(t1, yh * d1[mt][nt][rh * 2 + 1]);
                    float g0 = 0.5f * t0;
                    float g1 = 0.5f * t1;
                    unsigned short h0, l0, h1, l1;
                    f16_split(g0, h0, l0);
                    f16_split(g1, h1, l1);
                    int m = wm + mt * 16 + (lane >> 2) + 8 * rh;
                    int coff = (wn + nt * 8 + (lane & 3) * 2) * 2;
                    *(uint32_t*)(A2_hi + m * SA + coff) = (uint32_t)h0 | ((uint32_t)h1 << 16);
                    *(uint32_t*)(A2_lo + m * SA + coff) = (uint32_t)l0 | ((uint32_t)l1 << 16);
                }
        __syncthreads();

#pragma unroll
        for (int ks = 0; ks < 4; ks++) {
            int kb = ks * 32;
            uint32_t Ah[2][4], Al[2][4], Bh[4][2];
#pragma unroll
            for (int mt = 0; mt < 2; mt++) {
                uint32_t off = (uint32_t)((wm + mt * 16 + arow) * SA + kb + akoff);
                LDSM_X4(Ah[mt][0], Ah[mt][1], Ah[mt][2], Ah[mt][3], a2h_u + off);
                LDSM_X4(Al[mt][0], Al[mt][1], Al[mt][2], Al[mt][3], a2l_u + off);
            }
#pragma unroll
            for (int np = 0; np < 2; np++) {
                uint32_t off = (uint32_t)((wn + np * 16 + brow) * SA + kb + bkoff);
                uint32_t r0, r1, r2, r3;
                LDSM_X4(r0, r1, r2, r3, b2h_u + off);
                Bh[np * 2][0] = r0; Bh[np * 2][1] = r1;
                Bh[np * 2 + 1][0] = r2; Bh[np * 2 + 1][1] = r3;
            }
#pragma unroll
            for (int mt = 0; mt < 2; mt++)
#pragma unroll
                for (int nt = 0; nt < 4; nt++) {
                    MMA_F16(d2[mt][nt], Ah[mt], Bh[nt]);
                    MMA_F16(d2[mt][nt], Al[mt], Bh[nt]);
                }
        }
    }

    __syncthreads();
    float* stage = (float*)sm;
#pragma unroll
    for (int mt = 0; mt < 2; mt++)
#pragma unroll
        for (int nt = 0; nt < 4; nt++)
#pragma unroll
            for (int r = 0; r < 4; r++) {
                int m = wm + mt * 16 + (lane >> 2) + ((r >> 1) & 1) * 8;
                int n = wn + nt * 8 + (lane & 3) * 2 + (r & 1);
                stage[m * STG + n] = d2[mt][nt][r];
            }
    __syncthreads();
    float wscale = w2s[branch];
    int row = tid >> 1, half = tid & 1;
    const float* srow = &stage[row * STG + half * 32];
    float* dst = &g_featb[branch][((size_t)t * HWSZ + hw0 + row) * CCH + half * 32];
#pragma unroll
    for (int q = 0; q < 8; q++) {
        float4 b = *(const float4*)&srow[q * 4];
        float4 o4 = make_float4(b.x * wscale, b.y * wscale, b.z * wscale, b.w * wscale);
        *(float4*)&dst[q * 4] = o4;
    }
}

// ---------------- xd = w_down @ x (one thread per pos, 4 outputs) ---------------
__global__ void k_xd(const float* __restrict__ x, const float* __restrict__ wd) {
    int pos = blockIdx.x * blockDim.x + threadIdx.x;
    if (pos >= THWSZ) return;
    float a0 = 0.0f, a1 = 0.0f, a2 = 0.0f, a3 = 0.0f;
    for (int c = 0; c < CCH; c++) {
        float v = x[c * THWSZ + pos];
        a0 = fmaf(wd[c], v, a0);
        a1 = fmaf(wd[CCH + c], v, a1);
        a2 = fmaf(wd[2 * CCH + c], v, a2);
        a3 = fmaf(wd[3 * CCH + c], v, a3);
    }
    g_xd[pos] = a0;
    g_xd[THWSZ + pos] = a1;
    g_xd[2 * THWSZ + pos] = a2;
    g_xd[3 * THWSZ + pos] = a3;
}

// ---------------- 3x depthwise 3D convs ------------------------------------------
__global__ void k_agg(const float* __restrict__ w1, const float* __restrict__ b1,
                      const float* __restrict__ w2, const float* __restrict__ b2,
                      const float* __restrict__ w3, const float* __restrict__ b3,
                      const float* __restrict__ wts) {
    int idx = blockIdx.x * blockDim.x + threadIdx.x;
    if (idx >= RCC * THWSZ) return;
    int r = idx / THWSZ;
    int rem = idx % THWSZ;
    int t = rem / HWSZ;
    int hw = rem % HWSZ;
    int h = hw / WWI, w = hw % WWI;
    const float* xb = g_xd + r * THWSZ;
    const float* ws_[3] = {w1, w2, w3};
    const float* bs_[3] = {b1, b2, b3};
    float total = 0.0f;
#pragma unroll
    for (int m = 0; m < 3; m++) {
        int d = m + 1;
        float cs = bs_[m][r];
        const float* wp = ws_[m] + r * 81;
        for (int kt = 0; kt < 9; kt++) {
            int ti = t + kt - 4;
            if (ti < 0 || ti >= TT) continue;
#pragma unroll
            for (int kh = 0; kh < 3; kh++) {
                int hi = h + (kh - 1) * d;
                if (hi < 0 || hi >= HHH) continue;
#pragma unroll
                for (int kw = 0; kw < 3; kw++) {
                    int wi = w + (kw - 1) * d;
                    if (wi < 0 || wi >= WWI) continue;
                    cs = fmaf(xb[ti * HWSZ + hi * WWI + wi], wp[(kt * 3 + kh) * 3 + kw], cs);
                }
            }
        }
        total = fmaf(wts[m], cs, total);
    }
    g_agg[idx] = total;
}

// ---------------- final ----------------------------------------------------------
__global__ void k_final(float* __restrict__ out, const float* __restrict__ wback) {
    int pos = blockIdx.x * 256 + threadIdx.x;
    if (pos >= THWSZ) return;
    float ag0 = g_agg[pos];
    float ag1 = g_agg[THWSZ + pos];
    float ag2 = g_agg[2 * THWSZ + pos];
    float ag3 = g_agg[3 * THWSZ + pos];
    const float4* f0 = (const float4*)&g_featb[0][(size_t)pos * CCH];
    const float4* f1 = (const float4*)&g_featb[1][(size_t)pos * CCH];
#pragma unroll
    for (int c4 = 0; c4 < 16; c4++) {
        float4 a = f0[c4];
        float4 b = f1[c4];
        float fv[4] = {a.x + b.x, a.y + b.y, a.z + b.z, a.w + b.w};
#pragma unroll
        for (int u = 0; u < 4; u++) {
            int c = c4 * 4 + u;
            float z = wback[c * 4 + 0] * ag0 + wback[c * 4 + 1] * ag1 +
                      wback[c * 4 + 2] * ag2 + wback[c * 4 + 3] * ag3;
            out[c * THWSZ + pos] = fv[u] * (sigm(z) - 0.5f);
        }
    }
}

extern "C" void kernel_launch(void* const* d_in, const int* in_sizes, int n_in,
                              void* d_out, int out_size) {
    const float* x       = (const float*)d_in[0];
    const float* w_dc2   = (const float*)d_in[1];
    const float* w_ofs_l = (const float*)d_in[2];
    const float* b_ofs_l = (const float*)d_in[3];
    const float* w_ofs_r = (const float*)d_in[4];
    const float* b_ofs_r = (const float*)d_in[5];
    const float* ca_w1   = (const float*)d_in[6];
    const float* ca_w2   = (const float*)d_in[7];
    const float* w_down  = (const float*)d_in[8];
    const float* sa1_w   = (const float*)d_in[9];
    const float* sa1_b   = (const float*)d_in[10];
    const float* sa2_w   = (const float*)d_in[11];
    const float* sa2_b   = (const float*)d_in[12];
    const float* sa3_w   = (const float*)d_in[13];
    const float* sa3_b   = (const float*)d_in[14];
    const float* weights = (const float*)d_in[15];
    const float* weights2= (const float*)d_in[16];
    const float* w_back  = (const float*)d_in[17];
    float* out = (float*)d_out;

    cudaFuncSetAttribute(k_gemm1_stats, cudaFuncAttributeMaxDynamicSharedMemorySize, SM1_TOT);
    cudaFuncSetAttribute(k_gemm2f, cudaFuncAttributeMaxDynamicSharedMemorySize, SM2_TOT);

    k_x2<<<THWSZ / 128, 256>>>(x, w_dc2);
    k_xt<<<(THWSZ + 255) / 256, 256>>>(x);
    k_offp<<<(NCC * 2 * TT * 2 * SS) / 256, 256>>>(x, w_ofs_l, w_ofs_r);
    k_offred<<<(2 * TT * 2 * SS + 255) / 256, 256>>>(b_ofs_l, b_ofs_r);
    k_sample<<<(2 * TT * 16 * SS) / 256, 256>>>();

    dim3 gg(HWSZ / 128, TT, 2);
    k_gemm1_stats<<<gg, 256, SM1_TOT>>>();
    k_y<<<(2 * TT * HWSZ + 255) / 256, 256>>>(ca_w1, ca_w2);
    k_gemm2f<<<gg, 256, SM2_TOT>>>(weights2);

    k_xd<<<(THWSZ + 255) / 256, 256>>>(x, w_down);
    k_agg<<<(RCC * THWSZ + 255) / 256, 256>>>(sa1_w, sa1_b, sa2_w, sa2_b, sa3_w, sa3_b, weights);
    k_final<<<(THWSZ + 255) / 256, 256>>>(out, w_back);
}

// round 12
// speedup vs baseline: 3.8239x; 1.1781x over previous
#include <cuda_runtime.h>
#include <cuda_fp16.h>
#include <math.h>
#include <stdint.h>

#define TT 16
#define CCH 64
#define HHH 48
#define WWI 48
#define HWSZ 2304
#define THWSZ 36864
#define WW2 24
#define SS 576
#define RCC 4
#define NCC 16   // channel chunks of 4 in k_offp

typedef unsigned long long u64t;

// ---------------- FFMA2 helpers (k_x2) ----------------
#define FMA_F32X2(d, a, b, c) \
    asm("fma.rn.f32x2 %0, %1, %2, %3;" : "=l"(d) : "l"(a), "l"(b), "l"(c))
#define DUP_F32X2(out, v) \
    asm("mov.b64 %0, {%1, %1};" : "=l"(out) : "r"(v))
#define UNPACK_F32X2(lo, hi, in) \
    asm("mov.b64 {%0, %1}, %2;" : "=r"(lo), "=r"(hi) : "l"(in))
union F4U { float4 f; u64t u[2]; };

// ---------------- mma.sync / ldmatrix helpers ----------------
__device__ __forceinline__ uint32_t smem_to_u32(const void* p) {
    uint32_t a;
    asm("{ .reg .u64 tmp; cvta.to.shared.u64 tmp, %1; cvt.u32.u64 %0, tmp; }"
        : "=r"(a) : "l"(p));
    return a;
}
#define LDSM_X4(r0, r1, r2, r3, addr) \
    asm volatile("ldmatrix.sync.aligned.m8n8.x4.shared.b16 {%0,%1,%2,%3}, [%4];" \
        : "=r"(r0), "=r"(r1), "=r"(r2), "=r"(r3) : "r"(addr))
#define MMA_F16(d, a, b) \
    asm volatile("mma.sync.aligned.m16n8k16.row.col.f32.f16.f16.f32 " \
        "{%0,%1,%2,%3}, {%4,%5,%6,%7}, {%8,%9}, {%0,%1,%2,%3};" \
        : "+f"((d)[0]), "+f"((d)[1]), "+f"((d)[2]), "+f"((d)[3]) \
        : "r"((a)[0]), "r"((a)[1]), "r"((a)[2]), "r"((a)[3]), "r"((b)[0]), "r"((b)[1]))
#define TANH_APPROX(d, a) \
    asm("tanh.approx.f32 %0, %1;" : "=f"(d) : "f"(a))

// smem tile geometry: fp16 rows padded to 72 elems (144 B)
#define SA 144
#define A_TILE_B (128 * SA)   // 18432
#define B_TILE_B (64 * SA)    // 9216
#define SM1_TOT (A_TILE_B + B_TILE_B)                     // 27648
#define SM2_TOT (3 * A_TILE_B + 2 * B_TILE_B)             // 73728
#define STG 68

// ---------------- scratch (device globals; no allocations) ----------------
static __device__ float g_x2[CCH * THWSZ];            // [c][t][h][w]
static __device__ float g_offp[NCC][2 * TT * 2 * SS];
static __device__ float g_off[2 * TT * 2 * SS];
static __device__ __align__(16) unsigned short g_xt_hi[THWSZ * CCH];  // fp16 [t][hw][c]
static __device__ __align__(16) unsigned short g_xt_lo[THWSZ * CCH];
static __device__ __align__(16) unsigned short pb_sc_hi[2][TT * SS * CCH]; // fp16 [t][s][c]
static __device__ __align__(16) unsigned short pb_cs_hi[2][TT * CCH * SS]; // fp16 [t][c][s]
static __device__ float g_mean[2][TT * HWSZ];
static __device__ float g_maxv[2][TT * HWSZ];
static __device__ float g_varv[2][TT * HWSZ];
static __device__ float g_yv[2][TT * HWSZ];
static __device__ float g_featb[2][TT * HWSZ * CCH]; // [branch][t][hw][c]
static __device__ float g_xd[RCC * THWSZ];
static __device__ float g_agg[RCC * THWSZ];

__device__ __forceinline__ float sigm(float v) { return 1.0f / (1.0f + __expf(-v)); }

__device__ __forceinline__ void f16_split(float v, unsigned short& hs, unsigned short& ls) {
    __half h = __float2half_rn(v);
    float hf = __half2float(h);
    __half l = __float2half_rn(v - hf);
    hs = *(unsigned short*)&h;
    ls = *(unsigned short*)&l;
}
__device__ __forceinline__ unsigned short f16_of(float v) {
    __half h = __float2half_rn(v);
    return *(unsigned short*)&h;
}

// ---------------- x2 = w_dc2 @ x (FFMA2) -------------------------------------
__device__ __forceinline__ void mma4x8(const float4& a, const F4U& b0, const F4U& b1,
                                       u64t accp[4][4]) {
    float av[4] = {a.x, a.y, a.z, a.w};
    u64t bp[4] = {b0.u[0], b0.u[1], b1.u[0], b1.u[1]};
#pragma unroll
    for (int i = 0; i < 4; i++) {
        u64t ad;
        DUP_F32X2(ad, __float_as_uint(av[i]));
#pragma unroll
        for (int j = 0; j < 4; j++) FMA_F32X2(accp[i][j], ad, bp[j], accp[i][j]);
    }
}
__device__ __forceinline__ void unpack_acc(const u64t accp[4][4], float acc[4][8]) {
#pragma unroll
    for (int i = 0; i < 4; i++)
#pragma unroll
        for (int j = 0; j < 4; j++) {
            unsigned lo, hi;
            UNPACK_F32X2(lo, hi, accp[i][j]);
            acc[i][2 * j] = __uint_as_float(lo);
            acc[i][2 * j + 1] = __uint_as_float(hi);
        }
}

__global__ void __launch_bounds__(256) k_x2(const float* __restrict__ x, const float* __restrict__ w) {
    __shared__ float Ws[64][64];
    __shared__ float Xs[64][128];
    int tid = threadIdx.x;
    int pos0 = blockIdx.x * 128;
#pragma unroll
    for (int v = 0; v < 16; v++) {
        int i = v * 256 + tid;
        Ws[i & 63][i >> 6] = w[i];
    }
#pragma unroll
    for (int v = 0; v < 8; v++) {
        int i = v * 256 + tid;
        int row = i >> 5, col = (i & 31) * 4;
        *(float4*)&Xs[row][col] = *(const float4*)&x[row * THWSZ + pos0 + col];
    }
    __syncthreads();
    int tx = tid & 31, ty = tid >> 5;
    u64t accp[4][4];
#pragma unroll
    for (int i = 0; i < 4; i++)
#pragma unroll
        for (int j = 0; j < 4; j++) accp[i][j] = 0ULL;
    float4 a_c = *(float4*)&Xs[0][tx * 4];
    F4U b0_c, b1_c;
    b0_c.f = *(float4*)&Ws[0][ty * 8];
    b1_c.f = *(float4*)&Ws[0][ty * 8 + 4];
#pragma unroll 7
    for (int k = 0; k < 63; k++) {
        float4 a_n = *(float4*)&Xs[k + 1][tx * 4];
        F4U b0_n, b1_n;
        b0_n.f = *(float4*)&Ws[k + 1][ty * 8];
        b1_n.f = *(float4*)&Ws[k + 1][ty * 8 + 4];
        mma4x8(a_c, b0_c, b1_c, accp);
        a_c = a_n; b0_c = b0_n; b1_c = b1_n;
    }
    mma4x8(a_c, b0_c, b1_c, accp);
    float acc[4][8];
    unpack_acc(accp, acc);
#pragma unroll
    for (int j = 0; j < 8; j++) {
        int o = ty * 8 + j;
        float4 o4 = make_float4(acc[0][j], acc[1][j], acc[2][j], acc[3][j]);
        *(float4*)&g_x2[o * THWSZ + pos0 + tx * 4] = o4;
    }
}

// ---------------- x transpose + fp16 split -----------------------------------
__global__ void __launch_bounds__(256) k_xt(const float* __restrict__ x) {
    int idx = blockIdx.x * 256 + threadIdx.x;
    if (idx >= THWSZ) return;
    unsigned short* dh = &g_xt_hi[(size_t)idx * 64];
    unsigned short* dl = &g_xt_lo[(size_t)idx * 64];
#pragma unroll 8
    for (int c = 0; c < CCH; c++) {
        float v = x[c * THWSZ + idx];
        unsigned short hs, ls;
        f16_split(v, hs, ls);
        dh[c] = hs; dl[c] = ls;
    }
}

// ------- offset conv partials (both o per thread) + reduce ---------------------
__global__ void __launch_bounds__(256) k_offp(const float* __restrict__ x,
                      const float* __restrict__ wl, const float* __restrict__ wr) {
    int idx = blockIdx.x * 256 + threadIdx.x;  // NCC*2*TT*SS = 294912
    int s = idx % SS;
    int t = (idx / SS) & 15;
    int branch = (idx / (SS * TT)) & 1;
    int cc = idx / (SS * TT * 2);
    int i = s / WW2, j = s % WW2;
    int tsrc = (branch == 0) ? min(t + 1, TT - 1) : max(t - 1, 0);
    const float* wofs = (branch == 0) ? wl : wr;
    float acc0 = 0.0f, acc1 = 0.0f;
#pragma unroll
    for (int u = 0; u < 4; u++) {
        int c = cc * 4 + u;
        const float* xp = x + c * THWSZ + t * HWSZ;
        const float* x2p = g_x2 + c * THWSZ + tsrc * HWSZ;
        const float* wp0 = wofs + c * 9;
        const float* wp1 = wofs + (CCH + c) * 9;
#pragma unroll
        for (int ki = 0; ki < 3; ki++) {
            int h = 2 * i - 1 + ki;
            if (h < 0 || h >= HHH) continue;
#pragma unroll
            for (int kj = 0; kj < 3; kj++) {
                int w = 2 * j - 1 + kj;
                if (w < 0 || w >= WWI) continue;
                float v = xp[h * WWI + w] + x2p[h * WWI + w];
                acc0 = fmaf(v, wp0[ki * 3 + kj], acc0);
                acc1 = fmaf(v, wp1[ki * 3 + kj], acc1);
            }
        }
    }
    g_offp[cc][((branch * TT + t) * 2 + 0) * SS + s] = acc0;
    g_offp[cc][((branch * TT + t) * 2 + 1) * SS + s] = acc1;
}

__global__ void k_offred(const float* __restrict__ bl, const float* __restrict__ br_) {
    int i = blockIdx.x * 256 + threadIdx.x;
    if (i >= 2 * TT * 2 * SS) return;
    int branch = i / (TT * 2 * SS);
    int o = (i / SS) & 1;
    float acc = (branch == 0) ? bl[o] : br_[o];
#pragma unroll
    for (int cc = 0; cc < NCC; cc++) acc += g_offp[cc][i];
    g_off[i] = acc;
}

// ------- bilinear grid-sample -> fp16 parts ------------------------------------
__global__ void __launch_bounds__(256) k_sample() {
    int idx = blockIdx.x * 256 + threadIdx.x;
    int s = idx % SS;
    int c4 = (idx / SS) & 15;
    int t = (idx / (SS * 16)) & 15;
    int branch = idx / (SS * 16 * 16);
    int i = s / WW2, j = s % WW2;
    float off0 = g_off[((branch * TT + t) * 2 + 0) * SS + s];
    float off1 = g_off[((branch * TT + t) * 2 + 1) * SS + s];
    float v0 = 2.0f * (float)j + off0;
    float v1 = 2.0f * (float)i + off1;
    float gh = 2.0f * v0 / 23.0f - 1.0f;
    float gw = 2.0f * v1 / 23.0f - 1.0f;
    float xs = ((gh + 1.0f) * 48.0f - 1.0f) * 0.5f;
    float ys = ((gw + 1.0f) * 48.0f - 1.0f) * 0.5f;
    float x0f = floorf(xs), y0f = floorf(ys);
    int x0 = (int)x0f, y0 = (int)y0f;
    float fx = xs - x0f, fy = ys - y0f;
    float wgt[4] = {(1.0f - fx) * (1.0f - fy), fx * (1.0f - fy),
                    (1.0f - fx) * fy, fx * fy};
    int xi[4] = {x0, x0 + 1, x0, x0 + 1};
    int yi[4] = {y0, y0, y0 + 1, y0 + 1};
    float wv[4];
    int id[4];
#pragma unroll
    for (int k = 0; k < 4; k++) {
        bool valid = (xi[k] >= 0) && (xi[k] < WWI) && (yi[k] >= 0) && (yi[k] < HHH);
        wv[k] = valid ? wgt[k] : 0.0f;
        int cy = min(max(yi[k], 0), HHH - 1);
        int cx = min(max(xi[k], 0), WWI - 1);
        id[k] = cy * WWI + cx;
    }
    int tsrc = (branch == 0) ? min(t + 1, TT - 1) : max(t - 1, 0);
#pragma unroll
    for (int u = 0; u < 4; u++) {
        int c = c4 * 4 + u;
        const float* img = g_x2 + c * THWSZ + tsrc * HWSZ;
        float val = wv[0] * img[id[0]] + wv[1] * img[id[1]] +
                    wv[2] * img[id[2]] + wv[3] * img[id[3]];
        unsigned short hs = f16_of(val);
        pb_sc_hi[branch][(t * SS + s) * CCH + c] = hs;
        pb_cs_hi[branch][(t * CCH + c) * SS + s] = hs;
    }
}

// ------- GEMM1-stats: single-pass fp16, both branches ---------------------------
__global__ void __launch_bounds__(256, 3) k_gemm1_stats() {
    extern __shared__ __align__(16) char sm[];
    char* A_hi = sm;
    char* B_hi = sm + A_TILE_B;
    float* red = (float*)(sm + A_TILE_B);
    int tid = threadIdx.x;
    int t = blockIdx.y, hw0 = blockIdx.x * 128, branch = blockIdx.z;

    {
        const uint4* sh = (const uint4*)&g_xt_hi[(size_t)(t * HWSZ + hw0) * 64];
#pragma unroll
        for (int v = 0; v < 4; v++) {
            int i = v * 256 + tid;
            int row = i >> 3, j = i & 7;
            *(uint4*)(A_hi + row * SA + j * 16) = sh[i];
        }
    }

    int wid = tid >> 5, lane = tid & 31;
    int wm = (wid & 3) * 32;
    int wn = (wid >> 2) * 32;
    uint32_t ah_u = smem_to_u32(A_hi);
    uint32_t bh_u = smem_to_u32(B_hi);
    int arow = lane & 15;
    int akoff = (lane >> 4) * 16;
    int brow = (lane & 7) + ((lane & 16) ? 8 : 0);
    int bkoff = ((lane >> 3) & 1) * 16;

    float s_sum[2][2] = {}, s_sq[2][2] = {};
    float s_mx[2][2] = {{-3.4e38f, -3.4e38f}, {-3.4e38f, -3.4e38f}};

    for (int kc = 0; kc < 9; kc++) {
        __syncthreads();
        {
            const uint4* bh = (const uint4*)&pb_sc_hi[branch][(size_t)(t * SS + kc * 64) * 64];
#pragma unroll
            for (int v = 0; v < 2; v++) {
                int i = v * 256 + tid;
                int row = i >> 3, j = i & 7;
                *(uint4*)(B_hi + row * SA + j * 16) = bh[i];
            }
        }
        __syncthreads();

        float d[2][4][4] = {};
#pragma unroll
        for (int ks = 0; ks < 4; ks++) {
            int kb = ks * 32;
            uint32_t Ah[2][4], Bh[4][2];
#pragma unroll
            for (int mt = 0; mt < 2; mt++) {
                uint32_t off = (uint32_t)((wm + mt * 16 + arow) * SA + kb + akoff);
                LDSM_X4(Ah[mt][0], Ah[mt][1], Ah[mt][2], Ah[mt][3], ah_u + off);
            }
#pragma unroll
            for (int np = 0; np < 2; np++) {
                uint32_t off = (uint32_t)((wn + np * 16 + brow) * SA + kb + bkoff);
                uint32_t r0, r1, r2, r3;
                LDSM_X4(r0, r1, r2, r3, bh_u + off);
                Bh[np * 2][0] = r0; Bh[np * 2][1] = r1;
                Bh[np * 2 + 1][0] = r2; Bh[np * 2 + 1][1] = r3;
            }
#pragma unroll
            for (int mt = 0; mt < 2; mt++)
#pragma unroll
                for (int nt = 0; nt < 4; nt++)
                    MMA_F16(d[mt][nt], Ah[mt], Bh[nt]);
        }
#pragma unroll
        for (int mt = 0; mt < 2; mt++)
#pragma unroll
            for (int nt = 0; nt < 4; nt++)
#pragma unroll
                for (int r = 0; r < 4; r++) {
                    int rh = (r >> 1) & 1;
                    float v = d[mt][nt][r];
                    s_sum[mt][rh] += v;
                    s_sq[mt][rh] = fmaf(v, v, s_sq[mt][rh]);
                    s_mx[mt][rh] = fmaxf(s_mx[mt][rh], v);
                }
    }

#pragma unroll
    for (int mt = 0; mt < 2; mt++)
#pragma unroll
        for (int rh = 0; rh < 2; rh++) {
            s_sum[mt][rh] += __shfl_xor_sync(0xFFFFFFFFu, s_sum[mt][rh], 1);
            s_sum[mt][rh] += __shfl_xor_sync(0xFFFFFFFFu, s_sum[mt][rh], 2);
            s_sq[mt][rh] += __shfl_xor_sync(0xFFFFFFFFu, s_sq[mt][rh], 1);
            s_sq[mt][rh] += __shfl_xor_sync(0xFFFFFFFFu, s_sq[mt][rh], 2);
            s_mx[mt][rh] = fmaxf(s_mx[mt][rh], __shfl_xor_sync(0xFFFFFFFFu, s_mx[mt][rh], 1));
            s_mx[mt][rh] = fmaxf(s_mx[mt][rh], __shfl_xor_sync(0xFFFFFFFFu, s_mx[mt][rh], 2));
        }
    __syncthreads();
    if ((lane & 3) == 0) {
        int nw = wid >> 2;
#pragma unroll
        for (int mt = 0; mt < 2; mt++)
#pragma unroll
            for (int rh = 0; rh < 2; rh++) {
                int m = wm + mt * 16 + (lane >> 2) + 8 * rh;
                float* p = &red[(nw * 128 + m) * 3];
                p[0] = s_sum[mt][rh];
                p[1] = s_sq[mt][rh];
                p[2] = s_mx[mt][rh];
            }
    }
    __syncthreads();
    if (tid < 128) {
        int m = tid;
        const float* p0 = &red[m * 3];
        const float* p1 = &red[(128 + m) * 3];
        float sum = p0[0] + p1[0];
        float sq = p0[1] + p1[1];
        float mx = fmaxf(p0[2], p1[2]);
        int o = t * HWSZ + hw0 + m;
        g_mean[branch][o] = sum / 576.0f;
        g_maxv[branch][o] = mx;
        g_varv[branch][o] = (sq - sum * sum / 576.0f) / 575.0f;
    }
}

// ---------------- attention gate (both branches) --------------------------------
__global__ void k_y(const float* __restrict__ w1, const float* __restrict__ w2) {
    int gidx = blockIdx.x * 256 + threadIdx.x;
    if (gidx >= 2 * TT * HWSZ) return;
    int branch = gidx / (TT * HWSZ);
    int idx = gidx % (TT * HWSZ);
    int t = idx / HWSZ;
    int hw = idx % HWSZ;
    int h = hw / WWI, w = hw % WWI;
    float acc = 0.0f;
#pragma unroll
    for (int dh = 0; dh < 3; dh++) {
        int hh = h + dh - 1;
        if (hh < 0 || hh >= HHH) continue;
#pragma unroll
        for (int dw = 0; dw < 3; dw++) {
            int ww = w + dw - 1;
            if (ww < 0 || ww >= WWI) continue;
            int p = t * HWSZ + hh * WWI + ww;
            acc = fmaf(w1[(0 * 3 + dh) * 3 + dw], g_mean[branch][p], acc);
            acc = fmaf(w1[(3 + dh) * 3 + dw], g_maxv[branch][p], acc);
            acc = fmaf(w2[dh * 3 + dw], g_varv[branch][p], acc);
        }
    }
    g_yv[branch][idx] = sigm(acc);
}

// ------- fused GEMM2: 2-pass aff, single-pass gated A2, tanh gate ---------------
// grid (18, 16, 2), 256 thr, 2 CTA/SM.
__global__ void __launch_bounds__(256, 2) k_gemm2f(const float* __restrict__ w2s) {
    extern __shared__ __align__(16) char sm[];
    char* A1_hi = sm;
    char* A1_lo = sm + A_TILE_B;
    char* B1_hi = sm + 2 * A_TILE_B;
    char* A2_hi = sm + 2 * A_TILE_B + B_TILE_B;
    char* B2_hi = A2_hi + A_TILE_B;
    int tid = threadIdx.x;
    int t = blockIdx.y, hw0 = blockIdx.x * 128, branch = blockIdx.z;

    {
        const uint4* sh = (const uint4*)&g_xt_hi[(size_t)(t * HWSZ + hw0) * 64];
        const uint4* sl = (const uint4*)&g_xt_lo[(size_t)(t * HWSZ + hw0) * 64];
#pragma unroll
        for (int v = 0; v < 4; v++) {
            int i = v * 256 + tid;
            int row = i >> 3, j = i & 7;
            *(uint4*)(A1_hi + row * SA + j * 16) = sh[i];
            *(uint4*)(A1_lo + row * SA + j * 16) = sl[i];
        }
    }

    int wid = tid >> 5, lane = tid & 31;
    int wm = (wid & 3) * 32;
    int wn = (wid >> 2) * 32;
    uint32_t a1h_u = smem_to_u32(A1_hi), a1l_u = smem_to_u32(A1_lo);
    uint32_t b1h_u = smem_to_u32(B1_hi);
    uint32_t a2h_u = smem_to_u32(A2_hi);
    uint32_t b2h_u = smem_to_u32(B2_hi);
    int arow = lane & 15;
    int akoff = (lane >> 4) * 16;
    int brow = (lane & 7) + ((lane & 16) ? 8 : 0);
    int bkoff = ((lane >> 3) & 1) * 16;

    // pre-scale y by 0.5 for the tanh identity: sigm(u)-0.5 = 0.5*tanh(u/2)
    float yv_[2][2];
#pragma unroll
    for (int mt = 0; mt < 2; mt++)
#pragma unroll
        for (int rh = 0; rh < 2; rh++) {
            int m = wm + mt * 16 + (lane >> 2) + 8 * rh;
            yv_[mt][rh] = 0.5f * g_yv[branch][t * HWSZ + hw0 + m];
        }

    float d2[2][4][4] = {};
    for (int kc = 0; kc < 9; kc++) {
        __syncthreads();
        {
            const uint4* bh = (const uint4*)&pb_sc_hi[branch][(size_t)(t * SS + kc * 64) * 64];
#pragma unroll
            for (int v = 0; v < 2; v++) {
                int i = v * 256 + tid;
                int row = i >> 3, j = i & 7;
                *(uint4*)(B1_hi + row * SA + j * 16) = bh[i];
            }
#pragma unroll
            for (int v = 0; v < 2; v++) {
                int i = v * 256 + tid;
                int row = i >> 3, j = i & 7;
                size_t src = (size_t)(t * CCH + row) * SS + kc * 64 + j * 8;
                *(uint4*)(B2_hi + row * SA + j * 16) = *(const uint4*)&pb_cs_hi[branch][src];
            }
        }
        __syncthreads();

        float d1[2][4][4] = {};
#pragma unroll
        for (int ks = 0; ks < 4; ks++) {
            int kb = ks * 32;
            uint32_t Ah[2][4], Al[2][4], Bh[4][2];
#pragma unroll
            for (int mt = 0; mt < 2; mt++) {
                uint32_t off = (uint32_t)((wm + mt * 16 + arow) * SA + kb + akoff);
                LDSM_X4(Ah[mt][0], Ah[mt][1], Ah[mt][2], Ah[mt][3], a1h_u + off);
                LDSM_X4(Al[mt][0], Al[mt][1], Al[mt][2], Al[mt][3], a1l_u + off);
            }
#pragma unroll
            for (int np = 0; np < 2; np++) {
                uint32_t off = (uint32_t)((wn + np * 16 + brow) * SA + kb + bkoff);
                uint32_t r0, r1, r2, r3;
                LDSM_X4(r0, r1, r2, r3, b1h_u + off);
                Bh[np * 2][0] = r0; Bh[np * 2][1] = r1;
                Bh[np * 2 + 1][0] = r2; Bh[np * 2 + 1][1] = r3;
            }
#pragma unroll
            for (int mt = 0; mt < 2; mt++)
#pragma unroll
                for (int nt = 0; nt < 4; nt++) {
                    MMA_F16(d1[mt][nt], Ah[mt], Bh[nt]);
                    MMA_F16(d1[mt][nt], Al[mt], Bh[nt]);
                }
        }

#pragma unroll
        for (int mt = 0; mt < 2; mt++)
#pragma unroll
            for (int nt = 0; nt < 4; nt++)
#pragma unroll
                for (int rh = 0; rh < 2; rh++) {
                    float yh = yv_[mt][rh];
                    float t0, t1;
                    TANH_APPROX(t0, yh * d1[mt][nt][rh * 2 + 0]);
                    TANH_APPROX(t1, yh * d1[mt][nt][rh * 2 + 1]);
                    unsigned short h0 = f16_of(0.5f * t0);
                    unsigned short h1 = f16_of(0.5f * t1);
                    int m = wm + mt * 16 + (lane >> 2) + 8 * rh;
                    int coff = (wn + nt * 8 + (lane & 3) * 2) * 2;
                    *(uint32_t*)(A2_hi + m * SA + coff) = (uint32_t)h0 | ((uint32_t)h1 << 16);
                }
        __syncthreads();

#pragma unroll
        for (int ks = 0; ks < 4; ks++) {
            int kb = ks * 32;
            uint32_t Ah[2][4], Bh[4][2];
#pragma unroll
            for (int mt = 0; mt < 2; mt++) {
                uint32_t off = (uint32_t)((wm + mt * 16 + arow) * SA + kb + akoff);
                LDSM_X4(Ah[mt][0], Ah[mt][1], Ah[mt][2], Ah[mt][3], a2h_u + off);
            }
#pragma unroll
            for (int np = 0; np < 2; np++) {
                uint32_t off = (uint32_t)((wn + np * 16 + brow) * SA + kb + bkoff);
                uint32_t r0, r1, r2, r3;
                LDSM_X4(r0, r1, r2, r3, b2h_u + off);
                Bh[np * 2][0] = r0; Bh[np * 2][1] = r1;
                Bh[np * 2 + 1][0] = r2; Bh[np * 2 + 1][1] = r3;
            }
#pragma unroll
            for (int mt = 0; mt < 2; mt++)
#pragma unroll
                for (int nt = 0; nt < 4; nt++)
                    MMA_F16(d2[mt][nt], Ah[mt], Bh[nt]);
        }
    }

    __syncthreads();
    float* stage = (float*)sm;
#pragma unroll
    for (int mt = 0; mt < 2; mt++)
#pragma unroll
        for (int nt = 0; nt < 4; nt++)
#pragma unroll
            for (int r = 0; r < 4; r++) {
                int m = wm + mt * 16 + (lane >> 2) + ((r >> 1) & 1) * 8;
                int n = wn + nt * 8 + (lane & 3) * 2 + (r & 1);
                stage[m * STG + n] = d2[mt][nt][r];
            }
    __syncthreads();
    float wscale = w2s[branch];
    int row = tid >> 1, half = tid & 1;
    const float* srow = &stage[row * STG + half * 32];
    float* dst = &g_featb[branch][((size_t)t * HWSZ + hw0 + row) * CCH + half * 32];
#pragma unroll
    for (int q = 0; q < 8; q++) {
        float4 b = *(const float4*)&srow[q * 4];
        float4 o4 = make_float4(b.x * wscale, b.y * wscale, b.z * wscale, b.w * wscale);
        *(float4*)&dst[q * 4] = o4;
    }
}

// ---------------- xd = w_down @ x (one thread per pos, 4 outputs) ---------------
__global__ void k_xd(const float* __restrict__ x, const float* __restrict__ wd) {
    int pos = blockIdx.x * blockDim.x + threadIdx.x;
    if (pos >= THWSZ) return;
    float a0 = 0.0f, a1 = 0.0f, a2 = 0.0f, a3 = 0.0f;
    for (int c = 0; c < CCH; c++) {
        float v = x[c * THWSZ + pos];
        a0 = fmaf(wd[c], v, a0);
        a1 = fmaf(wd[CCH + c], v, a1);
        a2 = fmaf(wd[2 * CCH + c], v, a2);
        a3 = fmaf(wd[3 * CCH + c], v, a3);
    }
    g_xd[pos] = a0;
    g_xd[THWSZ + pos] = a1;
    g_xd[2 * THWSZ + pos] = a2;
    g_xd[3 * THWSZ + pos] = a3;
}

// ---------------- 3x depthwise 3D convs ------------------------------------------
__global__ void k_agg(const float* __restrict__ w1, const float* __restrict__ b1,
                      const float* __restrict__ w2, const float* __restrict__ b2,
                      const float* __restrict__ w3, const float* __restrict__ b3,
                      const float* __restrict__ wts) {
    int idx = blockIdx.x * blockDim.x + threadIdx.x;
    if (idx >= RCC * THWSZ) return;
    int r = idx / THWSZ;
    int rem = idx % THWSZ;
    int t = rem / HWSZ;
    int hw = rem % HWSZ;
    int h = hw / WWI, w = hw % WWI;
    const float* xb = g_xd + r * THWSZ;
    const float* ws_[3] = {w1, w2, w3};
    const float* bs_[3] = {b1, b2, b3};
    float total = 0.0f;
#pragma unroll
    for (int m = 0; m < 3; m++) {
        int d = m + 1;
        float cs = bs_[m][r];
        const float* wp = ws_[m] + r * 81;
        for (int kt = 0; kt < 9; kt++) {
            int ti = t + kt - 4;
            if (ti < 0 || ti >= TT) continue;
#pragma unroll
            for (int kh = 0; kh < 3; kh++) {
                int hi = h + (kh - 1) * d;
                if (hi < 0 || hi >= HHH) continue;
#pragma unroll
                for (int kw = 0; kw < 3; kw++) {
                    int wi = w + (kw - 1) * d;
                    if (wi < 0 || wi >= WWI) continue;
                    cs = fmaf(xb[ti * HWSZ + hi * WWI + wi], wp[(kt * 3 + kh) * 3 + kw], cs);
                }
            }
        }
        total = fmaf(wts[m], cs, total);
    }
    g_agg[idx] = total;
}

// ---------------- final ----------------------------------------------------------
__global__ void k_final(float* __restrict__ out, const float* __restrict__ wback) {
    int pos = blockIdx.x * 256 + threadIdx.x;
    if (pos >= THWSZ) return;
    float ag0 = g_agg[pos];
    float ag1 = g_agg[THWSZ + pos];
    float ag2 = g_agg[2 * THWSZ + pos];
    float ag3 = g_agg[3 * THWSZ + pos];
    const float4* f0 = (const float4*)&g_featb[0][(size_t)pos * CCH];
    const float4* f1 = (const float4*)&g_featb[1][(size_t)pos * CCH];
#pragma unroll
    for (int c4 = 0; c4 < 16; c4++) {
        float4 a = f0[c4];
        float4 b = f1[c4];
        float fv[4] = {a.x + b.x, a.y + b.y, a.z + b.z, a.w + b.w};
#pragma unroll
        for (int u = 0; u < 4; u++) {
            int c = c4 * 4 + u;
            float z = wback[c * 4 + 0] * ag0 + wback[c * 4 + 1] * ag1 +
                      wback[c * 4 + 2] * ag2 + wback[c * 4 + 3] * ag3;
            out[c * THWSZ + pos] = fv[u] * (sigm(z) - 0.5f);
        }
    }
}

extern "C" void kernel_launch(void* const* d_in, const int* in_sizes, int n_in,
                              void* d_out, int out_size) {
    const float* x       = (const float*)d_in[0];
    const float* w_dc2   = (const float*)d_in[1];
    const float* w_ofs_l = (const float*)d_in[2];
    const float* b_ofs_l = (const float*)d_in[3];
    const float* w_ofs_r = (const float*)d_in[4];
    const float* b_ofs_r = (const float*)d_in[5];
    const float* ca_w1   = (const float*)d_in[6];
    const float* ca_w2   = (const float*)d_in[7];
    const float* w_down  = (const float*)d_in[8];
    const float* sa1_w   = (const float*)d_in[9];
    const float* sa1_b   = (const float*)d_in[10];
    const float* sa2_w   = (const float*)d_in[11];
    const float* sa2_b   = (const float*)d_in[12];
    const float* sa3_w   = (const float*)d_in[13];
    const float* sa3_b   = (const float*)d_in[14];
    const float* weights = (const float*)d_in[15];
    const float* weights2= (const float*)d_in[16];
    const float* w_back  = (const float*)d_in[17];
    float* out = (float*)d_out;

    static cudaStream_t s2 = 0;
    static cudaEvent_t evFork = 0, evXT = 0, evAGG = 0;
    if (s2 == 0) {
        cudaStreamCreateWithFlags(&s2, cudaStreamNonBlocking);
        cudaEventCreateWithFlags(&evFork, cudaEventDisableTiming);
        cudaEventCreateWithFlags(&evXT, cudaEventDisableTiming);
        cudaEventCreateWithFlags(&evAGG, cudaEventDisableTiming);
        cudaFuncSetAttribute(k_gemm1_stats, cudaFuncAttributeMaxDynamicSharedMemorySize, SM1_TOT);
        cudaFuncSetAttribute(k_gemm2f, cudaFuncAttributeMaxDynamicSharedMemorySize, SM2_TOT);
    }

    // fork side stream off the main (capture) stream
    cudaEventRecord(evFork, 0);
    cudaStreamWaitEvent(s2, evFork, 0);

    // side stream: depends only on x
    k_xt<<<(THWSZ + 255) / 256, 256, 0, s2>>>(x);
    cudaEventRecord(evXT, s2);
    k_xd<<<(THWSZ + 255) / 256, 256, 0, s2>>>(x, w_down);
    k_agg<<<(RCC * THWSZ + 255) / 256, 256, 0, s2>>>(sa1_w, sa1_b, sa2_w, sa2_b, sa3_w, sa3_b, weights);
    cudaEventRecord(evAGG, s2);

    // main stream
    k_x2<<<THWSZ / 128, 256>>>(x, w_dc2);
    k_offp<<<(NCC * 2 * TT * SS) / 256, 256>>>(x, w_ofs_l, w_ofs_r);
    k_offred<<<(2 * TT * 2 * SS + 255) / 256, 256>>>(b_ofs_l, b_ofs_r);
    k_sample<<<(2 * TT * 16 * SS) / 256, 256>>>();

    cudaStreamWaitEvent(0, evXT, 0);  // gemm1/gemm2 need g_xt_*
    dim3 gg(HWSZ / 128, TT, 2);
    k_gemm1_stats<<<gg, 256, SM1_TOT>>>();
    k_y<<<(2 * TT * HWSZ + 255) / 256, 256>>>(ca_w1, ca_w2);
    k_gemm2f<<<gg, 256, SM2_TOT>>>(weights2);

    cudaStreamWaitEvent(0, evAGG, 0);  // k_final needs g_agg
    k_final<<<(THWSZ + 255) / 256, 256>>>(out, w_back);
}

// round 13
// speedup vs baseline: 4.0030x; 1.0469x over previous
#include <cuda_runtime.h>
#include <cuda_fp16.h>
#include <math.h>
#include <stdint.h>

#define TT 16
#define CCH 64
#define HHH 48
#define WWI 48
#define HWSZ 2304
#define THWSZ 36864
#define WW2 24
#define SS 576
#define RCC 4
#define NCC 16   // channel chunks of 4 in k_offp

typedef unsigned long long u64t;

// ---------------- FFMA2 helpers (k_x2) ----------------
#define FMA_F32X2(d, a, b, c) \
    asm("fma.rn.f32x2 %0, %1, %2, %3;" : "=l"(d) : "l"(a), "l"(b), "l"(c))
#define DUP_F32X2(out, v) \
    asm("mov.b64 %0, {%1, %1};" : "=l"(out) : "r"(v))
#define UNPACK_F32X2(lo, hi, in) \
    asm("mov.b64 {%0, %1}, %2;" : "=r"(lo), "=r"(hi) : "l"(in))
union F4U { float4 f; u64t u[2]; };

// ---------------- mma.sync / ldmatrix helpers ----------------
__device__ __forceinline__ uint32_t smem_to_u32(const void* p) {
    uint32_t a;
    asm("{ .reg .u64 tmp; cvta.to.shared.u64 tmp, %1; cvt.u32.u64 %0, tmp; }"
        : "=r"(a) : "l"(p));
    return a;
}
#define LDSM_X4(r0, r1, r2, r3, addr) \
    asm volatile("ldmatrix.sync.aligned.m8n8.x4.shared.b16 {%0,%1,%2,%3}, [%4];" \
        : "=r"(r0), "=r"(r1), "=r"(r2), "=r"(r3) : "r"(addr))
#define MMA_F16(d, a, b) \
    asm volatile("mma.sync.aligned.m16n8k16.row.col.f32.f16.f16.f32 " \
        "{%0,%1,%2,%3}, {%4,%5,%6,%7}, {%8,%9}, {%0,%1,%2,%3};" \
        : "+f"((d)[0]), "+f"((d)[1]), "+f"((d)[2]), "+f"((d)[3]) \
        : "r"((a)[0]), "r"((a)[1]), "r"((a)[2]), "r"((a)[3]), "r"((b)[0]), "r"((b)[1]))
#define TANH_APPROX(d, a) \
    asm("tanh.approx.f32 %0, %1;" : "=f"(d) : "f"(a))

// smem tile geometry: fp16 rows padded to 72 elems (144 B)
#define SA 144
#define A_TILE_B (128 * SA)   // 18432
#define B_TILE_B (64 * SA)    // 9216
#define SM1_TOT (A_TILE_B + B_TILE_B)                     // 27648
#define SM2_TOT (2 * A_TILE_B + 2 * B_TILE_B)             // 55296
#define STG 68

// ---------------- scratch (device globals; no allocations) ----------------
static __device__ float g_x2[CCH * THWSZ];            // [c][t][h][w]
static __device__ float g_offp[NCC][2 * TT * 2 * SS];
static __device__ float g_off[2 * TT * 2 * SS];
static __device__ __align__(16) unsigned short g_xt_hi[THWSZ * CCH];  // fp16 [t][hw][c]
static __device__ __align__(16) unsigned short pb_sc_hi[2][TT * SS * CCH]; // fp16 [t][s][c]
static __device__ __align__(16) unsigned short pb_cs_hi[2][TT * CCH * SS]; // fp16 [t][c][s]
static __device__ float g_mean[2][TT * HWSZ];
static __device__ float g_maxv[2][TT * HWSZ];
static __device__ float g_varv[2][TT * HWSZ];
static __device__ float g_yv[2][TT * HWSZ];
static __device__ float g_featb[2][TT * HWSZ * CCH]; // [branch][t][hw][c]
static __device__ float g_xd[RCC * THWSZ];
static __device__ float g_agg[RCC * THWSZ];

__device__ __forceinline__ float sigm(float v) { return 1.0f / (1.0f + __expf(-v)); }

__device__ __forceinline__ unsigned short f16_of(float v) {
    __half h = __float2half_rn(v);
    return *(unsigned short*)&h;
}

// ---------------- x2 = w_dc2 @ x (FFMA2) -------------------------------------
__device__ __forceinline__ void mma4x8(const float4& a, const F4U& b0, const F4U& b1,
                                       u64t accp[4][4]) {
    float av[4] = {a.x, a.y, a.z, a.w};
    u64t bp[4] = {b0.u[0], b0.u[1], b1.u[0], b1.u[1]};
#pragma unroll
    for (int i = 0; i < 4; i++) {
        u64t ad;
        DUP_F32X2(ad, __float_as_uint(av[i]));
#pragma unroll
        for (int j = 0; j < 4; j++) FMA_F32X2(accp[i][j], ad, bp[j], accp[i][j]);
    }
}
__device__ __forceinline__ void unpack_acc(const u64t accp[4][4], float acc[4][8]) {
#pragma unroll
    for (int i = 0; i < 4; i++)
#pragma unroll
        for (int j = 0; j < 4; j++) {
            unsigned lo, hi;
            UNPACK_F32X2(lo, hi, accp[i][j]);
            acc[i][2 * j] = __uint_as_float(lo);
            acc[i][2 * j + 1] = __uint_as_float(hi);
        }
}

__global__ void __launch_bounds__(256) k_x2(const float* __restrict__ x, const float* __restrict__ w) {
    __shared__ float Ws[64][64];
    __shared__ float Xs[64][128];
    int tid = threadIdx.x;
    int pos0 = blockIdx.x * 128;
#pragma unroll
    for (int v = 0; v < 16; v++) {
        int i = v * 256 + tid;
        Ws[i & 63][i >> 6] = w[i];
    }
#pragma unroll
    for (int v = 0; v < 8; v++) {
        int i = v * 256 + tid;
        int row = i >> 5, col = (i & 31) * 4;
        *(float4*)&Xs[row][col] = *(const float4*)&x[row * THWSZ + pos0 + col];
    }
    __syncthreads();
    int tx = tid & 31, ty = tid >> 5;
    u64t accp[4][4];
#pragma unroll
    for (int i = 0; i < 4; i++)
#pragma unroll
        for (int j = 0; j < 4; j++) accp[i][j] = 0ULL;
    float4 a_c = *(float4*)&Xs[0][tx * 4];
    F4U b0_c, b1_c;
    b0_c.f = *(float4*)&Ws[0][ty * 8];
    b1_c.f = *(float4*)&Ws[0][ty * 8 + 4];
#pragma unroll 7
    for (int k = 0; k < 63; k++) {
        float4 a_n = *(float4*)&Xs[k + 1][tx * 4];
        F4U b0_n, b1_n;
        b0_n.f = *(float4*)&Ws[k + 1][ty * 8];
        b1_n.f = *(float4*)&Ws[k + 1][ty * 8 + 4];
        mma4x8(a_c, b0_c, b1_c, accp);
        a_c = a_n; b0_c = b0_n; b1_c = b1_n;
    }
    mma4x8(a_c, b0_c, b1_c, accp);
    float acc[4][8];
    unpack_acc(accp, acc);
#pragma unroll
    for (int j = 0; j < 8; j++) {
        int o = ty * 8 + j;
        float4 o4 = make_float4(acc[0][j], acc[1][j], acc[2][j], acc[3][j]);
        *(float4*)&g_x2[o * THWSZ + pos0 + tx * 4] = o4;
    }
}

// ---------------- x transpose + fp16 convert -----------------------------------
__global__ void __launch_bounds__(256) k_xt(const float* __restrict__ x) {
    int idx = blockIdx.x * 256 + threadIdx.x;
    if (idx >= THWSZ) return;
    unsigned short* dh = &g_xt_hi[(size_t)idx * 64];
#pragma unroll 8
    for (int c = 0; c < CCH; c++) {
        dh[c] = f16_of(x[c * THWSZ + idx]);
    }
}

// ------- offset conv partials (both o per thread) + reduce ---------------------
__global__ void __launch_bounds__(256) k_offp(const float* __restrict__ x,
                      const float* __restrict__ wl, const float* __restrict__ wr) {
    int idx = blockIdx.x * 256 + threadIdx.x;  // NCC*2*TT*SS = 294912
    int s = idx % SS;
    int t = (idx / SS) & 15;
    int branch = (idx / (SS * TT)) & 1;
    int cc = idx / (SS * TT * 2);
    int i = s / WW2, j = s % WW2;
    int tsrc = (branch == 0) ? min(t + 1, TT - 1) : max(t - 1, 0);
    const float* wofs = (branch == 0) ? wl : wr;
    float acc0 = 0.0f, acc1 = 0.0f;
#pragma unroll
    for (int u = 0; u < 4; u++) {
        int c = cc * 4 + u;
        const float* xp = x + c * THWSZ + t * HWSZ;
        const float* x2p = g_x2 + c * THWSZ + tsrc * HWSZ;
        const float* wp0 = wofs + c * 9;
        const float* wp1 = wofs + (CCH + c) * 9;
#pragma unroll
        for (int ki = 0; ki < 3; ki++) {
            int h = 2 * i - 1 + ki;
            if (h < 0 || h >= HHH) continue;
#pragma unroll
            for (int kj = 0; kj < 3; kj++) {
                int w = 2 * j - 1 + kj;
                if (w < 0 || w >= WWI) continue;
                float v = xp[h * WWI + w] + x2p[h * WWI + w];
                acc0 = fmaf(v, wp0[ki * 3 + kj], acc0);
                acc1 = fmaf(v, wp1[ki * 3 + kj], acc1);
            }
        }
    }
    g_offp[cc][((branch * TT + t) * 2 + 0) * SS + s] = acc0;
    g_offp[cc][((branch * TT + t) * 2 + 1) * SS + s] = acc1;
}

__global__ void k_offred(const float* __restrict__ bl, const float* __restrict__ br_) {
    int i = blockIdx.x * 256 + threadIdx.x;
    if (i >= 2 * TT * 2 * SS) return;
    int branch = i / (TT * 2 * SS);
    int o = (i / SS) & 1;
    float acc = (branch == 0) ? bl[o] : br_[o];
#pragma unroll
    for (int cc = 0; cc < NCC; cc++) acc += g_offp[cc][i];
    g_off[i] = acc;
}

// ------- bilinear grid-sample -> fp16 parts ------------------------------------
__global__ void __launch_bounds__(256) k_sample() {
    int idx = blockIdx.x * 256 + threadIdx.x;
    int s = idx % SS;
    int c4 = (idx / SS) & 15;
    int t = (idx / (SS * 16)) & 15;
    int branch = idx / (SS * 16 * 16);
    int i = s / WW2, j = s % WW2;
    float off0 = g_off[((branch * TT + t) * 2 + 0) * SS + s];
    float off1 = g_off[((branch * TT + t) * 2 + 1) * SS + s];
    float v0 = 2.0f * (float)j + off0;
    float v1 = 2.0f * (float)i + off1;
    float gh = 2.0f * v0 / 23.0f - 1.0f;
    float gw = 2.0f * v1 / 23.0f - 1.0f;
    float xs = ((gh + 1.0f) * 48.0f - 1.0f) * 0.5f;
    float ys = ((gw + 1.0f) * 48.0f - 1.0f) * 0.5f;
    float x0f = floorf(xs), y0f = floorf(ys);
    int x0 = (int)x0f, y0 = (int)y0f;
    float fx = xs - x0f, fy = ys - y0f;
    float wgt[4] = {(1.0f - fx) * (1.0f - fy), fx * (1.0f - fy),
                    (1.0f - fx) * fy, fx * fy};
    int xi[4] = {x0, x0 + 1, x0, x0 + 1};
    int yi[4] = {y0, y0, y0 + 1, y0 + 1};
    float wv[4];
    int id[4];
#pragma unroll
    for (int k = 0; k < 4; k++) {
        bool valid = (xi[k] >= 0) && (xi[k] < WWI) && (yi[k] >= 0) && (yi[k] < HHH);
        wv[k] = valid ? wgt[k] : 0.0f;
        int cy = min(max(yi[k], 0), HHH - 1);
        int cx = min(max(xi[k], 0), WWI - 1);
        id[k] = cy * WWI + cx;
    }
    int tsrc = (branch == 0) ? min(t + 1, TT - 1) : max(t - 1, 0);
#pragma unroll
    for (int u = 0; u < 4; u++) {
        int c = c4 * 4 + u;
        const float* img = g_x2 + c * THWSZ + tsrc * HWSZ;
        float val = wv[0] * img[id[0]] + wv[1] * img[id[1]] +
                    wv[2] * img[id[2]] + wv[3] * img[id[3]];
        unsigned short hs = f16_of(val);
        pb_sc_hi[branch][(t * SS + s) * CCH + c] = hs;
        pb_cs_hi[branch][(t * CCH + c) * SS + s] = hs;
    }
}

// ------- GEMM1-stats: single-pass fp16, both branches ---------------------------
__global__ void __launch_bounds__(256, 3) k_gemm1_stats() {
    extern __shared__ __align__(16) char sm[];
    char* A_hi = sm;
    char* B_hi = sm + A_TILE_B;
    float* red = (float*)(sm + A_TILE_B);
    int tid = threadIdx.x;
    int t = blockIdx.y, hw0 = blockIdx.x * 128, branch = blockIdx.z;

    {
        const uint4* sh = (const uint4*)&g_xt_hi[(size_t)(t * HWSZ + hw0) * 64];
#pragma unroll
        for (int v = 0; v < 4; v++) {
            int i = v * 256 + tid;
            int row = i >> 3, j = i & 7;
            *(uint4*)(A_hi + row * SA + j * 16) = sh[i];
        }
    }

    int wid = tid >> 5, lane = tid & 31;
    int wm = (wid & 3) * 32;
    int wn = (wid >> 2) * 32;
    uint32_t ah_u = smem_to_u32(A_hi);
    uint32_t bh_u = smem_to_u32(B_hi);
    int arow = lane & 15;
    int akoff = (lane >> 4) * 16;
    int brow = (lane & 7) + ((lane & 16) ? 8 : 0);
    int bkoff = ((lane >> 3) & 1) * 16;

    float s_sum[2][2] = {}, s_sq[2][2] = {};
    float s_mx[2][2] = {{-3.4e38f, -3.4e38f}, {-3.4e38f, -3.4e38f}};

    for (int kc = 0; kc < 9; kc++) {
        __syncthreads();
        {
            const uint4* bh = (const uint4*)&pb_sc_hi[branch][(size_t)(t * SS + kc * 64) * 64];
#pragma unroll
            for (int v = 0; v < 2; v++) {
                int i = v * 256 + tid;
                int row = i >> 3, j = i & 7;
                *(uint4*)(B_hi + row * SA + j * 16) = bh[i];
            }
        }
        __syncthreads();

        float d[2][4][4] = {};
#pragma unroll
        for (int ks = 0; ks < 4; ks++) {
            int kb = ks * 32;
            uint32_t Ah[2][4], Bh[4][2];
#pragma unroll
            for (int mt = 0; mt < 2; mt++) {
                uint32_t off = (uint32_t)((wm + mt * 16 + arow) * SA + kb + akoff);
                LDSM_X4(Ah[mt][0], Ah[mt][1], Ah[mt][2], Ah[mt][3], ah_u + off);
            }
#pragma unroll
            for (int np = 0; np < 2; np++) {
                uint32_t off = (uint32_t)((wn + np * 16 + brow) * SA + kb + bkoff);
                uint32_t r0, r1, r2, r3;
                LDSM_X4(r0, r1, r2, r3, bh_u + off);
                Bh[np * 2][0] = r0; Bh[np * 2][1] = r1;
                Bh[np * 2 + 1][0] = r2; Bh[np * 2 + 1][1] = r3;
            }
#pragma unroll
            for (int mt = 0; mt < 2; mt++)
#pragma unroll
                for (int nt = 0; nt < 4; nt++)
                    MMA_F16(d[mt][nt], Ah[mt], Bh[nt]);
        }
#pragma unroll
        for (int mt = 0; mt < 2; mt++)
#pragma unroll
            for (int nt = 0; nt < 4; nt++)
#pragma unroll
                for (int r = 0; r < 4; r++) {
                    int rh = (r >> 1) & 1;
                    float v = d[mt][nt][r];
                    s_sum[mt][rh] += v;
                    s_sq[mt][rh] = fmaf(v, v, s_sq[mt][rh]);
                    s_mx[mt][rh] = fmaxf(s_mx[mt][rh], v);
                }
    }

#pragma unroll
    for (int mt = 0; mt < 2; mt++)
#pragma unroll
        for (int rh = 0; rh < 2; rh++) {
            s_sum[mt][rh] += __shfl_xor_sync(0xFFFFFFFFu, s_sum[mt][rh], 1);
            s_sum[mt][rh] += __shfl_xor_sync(0xFFFFFFFFu, s_sum[mt][rh], 2);
            s_sq[mt][rh] += __shfl_xor_sync(0xFFFFFFFFu, s_sq[mt][rh], 1);
            s_sq[mt][rh] += __shfl_xor_sync(0xFFFFFFFFu, s_sq[mt][rh], 2);
            s_mx[mt][rh] = fmaxf(s_mx[mt][rh], __shfl_xor_sync(0xFFFFFFFFu, s_mx[mt][rh], 1));
            s_mx[mt][rh] = fmaxf(s_mx[mt][rh], __shfl_xor_sync(0xFFFFFFFFu, s_mx[mt][rh], 2));
        }
    __syncthreads();
    if ((lane & 3) == 0) {
        int nw = wid >> 2;
#pragma unroll
        for (int mt = 0; mt < 2; mt++)
#pragma unroll
            for (int rh = 0; rh < 2; rh++) {
                int m = wm + mt * 16 + (lane >> 2) + 8 * rh;
                float* p = &red[(nw * 128 + m) * 3];
                p[0] = s_sum[mt][rh];
                p[1] = s_sq[mt][rh];
                p[2] = s_mx[mt][rh];
            }
    }
    __syncthreads();
    if (tid < 128) {
        int m = tid;
        const float* p0 = &red[m * 3];
        const float* p1 = &red[(128 + m) * 3];
        float sum = p0[0] + p1[0];
        float sq = p0[1] + p1[1];
        float mx = fmaxf(p0[2], p1[2]);
        int o = t * HWSZ + hw0 + m;
        g_mean[branch][o] = sum / 576.0f;
        g_maxv[branch][o] = mx;
        g_varv[branch][o] = (sq - sum * sum / 576.0f) / 575.0f;
    }
}

// ---------------- attention gate (both branches) --------------------------------
__global__ void k_y(const float* __restrict__ w1, const float* __restrict__ w2) {
    int gidx = blockIdx.x * 256 + threadIdx.x;
    if (gidx >= 2 * TT * HWSZ) return;
    int branch = gidx / (TT * HWSZ);
    int idx = gidx % (TT * HWSZ);
    int t = idx / HWSZ;
    int hw = idx % HWSZ;
    int h = hw / WWI, w = hw % WWI;
    float acc = 0.0f;
#pragma unroll
    for (int dh = 0; dh < 3; dh++) {
        int hh = h + dh - 1;
        if (hh < 0 || hh >= HHH) continue;
#pragma unroll
        for (int dw = 0; dw < 3; dw++) {
            int ww = w + dw - 1;
            if (ww < 0 || ww >= WWI) continue;
            int p = t * HWSZ + hh * WWI + ww;
            acc = fmaf(w1[(0 * 3 + dh) * 3 + dw], g_mean[branch][p], acc);
            acc = fmaf(w1[(3 + dh) * 3 + dw], g_maxv[branch][p], acc);
            acc = fmaf(w2[dh * 3 + dw], g_varv[branch][p], acc);
        }
    }
    g_yv[branch][idx] = sigm(acc);
}

// ------- fused GEMM2: single-pass fp16 everywhere, tanh gate --------------------
// grid (18, 16, 2), 256 thr, 2 CTA/SM (smem 55.3KB).
__global__ void __launch_bounds__(256, 2) k_gemm2f(const float* __restrict__ w2s) {
    extern __shared__ __align__(16) char sm[];
    char* A1_hi = sm;
    char* B1_hi = sm + A_TILE_B;
    char* A2_hi = sm + A_TILE_B + B_TILE_B;
    char* B2_hi = A2_hi + A_TILE_B;
    int tid = threadIdx.x;
    int t = blockIdx.y, hw0 = blockIdx.x * 128, branch = blockIdx.z;

    {
        const uint4* sh = (const uint4*)&g_xt_hi[(size_t)(t * HWSZ + hw0) * 64];
#pragma unroll
        for (int v = 0; v < 4; v++) {
            int i = v * 256 + tid;
            int row = i >> 3, j = i & 7;
            *(uint4*)(A1_hi + row * SA + j * 16) = sh[i];
        }
    }

    int wid = tid >> 5, lane = tid & 31;
    int wm = (wid & 3) * 32;
    int wn = (wid >> 2) * 32;
    uint32_t a1h_u = smem_to_u32(A1_hi);
    uint32_t b1h_u = smem_to_u32(B1_hi);
    uint32_t a2h_u = smem_to_u32(A2_hi);
    uint32_t b2h_u = smem_to_u32(B2_hi);
    int arow = lane & 15;
    int akoff = (lane >> 4) * 16;
    int brow = (lane & 7) + ((lane & 16) ? 8 : 0);
    int bkoff = ((lane >> 3) & 1) * 16;

    // pre-scale y by 0.5 for the tanh identity: sigm(u)-0.5 = 0.5*tanh(u/2)
    float yv_[2][2];
#pragma unroll
    for (int mt = 0; mt < 2; mt++)
#pragma unroll
        for (int rh = 0; rh < 2; rh++) {
            int m = wm + mt * 16 + (lane >> 2) + 8 * rh;
            yv_[mt][rh] = 0.5f * g_yv[branch][t * HWSZ + hw0 + m];
        }

    float d2[2][4][4] = {};
    for (int kc = 0; kc < 9; kc++) {
        __syncthreads();
        {
            const uint4* bh = (const uint4*)&pb_sc_hi[branch][(size_t)(t * SS + kc * 64) * 64];
#pragma unroll
            for (int v = 0; v < 2; v++) {
                int i = v * 256 + tid;
                int row = i >> 3, j = i & 7;
                *(uint4*)(B1_hi + row * SA + j * 16) = bh[i];
            }
#pragma unroll
            for (int v = 0; v < 2; v++) {
                int i = v * 256 + tid;
                int row = i >> 3, j = i & 7;
                size_t src = (size_t)(t * CCH + row) * SS + kc * 64 + j * 8;
                *(uint4*)(B2_hi + row * SA + j * 16) = *(const uint4*)&pb_cs_hi[branch][src];
            }
        }
        __syncthreads();

        float d1[2][4][4] = {};
#pragma unroll
        for (int ks = 0; ks < 4; ks++) {
            int kb = ks * 32;
            uint32_t Ah[2][4], Bh[4][2];
#pragma unroll
            for (int mt = 0; mt < 2; mt++) {
                uint32_t off = (uint32_t)((wm + mt * 16 + arow) * SA + kb + akoff);
                LDSM_X4(Ah[mt][0], Ah[mt][1], Ah[mt][2], Ah[mt][3], a1h_u + off);
            }
#pragma unroll
            for (int np = 0; np < 2; np++) {
                uint32_t off = (uint32_t)((wn + np * 16 + brow) * SA + kb + bkoff);
                uint32_t r0, r1, r2, r3;
                LDSM_X4(r0, r1, r2, r3, b1h_u + off);
                Bh[np * 2][0] = r0; Bh[np * 2][1] = r1;
                Bh[np * 2 + 1][0] = r2; Bh[np * 2 + 1][1] = r3;
            }
#pragma unroll
            for (int mt = 0; mt < 2; mt++)
#pragma unroll
                for (int nt = 0; nt < 4; nt++)
                    MMA_F16(d1[mt][nt], Ah[mt], Bh[nt]);
        }

#pragma unroll
        for (int mt = 0; mt < 2; mt++)
#pragma unroll
            for (int nt = 0; nt < 4; nt++)
#pragma unroll
                for (int rh = 0; rh < 2; rh++) {
                    float yh = yv_[mt][rh];
                    float t0, t1;
                    TANH_APPROX(t0, yh * d1[mt][nt][rh * 2 + 0]);
                    TANH_APPROX(t1, yh * d1[mt][nt][rh * 2 + 1]);
                    unsigned short h0 = f16_of(0.5f * t0);
                    unsigned short h1 = f16_of(0.5f * t1);
                    int m = wm + mt * 16 + (lane >> 2) + 8 * rh;
                    int coff = (wn + nt * 8 + (lane & 3) * 2) * 2;
                    *(uint32_t*)(A2_hi + m * SA + coff) = (uint32_t)h0 | ((uint32_t)h1 << 16);
                }
        __syncthreads();

#pragma unroll
        for (int ks = 0; ks < 4; ks++) {
            int kb = ks * 32;
            uint32_t Ah[2][4], Bh[4][2];
#pragma unroll
            for (int mt = 0; mt < 2; mt++) {
                uint32_t off = (uint32_t)((wm + mt * 16 + arow) * SA + kb + akoff);
                LDSM_X4(Ah[mt][0], Ah[mt][1], Ah[mt][2], Ah[mt][3], a2h_u + off);
            }
#pragma unroll
            for (int np = 0; np < 2; np++) {
                uint32_t off = (uint32_t)((wn + np * 16 + brow) * SA + kb + bkoff);
                uint32_t r0, r1, r2, r3;
                LDSM_X4(r0, r1, r2, r3, b2h_u + off);
                Bh[np * 2][0] = r0; Bh[np * 2][1] = r1;
                Bh[np * 2 + 1][0] = r2; Bh[np * 2 + 1][1] = r3;
            }
#pragma unroll
            for (int mt = 0; mt < 2; mt++)
#pragma unroll
                for (int nt = 0; nt < 4; nt++)
                    MMA_F16(d2[mt][nt], Ah[mt], Bh[nt]);
        }
    }

    __syncthreads();
    float* stage = (float*)sm;
#pragma unroll
    for (int mt = 0; mt < 2; mt++)
#pragma unroll
        for (int nt = 0; nt < 4; nt++)
#pragma unroll
            for (int r = 0; r < 4; r++) {
                int m = wm + mt * 16 + (lane >> 2) + ((r >> 1) & 1) * 8;
                int n = wn + nt * 8 + (lane & 3) * 2 + (r & 1);
                stage[m * STG + n] = d2[mt][nt][r];
            }
    __syncthreads();
    float wscale = w2s[branch];
    int row = tid >> 1, half = tid & 1;
    const float* srow = &stage[row * STG + half * 32];
    float* dst = &g_featb[branch][((size_t)t * HWSZ + hw0 + row) * CCH + half * 32];
#pragma unroll
    for (int q = 0; q < 8; q++) {
        float4 b = *(const float4*)&srow[q * 4];
        float4 o4 = make_float4(b.x * wscale, b.y * wscale, b.z * wscale, b.w * wscale);
        *(float4*)&dst[q * 4] = o4;
    }
}

// ---------------- xd = w_down @ x (one thread per pos, 4 outputs) ---------------
__global__ void k_xd(const float* __restrict__ x, const float* __restrict__ wd) {
    int pos = blockIdx.x * blockDim.x + threadIdx.x;
    if (pos >= THWSZ) return;
    float a0 = 0.0f, a1 = 0.0f, a2 = 0.0f, a3 = 0.0f;
    for (int c = 0; c < CCH; c++) {
        float v = x[c * THWSZ + pos];
        a0 = fmaf(wd[c], v, a0);
        a1 = fmaf(wd[CCH + c], v, a1);
        a2 = fmaf(wd[2 * CCH + c], v, a2);
        a3 = fmaf(wd[3 * CCH + c], v, a3);
    }
    g_xd[pos] = a0;
    g_xd[THWSZ + pos] = a1;
    g_xd[2 * THWSZ + pos] = a2;
    g_xd[3 * THWSZ + pos] = a3;
}

// ---------------- 3x depthwise 3D convs ------------------------------------------
__global__ void k_agg(const float* __restrict__ w1, const float* __restrict__ b1,
                      const float* __restrict__ w2, const float* __restrict__ b2,
                      const float* __restrict__ w3, const float* __restrict__ b3,
                      const float* __restrict__ wts) {
    int idx = blockIdx.x * blockDim.x + threadIdx.x;
    if (idx >= RCC * THWSZ) return;
    int r = idx / THWSZ;
    int rem = idx % THWSZ;
    int t = rem / HWSZ;
    int hw = rem % HWSZ;
    int h = hw / WWI, w = hw % WWI;
    const float* xb = g_xd + r * THWSZ;
    const float* ws_[3] = {w1, w2, w3};
    const float* bs_[3] = {b1, b2, b3};
    float total = 0.0f;
#pragma unroll
    for (int m = 0; m < 3; m++) {
        int d = m + 1;
        float cs = bs_[m][r];
        const float* wp = ws_[m] + r * 81;
        for (int kt = 0; kt < 9; kt++) {
            int ti = t + kt - 4;
            if (ti < 0 || ti >= TT) continue;
#pragma unroll
            for (int kh = 0; kh < 3; kh++) {
                int hi = h + (kh - 1) * d;
                if (hi < 0 || hi >= HHH) continue;
#pragma unroll
                for (int kw = 0; kw < 3; kw++) {
                    int wi = w + (kw - 1) * d;
                    if (wi < 0 || wi >= WWI) continue;
                    cs = fmaf(xb[ti * HWSZ + hi * WWI + wi], wp[(kt * 3 + kh) * 3 + kw], cs);
                }
            }
        }
        total = fmaf(wts[m], cs, total);
    }
    g_agg[idx] = total;
}

// ---------------- final ----------------------------------------------------------
__global__ void k_final(float* __restrict__ out, const float* __restrict__ wback) {
    int pos = blockIdx.x * 256 + threadIdx.x;
    if (pos >= THWSZ) return;
    float ag0 = g_agg[pos];
    float ag1 = g_agg[THWSZ + pos];
    float ag2 = g_agg[2 * THWSZ + pos];
    float ag3 = g_agg[3 * THWSZ + pos];
    const float4* f0 = (const float4*)&g_featb[0][(size_t)pos * CCH];
    const float4* f1 = (const float4*)&g_featb[1][(size_t)pos * CCH];
#pragma unroll
    for (int c4 = 0; c4 < 16; c4++) {
        float4 a = f0[c4];
        float4 b = f1[c4];
        float fv[4] = {a.x + b.x, a.y + b.y, a.z + b.z, a.w + b.w};
#pragma unroll
        for (int u = 0; u < 4; u++) {
            int c = c4 * 4 + u;
            float z = wback[c * 4 + 0] * ag0 + wback[c * 4 + 1] * ag1 +
                      wback[c * 4 + 2] * ag2 + wback[c * 4 + 3] * ag3;
            out[c * THWSZ + pos] = fv[u] * (sigm(z) - 0.5f);
        }
    }
}

extern "C" void kernel_launch(void* const* d_in, const int* in_sizes, int n_in,
                              void* d_out, int out_size) {
    const float* x       = (const float*)d_in[0];
    const float* w_dc2   = (const float*)d_in[1];
    const float* w_ofs_l = (const float*)d_in[2];
    const float* b_ofs_l = (const float*)d_in[3];
    const float* w_ofs_r = (const float*)d_in[4];
    const float* b_ofs_r = (const float*)d_in[5];
    const float* ca_w1   = (const float*)d_in[6];
    const float* ca_w2   = (const float*)d_in[7];
    const float* w_down  = (const float*)d_in[8];
    const float* sa1_w   = (const float*)d_in[9];
    const float* sa1_b   = (const float*)d_in[10];
    const float* sa2_w   = (const float*)d_in[11];
    const float* sa2_b   = (const float*)d_in[12];
    const float* sa3_w   = (const float*)d_in[13];
    const float* sa3_b   = (const float*)d_in[14];
    const float* weights = (const float*)d_in[15];
    const float* weights2= (const float*)d_in[16];
    const float* w_back  = (const float*)d_in[17];
    float* out = (float*)d_out;

    static cudaStream_t s2 = 0;
    static cudaEvent_t evFork = 0, evXT = 0, evAGG = 0;
    if (s2 == 0) {
        cudaStreamCreateWithFlags(&s2, cudaStreamNonBlocking);
        cudaEventCreateWithFlags(&evFork, cudaEventDisableTiming);
        cudaEventCreateWithFlags(&evXT, cudaEventDisableTiming);
        cudaEventCreateWithFlags(&evAGG, cudaEventDisableTiming);
        cudaFuncSetAttribute(k_gemm1_stats, cudaFuncAttributeMaxDynamicSharedMemorySize, SM1_TOT);
        cudaFuncSetAttribute(k_gemm2f, cudaFuncAttributeMaxDynamicSharedMemorySize, SM2_TOT);
    }

    // fork side stream off the main (capture) stream
    cudaEventRecord(evFork, 0);
    cudaStreamWaitEvent(s2, evFork, 0);

    // side stream: depends only on x
    k_xt<<<(THWSZ + 255) / 256, 256, 0, s2>>>(x);
    cudaEventRecord(evXT, s2);
    k_xd<<<(THWSZ + 255) / 256, 256, 0, s2>>>(x, w_down);
    k_agg<<<(RCC * THWSZ + 255) / 256, 256, 0, s2>>>(sa1_w, sa1_b, sa2_w, sa2_b, sa3_w, sa3_b, weights);
    cudaEventRecord(evAGG, s2);

    // main stream
    k_x2<<<THWSZ / 128, 256>>>(x, w_dc2);
    k_offp<<<(NCC * 2 * TT * SS) / 256, 256>>>(x, w_ofs_l, w_ofs_r);
    k_offred<<<(2 * TT * 2 * SS + 255) / 256, 256>>>(b_ofs_l, b_ofs_r);
    k_sample<<<(2 * TT * 16 * SS) / 256, 256>>>();

    cudaStreamWaitEvent(0, evXT, 0);  // gemm1/gemm2 need g_xt_hi
    dim3 gg(HWSZ / 128, TT, 2);
    k_gemm1_stats<<<gg, 256, SM1_TOT>>>();
    k_y<<<(2 * TT * HWSZ + 255) / 256, 256>>>(ca_w1, ca_w2);
    k_gemm2f<<<gg, 256, SM2_TOT>>>(weights2);

    cudaStreamWaitEvent(0, evAGG, 0);  // k_final needs g_agg
    k_final<<<(THWSZ + 255) / 256, 256>>>(out, w_back);
}

// round 14
// speedup vs baseline: 4.1972x; 1.0485x over previous
#include <cuda_runtime.h>
#include <cuda_fp16.h>
#include <math.h>
#include <stdint.h>

#define TT 16
#define CCH 64
#define HHH 48
#define WWI 48
#define HWSZ 2304
#define THWSZ 36864
#define WW2 24
#define SS 576
#define RCC 4
#define NCC 16   // channel chunks of 4 in k_offp

typedef unsigned long long u64t;

// ---------------- FFMA2 helpers (k_x2) ----------------
#define FMA_F32X2(d, a, b, c) \
    asm("fma.rn.f32x2 %0, %1, %2, %3;" : "=l"(d) : "l"(a), "l"(b), "l"(c))
#define DUP_F32X2(out, v) \
    asm("mov.b64 %0, {%1, %1};" : "=l"(out) : "r"(v))
#define UNPACK_F32X2(lo, hi, in) \
    asm("mov.b64 {%0, %1}, %2;" : "=r"(lo), "=r"(hi) : "l"(in))
union F4U { float4 f; u64t u[2]; };

// ---------------- mma.sync / ldmatrix helpers ----------------
__device__ __forceinline__ uint32_t smem_to_u32(const void* p) {
    uint32_t a;
    asm("{ .reg .u64 tmp; cvta.to.shared.u64 tmp, %1; cvt.u32.u64 %0, tmp; }"
        : "=r"(a) : "l"(p));
    return a;
}
#define LDSM_X4(r0, r1, r2, r3, addr) \
    asm volatile("ldmatrix.sync.aligned.m8n8.x4.shared.b16 {%0,%1,%2,%3}, [%4];" \
        : "=r"(r0), "=r"(r1), "=r"(r2), "=r"(r3) : "r"(addr))
#define MMA_F16(d, a, b) \
    asm volatile("mma.sync.aligned.m16n8k16.row.col.f32.f16.f16.f32 " \
        "{%0,%1,%2,%3}, {%4,%5,%6,%7}, {%8,%9}, {%0,%1,%2,%3};" \
        : "+f"((d)[0]), "+f"((d)[1]), "+f"((d)[2]), "+f"((d)[3]) \
        : "r"((a)[0]), "r"((a)[1]), "r"((a)[2]), "r"((a)[3]), "r"((b)[0]), "r"((b)[1]))
#define TANH_APPROX(d, a) \
    asm("tanh.approx.f32 %0, %1;" : "=f"(d) : "f"(a))

// smem tile geometry: fp16 rows padded to 72 elems (144 B)
#define SA 144
#define A_TILE_B (128 * SA)   // 18432
#define B_TILE_B (64 * SA)    // 9216
#define SM1_TOT (A_TILE_B + B_TILE_B)                     // 27648
#define SM2_TOT (A_TILE_B + 2 * B_TILE_B)                 // 36864
#define STG 68

// ---------------- scratch (device globals; no allocations) ----------------
static __device__ float g_x2[CCH * THWSZ];            // [c][t][h][w]
static __device__ float g_offp[NCC][2 * TT * 2 * SS];
static __device__ float g_off[2 * TT * 2 * SS];
static __device__ __align__(16) unsigned short g_xt_hi[THWSZ * CCH];  // fp16 [t][hw][c]
static __device__ __align__(16) unsigned short pb_sc_hi[2][TT * SS * CCH]; // fp16 [t][s][c]
static __device__ __align__(16) unsigned short pb_cs_hi[2][TT * CCH * SS]; // fp16 [t][c][s]
static __device__ float g_mean[2][TT * HWSZ];
static __device__ float g_maxv[2][TT * HWSZ];
static __device__ float g_varv[2][TT * HWSZ];
static __device__ float g_yv[2][TT * HWSZ];
static __device__ float g_featb[2][TT * HWSZ * CCH]; // [branch][t][hw][c]
static __device__ float g_xd[RCC * THWSZ];
static __device__ float g_agg[RCC * THWSZ];

__device__ __forceinline__ float sigm(float v) { return 1.0f / (1.0f + __expf(-v)); }

__device__ __forceinline__ unsigned short f16_of(float v) {
    __half h = __float2half_rn(v);
    return *(unsigned short*)&h;
}

// ---------------- x2 = w_dc2 @ x (FFMA2) -------------------------------------
__device__ __forceinline__ void mma4x8(const float4& a, const F4U& b0, const F4U& b1,
                                       u64t accp[4][4]) {
    float av[4] = {a.x, a.y, a.z, a.w};
    u64t bp[4] = {b0.u[0], b0.u[1], b1.u[0], b1.u[1]};
#pragma unroll
    for (int i = 0; i < 4; i++) {
        u64t ad;
        DUP_F32X2(ad, __float_as_uint(av[i]));
#pragma unroll
        for (int j = 0; j < 4; j++) FMA_F32X2(accp[i][j], ad, bp[j], accp[i][j]);
    }
}
__device__ __forceinline__ void unpack_acc(const u64t accp[4][4], float acc[4][8]) {
#pragma unroll
    for (int i = 0; i < 4; i++)
#pragma unroll
        for (int j = 0; j < 4; j++) {
            unsigned lo, hi;
            UNPACK_F32X2(lo, hi, accp[i][j]);
            acc[i][2 * j] = __uint_as_float(lo);
            acc[i][2 * j + 1] = __uint_as_float(hi);
        }
}

__global__ void __launch_bounds__(256) k_x2(const float* __restrict__ x, const float* __restrict__ w) {
    __shared__ float Ws[64][64];
    __shared__ float Xs[64][128];
    int tid = threadIdx.x;
    int pos0 = blockIdx.x * 128;
#pragma unroll
    for (int v = 0; v < 16; v++) {
        int i = v * 256 + tid;
        Ws[i & 63][i >> 6] = w[i];
    }
#pragma unroll
    for (int v = 0; v < 8; v++) {
        int i = v * 256 + tid;
        int row = i >> 5, col = (i & 31) * 4;
        *(float4*)&Xs[row][col] = *(const float4*)&x[row * THWSZ + pos0 + col];
    }
    __syncthreads();
    int tx = tid & 31, ty = tid >> 5;
    u64t accp[4][4];
#pragma unroll
    for (int i = 0; i < 4; i++)
#pragma unroll
        for (int j = 0; j < 4; j++) accp[i][j] = 0ULL;
    float4 a_c = *(float4*)&Xs[0][tx * 4];
    F4U b0_c, b1_c;
    b0_c.f = *(float4*)&Ws[0][ty * 8];
    b1_c.f = *(float4*)&Ws[0][ty * 8 + 4];
#pragma unroll 7
    for (int k = 0; k < 63; k++) {
        float4 a_n = *(float4*)&Xs[k + 1][tx * 4];
        F4U b0_n, b1_n;
        b0_n.f = *(float4*)&Ws[k + 1][ty * 8];
        b1_n.f = *(float4*)&Ws[k + 1][ty * 8 + 4];
        mma4x8(a_c, b0_c, b1_c, accp);
        a_c = a_n; b0_c = b0_n; b1_c = b1_n;
    }
    mma4x8(a_c, b0_c, b1_c, accp);
    float acc[4][8];
    unpack_acc(accp, acc);
#pragma unroll
    for (int j = 0; j < 8; j++) {
        int o = ty * 8 + j;
        float4 o4 = make_float4(acc[0][j], acc[1][j], acc[2][j], acc[3][j]);
        *(float4*)&g_x2[o * THWSZ + pos0 + tx * 4] = o4;
    }
}

// ---------------- x transpose + fp16 convert -----------------------------------
__global__ void __launch_bounds__(256) k_xt(const float* __restrict__ x) {
    int idx = blockIdx.x * 256 + threadIdx.x;
    if (idx >= THWSZ) return;
    unsigned short* dh = &g_xt_hi[(size_t)idx * 64];
#pragma unroll 8
    for (int c = 0; c < CCH; c++) {
        dh[c] = f16_of(x[c * THWSZ + idx]);
    }
}

// ------- offset conv partials (both o per thread) + reduce ---------------------
__global__ void __launch_bounds__(256) k_offp(const float* __restrict__ x,
                      const float* __restrict__ wl, const float* __restrict__ wr) {
    int idx = blockIdx.x * 256 + threadIdx.x;  // NCC*2*TT*SS = 294912
    int s = idx % SS;
    int t = (idx / SS) & 15;
    int branch = (idx / (SS * TT)) & 1;
    int cc = idx / (SS * TT * 2);
    int i = s / WW2, j = s % WW2;
    int tsrc = (branch == 0) ? min(t + 1, TT - 1) : max(t - 1, 0);
    const float* wofs = (branch == 0) ? wl : wr;
    float acc0 = 0.0f, acc1 = 0.0f;
#pragma unroll
    for (int u = 0; u < 4; u++) {
        int c = cc * 4 + u;
        const float* xp = x + c * THWSZ + t * HWSZ;
        const float* x2p = g_x2 + c * THWSZ + tsrc * HWSZ;
        const float* wp0 = wofs + c * 9;
        const float* wp1 = wofs + (CCH + c) * 9;
#pragma unroll
        for (int ki = 0; ki < 3; ki++) {
            int h = 2 * i - 1 + ki;
            if (h < 0 || h >= HHH) continue;
#pragma unroll
            for (int kj = 0; kj < 3; kj++) {
                int w = 2 * j - 1 + kj;
                if (w < 0 || w >= WWI) continue;
                float v = xp[h * WWI + w] + x2p[h * WWI + w];
                acc0 = fmaf(v, wp0[ki * 3 + kj], acc0);
                acc1 = fmaf(v, wp1[ki * 3 + kj], acc1);
            }
        }
    }
    g_offp[cc][((branch * TT + t) * 2 + 0) * SS + s] = acc0;
    g_offp[cc][((branch * TT + t) * 2 + 1) * SS + s] = acc1;
}

__global__ void k_offred(const float* __restrict__ bl, const float* __restrict__ br_) {
    int i = blockIdx.x * 256 + threadIdx.x;
    if (i >= 2 * TT * 2 * SS) return;
    int branch = i / (TT * 2 * SS);
    int o = (i / SS) & 1;
    float acc = (branch == 0) ? bl[o] : br_[o];
#pragma unroll
    for (int cc = 0; cc < NCC; cc++) acc += g_offp[cc][i];
    g_off[i] = acc;
}

// ------- bilinear grid-sample -> fp16 parts ------------------------------------
__global__ void __launch_bounds__(256) k_sample() {
    int idx = blockIdx.x * 256 + threadIdx.x;
    int s = idx % SS;
    int c4 = (idx / SS) & 15;
    int t = (idx / (SS * 16)) & 15;
    int branch = idx / (SS * 16 * 16);
    int i = s / WW2, j = s % WW2;
    float off0 = g_off[((branch * TT + t) * 2 + 0) * SS + s];
    float off1 = g_off[((branch * TT + t) * 2 + 1) * SS + s];
    float v0 = 2.0f * (float)j + off0;
    float v1 = 2.0f * (float)i + off1;
    float gh = 2.0f * v0 / 23.0f - 1.0f;
    float gw = 2.0f * v1 / 23.0f - 1.0f;
    float xs = ((gh + 1.0f) * 48.0f - 1.0f) * 0.5f;
    float ys = ((gw + 1.0f) * 48.0f - 1.0f) * 0.5f;
    float x0f = floorf(xs), y0f = floorf(ys);
    int x0 = (int)x0f, y0 = (int)y0f;
    float fx = xs - x0f, fy = ys - y0f;
    float wgt[4] = {(1.0f - fx) * (1.0f - fy), fx * (1.0f - fy),
                    (1.0f - fx) * fy, fx * fy};
    int xi[4] = {x0, x0 + 1, x0, x0 + 1};
    int yi[4] = {y0, y0, y0 + 1, y0 + 1};
    float wv[4];
    int id[4];
#pragma unroll
    for (int k = 0; k < 4; k++) {
        bool valid = (xi[k] >= 0) && (xi[k] < WWI) && (yi[k] >= 0) && (yi[k] < HHH);
        wv[k] = valid ? wgt[k] : 0.0f;
        int cy = min(max(yi[k], 0), HHH - 1);
        int cx = min(max(xi[k], 0), WWI - 1);
        id[k] = cy * WWI + cx;
    }
    int tsrc = (branch == 0) ? min(t + 1, TT - 1) : max(t - 1, 0);
#pragma unroll
    for (int u = 0; u < 4; u++) {
        int c = c4 * 4 + u;
        const float* img = g_x2 + c * THWSZ + tsrc * HWSZ;
        float val = wv[0] * img[id[0]] + wv[1] * img[id[1]] +
                    wv[2] * img[id[2]] + wv[3] * img[id[3]];
        unsigned short hs = f16_of(val);
        pb_sc_hi[branch][(t * SS + s) * CCH + c] = hs;
        pb_cs_hi[branch][(t * CCH + c) * SS + s] = hs;
    }
}

// ------- GEMM1-stats: single-pass fp16, both branches ---------------------------
__global__ void __launch_bounds__(256, 3) k_gemm1_stats() {
    extern __shared__ __align__(16) char sm[];
    char* A_hi = sm;
    char* B_hi = sm + A_TILE_B;
    float* red = (float*)(sm + A_TILE_B);
    int tid = threadIdx.x;
    int t = blockIdx.y, hw0 = blockIdx.x * 128, branch = blockIdx.z;

    {
        const uint4* sh = (const uint4*)&g_xt_hi[(size_t)(t * HWSZ + hw0) * 64];
#pragma unroll
        for (int v = 0; v < 4; v++) {
            int i = v * 256 + tid;
            int row = i >> 3, j = i & 7;
            *(uint4*)(A_hi + row * SA + j * 16) = sh[i];
        }
    }

    int wid = tid >> 5, lane = tid & 31;
    int wm = (wid & 3) * 32;
    int wn = (wid >> 2) * 32;
    uint32_t ah_u = smem_to_u32(A_hi);
    uint32_t bh_u = smem_to_u32(B_hi);
    int arow = lane & 15;
    int akoff = (lane >> 4) * 16;
    int brow = (lane & 7) + ((lane & 16) ? 8 : 0);
    int bkoff = ((lane >> 3) & 1) * 16;

    float s_sum[2][2] = {}, s_sq[2][2] = {};
    float s_mx[2][2] = {{-3.4e38f, -3.4e38f}, {-3.4e38f, -3.4e38f}};

    for (int kc = 0; kc < 9; kc++) {
        __syncthreads();
        {
            const uint4* bh = (const uint4*)&pb_sc_hi[branch][(size_t)(t * SS + kc * 64) * 64];
#pragma unroll
            for (int v = 0; v < 2; v++) {
                int i = v * 256 + tid;
                int row = i >> 3, j = i & 7;
                *(uint4*)(B_hi + row * SA + j * 16) = bh[i];
            }
        }
        __syncthreads();

        float d[2][4][4] = {};
#pragma unroll
        for (int ks = 0; ks < 4; ks++) {
            int kb = ks * 32;
            uint32_t Ah[2][4], Bh[4][2];
#pragma unroll
            for (int mt = 0; mt < 2; mt++) {
                uint32_t off = (uint32_t)((wm + mt * 16 + arow) * SA + kb + akoff);
                LDSM_X4(Ah[mt][0], Ah[mt][1], Ah[mt][2], Ah[mt][3], ah_u + off);
            }
#pragma unroll
            for (int np = 0; np < 2; np++) {
                uint32_t off = (uint32_t)((wn + np * 16 + brow) * SA + kb + bkoff);
                uint32_t r0, r1, r2, r3;
                LDSM_X4(r0, r1, r2, r3, bh_u + off);
                Bh[np * 2][0] = r0; Bh[np * 2][1] = r1;
                Bh[np * 2 + 1][0] = r2; Bh[np * 2 + 1][1] = r3;
            }
#pragma unroll
            for (int mt = 0; mt < 2; mt++)
#pragma unroll
                for (int nt = 0; nt < 4; nt++)
                    MMA_F16(d[mt][nt], Ah[mt], Bh[nt]);
        }
#pragma unroll
        for (int mt = 0; mt < 2; mt++)
#pragma unroll
            for (int nt = 0; nt < 4; nt++)
#pragma unroll
                for (int r = 0; r < 4; r++) {
                    int rh = (r >> 1) & 1;
                    float v = d[mt][nt][r];
                    s_sum[mt][rh] += v;
                    s_sq[mt][rh] = fmaf(v, v, s_sq[mt][rh]);
                    s_mx[mt][rh] = fmaxf(s_mx[mt][rh], v);
                }
    }

#pragma unroll
    for (int mt = 0; mt < 2; mt++)
#pragma unroll
        for (int rh = 0; rh < 2; rh++) {
            s_sum[mt][rh] += __shfl_xor_sync(0xFFFFFFFFu, s_sum[mt][rh], 1);
            s_sum[mt][rh] += __shfl_xor_sync(0xFFFFFFFFu, s_sum[mt][rh], 2);
            s_sq[mt][rh] += __shfl_xor_sync(0xFFFFFFFFu, s_sq[mt][rh], 1);
            s_sq[mt][rh] += __shfl_xor_sync(0xFFFFFFFFu, s_sq[mt][rh], 2);
            s_mx[mt][rh] = fmaxf(s_mx[mt][rh], __shfl_xor_sync(0xFFFFFFFFu, s_mx[mt][rh], 1));
            s_mx[mt][rh] = fmaxf(s_mx[mt][rh], __shfl_xor_sync(0xFFFFFFFFu, s_mx[mt][rh], 2));
        }
    __syncthreads();
    if ((lane & 3) == 0) {
        int nw = wid >> 2;
#pragma unroll
        for (int mt = 0; mt < 2; mt++)
#pragma unroll
            for (int rh = 0; rh < 2; rh++) {
                int m = wm + mt * 16 + (lane >> 2) + 8 * rh;
                float* p = &red[(nw * 128 + m) * 3];
                p[0] = s_sum[mt][rh];
                p[1] = s_sq[mt][rh];
                p[2] = s_mx[mt][rh];
            }
    }
    __syncthreads();
    if (tid < 128) {
        int m = tid;
        const float* p0 = &red[m * 3];
        const float* p1 = &red[(128 + m) * 3];
        float sum = p0[0] + p1[0];
        float sq = p0[1] + p1[1];
        float mx = fmaxf(p0[2], p1[2]);
        int o = t * HWSZ + hw0 + m;
        g_mean[branch][o] = sum / 576.0f;
        g_maxv[branch][o] = mx;
        g_varv[branch][o] = (sq - sum * sum / 576.0f) / 575.0f;
    }
}

// ---------------- attention gate (both branches) --------------------------------
__global__ void k_y(const float* __restrict__ w1, const float* __restrict__ w2) {
    int gidx = blockIdx.x * 256 + threadIdx.x;
    if (gidx >= 2 * TT * HWSZ) return;
    int branch = gidx / (TT * HWSZ);
    int idx = gidx % (TT * HWSZ);
    int t = idx / HWSZ;
    int hw = idx % HWSZ;
    int h = hw / WWI, w = hw % WWI;
    float acc = 0.0f;
#pragma unroll
    for (int dh = 0; dh < 3; dh++) {
        int hh = h + dh - 1;
        if (hh < 0 || hh >= HHH) continue;
#pragma unroll
        for (int dw = 0; dw < 3; dw++) {
            int ww = w + dw - 1;
            if (ww < 0 || ww >= WWI) continue;
            int p = t * HWSZ + hh * WWI + ww;
            acc = fmaf(w1[(0 * 3 + dh) * 3 + dw], g_mean[branch][p], acc);
            acc = fmaf(w1[(3 + dh) * 3 + dw], g_maxv[branch][p], acc);
            acc = fmaf(w2[dh * 3 + dw], g_varv[branch][p], acc);
        }
    }
    g_yv[branch][idx] = sigm(acc);
}

// ------- fused GEMM2: register-forwarded gate, 8mx1n warps ----------------------
// grid (18, 16, 2), 256 thr, smem 36.9KB.
__global__ void __launch_bounds__(256, 2) k_gemm2f(const float* __restrict__ w2s) {
    extern __shared__ __align__(16) char sm[];
    char* A1_hi = sm;                          // xt [128hw x 64c]
    char* B1_hi = sm + A_TILE_B;               // part_sc [64s x 64c]
    char* B2_hi = sm + A_TILE_B + B_TILE_B;    // part_cs [64c x 64s]
    int tid = threadIdx.x;
    int t = blockIdx.y, hw0 = blockIdx.x * 128, branch = blockIdx.z;

    {
        const uint4* sh = (const uint4*)&g_xt_hi[(size_t)(t * HWSZ + hw0) * 64];
#pragma unroll
        for (int v = 0; v < 4; v++) {
            int i = v * 256 + tid;
            int row = i >> 3, j = i & 7;
            *(uint4*)(A1_hi + row * SA + j * 16) = sh[i];
        }
    }

    int wid = tid >> 5, lane = tid & 31;
    int wm = wid * 16;  // 8 warps x 16 hw-rows each
    uint32_t a1h_u = smem_to_u32(A1_hi);
    uint32_t b1h_u = smem_to_u32(B1_hi);
    uint32_t b2h_u = smem_to_u32(B2_hi);
    int arow = lane & 15;
    int akoff = (lane >> 4) * 16;
    int brow = (lane & 7) + ((lane & 16) ? 8 : 0);
    int bkoff = ((lane >> 3) & 1) * 16;

    // gate y for this thread's two fragment rows (g, g+8), pre-scaled by 0.5
    float yv0 = 0.5f * g_yv[branch][t * HWSZ + hw0 + wm + (lane >> 2)];
    float yv1 = 0.5f * g_yv[branch][t * HWSZ + hw0 + wm + (lane >> 2) + 8];

    float d2[8][4];
#pragma unroll
    for (int nt = 0; nt < 8; nt++)
#pragma unroll
        for (int r = 0; r < 4; r++) d2[nt][r] = 0.0f;

    for (int kc = 0; kc < 9; kc++) {
        __syncthreads();
        {
            const uint4* bh = (const uint4*)&pb_sc_hi[branch][(size_t)(t * SS + kc * 64) * 64];
#pragma unroll
            for (int v = 0; v < 2; v++) {
                int i = v * 256 + tid;
                int row = i >> 3, j = i & 7;
                *(uint4*)(B1_hi + row * SA + j * 16) = bh[i];
            }
#pragma unroll
            for (int v = 0; v < 2; v++) {
                int i = v * 256 + tid;
                int row = i >> 3, j = i & 7;
                size_t src = (size_t)(t * CCH + row) * SS + kc * 64 + j * 8;
                *(uint4*)(B2_hi + row * SA + j * 16) = *(const uint4*)&pb_cs_hi[branch][src];
            }
        }
        __syncthreads();

        // mma1: d1[8 nt_s][4] = A1(16 hw x 64 c) x B1(64 s x 64 c)^T
        float d1[8][4];
#pragma unroll
        for (int nt = 0; nt < 8; nt++)
#pragma unroll
            for (int r = 0; r < 4; r++) d1[nt][r] = 0.0f;
#pragma unroll
        for (int ks = 0; ks < 4; ks++) {
            int kb = ks * 32;
            uint32_t Ah[4], Bh[8][2];
            LDSM_X4(Ah[0], Ah[1], Ah[2], Ah[3],
                    a1h_u + (uint32_t)((wm + arow) * SA + kb + akoff));
#pragma unroll
            for (int np = 0; np < 4; np++) {
                uint32_t r0, r1, r2, r3;
                LDSM_X4(r0, r1, r2, r3,
                        b1h_u + (uint32_t)((np * 16 + brow) * SA + kb + bkoff));
                Bh[np * 2][0] = r0; Bh[np * 2][1] = r1;
                Bh[np * 2 + 1][0] = r2; Bh[np * 2 + 1][1] = r3;
            }
#pragma unroll
            for (int nt = 0; nt < 8; nt++)
                MMA_F16(d1[nt], Ah, Bh[nt]);
        }

        // gate d1 in registers -> A2 fragments, feed mma2 directly
#pragma unroll
        for (int ks2 = 0; ks2 < 4; ks2++) {
            uint32_t Af[4];
            {
                float t0, t1;
                TANH_APPROX(t0, yv0 * d1[2 * ks2][0]);
                TANH_APPROX(t1, yv0 * d1[2 * ks2][1]);
                Af[0] = (uint32_t)f16_of(0.5f * t0) | ((uint32_t)f16_of(0.5f * t1) << 16);
                TANH_APPROX(t0, yv1 * d1[2 * ks2][2]);
                TANH_APPROX(t1, yv1 * d1[2 * ks2][3]);
                Af[1] = (uint32_t)f16_of(0.5f * t0) | ((uint32_t)f16_of(0.5f * t1) << 16);
                TANH_APPROX(t0, yv0 * d1[2 * ks2 + 1][0]);
                TANH_APPROX(t1, yv0 * d1[2 * ks2 + 1][1]);
                Af[2] = (uint32_t)f16_of(0.5f * t0) | ((uint32_t)f16_of(0.5f * t1) << 16);
                TANH_APPROX(t0, yv1 * d1[2 * ks2 + 1][2]);
                TANH_APPROX(t1, yv1 * d1[2 * ks2 + 1][3]);
                Af[3] = (uint32_t)f16_of(0.5f * t0) | ((uint32_t)f16_of(0.5f * t1) << 16);
            }
            uint32_t Bh2[8][2];
#pragma unroll
            for (int np = 0; np < 4; np++) {
                uint32_t r0, r1, r2, r3;
                LDSM_X4(r0, r1, r2, r3,
                        b2h_u + (uint32_t)((np * 16 + brow) * SA + ks2 * 32 + bkoff));
                Bh2[np * 2][0] = r0; Bh2[np * 2][1] = r1;
                Bh2[np * 2 + 1][0] = r2; Bh2[np * 2 + 1][1] = r3;
            }
#pragma unroll
            for (int nt = 0; nt < 8; nt++)
                MMA_F16(d2[nt], Af, Bh2[nt]);
        }
    }

    // stage + scaled store (d2: m = wm + g + 8*(r>>1), n = nt*8 + ctg*2 + (r&1))
    __syncthreads();
    float* stage = (float*)sm;
#pragma unroll
    for (int nt = 0; nt < 8; nt++)
#pragma unroll
        for (int r = 0; r < 4; r++) {
            int m = wm + (lane >> 2) + ((r >> 1) & 1) * 8;
            int n = nt * 8 + (lane & 3) * 2 + (r & 1);
            stage[m * STG + n] = d2[nt][r];
        }
    __syncthreads();
    float wscale = w2s[branch];
    int row = tid >> 1, half = tid & 1;
    const float* srow = &stage[row * STG + half * 32];
    float* dst = &g_featb[branch][((size_t)t * HWSZ + hw0 + row) * CCH + half * 32];
#pragma unroll
    for (int q = 0; q < 8; q++) {
        float4 b = *(const float4*)&srow[q * 4];
        float4 o4 = make_float4(b.x * wscale, b.y * wscale, b.z * wscale, b.w * wscale);
        *(float4*)&dst[q * 4] = o4;
    }
}

// ---------------- xd = w_down @ x (one thread per pos, 4 outputs) ---------------
__global__ void k_xd(const float* __restrict__ x, const float* __restrict__ wd) {
    int pos = blockIdx.x * blockDim.x + threadIdx.x;
    if (pos >= THWSZ) return;
    float a0 = 0.0f, a1 = 0.0f, a2 = 0.0f, a3 = 0.0f;
    for (int c = 0; c < CCH; c++) {
        float v = x[c * THWSZ + pos];
        a0 = fmaf(wd[c], v, a0);
        a1 = fmaf(wd[CCH + c], v, a1);
        a2 = fmaf(wd[2 * CCH + c], v, a2);
        a3 = fmaf(wd[3 * CCH + c], v, a3);
    }
    g_xd[pos] = a0;
    g_xd[THWSZ + pos] = a1;
    g_xd[2 * THWSZ + pos] = a2;
    g_xd[3 * THWSZ + pos] = a3;
}

// ---------------- 3x depthwise 3D convs ------------------------------------------
__global__ void k_agg(const float* __restrict__ w1, const float* __restrict__ b1,
                      const float* __restrict__ w2, const float* __restrict__ b2,
                      const float* __restrict__ w3, const float* __restrict__ b3,
                      const float* __restrict__ wts) {
    int idx = blockIdx.x * blockDim.x + threadIdx.x;
    if (idx >= RCC * THWSZ) return;
    int r = idx / THWSZ;
    int rem = idx % THWSZ;
    int t = rem / HWSZ;
    int hw = rem % HWSZ;
    int h = hw / WWI, w = hw % WWI;
    const float* xb = g_xd + r * THWSZ;
    const float* ws_[3] = {w1, w2, w3};
    const float* bs_[3] = {b1, b2, b3};
    float total = 0.0f;
#pragma unroll
    for (int m = 0; m < 3; m++) {
        int d = m + 1;
        float cs = bs_[m][r];
        const float* wp = ws_[m] + r * 81;
        for (int kt = 0; kt < 9; kt++) {
            int ti = t + kt - 4;
            if (ti < 0 || ti >= TT) continue;
#pragma unroll
            for (int kh = 0; kh < 3; kh++) {
                int hi = h + (kh - 1) * d;
                if (hi < 0 || hi >= HHH) continue;
#pragma unroll
                for (int kw = 0; kw < 3; kw++) {
                    int wi = w + (kw - 1) * d;
                    if (wi < 0 || wi >= WWI) continue;
                    cs = fmaf(xb[ti * HWSZ + hi * WWI + wi], wp[(kt * 3 + kh) * 3 + kw], cs);
                }
            }
        }
        total = fmaf(wts[m], cs, total);
    }
    g_agg[idx] = total;
}

// ---------------- final ----------------------------------------------------------
__global__ void k_final(float* __restrict__ out, const float* __restrict__ wback) {
    int pos = blockIdx.x * 256 + threadIdx.x;
    if (pos >= THWSZ) return;
    float ag0 = g_agg[pos];
    float ag1 = g_agg[THWSZ + pos];
    float ag2 = g_agg[2 * THWSZ + pos];
    float ag3 = g_agg[3 * THWSZ + pos];
    const float4* f0 = (const float4*)&g_featb[0][(size_t)pos * CCH];
    const float4* f1 = (const float4*)&g_featb[1][(size_t)pos * CCH];
#pragma unroll
    for (int c4 = 0; c4 < 16; c4++) {
        float4 a = f0[c4];
        float4 b = f1[c4];
        float fv[4] = {a.x + b.x, a.y + b.y, a.z + b.z, a.w + b.w};
#pragma unroll
        for (int u = 0; u < 4; u++) {
            int c = c4 * 4 + u;
            float z = wback[c * 4 + 0] * ag0 + wback[c * 4 + 1] * ag1 +
                      wback[c * 4 + 2] * ag2 + wback[c * 4 + 3] * ag3;
            out[c * THWSZ + pos] = fv[u] * (sigm(z) - 0.5f);
        }
    }
}

extern "C" void kernel_launch(void* const* d_in, const int* in_sizes, int n_in,
                              void* d_out, int out_size) {
    const float* x       = (const float*)d_in[0];
    const float* w_dc2   = (const float*)d_in[1];
    const float* w_ofs_l = (const float*)d_in[2];
    const float* b_ofs_l = (const float*)d_in[3];
    const float* w_ofs_r = (const float*)d_in[4];
    const float* b_ofs_r = (const float*)d_in[5];
    const float* ca_w1   = (const float*)d_in[6];
    const float* ca_w2   = (const float*)d_in[7];
    const float* w_down  = (const float*)d_in[8];
    const float* sa1_w   = (const float*)d_in[9];
    const float* sa1_b   = (const float*)d_in[10];
    const float* sa2_w   = (const float*)d_in[11];
    const float* sa2_b   = (const float*)d_in[12];
    const float* sa3_w   = (const float*)d_in[13];
    const float* sa3_b   = (const float*)d_in[14];
    const float* weights = (const float*)d_in[15];
    const float* weights2= (const float*)d_in[16];
    const float* w_back  = (const float*)d_in[17];
    float* out = (float*)d_out;

    static cudaStream_t s2 = 0;
    static cudaEvent_t evFork = 0, evXT = 0, evAGG = 0;
    if (s2 == 0) {
        cudaStreamCreateWithFlags(&s2, cudaStreamNonBlocking);
        cudaEventCreateWithFlags(&evFork, cudaEventDisableTiming);
        cudaEventCreateWithFlags(&evXT, cudaEventDisableTiming);
        cudaEventCreateWithFlags(&evAGG, cudaEventDisableTiming);
        cudaFuncSetAttribute(k_gemm1_stats, cudaFuncAttributeMaxDynamicSharedMemorySize, SM1_TOT);
        cudaFuncSetAttribute(k_gemm2f, cudaFuncAttributeMaxDynamicSharedMemorySize, SM2_TOT);
    }

    // fork side stream off the main (capture) stream
    cudaEventRecord(evFork, 0);
    cudaStreamWaitEvent(s2, evFork, 0);

    // side stream: depends only on x
    k_xt<<<(THWSZ + 255) / 256, 256, 0, s2>>>(x);
    cudaEventRecord(evXT, s2);
    k_xd<<<(THWSZ + 255) / 256, 256, 0, s2>>>(x, w_down);
    k_agg<<<(RCC * THWSZ + 255) / 256, 256, 0, s2>>>(sa1_w, sa1_b, sa2_w, sa2_b, sa3_w, sa3_b, weights);
    cudaEventRecord(evAGG, s2);

    // main stream
    k_x2<<<THWSZ / 128, 256>>>(x, w_dc2);
    k_offp<<<(NCC * 2 * TT * SS) / 256, 256>>>(x, w_ofs_l, w_ofs_r);
    k_offred<<<(2 * TT * 2 * SS + 255) / 256, 256>>>(b_ofs_l, b_ofs_r);
    k_sample<<<(2 * TT * 16 * SS) / 256, 256>>>();

    cudaStreamWaitEvent(0, evXT, 0);  // gemm1/gemm2 need g_xt_hi
    dim3 gg(HWSZ / 128, TT, 2);
    k_gemm1_stats<<<gg, 256, SM1_TOT>>>();
    k_y<<<(2 * TT * HWSZ + 255) / 256, 256>>>(ca_w1, ca_w2);
    k_gemm2f<<<gg, 256, SM2_TOT>>>(weights2);

    cudaStreamWaitEvent(0, evAGG, 0);  // k_final needs g_agg
    k_final<<<(THWSZ + 255) / 256, 256>>>(out, w_back);
}

// round 15
// speedup vs baseline: 4.2214x; 1.0058x over previous
#include <cuda_runtime.h>
#include <cuda_fp16.h>
#include <math.h>
#include <stdint.h>

#define TT 16
#define CCH 64
#define HHH 48
#define WWI 48
#define HWSZ 2304
#define THWSZ 36864
#define WW2 24
#define SS 576
#define RCC 4
#define NCC 16   // channel chunks of 4 in k_offp

// ---------------- mma.sync / ldmatrix helpers ----------------
__device__ __forceinline__ uint32_t smem_to_u32(const void* p) {
    uint32_t a;
    asm("{ .reg .u64 tmp; cvta.to.shared.u64 tmp, %1; cvt.u32.u64 %0, tmp; }"
        : "=r"(a) : "l"(p));
    return a;
}
#define LDSM_X4(r0, r1, r2, r3, addr) \
    asm volatile("ldmatrix.sync.aligned.m8n8.x4.shared.b16 {%0,%1,%2,%3}, [%4];" \
        : "=r"(r0), "=r"(r1), "=r"(r2), "=r"(r3) : "r"(addr))
#define MMA_F16(d, a, b) \
    asm volatile("mma.sync.aligned.m16n8k16.row.col.f32.f16.f16.f32 " \
        "{%0,%1,%2,%3}, {%4,%5,%6,%7}, {%8,%9}, {%0,%1,%2,%3};" \
        : "+f"((d)[0]), "+f"((d)[1]), "+f"((d)[2]), "+f"((d)[3]) \
        : "r"((a)[0]), "r"((a)[1]), "r"((a)[2]), "r"((a)[3]), "r"((b)[0]), "r"((b)[1]))
#define TANH_APPROX(d, a) \
    asm("tanh.approx.f32 %0, %1;" : "=f"(d) : "f"(a))

// smem tile geometry: fp16 rows padded to 72 elems (144 B)
#define SA 144
#define A_TILE_B (128 * SA)   // 18432
#define B_TILE_B (64 * SA)    // 9216
#define STG 68
#define SM0_TOT (128 * STG * 4)                           // 34816 (k_x2m: tiles + stage)
#define SM1_TOT (A_TILE_B + B_TILE_B)                     // 27648
#define SM2_TOT (A_TILE_B + 2 * B_TILE_B)                 // 36864

// ---------------- scratch (device globals; no allocations) ----------------
static __device__ float g_x2[CCH * THWSZ];            // [c][t][h][w]
static __device__ float g_offp[NCC][2 * TT * 2 * SS];
static __device__ float g_off[2 * TT * 2 * SS];
static __device__ __align__(16) unsigned short g_xt_hi[THWSZ * CCH];  // fp16 [t][hw][c]
static __device__ __align__(16) unsigned short pb_sc_hi[2][TT * SS * CCH]; // fp16 [t][s][c]
static __device__ __align__(16) unsigned short pb_cs_hi[2][TT * CCH * SS]; // fp16 [t][c][s]
static __device__ float g_mean[2][TT * HWSZ];
static __device__ float g_maxv[2][TT * HWSZ];
static __device__ float g_varv[2][TT * HWSZ];
static __device__ float g_yv[2][TT * HWSZ];
static __device__ float g_featb[2][TT * HWSZ * CCH]; // [branch][t][hw][c]
static __device__ float g_xd[RCC * THWSZ];
static __device__ float g_agg[RCC * THWSZ];

__device__ __forceinline__ float sigm(float v) { return 1.0f / (1.0f + __expf(-v)); }

__device__ __forceinline__ unsigned short f16_of(float v) {
    __half h = __float2half_rn(v);
    return *(unsigned short*)&h;
}

// ---------------- x transpose + fp16 convert -----------------------------------
__global__ void __launch_bounds__(256) k_xt(const float* __restrict__ x) {
    int idx = blockIdx.x * 256 + threadIdx.x;
    if (idx >= THWSZ) return;
    unsigned short* dh = &g_xt_hi[(size_t)idx * 64];
#pragma unroll 8
    for (int c = 0; c < CCH; c++) {
        dh[c] = f16_of(x[c * THWSZ + idx]);
    }
}

// ---------------- x2 = w_dc2 @ x via fp16 MMA ------------------------------------
// block: 128 pos x 64 out, K=64. 8 warps (4m x 2n). grid 288.
__global__ void __launch_bounds__(256, 3) k_x2m(const float* __restrict__ w) {
    extern __shared__ __align__(16) char sm[];
    char* A_hi = sm;                 // xt [128 pos x 64 c]
    char* B_hi = sm + A_TILE_B;      // w16 [64 o x 64 c]
    int tid = threadIdx.x;
    int pos0 = blockIdx.x * 128;

    {
        const uint4* sh = (const uint4*)&g_xt_hi[(size_t)pos0 * 64];
#pragma unroll
        for (int v = 0; v < 4; v++) {
            int i = v * 256 + tid;
            int row = i >> 3, j = i & 7;
            *(uint4*)(A_hi + row * SA + j * 16) = sh[i];
        }
#pragma unroll
        for (int v = 0; v < 16; v++) {
            int i = v * 256 + tid;
            int o = i >> 6, c = i & 63;
            *(unsigned short*)(B_hi + o * SA + c * 2) = f16_of(w[i]);
        }
    }
    __syncthreads();

    int wid = tid >> 5, lane = tid & 31;
    int wm = (wid & 3) * 32;   // pos
    int wn = (wid >> 2) * 32;  // o
    uint32_t ah_u = smem_to_u32(A_hi);
    uint32_t bh_u = smem_to_u32(B_hi);
    int arow = lane & 15;
    int akoff = (lane >> 4) * 16;
    int brow = (lane & 7) + ((lane & 16) ? 8 : 0);
    int bkoff = ((lane >> 3) & 1) * 16;

    float d[2][4][4] = {};
#pragma unroll
    for (int ks = 0; ks < 4; ks++) {
        int kb = ks * 32;
        uint32_t Ah[2][4], Bh[4][2];
#pragma unroll
        for (int mt = 0; mt < 2; mt++) {
            uint32_t off = (uint32_t)((wm + mt * 16 + arow) * SA + kb + akoff);
            LDSM_X4(Ah[mt][0], Ah[mt][1], Ah[mt][2], Ah[mt][3], ah_u + off);
        }
#pragma unroll
        for (int np = 0; np < 2; np++) {
            uint32_t off = (uint32_t)((wn + np * 16 + brow) * SA + kb + bkoff);
            uint32_t r0, r1, r2, r3;
            LDSM_X4(r0, r1, r2, r3, bh_u + off);
            Bh[np * 2][0] = r0; Bh[np * 2][1] = r1;
            Bh[np * 2 + 1][0] = r2; Bh[np * 2 + 1][1] = r3;
        }
#pragma unroll
        for (int mt = 0; mt < 2; mt++)
#pragma unroll
            for (int nt = 0; nt < 4; nt++)
                MMA_F16(d[mt][nt], Ah[mt], Bh[nt]);
    }

    // stage D[pos][o] then transposed coalesced write to g_x2[o][pos]
    __syncthreads();
    float* stage = (float*)sm;
#pragma unroll
    for (int mt = 0; mt < 2; mt++)
#pragma unroll
        for (int nt = 0; nt < 4; nt++)
#pragma unroll
            for (int r = 0; r < 4; r++) {
                int m = wm + mt * 16 + (lane >> 2) + ((r >> 1) & 1) * 8;
                int n = wn + nt * 8 + (lane & 3) * 2 + (r & 1);
                stage[m * STG + n] = d[mt][nt][r];
            }
    __syncthreads();
    int o = tid >> 2;
    int pg = (tid & 3) * 32;
    float* dst = &g_x2[(size_t)o * THWSZ + pos0 + pg];
#pragma unroll
    for (int q = 0; q < 8; q++) {
        float4 v;
        v.x = stage[(pg + q * 4 + 0) * STG + o];
        v.y = stage[(pg + q * 4 + 1) * STG + o];
        v.z = stage[(pg + q * 4 + 2) * STG + o];
        v.w = stage[(pg + q * 4 + 3) * STG + o];
        *(float4*)&dst[q * 4] = v;
    }
}

// ------- offset conv partials (both o per thread) + reduce ---------------------
__global__ void __launch_bounds__(256) k_offp(const float* __restrict__ x,
                      const float* __restrict__ wl, const float* __restrict__ wr) {
    int idx = blockIdx.x * 256 + threadIdx.x;  // NCC*2*TT*SS = 294912
    int s = idx % SS;
    int t = (idx / SS) & 15;
    int branch = (idx / (SS * TT)) & 1;
    int cc = idx / (SS * TT * 2);
    int i = s / WW2, j = s % WW2;
    int tsrc = (branch == 0) ? min(t + 1, TT - 1) : max(t - 1, 0);
    const float* wofs = (branch == 0) ? wl : wr;
    float acc0 = 0.0f, acc1 = 0.0f;
#pragma unroll
    for (int u = 0; u < 4; u++) {
        int c = cc * 4 + u;
        const float* xp = x + c * THWSZ + t * HWSZ;
        const float* x2p = g_x2 + c * THWSZ + tsrc * HWSZ;
        const float* wp0 = wofs + c * 9;
        const float* wp1 = wofs + (CCH + c) * 9;
#pragma unroll
        for (int ki = 0; ki < 3; ki++) {
            int h = 2 * i - 1 + ki;
            if (h < 0 || h >= HHH) continue;
#pragma unroll
            for (int kj = 0; kj < 3; kj++) {
                int w = 2 * j - 1 + kj;
                if (w < 0 || w >= WWI) continue;
                float v = xp[h * WWI + w] + x2p[h * WWI + w];
                acc0 = fmaf(v, wp0[ki * 3 + kj], acc0);
                acc1 = fmaf(v, wp1[ki * 3 + kj], acc1);
            }
        }
    }
    g_offp[cc][((branch * TT + t) * 2 + 0) * SS + s] = acc0;
    g_offp[cc][((branch * TT + t) * 2 + 1) * SS + s] = acc1;
}

__global__ void k_offred(const float* __restrict__ bl, const float* __restrict__ br_) {
    int i = blockIdx.x * 256 + threadIdx.x;
    if (i >= 2 * TT * 2 * SS) return;
    int branch = i / (TT * 2 * SS);
    int o = (i / SS) & 1;
    float acc = (branch == 0) ? bl[o] : br_[o];
#pragma unroll
    for (int cc = 0; cc < NCC; cc++) acc += g_offp[cc][i];
    g_off[i] = acc;
}

// ------- bilinear grid-sample -> fp16 parts ------------------------------------
__global__ void __launch_bounds__(256) k_sample() {
    int idx = blockIdx.x * 256 + threadIdx.x;
    int s = idx % SS;
    int c4 = (idx / SS) & 15;
    int t = (idx / (SS * 16)) & 15;
    int branch = idx / (SS * 16 * 16);
    int i = s / WW2, j = s % WW2;
    float off0 = g_off[((branch * TT + t) * 2 + 0) * SS + s];
    float off1 = g_off[((branch * TT + t) * 2 + 1) * SS + s];
    float v0 = 2.0f * (float)j + off0;
    float v1 = 2.0f * (float)i + off1;
    float gh = 2.0f * v0 / 23.0f - 1.0f;
    float gw = 2.0f * v1 / 23.0f - 1.0f;
    float xs = ((gh + 1.0f) * 48.0f - 1.0f) * 0.5f;
    float ys = ((gw + 1.0f) * 48.0f - 1.0f) * 0.5f;
    float x0f = floorf(xs), y0f = floorf(ys);
    int x0 = (int)x0f, y0 = (int)y0f;
    float fx = xs - x0f, fy = ys - y0f;
    float wgt[4] = {(1.0f - fx) * (1.0f - fy), fx * (1.0f - fy),
                    (1.0f - fx) * fy, fx * fy};
    int xi[4] = {x0, x0 + 1, x0, x0 + 1};
    int yi[4] = {y0, y0, y0 + 1, y0 + 1};
    float wv[4];
    int id[4];
#pragma unroll
    for (int k = 0; k < 4; k++) {
        bool valid = (xi[k] >= 0) && (xi[k] < WWI) && (yi[k] >= 0) && (yi[k] < HHH);
        wv[k] = valid ? wgt[k] : 0.0f;
        int cy = min(max(yi[k], 0), HHH - 1);
        int cx = min(max(xi[k], 0), WWI - 1);
        id[k] = cy * WWI + cx;
    }
    int tsrc = (branch == 0) ? min(t + 1, TT - 1) : max(t - 1, 0);
#pragma unroll
    for (int u = 0; u < 4; u++) {
        int c = c4 * 4 + u;
        const float* img = g_x2 + c * THWSZ + tsrc * HWSZ;
        float val = wv[0] * img[id[0]] + wv[1] * img[id[1]] +
                    wv[2] * img[id[2]] + wv[3] * img[id[3]];
        unsigned short hs = f16_of(val);
        pb_sc_hi[branch][(t * SS + s) * CCH + c] = hs;
        pb_cs_hi[branch][(t * CCH + c) * SS + s] = hs;
    }
}

// ------- GEMM1-stats: single-pass fp16, both branches ---------------------------
__global__ void __launch_bounds__(256, 3) k_gemm1_stats() {
    extern __shared__ __align__(16) char sm[];
    char* A_hi = sm;
    char* B_hi = sm + A_TILE_B;
    float* red = (float*)(sm + A_TILE_B);
    int tid = threadIdx.x;
    int t = blockIdx.y, hw0 = blockIdx.x * 128, branch = blockIdx.z;

    {
        const uint4* sh = (const uint4*)&g_xt_hi[(size_t)(t * HWSZ + hw0) * 64];
#pragma unroll
        for (int v = 0; v < 4; v++) {
            int i = v * 256 + tid;
            int row = i >> 3, j = i & 7;
            *(uint4*)(A_hi + row * SA + j * 16) = sh[i];
        }
    }

    int wid = tid >> 5, lane = tid & 31;
    int wm = (wid & 3) * 32;
    int wn = (wid >> 2) * 32;
    uint32_t ah_u = smem_to_u32(A_hi);
    uint32_t bh_u = smem_to_u32(B_hi);
    int arow = lane & 15;
    int akoff = (lane >> 4) * 16;
    int brow = (lane & 7) + ((lane & 16) ? 8 : 0);
    int bkoff = ((lane >> 3) & 1) * 16;

    float s_sum[2][2] = {}, s_sq[2][2] = {};
    float s_mx[2][2] = {{-3.4e38f, -3.4e38f}, {-3.4e38f, -3.4e38f}};

    for (int kc = 0; kc < 9; kc++) {
        __syncthreads();
        {
            const uint4* bh = (const uint4*)&pb_sc_hi[branch][(size_t)(t * SS + kc * 64) * 64];
#pragma unroll
            for (int v = 0; v < 2; v++) {
                int i = v * 256 + tid;
                int row = i >> 3, j = i & 7;
                *(uint4*)(B_hi + row * SA + j * 16) = bh[i];
            }
        }
        __syncthreads();

        float d[2][4][4] = {};
#pragma unroll
        for (int ks = 0; ks < 4; ks++) {
            int kb = ks * 32;
            uint32_t Ah[2][4], Bh[4][2];
#pragma unroll
            for (int mt = 0; mt < 2; mt++) {
                uint32_t off = (uint32_t)((wm + mt * 16 + arow) * SA + kb + akoff);
                LDSM_X4(Ah[mt][0], Ah[mt][1], Ah[mt][2], Ah[mt][3], ah_u + off);
            }
#pragma unroll
            for (int np = 0; np < 2; np++) {
                uint32_t off = (uint32_t)((wn + np * 16 + brow) * SA + kb + bkoff);
                uint32_t r0, r1, r2, r3;
                LDSM_X4(r0, r1, r2, r3, bh_u + off);
                Bh[np * 2][0] = r0; Bh[np * 2][1] = r1;
                Bh[np * 2 + 1][0] = r2; Bh[np * 2 + 1][1] = r3;
            }
#pragma unroll
            for (int mt = 0; mt < 2; mt++)
#pragma unroll
                for (int nt = 0; nt < 4; nt++)
                    MMA_F16(d[mt][nt], Ah[mt], Bh[nt]);
        }
#pragma unroll
        for (int mt = 0; mt < 2; mt++)
#pragma unroll
            for (int nt = 0; nt < 4; nt++)
#pragma unroll
                for (int r = 0; r < 4; r++) {
                    int rh = (r >> 1) & 1;
                    float v = d[mt][nt][r];
                    s_sum[mt][rh] += v;
                    s_sq[mt][rh] = fmaf(v, v, s_sq[mt][rh]);
                    s_mx[mt][rh] = fmaxf(s_mx[mt][rh], v);
                }
    }

#pragma unroll
    for (int mt = 0; mt < 2; mt++)
#pragma unroll
        for (int rh = 0; rh < 2; rh++) {
            s_sum[mt][rh] += __shfl_xor_sync(0xFFFFFFFFu, s_sum[mt][rh], 1);
            s_sum[mt][rh] += __shfl_xor_sync(0xFFFFFFFFu, s_sum[mt][rh], 2);
            s_sq[mt][rh] += __shfl_xor_sync(0xFFFFFFFFu, s_sq[mt][rh], 1);
            s_sq[mt][rh] += __shfl_xor_sync(0xFFFFFFFFu, s_sq[mt][rh], 2);
            s_mx[mt][rh] = fmaxf(s_mx[mt][rh], __shfl_xor_sync(0xFFFFFFFFu, s_mx[mt][rh], 1));
            s_mx[mt][rh] = fmaxf(s_mx[mt][rh], __shfl_xor_sync(0xFFFFFFFFu, s_mx[mt][rh], 2));
        }
    __syncthreads();
    if ((lane & 3) == 0) {
        int nw = wid >> 2;
#pragma unroll
        for (int mt = 0; mt < 2; mt++)
#pragma unroll
            for (int rh = 0; rh < 2; rh++) {
                int m = wm + mt * 16 + (lane >> 2) + 8 * rh;
                float* p = &red[(nw * 128 + m) * 3];
                p[0] = s_sum[mt][rh];
                p[1] = s_sq[mt][rh];
                p[2] = s_mx[mt][rh];
            }
    }
    __syncthreads();
    if (tid < 128) {
        int m = tid;
        const float* p0 = &red[m * 3];
        const float* p1 = &red[(128 + m) * 3];
        float sum = p0[0] + p1[0];
        float sq = p0[1] + p1[1];
        float mx = fmaxf(p0[2], p1[2]);
        int o = t * HWSZ + hw0 + m;
        g_mean[branch][o] = sum / 576.0f;
        g_maxv[branch][o] = mx;
        g_varv[branch][o] = (sq - sum * sum / 576.0f) / 575.0f;
    }
}

// ---------------- attention gate (both branches) --------------------------------
__global__ void k_y(const float* __restrict__ w1, const float* __restrict__ w2) {
    int gidx = blockIdx.x * 256 + threadIdx.x;
    if (gidx >= 2 * TT * HWSZ) return;
    int branch = gidx / (TT * HWSZ);
    int idx = gidx % (TT * HWSZ);
    int t = idx / HWSZ;
    int hw = idx % HWSZ;
    int h = hw / WWI, w = hw % WWI;
    float acc = 0.0f;
#pragma unroll
    for (int dh = 0; dh < 3; dh++) {
        int hh = h + dh - 1;
        if (hh < 0 || hh >= HHH) continue;
#pragma unroll
        for (int dw = 0; dw < 3; dw++) {
            int ww = w + dw - 1;
            if (ww < 0 || ww >= WWI) continue;
            int p = t * HWSZ + hh * WWI + ww;
            acc = fmaf(w1[(0 * 3 + dh) * 3 + dw], g_mean[branch][p], acc);
            acc = fmaf(w1[(3 + dh) * 3 + dw], g_maxv[branch][p], acc);
            acc = fmaf(w2[dh * 3 + dw], g_varv[branch][p], acc);
        }
    }
    g_yv[branch][idx] = sigm(acc);
}

// ------- fused GEMM2: register-forwarded gate, 8mx1n warps ----------------------
// grid (18, 16, 2), 256 thr, smem 36.9KB.
__global__ void __launch_bounds__(256, 2) k_gemm2f(const float* __restrict__ w2s) {
    extern __shared__ __align__(16) char sm[];
    char* A1_hi = sm;                          // xt [128hw x 64c]
    char* B1_hi = sm + A_TILE_B;               // part_sc [64s x 64c]
    char* B2_hi = sm + A_TILE_B + B_TILE_B;    // part_cs [64c x 64s]
    int tid = threadIdx.x;
    int t = blockIdx.y, hw0 = blockIdx.x * 128, branch = blockIdx.z;

    {
        const uint4* sh = (const uint4*)&g_xt_hi[(size_t)(t * HWSZ + hw0) * 64];
#pragma unroll
        for (int v = 0; v < 4; v++) {
            int i = v * 256 + tid;
            int row = i >> 3, j = i & 7;
            *(uint4*)(A1_hi + row * SA + j * 16) = sh[i];
        }
    }

    int wid = tid >> 5, lane = tid & 31;
    int wm = wid * 16;  // 8 warps x 16 hw-rows each
    uint32_t a1h_u = smem_to_u32(A1_hi);
    uint32_t b1h_u = smem_to_u32(B1_hi);
    uint32_t b2h_u = smem_to_u32(B2_hi);
    int arow = lane & 15;
    int akoff = (lane >> 4) * 16;
    int brow = (lane & 7) + ((lane & 16) ? 8 : 0);
    int bkoff = ((lane >> 3) & 1) * 16;

    // gate y for this thread's two fragment rows (g, g+8), pre-scaled by 0.5
    float yv0 = 0.5f * g_yv[branch][t * HWSZ + hw0 + wm + (lane >> 2)];
    float yv1 = 0.5f * g_yv[branch][t * HWSZ + hw0 + wm + (lane >> 2) + 8];

    float d2[8][4];
#pragma unroll
    for (int nt = 0; nt < 8; nt++)
#pragma unroll
        for (int r = 0; r < 4; r++) d2[nt][r] = 0.0f;

    for (int kc = 0; kc < 9; kc++) {
        __syncthreads();
        {
            const uint4* bh = (const uint4*)&pb_sc_hi[branch][(size_t)(t * SS + kc * 64) * 64];
#pragma unroll
            for (int v = 0; v < 2; v++) {
                int i = v * 256 + tid;
                int row = i >> 3, j = i & 7;
                *(uint4*)(B1_hi + row * SA + j * 16) = bh[i];
            }
#pragma unroll
            for (int v = 0; v < 2; v++) {
                int i = v * 256 + tid;
                int row = i >> 3, j = i & 7;
                size_t src = (size_t)(t * CCH + row) * SS + kc * 64 + j * 8;
                *(uint4*)(B2_hi + row * SA + j * 16) = *(const uint4*)&pb_cs_hi[branch][src];
            }
        }
        __syncthreads();

        // mma1: d1[8 nt_s][4] = A1(16 hw x 64 c) x B1(64 s x 64 c)^T
        float d1[8][4];
#pragma unroll
        for (int nt = 0; nt < 8; nt++)
#pragma unroll
            for (int r = 0; r < 4; r++) d1[nt][r] = 0.0f;
#pragma unroll
        for (int ks = 0; ks < 4; ks++) {
            int kb = ks * 32;
            uint32_t Ah[4], Bh[8][2];
            LDSM_X4(Ah[0], Ah[1], Ah[2], Ah[3],
                    a1h_u + (uint32_t)((wm + arow) * SA + kb + akoff));
#pragma unroll
            for (int np = 0; np < 4; np++) {
                uint32_t r0, r1, r2, r3;
                LDSM_X4(r0, r1, r2, r3,
                        b1h_u + (uint32_t)((np * 16 + brow) * SA + kb + bkoff));
                Bh[np * 2][0] = r0; Bh[np * 2][1] = r1;
                Bh[np * 2 + 1][0] = r2; Bh[np * 2 + 1][1] = r3;
            }
#pragma unroll
            for (int nt = 0; nt < 8; nt++)
                MMA_F16(d1[nt], Ah, Bh[nt]);
        }

        // gate d1 in registers -> A2 fragments, feed mma2 directly
#pragma unroll
        for (int ks2 = 0; ks2 < 4; ks2++) {
            uint32_t Af[4];
            {
                float t0, t1;
                TANH_APPROX(t0, yv0 * d1[2 * ks2][0]);
                TANH_APPROX(t1, yv0 * d1[2 * ks2][1]);
                Af[0] = (uint32_t)f16_of(0.5f * t0) | ((uint32_t)f16_of(0.5f * t1) << 16);
                TANH_APPROX(t0, yv1 * d1[2 * ks2][2]);
                TANH_APPROX(t1, yv1 * d1[2 * ks2][3]);
                Af[1] = (uint32_t)f16_of(0.5f * t0) | ((uint32_t)f16_of(0.5f * t1) << 16);
                TANH_APPROX(t0, yv0 * d1[2 * ks2 + 1][0]);
                TANH_APPROX(t1, yv0 * d1[2 * ks2 + 1][1]);
                Af[2] = (uint32_t)f16_of(0.5f * t0) | ((uint32_t)f16_of(0.5f * t1) << 16);
                TANH_APPROX(t0, yv1 * d1[2 * ks2 + 1][2]);
                TANH_APPROX(t1, yv1 * d1[2 * ks2 + 1][3]);
                Af[3] = (uint32_t)f16_of(0.5f * t0) | ((uint32_t)f16_of(0.5f * t1) << 16);
            }
            uint32_t Bh2[8][2];
#pragma unroll
            for (int np = 0; np < 4; np++) {
                uint32_t r0, r1, r2, r3;
                LDSM_X4(r0, r1, r2, r3,
                        b2h_u + (uint32_t)((np * 16 + brow) * SA + ks2 * 32 + bkoff));
                Bh2[np * 2][0] = r0; Bh2[np * 2][1] = r1;
                Bh2[np * 2 + 1][0] = r2; Bh2[np * 2 + 1][1] = r3;
            }
#pragma unroll
            for (int nt = 0; nt < 8; nt++)
                MMA_F16(d2[nt], Af, Bh2[nt]);
        }
    }

    // stage + scaled store
    __syncthreads();
    float* stage = (float*)sm;
#pragma unroll
    for (int nt = 0; nt < 8; nt++)
#pragma unroll
        for (int r = 0; r < 4; r++) {
            int m = wm + (lane >> 2) + ((r >> 1) & 1) * 8;
            int n = nt * 8 + (lane & 3) * 2 + (r & 1);
            stage[m * STG + n] = d2[nt][r];
        }
    __syncthreads();
    float wscale = w2s[branch];
    int row = tid >> 1, half = tid & 1;
    const float* srow = &stage[row * STG + half * 32];
    float* dst = &g_featb[branch][((size_t)t * HWSZ + hw0 + row) * CCH + half * 32];
#pragma unroll
    for (int q = 0; q < 8; q++) {
        float4 b = *(const float4*)&srow[q * 4];
        float4 o4 = make_float4(b.x * wscale, b.y * wscale, b.z * wscale, b.w * wscale);
        *(float4*)&dst[q * 4] = o4;
    }
}

// ---------------- xd = w_down @ x (one thread per pos, 4 outputs) ---------------
__global__ void k_xd(const float* __restrict__ x, const float* __restrict__ wd) {
    int pos = blockIdx.x * blockDim.x + threadIdx.x;
    if (pos >= THWSZ) return;
    float a0 = 0.0f, a1 = 0.0f, a2 = 0.0f, a3 = 0.0f;
    for (int c = 0; c < CCH; c++) {
        float v = x[c * THWSZ + pos];
        a0 = fmaf(wd[c], v, a0);
        a1 = fmaf(wd[CCH + c], v, a1);
        a2 = fmaf(wd[2 * CCH + c], v, a2);
        a3 = fmaf(wd[3 * CCH + c], v, a3);
    }
    g_xd[pos] = a0;
    g_xd[THWSZ + pos] = a1;
    g_xd[2 * THWSZ + pos] = a2;
    g_xd[3 * THWSZ + pos] = a3;
}

// ---------------- 3x depthwise 3D convs ------------------------------------------
__global__ void k_agg(const float* __restrict__ w1, const float* __restrict__ b1,
                      const float* __restrict__ w2, const float* __restrict__ b2,
                      const float* __restrict__ w3, const float* __restrict__ b3,
                      const float* __restrict__ wts) {
    int idx = blockIdx.x * blockDim.x + threadIdx.x;
    if (idx >= RCC * THWSZ) return;
    int r = idx / THWSZ;
    int rem = idx % THWSZ;
    int t = rem / HWSZ;
    int hw = rem % HWSZ;
    int h = hw / WWI, w = hw % WWI;
    const float* xb = g_xd + r * THWSZ;
    const float* ws_[3] = {w1, w2, w3};
    const float* bs_[3] = {b1, b2, b3};
    float total = 0.0f;
#pragma unroll
    for (int m = 0; m < 3; m++) {
        int d = m + 1;
        float cs = bs_[m][r];
        const float* wp = ws_[m] + r * 81;
        for (int kt = 0; kt < 9; kt++) {
            int ti = t + kt - 4;
            if (ti < 0 || ti >= TT) continue;
#pragma unroll
            for (int kh = 0; kh < 3; kh++) {
                int hi = h + (kh - 1) * d;
                if (hi < 0 || hi >= HHH) continue;
#pragma unroll
                for (int kw = 0; kw < 3; kw++) {
                    int wi = w + (kw - 1) * d;
                    if (wi < 0 || wi >= WWI) continue;
                    cs = fmaf(xb[ti * HWSZ + hi * WWI + wi], wp[(kt * 3 + kh) * 3 + kw], cs);
                }
            }
        }
        total = fmaf(wts[m], cs, total);
    }
    g_agg[idx] = total;
}

// ---------------- final ----------------------------------------------------------
__global__ void k_final(float* __restrict__ out, const float* __restrict__ wback) {
    int pos = blockIdx.x * 256 + threadIdx.x;
    if (pos >= THWSZ) return;
    float ag0 = g_agg[pos];
    float ag1 = g_agg[THWSZ + pos];
    float ag2 = g_agg[2 * THWSZ + pos];
    float ag3 = g_agg[3 * THWSZ + pos];
    const float4* f0 = (const float4*)&g_featb[0][(size_t)pos * CCH];
    const float4* f1 = (const float4*)&g_featb[1][(size_t)pos * CCH];
#pragma unroll
    for (int c4 = 0; c4 < 16; c4++) {
        float4 a = f0[c4];
        float4 b = f1[c4];
        float fv[4] = {a.x + b.x, a.y + b.y, a.z + b.z, a.w + b.w};
#pragma unroll
        for (int u = 0; u < 4; u++) {
            int c = c4 * 4 + u;
            float z = wback[c * 4 + 0] * ag0 + wback[c * 4 + 1] * ag1 +
                      wback[c * 4 + 2] * ag2 + wback[c * 4 + 3] * ag3;
            out[c * THWSZ + pos] = fv[u] * (sigm(z) - 0.5f);
        }
    }
}

extern "C" void kernel_launch(void* const* d_in, const int* in_sizes, int n_in,
                              void* d_out, int out_size) {
    const float* x       = (const float*)d_in[0];
    const float* w_dc2   = (const float*)d_in[1];
    const float* w_ofs_l = (const float*)d_in[2];
    const float* b_ofs_l = (const float*)d_in[3];
    const float* w_ofs_r = (const float*)d_in[4];
    const float* b_ofs_r = (const float*)d_in[5];
    const float* ca_w1   = (const float*)d_in[6];
    const float* ca_w2   = (const float*)d_in[7];
    const float* w_down  = (const float*)d_in[8];
    const float* sa1_w   = (const float*)d_in[9];
    const float* sa1_b   = (const float*)d_in[10];
    const float* sa2_w   = (const float*)d_in[11];
    const float* sa2_b   = (const float*)d_in[12];
    const float* sa3_w   = (const float*)d_in[13];
    const float* sa3_b   = (const float*)d_in[14];
    const float* weights = (const float*)d_in[15];
    const float* weights2= (const float*)d_in[16];
    const float* w_back  = (const float*)d_in[17];
    float* out = (float*)d_out;

    static cudaStream_t s2 = 0;
    static cudaEvent_t evFork = 0, evAGG = 0;
    if (s2 == 0) {
        cudaStreamCreateWithFlags(&s2, cudaStreamNonBlocking);
        cudaEventCreateWithFlags(&evFork, cudaEventDisableTiming);
        cudaEventCreateWithFlags(&evAGG, cudaEventDisableTiming);
        cudaFuncSetAttribute(k_x2m, cudaFuncAttributeMaxDynamicSharedMemorySize, SM0_TOT);
        cudaFuncSetAttribute(k_gemm1_stats, cudaFuncAttributeMaxDynamicSharedMemorySize, SM1_TOT);
        cudaFuncSetAttribute(k_gemm2f, cudaFuncAttributeMaxDynamicSharedMemorySize, SM2_TOT);
    }

    // fork side stream (xd/agg depend only on x)
    cudaEventRecord(evFork, 0);
    cudaStreamWaitEvent(s2, evFork, 0);
    k_xd<<<(THWSZ + 255) / 256, 256, 0, s2>>>(x, w_down);
    k_agg<<<(RCC * THWSZ + 255) / 256, 256, 0, s2>>>(sa1_w, sa1_b, sa2_w, sa2_b, sa3_w, sa3_b, weights);
    cudaEventRecord(evAGG, s2);

    // main stream
    k_xt<<<(THWSZ + 255) / 256, 256>>>(x);
    k_x2m<<<THWSZ / 128, 256, SM0_TOT>>>(w_dc2);
    k_offp<<<(NCC * 2 * TT * SS) / 256, 256>>>(x, w_ofs_l, w_ofs_r);
    k_offred<<<(2 * TT * 2 * SS + 255) / 256, 256>>>(b_ofs_l, b_ofs_r);
    k_sample<<<(2 * TT * 16 * SS) / 256, 256>>>();

    dim3 gg(HWSZ / 128, TT, 2);
    k_gemm1_stats<<<gg, 256, SM1_TOT>>>();
    k_y<<<(2 * TT * HWSZ + 255) / 256, 256>>>(ca_w1, ca_w2);
    k_gemm2f<<<gg, 256, SM2_TOT>>>(weights2);

    cudaStreamWaitEvent(0, evAGG, 0);  // k_final needs g_agg
    k_final<<<(THWSZ + 255) / 256, 256>>>(out, w_back);
}